// round 1
// baseline (speedup 1.0000x reference)
#include <cuda_runtime.h>
#include <math.h>
#include <stdint.h>

// ---------------- problem constants ----------------
constexpr int NN   = 65536;          // nodes
constexpr int NE   = 524288;         // raw edges
constexpr int ET   = NE + NN;        // edges + self loops = 589824
constexpr int GS   = 512;            // graph size
constexpr int NG   = NN / GS;        // 128 graphs
constexpr int D1   = 256;            // heads*hid
constexpr int D3   = 128;            // out dim

// ---------------- device scratch (static, no allocs) ----------------
// float scratch partition (floats):
constexpr size_t OFF_H    = 0;                       // 65536*256
constexpr size_t OFF_T    = OFF_H    + (size_t)NN*D1;
constexpr size_t OFF_H3   = OFF_T    + (size_t)NN*D1; // 65536*128
constexpr size_t OFF_R    = OFF_H3   + (size_t)NN*D3;
constexpr size_t OFF_HRES = OFF_R    + (size_t)NN*D3;
constexpr size_t OFF_Q    = OFF_HRES + (size_t)NN*D3;
constexpr size_t OFF_K    = OFF_Q    + (size_t)NN*D3;
constexpr size_t OFF_V    = OFF_K    + (size_t)NN*D3;
constexpr size_t OFF_S    = OFF_V    + (size_t)NN*D3; // 512 * 512*512
constexpr size_t OFF_ES   = OFF_S    + (size_t)NG*4*GS*GS;
constexpr size_t OFF_ED   = OFF_ES   + (size_t)NN*4;
constexpr size_t SCRATCH  = OFF_ED   + (size_t)NN*4;

__device__ __align__(256) float g_scratch[SCRATCH];

__device__ int g_rowptr[NN + 1];
__device__ int g_cnt[NN];
__device__ int g_cursor[NN];
__device__ int g_col[ET];

// ---------------- CSR build ----------------
__global__ void k_zero_cnt() {
    int i = blockIdx.x * blockDim.x + threadIdx.x;
    if (i < NN) g_cnt[i] = 0;
}

__global__ void k_count(const int* __restrict__ ei) {
    int stride = gridDim.x * blockDim.x;
    for (int idx = blockIdx.x * blockDim.x + threadIdx.x; idx < NE; idx += stride)
        atomicAdd(&g_cnt[ei[NE + idx]], 1);
}

// single-block exclusive scan of (cnt[i]+1)  -> rowptr, cursor
__global__ void k_scan() {
    __shared__ int warpsum[32];
    __shared__ int s_carry;
    int tid  = threadIdx.x;
    int lane = tid & 31, wid = tid >> 5;
    if (tid == 0) s_carry = 0;
    __syncthreads();
    for (int base = 0; base < NN; base += 1024) {
        int v = g_cnt[base + tid] + 1;   // +1 self loop
        int x = v;
        #pragma unroll
        for (int o = 1; o < 32; o <<= 1) {
            int t = __shfl_up_sync(0xffffffffu, x, o);
            if (lane >= o) x += t;
        }
        if (lane == 31) warpsum[wid] = x;
        __syncthreads();
        if (wid == 0) {
            int w = warpsum[lane];
            #pragma unroll
            for (int o = 1; o < 32; o <<= 1) {
                int t = __shfl_up_sync(0xffffffffu, w, o);
                if (lane >= o) w += t;
            }
            warpsum[lane] = w;
        }
        __syncthreads();
        int excl = (x - v) + (wid > 0 ? warpsum[wid - 1] : 0) + s_carry;
        g_rowptr[base + tid] = excl;
        g_cursor[base + tid] = excl;
        __syncthreads();
        if (tid == 1023) s_carry = excl + v;
        __syncthreads();
    }
    if (tid == 0) g_rowptr[NN] = ET;
}

__global__ void k_fill(const int* __restrict__ ei) {
    int stride = gridDim.x * blockDim.x;
    for (int idx = blockIdx.x * blockDim.x + threadIdx.x; idx < ET; idx += stride) {
        int s, d;
        if (idx < NE) { s = ei[idx]; d = ei[NE + idx]; }
        else          { s = d = idx - NE; }
        int pos = atomicAdd(&g_cursor[d], 1);
        g_col[pos] = s;
    }
}

// ---------------- generic SGEMM: C[M,N] = A[M,K] @ B[K,N] (+bias) ----------------
// 128x128 block tile, BK=8, 256 threads, 8x8 micro-tile. M%128==0, N%128==0, K%8==0.
__global__ __launch_bounds__(256) void sgemm128(
    const float* __restrict__ A, const float* __restrict__ B,
    const float* __restrict__ bias, float* __restrict__ C,
    int M, int N, int K)
{
    __shared__ float As[8][132];
    __shared__ float Bs[8][128];
    int tid = threadIdx.x;
    int bm = blockIdx.y, bn = blockIdx.x;
    const float* Ab = A + (size_t)bm * 128 * K;
    const float* Bb = B + (size_t)bn * 128;
    int arow = tid >> 1, ak = (tid & 1) * 4;
    int brow = tid >> 5, bcol = (tid & 31) * 4;
    int tx = tid & 15, ty = tid >> 4;
    float acc[8][8];
    #pragma unroll
    for (int i = 0; i < 8; i++)
        #pragma unroll
        for (int j = 0; j < 8; j++) acc[i][j] = 0.f;

    for (int k0 = 0; k0 < K; k0 += 8) {
        float4 av = *(const float4*)(Ab + (size_t)arow * K + k0 + ak);
        As[ak + 0][arow] = av.x; As[ak + 1][arow] = av.y;
        As[ak + 2][arow] = av.z; As[ak + 3][arow] = av.w;
        float4 bv = *(const float4*)(Bb + (size_t)(k0 + brow) * N + bcol);
        *(float4*)&Bs[brow][bcol] = bv;
        __syncthreads();
        #pragma unroll
        for (int k = 0; k < 8; k++) {
            float a[8], b[8];
            *(float4*)(a)     = *(const float4*)&As[k][ty * 8];
            *(float4*)(a + 4) = *(const float4*)&As[k][ty * 8 + 4];
            *(float4*)(b)     = *(const float4*)&Bs[k][tx * 8];
            *(float4*)(b + 4) = *(const float4*)&Bs[k][tx * 8 + 4];
            #pragma unroll
            for (int i = 0; i < 8; i++)
                #pragma unroll
                for (int j = 0; j < 8; j++)
                    acc[i][j] += a[i] * b[j];
        }
        __syncthreads();
    }
    float bi[8];
    #pragma unroll
    for (int j = 0; j < 8; j++)
        bi[j] = bias ? bias[bn * 128 + tx * 8 + j] : 0.f;
    #pragma unroll
    for (int i = 0; i < 8; i++) {
        size_t row = (size_t)bm * 128 + ty * 8 + i;
        float4 o0 = make_float4(acc[i][0] + bi[0], acc[i][1] + bi[1],
                                acc[i][2] + bi[2], acc[i][3] + bi[3]);
        float4 o1 = make_float4(acc[i][4] + bi[4], acc[i][5] + bi[5],
                                acc[i][6] + bi[6], acc[i][7] + bi[7]);
        *(float4*)(C + row * N + bn * 128 + tx * 8)     = o0;
        *(float4*)(C + row * N + bn * 128 + tx * 8 + 4) = o1;
    }
}

// ---------------- attention-score vectors: es/ed per (node, head) ----------------
__global__ void k_scores(const float* __restrict__ h, const float* __restrict__ as_,
                         const float* __restrict__ ad_, float* __restrict__ es,
                         float* __restrict__ ed, int H, int C)
{
    int idx = blockIdx.x * blockDim.x + threadIdx.x;
    if (idx >= NN * H) return;
    int node = idx / H, hd = idx % H;
    const float4* hp = (const float4*)(h + (size_t)node * H * C + (size_t)hd * C);
    const float4* ap = (const float4*)(as_ + (size_t)hd * C);
    const float4* bp = (const float4*)(ad_ + (size_t)hd * C);
    float s = 0.f, d = 0.f;
    for (int c = 0; c < C / 4; c++) {
        float4 hv = hp[c], av = ap[c], bv = bp[c];
        s += hv.x * av.x + hv.y * av.y + hv.z * av.z + hv.w * av.w;
        d += hv.x * bv.x + hv.y * bv.y + hv.z * bv.z + hv.w * bv.w;
    }
    es[idx] = s;
    ed[idx] = d;
}

// ---------------- GAT aggregation, warp per node, fused bias(+resid)(+elu+LN) ----------------
template <int D, int H>
__global__ __launch_bounds__(256) void k_gat_agg(
    const float* __restrict__ hfeat, const float* __restrict__ es,
    const float* __restrict__ ed, const float* __restrict__ bias,
    const float* __restrict__ gamma, const float* __restrict__ beta,
    const float* __restrict__ resid, float* __restrict__ out)
{
    constexpr int C = D / H;
    constexpr int R = D / 32;
    int warp = (blockIdx.x * blockDim.x + threadIdx.x) >> 5;
    int lane = threadIdx.x & 31;
    if (warp >= NN) return;
    int i = warp;
    int beg = g_rowptr[i], end = g_rowptr[i + 1];

    float edv[H], m[H], z[H];
    #pragma unroll
    for (int h = 0; h < H; h++) {
        edv[h] = ed[(size_t)i * H + h];
        m[h] = -1e30f; z[h] = 0.f;
    }
    // pass 1: per-head max over in-edges
    for (int e = beg + lane; e < end; e += 32) {
        int s = g_col[e];
        #pragma unroll
        for (int h = 0; h < H; h++) {
            float v = es[(size_t)s * H + h] + edv[h];
            v = v > 0.f ? v : 0.2f * v;
            m[h] = fmaxf(m[h], v);
        }
    }
    #pragma unroll
    for (int h = 0; h < H; h++)
        #pragma unroll
        for (int o = 16; o; o >>= 1)
            m[h] = fmaxf(m[h], __shfl_xor_sync(0xffffffffu, m[h], o));
    // pass 2: partition function
    for (int e = beg + lane; e < end; e += 32) {
        int s = g_col[e];
        #pragma unroll
        for (int h = 0; h < H; h++) {
            float v = es[(size_t)s * H + h] + edv[h];
            v = v > 0.f ? v : 0.2f * v;
            z[h] += expf(v - m[h]);
        }
    }
    #pragma unroll
    for (int h = 0; h < H; h++) {
        #pragma unroll
        for (int o = 16; o; o >>= 1)
            z[h] += __shfl_xor_sync(0xffffffffu, z[h], o);
        z[h] = 1.f / (z[h] + 1e-16f);
    }
    // pass 3: weighted feature aggregation (all lanes cooperate per edge)
    float acc[R];
    #pragma unroll
    for (int j = 0; j < R; j++) acc[j] = 0.f;
    for (int e = beg; e < end; e++) {
        int s = g_col[e];
        float al[H];
        #pragma unroll
        for (int h = 0; h < H; h++) {
            float v = es[(size_t)s * H + h] + edv[h];
            v = v > 0.f ? v : 0.2f * v;
            al[h] = expf(v - m[h]);
        }
        const float* hs = hfeat + (size_t)s * D;
        #pragma unroll
        for (int j = 0; j < R; j++) {
            int c = lane + 32 * j;
            acc[j] += al[(32 * j) / C] * hs[c];
        }
    }
    // epilogue
    float x[R];
    #pragma unroll
    for (int j = 0; j < R; j++) {
        int c = lane + 32 * j;
        float val = acc[j] * z[(32 * j) / C] + bias[c];
        if (resid) val += resid[(size_t)i * D + c];
        x[j] = val;
    }
    if (gamma) {
        #pragma unroll
        for (int j = 0; j < R; j++)
            x[j] = x[j] > 0.f ? x[j] : (expf(x[j]) - 1.f);   // ELU
        float s = 0.f;
        #pragma unroll
        for (int j = 0; j < R; j++) s += x[j];
        #pragma unroll
        for (int o = 16; o; o >>= 1) s += __shfl_xor_sync(0xffffffffu, s, o);
        float mu = s / (float)D;
        float vs = 0.f;
        #pragma unroll
        for (int j = 0; j < R; j++) { float d = x[j] - mu; vs += d * d; }
        #pragma unroll
        for (int o = 16; o; o >>= 1) vs += __shfl_xor_sync(0xffffffffu, vs, o);
        float inv = rsqrtf(vs / (float)D + 1e-5f);
        #pragma unroll
        for (int j = 0; j < R; j++) {
            int c = lane + 32 * j;
            x[j] = (x[j] - mu) * inv * gamma[c] + beta[c];
        }
    }
    #pragma unroll
    for (int j = 0; j < R; j++)
        out[(size_t)i * D + lane + 32 * j] = x[j];
}

// ---------------- MHA: S = Q K^T * scale (per graph-head) ----------------
// grid (4,4,512): 128x128 output tile, K=32 fully resident.
__global__ __launch_bounds__(256) void k_qkT(const float* __restrict__ q,
                                             const float* __restrict__ kk,
                                             float* __restrict__ S)
{
    int gh = blockIdx.z, g = gh >> 2, h = gh & 3;
    __shared__ float Qs[32][132];
    __shared__ float Ks[32][132];
    int tid = threadIdx.x;
    const float* qb = q  + ((size_t)g * GS + blockIdx.y * 128) * 128 + h * 32;
    const float* kb = kk + ((size_t)g * GS + blockIdx.x * 128) * 128 + h * 32;
    #pragma unroll
    for (int r = 0; r < 4; r++) {
        int idx = tid + r * 256;
        int row = idx >> 3, k4 = (idx & 7) * 4;
        float4 v = *(const float4*)(qb + (size_t)row * 128 + k4);
        Qs[k4 + 0][row] = v.x; Qs[k4 + 1][row] = v.y;
        Qs[k4 + 2][row] = v.z; Qs[k4 + 3][row] = v.w;
        float4 w = *(const float4*)(kb + (size_t)row * 128 + k4);
        Ks[k4 + 0][row] = w.x; Ks[k4 + 1][row] = w.y;
        Ks[k4 + 2][row] = w.z; Ks[k4 + 3][row] = w.w;
    }
    __syncthreads();
    int tx = tid & 15, ty = tid >> 4;
    float acc[8][8];
    #pragma unroll
    for (int i = 0; i < 8; i++)
        #pragma unroll
        for (int j = 0; j < 8; j++) acc[i][j] = 0.f;
    #pragma unroll
    for (int k = 0; k < 32; k++) {
        float a[8], b[8];
        *(float4*)(a)     = *(const float4*)&Qs[k][ty * 8];
        *(float4*)(a + 4) = *(const float4*)&Qs[k][ty * 8 + 4];
        *(float4*)(b)     = *(const float4*)&Ks[k][tx * 8];
        *(float4*)(b + 4) = *(const float4*)&Ks[k][tx * 8 + 4];
        #pragma unroll
        for (int i = 0; i < 8; i++)
            #pragma unroll
            for (int j = 0; j < 8; j++)
                acc[i][j] += a[i] * b[j];
    }
    const float scale = 0.088388347648318447f;   // 1/sqrt(128)
    float* ob = S + (size_t)gh * GS * GS + (size_t)(blockIdx.y * 128) * GS + blockIdx.x * 128;
    #pragma unroll
    for (int i = 0; i < 8; i++) {
        int row = ty * 8 + i;
        float4 o0 = make_float4(acc[i][0]*scale, acc[i][1]*scale, acc[i][2]*scale, acc[i][3]*scale);
        float4 o1 = make_float4(acc[i][4]*scale, acc[i][5]*scale, acc[i][6]*scale, acc[i][7]*scale);
        *(float4*)(ob + (size_t)row * GS + tx * 8)     = o0;
        *(float4*)(ob + (size_t)row * GS + tx * 8 + 4) = o1;
    }
}

// ---------------- rowwise softmax over S (rows of 512) ----------------
__global__ void k_softmax(float* __restrict__ S) {
    int r = (blockIdx.x * blockDim.x + threadIdx.x) >> 5;  // warp per row
    int lane = threadIdx.x & 31;
    float4* row = (float4*)(S + (size_t)r * GS);
    float v[16];
    #pragma unroll
    for (int p = 0; p < 4; p++) {
        float4 t = row[lane + 32 * p];
        v[p * 4 + 0] = t.x; v[p * 4 + 1] = t.y; v[p * 4 + 2] = t.z; v[p * 4 + 3] = t.w;
    }
    float m = -1e30f;
    #pragma unroll
    for (int j = 0; j < 16; j++) m = fmaxf(m, v[j]);
    #pragma unroll
    for (int o = 16; o; o >>= 1) m = fmaxf(m, __shfl_xor_sync(0xffffffffu, m, o));
    float s = 0.f;
    #pragma unroll
    for (int j = 0; j < 16; j++) { v[j] = expf(v[j] - m); s += v[j]; }
    #pragma unroll
    for (int o = 16; o; o >>= 1) s += __shfl_xor_sync(0xffffffffu, s, o);
    float inv = 1.f / s;
    #pragma unroll
    for (int p = 0; p < 4; p++) {
        float4 t = make_float4(v[p*4]*inv, v[p*4+1]*inv, v[p*4+2]*inv, v[p*4+3]*inv);
        row[lane + 32 * p] = t;
    }
}

// ---------------- O = P @ V per graph-head ----------------
// grid (2, 512): 256-row x 32-col tile, BK=16, 256 threads, 8x4 micro-tile.
__global__ __launch_bounds__(256) void k_pv(const float* __restrict__ S,
                                            const float* __restrict__ v,
                                            float* __restrict__ out)
{
    int gh = blockIdx.y, g = gh >> 2, h = gh & 3;
    const float* P  = S + (size_t)gh * GS * GS + (size_t)blockIdx.x * 256 * GS;
    const float* vb = v + (size_t)g * GS * 128 + h * 32;
    __shared__ float Ps[16][260];
    __shared__ float Vs[16][32];
    int tid = threadIdx.x;
    int tx = tid & 7;    // cols tx*4..+3
    int ty = tid >> 3;   // rows ty*8..+7
    float acc[8][4];
    #pragma unroll
    for (int i = 0; i < 8; i++)
        #pragma unroll
        for (int j = 0; j < 4; j++) acc[i][j] = 0.f;

    for (int k0 = 0; k0 < GS; k0 += 16) {
        #pragma unroll
        for (int r = 0; r < 4; r++) {
            int idx = tid + r * 256;
            int row = idx >> 2, k4 = (idx & 3) * 4;
            float4 pv = *(const float4*)(P + (size_t)row * GS + k0 + k4);
            Ps[k4 + 0][row] = pv.x; Ps[k4 + 1][row] = pv.y;
            Ps[k4 + 2][row] = pv.z; Ps[k4 + 3][row] = pv.w;
        }
        if (tid < 128) {
            int row = tid >> 3, c4 = (tid & 7) * 4;
            float4 vv = *(const float4*)(vb + (size_t)(k0 + row) * 128 + c4);
            *(float4*)&Vs[row][c4] = vv;
        }
        __syncthreads();
        #pragma unroll
        for (int k = 0; k < 16; k++) {
            float b[4], a[8];
            *(float4*)b       = *(const float4*)&Vs[k][tx * 4];
            *(float4*)(a)     = *(const float4*)&Ps[k][ty * 8];
            *(float4*)(a + 4) = *(const float4*)&Ps[k][ty * 8 + 4];
            #pragma unroll
            for (int i = 0; i < 8; i++)
                #pragma unroll
                for (int j = 0; j < 4; j++)
                    acc[i][j] += a[i] * b[j];
        }
        __syncthreads();
    }
    float* ob = out + ((size_t)g * GS + blockIdx.x * 256) * 128 + h * 32;
    #pragma unroll
    for (int i = 0; i < 8; i++) {
        int row = ty * 8 + i;
        *(float4*)(ob + (size_t)row * 128 + tx * 4) =
            make_float4(acc[i][0], acc[i][1], acc[i][2], acc[i][3]);
    }
}

// ---------------- host orchestration ----------------
extern "C" void kernel_launch(void* const* d_in, const int* in_sizes, int n_in,
                              void* d_out, int out_size)
{
    const float* x   = (const float*)d_in[0];
    const int*   ei  = (const int*)  d_in[1];
    const float* W1  = (const float*)d_in[3];
    const float* a1s = (const float*)d_in[4];
    const float* a1d = (const float*)d_in[5];
    const float* b1  = (const float*)d_in[6];
    const float* W2  = (const float*)d_in[7];
    const float* a2s = (const float*)d_in[8];
    const float* a2d = (const float*)d_in[9];
    const float* b2  = (const float*)d_in[10];
    const float* W3  = (const float*)d_in[11];
    const float* a3s = (const float*)d_in[12];
    const float* a3d = (const float*)d_in[13];
    const float* b3  = (const float*)d_in[14];
    const float* g1  = (const float*)d_in[15];
    const float* be1 = (const float*)d_in[16];
    const float* g2  = (const float*)d_in[17];
    const float* be2 = (const float*)d_in[18];
    const float* Wr  = (const float*)d_in[19];
    const float* br  = (const float*)d_in[20];
    const float* Wq  = (const float*)d_in[21];
    const float* Wk  = (const float*)d_in[22];
    const float* Wv  = (const float*)d_in[23];
    const float* Wo  = (const float*)d_in[24];
    const float* bo  = (const float*)d_in[25];
    float* out = (float*)d_out;

    float* sb = nullptr;
    cudaGetSymbolAddress((void**)&sb, g_scratch);
    float* p_h    = sb + OFF_H;
    float* p_t    = sb + OFF_T;
    float* p_h3   = sb + OFF_H3;
    float* p_r    = sb + OFF_R;
    float* p_hres = sb + OFF_HRES;
    float* p_q    = sb + OFF_Q;
    float* p_k    = sb + OFF_K;
    float* p_v    = sb + OFF_V;
    float* p_S    = sb + OFF_S;
    float* p_es   = sb + OFF_ES;
    float* p_ed   = sb + OFF_ED;

    // CSR build (dst-sorted adjacency incl. self loops)
    k_zero_cnt<<<NN / 256, 256>>>();
    k_count<<<1024, 256>>>(ei);
    k_scan<<<1, 1024>>>();
    k_fill<<<1152, 256>>>(ei);

    // layer 1
    sgemm128<<<dim3(2, 512), 256>>>(x, W1, nullptr, p_h, NN, 256, 64);
    k_scores<<<(NN * 4) / 256, 256>>>(p_h, a1s, a1d, p_es, p_ed, 4, 64);
    k_gat_agg<256, 4><<<NN / 8, 256>>>(p_h, p_es, p_ed, b1, g1, be1, nullptr, p_t);
    // layer 2
    sgemm128<<<dim3(2, 512), 256>>>(p_t, W2, nullptr, p_h, NN, 256, 256);
    k_scores<<<(NN * 4) / 256, 256>>>(p_h, a2s, a2d, p_es, p_ed, 4, 64);
    k_gat_agg<256, 4><<<NN / 8, 256>>>(p_h, p_es, p_ed, b2, g2, be2, nullptr, p_t);
    // layer 3 + residual
    sgemm128<<<dim3(1, 512), 256>>>(p_t, W3, nullptr, p_h3, NN, 128, 256);
    k_scores<<<NN / 256, 256>>>(p_h3, a3s, a3d, p_es, p_ed, 1, 128);
    sgemm128<<<dim3(1, 512), 256>>>(x, Wr, br, p_r, NN, 128, 64);
    k_gat_agg<128, 1><<<NN / 8, 256>>>(p_h3, p_es, p_ed, b3, nullptr, nullptr, p_r, p_hres);
    // MHA
    sgemm128<<<dim3(1, 512), 256>>>(p_hres, Wq, nullptr, p_q, NN, 128, 128);
    sgemm128<<<dim3(1, 512), 256>>>(p_hres, Wk, nullptr, p_k, NN, 128, 128);
    sgemm128<<<dim3(1, 512), 256>>>(p_hres, Wv, nullptr, p_v, NN, 128, 128);
    k_qkT<<<dim3(4, 4, NG * 4), 256>>>(p_q, p_k, p_S);
    k_softmax<<<(NG * 4 * GS) / 8, 256>>>(p_S);
    k_pv<<<dim3(2, NG * 4), 256>>>(p_S, p_v, p_h3);
    sgemm128<<<dim3(1, 512), 256>>>(p_h3, Wo, bo, out, NN, 128, 128);
}

// round 3
// speedup vs baseline: 1.1239x; 1.1239x over previous
#include <cuda_runtime.h>
#include <cuda_bf16.h>
#include <math.h>
#include <stdint.h>

// ---------------- problem constants ----------------
constexpr int NN   = 65536;          // nodes
constexpr int NE   = 524288;         // raw edges
constexpr int ET   = NE + NN;        // edges + self loops
constexpr int GS   = 512;            // graph size
constexpr int NG   = NN / GS;        // 128 graphs
constexpr int D1   = 256;            // heads*hid
constexpr int D3   = 128;            // out dim

// ---------------- fp32 scratch ----------------
constexpr size_t OFF_H    = 0;
constexpr size_t OFF_T    = OFF_H    + (size_t)NN*D1;
constexpr size_t OFF_H3   = OFF_T    + (size_t)NN*D1;
constexpr size_t OFF_R    = OFF_H3   + (size_t)NN*D3;
constexpr size_t OFF_HRES = OFF_R    + (size_t)NN*D3;
constexpr size_t OFF_Q    = OFF_HRES + (size_t)NN*D3;
constexpr size_t OFF_K    = OFF_Q    + (size_t)NN*D3;
constexpr size_t OFF_V    = OFF_K    + (size_t)NN*D3;
constexpr size_t OFF_S    = OFF_V    + (size_t)NN*D3;
constexpr size_t OFF_ES   = OFF_S    + (size_t)NG*4*GS*GS;
constexpr size_t OFF_ED   = OFF_ES   + (size_t)NN*4;
constexpr size_t SCRATCH  = OFF_ED   + (size_t)NN*4;

__device__ __align__(256) float g_scratch[SCRATCH];

// ---------------- bf16 scratch (hi/lo split operands) ----------------
constexpr size_t B_XH  = 0;
constexpr size_t B_XL  = B_XH  + (size_t)NN*64;
constexpr size_t B_TH  = B_XL  + (size_t)NN*64;
constexpr size_t B_TL  = B_TH  + (size_t)NN*256;
constexpr size_t B_HRH = B_TL  + (size_t)NN*256;
constexpr size_t B_HRL = B_HRH + (size_t)NN*128;
constexpr size_t B_AOH = B_HRL + (size_t)NN*128;
constexpr size_t B_AOL = B_AOH + (size_t)NN*128;
constexpr size_t B_W1H = B_AOL + (size_t)NN*128;
constexpr size_t B_W1L = B_W1H + 256*64;
constexpr size_t B_W2H = B_W1L + 256*64;
constexpr size_t B_W2L = B_W2H + 256*256;
constexpr size_t B_W3H = B_W2L + 256*256;
constexpr size_t B_W3L = B_W3H + 128*256;
constexpr size_t B_WRH = B_W3L + 128*256;
constexpr size_t B_WRL = B_WRH + 128*64;
constexpr size_t B_WQH = B_WRL + 128*64;
constexpr size_t B_WQL = B_WQH + 128*128;
constexpr size_t B_WKH = B_WQL + 128*128;
constexpr size_t B_WKL = B_WKH + 128*128;
constexpr size_t B_WVH = B_WKL + 128*128;
constexpr size_t B_WVL = B_WVH + 128*128;
constexpr size_t B_WOH = B_WVL + 128*128;
constexpr size_t B_WOL = B_WOH + 128*128;
constexpr size_t BF_TOTAL = B_WOL + 128*128;

__device__ __align__(256) __nv_bfloat16 g_bf[BF_TOTAL];

__device__ int g_rowptr[NN + 1];
__device__ int g_cnt[NN];
__device__ int g_cursor[NN];
__device__ int g_col[ET];

// ================= helpers =================
__device__ __forceinline__ uint32_t smem_u32(const void* p) {
    uint32_t a;
    asm("{ .reg .u64 t; cvta.to.shared.u64 t, %1; cvt.u32.u64 %0, t; }" : "=r"(a) : "l"(p));
    return a;
}
#define LDMX4(r, a) \
    asm volatile("ldmatrix.sync.aligned.m8n8.x4.shared.b16 {%0,%1,%2,%3}, [%4];" \
        : "=r"((r)[0]), "=r"((r)[1]), "=r"((r)[2]), "=r"((r)[3]) : "r"(a))
#define LDMX2(r, a) \
    asm volatile("ldmatrix.sync.aligned.m8n8.x2.shared.b16 {%0,%1}, [%2];" \
        : "=r"((r)[0]), "=r"((r)[1]) : "r"(a))
#define MMA16816(d, a, b) \
    asm volatile("mma.sync.aligned.m16n8k16.row.col.f32.bf16.bf16.f32 " \
        "{%0,%1,%2,%3}, {%4,%5,%6,%7}, {%8,%9}, {%0,%1,%2,%3};" \
        : "+f"((d)[0]), "+f"((d)[1]), "+f"((d)[2]), "+f"((d)[3]) \
        : "r"((a)[0]), "r"((a)[1]), "r"((a)[2]), "r"((a)[3]), \
          "r"((b)[0]), "r"((b)[1]))

// ================= CSR build =================
__global__ void k_zero_cnt() {
    int i = blockIdx.x * blockDim.x + threadIdx.x;
    if (i < NN) g_cnt[i] = 0;
}
__global__ void k_count(const int* __restrict__ ei) {
    int stride = gridDim.x * blockDim.x;
    for (int idx = blockIdx.x * blockDim.x + threadIdx.x; idx < NE; idx += stride)
        atomicAdd(&g_cnt[ei[NE + idx]], 1);
}
__global__ void k_scan() {
    __shared__ int warpsum[32];
    __shared__ int s_carry;
    int tid = threadIdx.x, lane = tid & 31, wid = tid >> 5;
    if (tid == 0) s_carry = 0;
    __syncthreads();
    for (int base = 0; base < NN; base += 1024) {
        int v = g_cnt[base + tid] + 1;
        int x = v;
        #pragma unroll
        for (int o = 1; o < 32; o <<= 1) {
            int t = __shfl_up_sync(0xffffffffu, x, o);
            if (lane >= o) x += t;
        }
        if (lane == 31) warpsum[wid] = x;
        __syncthreads();
        if (wid == 0) {
            int w = warpsum[lane];
            #pragma unroll
            for (int o = 1; o < 32; o <<= 1) {
                int t = __shfl_up_sync(0xffffffffu, w, o);
                if (lane >= o) w += t;
            }
            warpsum[lane] = w;
        }
        __syncthreads();
        int excl = (x - v) + (wid > 0 ? warpsum[wid - 1] : 0) + s_carry;
        g_rowptr[base + tid] = excl;
        g_cursor[base + tid] = excl;
        __syncthreads();
        if (tid == 1023) s_carry = excl + v;
        __syncthreads();
    }
    if (tid == 0) g_rowptr[NN] = ET;
}
__global__ void k_fill(const int* __restrict__ ei) {
    int stride = gridDim.x * blockDim.x;
    for (int idx = blockIdx.x * blockDim.x + threadIdx.x; idx < ET; idx += stride) {
        int s, d;
        if (idx < NE) { s = ei[idx]; d = ei[NE + idx]; }
        else          { s = d = idx - NE; }
        int pos = atomicAdd(&g_cursor[d], 1);
        g_col[pos] = s;
    }
}

// ================= fp32 -> bf16 hi/lo split =================
__global__ void k_cvt_split(const float* __restrict__ in, __nv_bfloat16* __restrict__ hi,
                            __nv_bfloat16* __restrict__ lo, int n4) {
    int i = blockIdx.x * blockDim.x + threadIdx.x;
    if (i >= n4) return;
    float4 v = ((const float4*)in)[i];
    __nv_bfloat16 h0 = __float2bfloat16(v.x), h1 = __float2bfloat16(v.y),
                  h2 = __float2bfloat16(v.z), h3 = __float2bfloat16(v.w);
    __nv_bfloat16 l0 = __float2bfloat16(v.x - __bfloat162float(h0));
    __nv_bfloat16 l1 = __float2bfloat16(v.y - __bfloat162float(h1));
    __nv_bfloat16 l2 = __float2bfloat16(v.z - __bfloat162float(h2));
    __nv_bfloat16 l3 = __float2bfloat16(v.w - __bfloat162float(h3));
    __nv_bfloat162* H = (__nv_bfloat162*)hi;
    __nv_bfloat162* L = (__nv_bfloat162*)lo;
    __nv_bfloat162 a; a.x = h0; a.y = h1;
    __nv_bfloat162 b; b.x = h2; b.y = h3;
    __nv_bfloat162 c; c.x = l0; c.y = l1;
    __nv_bfloat162 d; d.x = l2; d.y = l3;
    H[2 * i] = a; H[2 * i + 1] = b;
    L[2 * i] = c; L[2 * i + 1] = d;
}

// transpose weight W[K,N] -> WT hi/lo [N,K]
__global__ void k_cvt_wT(const float* __restrict__ W, __nv_bfloat16* __restrict__ hiT,
                         __nv_bfloat16* __restrict__ loT, int K, int N) {
    int idx = blockIdx.x * blockDim.x + threadIdx.x;
    if (idx >= N * K) return;
    int n = idx / K, k = idx % K;
    float v = W[(size_t)k * N + n];
    __nv_bfloat16 h = __float2bfloat16(v);
    hiT[idx] = h;
    loT[idx] = __float2bfloat16(v - __bfloat162float(h));
}

// ================= mma.sync bf16-split GEMM =================
// C[M,N] = (Ah+Al)[M,K] @ (Bh+Bl)[N,K]^T (+bias), fp32 out.
// CTA tile 128x128, BK=32, 256 threads (8 warps, 4m x 2n), warp tile 32x64.
constexpr int LDS_ = 40;  // bf16 row stride in smem (pad 32 -> 40)

__global__ __launch_bounds__(256) void mma_gemm(
    const __nv_bfloat16* __restrict__ Ah, const __nv_bfloat16* __restrict__ Al,
    const __nv_bfloat16* __restrict__ Bh, const __nv_bfloat16* __restrict__ Bl,
    const float* __restrict__ bias, float* __restrict__ C, int M, int N, int K)
{
    __shared__ __nv_bfloat16 sAh[128 * LDS_];
    __shared__ __nv_bfloat16 sAl[128 * LDS_];
    __shared__ __nv_bfloat16 sBh[128 * LDS_];
    __shared__ __nv_bfloat16 sBl[128 * LDS_];

    int tid = threadIdx.x, lane = tid & 31, warp = tid >> 5;
    int wm = warp & 3, wn = warp >> 2;
    int bm = blockIdx.y, bn = blockIdx.x;
    const __nv_bfloat16* gAh = Ah + (size_t)bm * 128 * K;
    const __nv_bfloat16* gAl = Al + (size_t)bm * 128 * K;
    const __nv_bfloat16* gBh = Bh + (size_t)bn * 128 * K;
    const __nv_bfloat16* gBl = Bl + (size_t)bn * 128 * K;

    float d[2][8][4];
    #pragma unroll
    for (int mi = 0; mi < 2; mi++)
        #pragma unroll
        for (int ni = 0; ni < 8; ni++)
            #pragma unroll
            for (int j = 0; j < 4; j++) d[mi][ni][j] = 0.f;

    for (int k0 = 0; k0 < K; k0 += 32) {
        if (k0) __syncthreads();   // WAR: prior iter's ldmatrix done
        #pragma unroll
        for (int r = 0; r < 2; r++) {
            int idx = tid + r * 256;
            int row = idx >> 2, seg = idx & 3;
            size_t go = (size_t)row * K + k0 + seg * 8;
            int so = row * LDS_ + seg * 8;
            *(uint4*)&sAh[so] = *(const uint4*)(gAh + go);
            *(uint4*)&sAl[so] = *(const uint4*)(gAl + go);
            *(uint4*)&sBh[so] = *(const uint4*)(gBh + go);
            *(uint4*)&sBl[so] = *(const uint4*)(gBl + go);
        }
        __syncthreads();
        #pragma unroll
        for (int ks = 0; ks < 2; ks++) {
            uint32_t ah[2][4], al[2][4];
            #pragma unroll
            for (int mi = 0; mi < 2; mi++) {
                int row = wm * 32 + mi * 16 + (lane & 15);
                int col = ks * 16 + (lane >> 4) * 8;
                LDMX4(ah[mi], smem_u32(&sAh[row * LDS_ + col]));
                LDMX4(al[mi], smem_u32(&sAl[row * LDS_ + col]));
            }
            #pragma unroll
            for (int ni = 0; ni < 8; ni++) {
                uint32_t bh[2], bl[2];
                int row = wn * 64 + ni * 8 + (lane & 7);
                int col = ks * 16 + ((lane >> 3) & 1) * 8;
                LDMX2(bh, smem_u32(&sBh[row * LDS_ + col]));
                LDMX2(bl, smem_u32(&sBl[row * LDS_ + col]));
                #pragma unroll
                for (int mi = 0; mi < 2; mi++) {
                    MMA16816(d[mi][ni], ah[mi], bh);
                    MMA16816(d[mi][ni], al[mi], bh);
                    MMA16816(d[mi][ni], ah[mi], bl);
                }
            }
        }
    }
    // epilogue
    #pragma unroll
    for (int mi = 0; mi < 2; mi++) {
        int row = bm * 128 + wm * 32 + mi * 16 + (lane >> 2);
        #pragma unroll
        for (int ni = 0; ni < 8; ni++) {
            int col = bn * 128 + wn * 64 + ni * 8 + (lane & 3) * 2;
            float b0 = bias ? bias[col] : 0.f;
            float b1 = bias ? bias[col + 1] : 0.f;
            *(float2*)(C + (size_t)row * N + col) =
                make_float2(d[mi][ni][0] + b0, d[mi][ni][1] + b1);
            *(float2*)(C + (size_t)(row + 8) * N + col) =
                make_float2(d[mi][ni][2] + b0, d[mi][ni][3] + b1);
        }
    }
}

// ================= GAT score vectors =================
__global__ void k_scores(const float* __restrict__ h, const float* __restrict__ as_,
                         const float* __restrict__ ad_, float* __restrict__ es,
                         float* __restrict__ ed, int H, int C)
{
    int idx = blockIdx.x * blockDim.x + threadIdx.x;
    if (idx >= NN * H) return;
    int node = idx / H, hd = idx % H;
    const float4* hp = (const float4*)(h + (size_t)node * H * C + (size_t)hd * C);
    const float4* ap = (const float4*)(as_ + (size_t)hd * C);
    const float4* bp = (const float4*)(ad_ + (size_t)hd * C);
    float s = 0.f, d = 0.f;
    for (int c = 0; c < C / 4; c++) {
        float4 hv = hp[c], av = ap[c], bv = bp[c];
        s += hv.x * av.x + hv.y * av.y + hv.z * av.z + hv.w * av.w;
        d += hv.x * bv.x + hv.y * bv.y + hv.z * bv.z + hv.w * bv.w;
    }
    es[idx] = s;
    ed[idx] = d;
}

// ================= GAT aggregation (warp/node, fused epilogue) =================
template <int D, int H>
__global__ __launch_bounds__(256) void k_gat_agg(
    const float* __restrict__ hfeat, const float* __restrict__ es,
    const float* __restrict__ ed, const float* __restrict__ bias,
    const float* __restrict__ gamma, const float* __restrict__ beta,
    const float* __restrict__ resid, float* __restrict__ out)
{
    constexpr int C = D / H;
    constexpr int R = D / 32;
    int warp = (blockIdx.x * blockDim.x + threadIdx.x) >> 5;
    int lane = threadIdx.x & 31;
    if (warp >= NN) return;
    int i = warp;
    int beg = g_rowptr[i], end = g_rowptr[i + 1];

    float edv[H], m[H], z[H];
    #pragma unroll
    for (int h = 0; h < H; h++) {
        edv[h] = ed[(size_t)i * H + h];
        m[h] = -1e30f; z[h] = 0.f;
    }
    for (int e = beg + lane; e < end; e += 32) {
        int s = g_col[e];
        #pragma unroll
        for (int h = 0; h < H; h++) {
            float v = es[(size_t)s * H + h] + edv[h];
            v = v > 0.f ? v : 0.2f * v;
            m[h] = fmaxf(m[h], v);
        }
    }
    #pragma unroll
    for (int h = 0; h < H; h++)
        #pragma unroll
        for (int o = 16; o; o >>= 1)
            m[h] = fmaxf(m[h], __shfl_xor_sync(0xffffffffu, m[h], o));
    for (int e = beg + lane; e < end; e += 32) {
        int s = g_col[e];
        #pragma unroll
        for (int h = 0; h < H; h++) {
            float v = es[(size_t)s * H + h] + edv[h];
            v = v > 0.f ? v : 0.2f * v;
            z[h] += expf(v - m[h]);
        }
    }
    #pragma unroll
    for (int h = 0; h < H; h++) {
        #pragma unroll
        for (int o = 16; o; o >>= 1)
            z[h] += __shfl_xor_sync(0xffffffffu, z[h], o);
        z[h] = 1.f / (z[h] + 1e-16f);
    }
    float acc[R];
    #pragma unroll
    for (int j = 0; j < R; j++) acc[j] = 0.f;
    for (int e = beg; e < end; e++) {
        int s = g_col[e];
        float al[H];
        #pragma unroll
        for (int h = 0; h < H; h++) {
            float v = es[(size_t)s * H + h] + edv[h];
            v = v > 0.f ? v : 0.2f * v;
            al[h] = expf(v - m[h]);
        }
        const float* hs = hfeat + (size_t)s * D;
        #pragma unroll
        for (int j = 0; j < R; j++) {
            int c = lane + 32 * j;
            acc[j] += al[(32 * j) / C] * hs[c];
        }
    }
    float x[R];
    #pragma unroll
    for (int j = 0; j < R; j++) {
        int c = lane + 32 * j;
        float val = acc[j] * z[(32 * j) / C] + bias[c];
        if (resid) val += resid[(size_t)i * D + c];
        x[j] = val;
    }
    if (gamma) {
        #pragma unroll
        for (int j = 0; j < R; j++)
            x[j] = x[j] > 0.f ? x[j] : (expf(x[j]) - 1.f);
        float s = 0.f;
        #pragma unroll
        for (int j = 0; j < R; j++) s += x[j];
        #pragma unroll
        for (int o = 16; o; o >>= 1) s += __shfl_xor_sync(0xffffffffu, s, o);
        float mu = s / (float)D;
        float vs = 0.f;
        #pragma unroll
        for (int j = 0; j < R; j++) { float d = x[j] - mu; vs += d * d; }
        #pragma unroll
        for (int o = 16; o; o >>= 1) vs += __shfl_xor_sync(0xffffffffu, vs, o);
        float inv = rsqrtf(vs / (float)D + 1e-5f);
        #pragma unroll
        for (int j = 0; j < R; j++) {
            int c = lane + 32 * j;
            x[j] = (x[j] - mu) * inv * gamma[c] + beta[c];
        }
    }
    #pragma unroll
    for (int j = 0; j < R; j++)
        out[(size_t)i * D + lane + 32 * j] = x[j];
}

// ================= fp32 MHA =================
__global__ __launch_bounds__(256) void k_qkT(const float* __restrict__ q,
                                             const float* __restrict__ kk,
                                             float* __restrict__ S)
{
    int gh = blockIdx.z, g = gh >> 2, h = gh & 3;
    __shared__ float Qs[32][132];
    __shared__ float Ks[32][132];
    int tid = threadIdx.x;
    const float* qb = q  + ((size_t)g * GS + blockIdx.y * 128) * 128 + h * 32;
    const float* kb = kk + ((size_t)g * GS + blockIdx.x * 128) * 128 + h * 32;
    #pragma unroll
    for (int r = 0; r < 4; r++) {
        int idx = tid + r * 256;
        int row = idx >> 3, k4 = (idx & 7) * 4;
        float4 v = *(const float4*)(qb + (size_t)row * 128 + k4);
        Qs[k4 + 0][row] = v.x; Qs[k4 + 1][row] = v.y;
        Qs[k4 + 2][row] = v.z; Qs[k4 + 3][row] = v.w;
        float4 w = *(const float4*)(kb + (size_t)row * 128 + k4);
        Ks[k4 + 0][row] = w.x; Ks[k4 + 1][row] = w.y;
        Ks[k4 + 2][row] = w.z; Ks[k4 + 3][row] = w.w;
    }
    __syncthreads();
    int tx = tid & 15, ty = tid >> 4;
    float acc[8][8];
    #pragma unroll
    for (int i = 0; i < 8; i++)
        #pragma unroll
        for (int j = 0; j < 8; j++) acc[i][j] = 0.f;
    #pragma unroll
    for (int k = 0; k < 32; k++) {
        float a[8], b[8];
        *(float4*)(a)     = *(const float4*)&Qs[k][ty * 8];
        *(float4*)(a + 4) = *(const float4*)&Qs[k][ty * 8 + 4];
        *(float4*)(b)     = *(const float4*)&Ks[k][tx * 8];
        *(float4*)(b + 4) = *(const float4*)&Ks[k][tx * 8 + 4];
        #pragma unroll
        for (int i = 0; i < 8; i++)
            #pragma unroll
            for (int j = 0; j < 8; j++)
                acc[i][j] += a[i] * b[j];
    }
    const float scale = 0.088388347648318447f;
    float* ob = S + (size_t)gh * GS * GS + (size_t)(blockIdx.y * 128) * GS + blockIdx.x * 128;
    #pragma unroll
    for (int i = 0; i < 8; i++) {
        int row = ty * 8 + i;
        float4 o0 = make_float4(acc[i][0]*scale, acc[i][1]*scale, acc[i][2]*scale, acc[i][3]*scale);
        float4 o1 = make_float4(acc[i][4]*scale, acc[i][5]*scale, acc[i][6]*scale, acc[i][7]*scale);
        *(float4*)(ob + (size_t)row * GS + tx * 8)     = o0;
        *(float4*)(ob + (size_t)row * GS + tx * 8 + 4) = o1;
    }
}

__global__ void k_softmax(float* __restrict__ S) {
    int r = (blockIdx.x * blockDim.x + threadIdx.x) >> 5;
    int lane = threadIdx.x & 31;
    float4* row = (float4*)(S + (size_t)r * GS);
    float v[16];
    #pragma unroll
    for (int p = 0; p < 4; p++) {
        float4 t = row[lane + 32 * p];
        v[p * 4 + 0] = t.x; v[p * 4 + 1] = t.y; v[p * 4 + 2] = t.z; v[p * 4 + 3] = t.w;
    }
    float m = -1e30f;
    #pragma unroll
    for (int j = 0; j < 16; j++) m = fmaxf(m, v[j]);
    #pragma unroll
    for (int o = 16; o; o >>= 1) m = fmaxf(m, __shfl_xor_sync(0xffffffffu, m, o));
    float s = 0.f;
    #pragma unroll
    for (int j = 0; j < 16; j++) { v[j] = expf(v[j] - m); s += v[j]; }
    #pragma unroll
    for (int o = 16; o; o >>= 1) s += __shfl_xor_sync(0xffffffffu, s, o);
    float inv = 1.f / s;
    #pragma unroll
    for (int p = 0; p < 4; p++) {
        float4 t = make_float4(v[p*4]*inv, v[p*4+1]*inv, v[p*4+2]*inv, v[p*4+3]*inv);
        row[lane + 32 * p] = t;
    }
}

__global__ __launch_bounds__(256) void k_pv(const float* __restrict__ S,
                                            const float* __restrict__ v,
                                            float* __restrict__ out)
{
    int gh = blockIdx.y, g = gh >> 2, h = gh & 3;
    const float* P  = S + (size_t)gh * GS * GS + (size_t)blockIdx.x * 256 * GS;
    const float* vb = v + (size_t)g * GS * 128 + h * 32;
    __shared__ float Ps[16][260];
    __shared__ float Vs[16][32];
    int tid = threadIdx.x;
    int tx = tid & 7;
    int ty = tid >> 3;
    float acc[8][4];
    #pragma unroll
    for (int i = 0; i < 8; i++)
        #pragma unroll
        for (int j = 0; j < 4; j++) acc[i][j] = 0.f;

    for (int k0 = 0; k0 < GS; k0 += 16) {
        #pragma unroll
        for (int r = 0; r < 4; r++) {
            int idx = tid + r * 256;
            int row = idx >> 2, k4 = (idx & 3) * 4;
            float4 pv = *(const float4*)(P + (size_t)row * GS + k0 + k4);
            Ps[k4 + 0][row] = pv.x; Ps[k4 + 1][row] = pv.y;
            Ps[k4 + 2][row] = pv.z; Ps[k4 + 3][row] = pv.w;
        }
        if (tid < 128) {
            int row = tid >> 3, c4 = (tid & 7) * 4;
            float4 vv = *(const float4*)(vb + (size_t)(k0 + row) * 128 + c4);
            *(float4*)&Vs[row][c4] = vv;
        }
        __syncthreads();
        #pragma unroll
        for (int k = 0; k < 16; k++) {
            float b[4], a[8];
            *(float4*)b       = *(const float4*)&Vs[k][tx * 4];
            *(float4*)(a)     = *(const float4*)&Ps[k][ty * 8];
            *(float4*)(a + 4) = *(const float4*)&Ps[k][ty * 8 + 4];
            #pragma unroll
            for (int i = 0; i < 8; i++)
                #pragma unroll
                for (int j = 0; j < 4; j++)
                    acc[i][j] += a[i] * b[j];
        }
        __syncthreads();
    }
    float* ob = out + ((size_t)g * GS + blockIdx.x * 256) * 128 + h * 32;
    #pragma unroll
    for (int i = 0; i < 8; i++) {
        int row = ty * 8 + i;
        *(float4*)(ob + (size_t)row * 128 + tx * 4) =
            make_float4(acc[i][0], acc[i][1], acc[i][2], acc[i][3]);
    }
}

// ================= host orchestration =================
extern "C" void kernel_launch(void* const* d_in, const int* in_sizes, int n_in,
                              void* d_out, int out_size)
{
    const float* x   = (const float*)d_in[0];
    const int*   ei  = (const int*)  d_in[1];
    const float* W1  = (const float*)d_in[3];
    const float* a1s = (const float*)d_in[4];
    const float* a1d = (const float*)d_in[5];
    const float* b1  = (const float*)d_in[6];
    const float* W2  = (const float*)d_in[7];
    const float* a2s = (const float*)d_in[8];
    const float* a2d = (const float*)d_in[9];
    const float* b2  = (const float*)d_in[10];
    const float* W3  = (const float*)d_in[11];
    const float* a3s = (const float*)d_in[12];
    const float* a3d = (const float*)d_in[13];
    const float* b3  = (const float*)d_in[14];
    const float* g1  = (const float*)d_in[15];
    const float* be1 = (const float*)d_in[16];
    const float* g2  = (const float*)d_in[17];
    const float* be2 = (const float*)d_in[18];
    const float* Wr  = (const float*)d_in[19];
    const float* br  = (const float*)d_in[20];
    const float* Wq  = (const float*)d_in[21];
    const float* Wk  = (const float*)d_in[22];
    const float* Wv  = (const float*)d_in[23];
    const float* Wo  = (const float*)d_in[24];
    const float* bo  = (const float*)d_in[25];
    float* out = (float*)d_out;

    float* sb = nullptr;
    cudaGetSymbolAddress((void**)&sb, g_scratch);
    __nv_bfloat16* bb = nullptr;
    cudaGetSymbolAddress((void**)&bb, g_bf);

    float* p_h    = sb + OFF_H;
    float* p_t    = sb + OFF_T;
    float* p_h3   = sb + OFF_H3;
    float* p_r    = sb + OFF_R;
    float* p_hres = sb + OFF_HRES;
    float* p_q    = sb + OFF_Q;
    float* p_k    = sb + OFF_K;
    float* p_v    = sb + OFF_V;
    float* p_S    = sb + OFF_S;
    float* p_es   = sb + OFF_ES;
    float* p_ed   = sb + OFF_ED;

    // CSR
    k_zero_cnt<<<NN / 256, 256>>>();
    k_count<<<1024, 256>>>(ei);
    k_scan<<<1, 1024>>>();
    k_fill<<<1152, 256>>>(ei);

    // weight conversions (transposed, hi/lo)
    k_cvt_wT<<<(256*64 + 255)/256, 256>>>(W1, bb + B_W1H, bb + B_W1L, 64, 256);
    k_cvt_wT<<<(256*256 + 255)/256, 256>>>(W2, bb + B_W2H, bb + B_W2L, 256, 256);
    k_cvt_wT<<<(128*256 + 255)/256, 256>>>(W3, bb + B_W3H, bb + B_W3L, 256, 128);
    k_cvt_wT<<<(128*64 + 255)/256, 256>>>(Wr, bb + B_WRH, bb + B_WRL, 64, 128);
    k_cvt_wT<<<(128*128 + 255)/256, 256>>>(Wq, bb + B_WQH, bb + B_WQL, 128, 128);
    k_cvt_wT<<<(128*128 + 255)/256, 256>>>(Wk, bb + B_WKH, bb + B_WKL, 128, 128);
    k_cvt_wT<<<(128*128 + 255)/256, 256>>>(Wv, bb + B_WVH, bb + B_WVL, 128, 128);
    k_cvt_wT<<<(128*128 + 255)/256, 256>>>(Wo, bb + B_WOH, bb + B_WOL, 128, 128);

    // x -> bf16 hi/lo
    k_cvt_split<<<(NN*64/4 + 255)/256, 256>>>(x, bb + B_XH, bb + B_XL, NN*64/4);

    // layer 1
    mma_gemm<<<dim3(2, 512), 256>>>(bb + B_XH, bb + B_XL, bb + B_W1H, bb + B_W1L,
                                    nullptr, p_h, NN, 256, 64);
    k_scores<<<(NN * 4) / 256, 256>>>(p_h, a1s, a1d, p_es, p_ed, 4, 64);
    k_gat_agg<256, 4><<<NN / 8, 256>>>(p_h, p_es, p_ed, b1, g1, be1, nullptr, p_t);
    k_cvt_split<<<(NN*256/4 + 255)/256, 256>>>(p_t, bb + B_TH, bb + B_TL, NN*256/4);

    // layer 2
    mma_gemm<<<dim3(2, 512), 256>>>(bb + B_TH, bb + B_TL, bb + B_W2H, bb + B_W2L,
                                    nullptr, p_h, NN, 256, 256);
    k_scores<<<(NN * 4) / 256, 256>>>(p_h, a2s, a2d, p_es, p_ed, 4, 64);
    k_gat_agg<256, 4><<<NN / 8, 256>>>(p_h, p_es, p_ed, b2, g2, be2, nullptr, p_t);
    k_cvt_split<<<(NN*256/4 + 255)/256, 256>>>(p_t, bb + B_TH, bb + B_TL, NN*256/4);

    // layer 3 + residual
    mma_gemm<<<dim3(1, 512), 256>>>(bb + B_TH, bb + B_TL, bb + B_W3H, bb + B_W3L,
                                    nullptr, p_h3, NN, 128, 256);
    k_scores<<<NN / 256, 256>>>(p_h3, a3s, a3d, p_es, p_ed, 1, 128);
    mma_gemm<<<dim3(1, 512), 256>>>(bb + B_XH, bb + B_XL, bb + B_WRH, bb + B_WRL,
                                    br, p_r, NN, 128, 64);
    k_gat_agg<128, 1><<<NN / 8, 256>>>(p_h3, p_es, p_ed, b3, nullptr, nullptr, p_r, p_hres);
    k_cvt_split<<<(NN*128/4 + 255)/256, 256>>>(p_hres, bb + B_HRH, bb + B_HRL, NN*128/4);

    // MHA projections
    mma_gemm<<<dim3(1, 512), 256>>>(bb + B_HRH, bb + B_HRL, bb + B_WQH, bb + B_WQL,
                                    nullptr, p_q, NN, 128, 128);
    mma_gemm<<<dim3(1, 512), 256>>>(bb + B_HRH, bb + B_HRL, bb + B_WKH, bb + B_WKL,
                                    nullptr, p_k, NN, 128, 128);
    mma_gemm<<<dim3(1, 512), 256>>>(bb + B_HRH, bb + B_HRL, bb + B_WVH, bb + B_WVL,
                                    nullptr, p_v, NN, 128, 128);
    // attention (fp32 this round)
    k_qkT<<<dim3(4, 4, NG * 4), 256>>>(p_q, p_k, p_S);
    k_softmax<<<(NG * 4 * GS) / 8, 256>>>(p_S);
    k_pv<<<dim3(2, NG * 4), 256>>>(p_S, p_v, p_h3);
    // output projection
    k_cvt_split<<<(NN*128/4 + 255)/256, 256>>>(p_h3, bb + B_AOH, bb + B_AOL, NN*128/4);
    mma_gemm<<<dim3(1, 512), 256>>>(bb + B_AOH, bb + B_AOL, bb + B_WOH, bb + B_WOL,
                                    bo, out, NN, 128, 128);
}

// round 4
// speedup vs baseline: 1.3473x; 1.1987x over previous
#include <cuda_runtime.h>
#include <cuda_bf16.h>
#include <math.h>
#include <stdint.h>

// ---------------- problem constants ----------------
constexpr int NN   = 65536;          // nodes
constexpr int NE   = 524288;         // raw edges
constexpr int ET   = NE + NN;        // edges + self loops
constexpr int GS   = 512;            // graph size
constexpr int NG   = NN / GS;        // 128 graphs
constexpr int D1   = 256;            // heads*hid
constexpr int D3   = 128;            // out dim
constexpr size_t SELEM = (size_t)NG * 4 * GS * GS;   // 134217728

// ---------------- fp32 scratch ----------------
constexpr size_t OFF_H    = 0;                        // NN*256 (gemm out, layers 1/2)
constexpr size_t OFF_H3   = OFF_H  + (size_t)NN*D1;   // NN*128
constexpr size_t OFF_R    = OFF_H3 + (size_t)NN*D3;   // NN*128
constexpr size_t OFF_V    = OFF_R  + (size_t)NN*D3;   // NN*128
constexpr size_t OFF_S    = OFF_V  + (size_t)NN*D3;   // SELEM
constexpr size_t OFF_ES   = OFF_S  + SELEM;
constexpr size_t OFF_ED   = OFF_ES + (size_t)NN*4;
constexpr size_t SCRATCH  = OFF_ED + (size_t)NN*4;

__device__ __align__(256) float g_scratch[SCRATCH];

// ---------------- bf16 scratch (hi/lo split operands) ----------------
constexpr size_t B_XH  = 0;
constexpr size_t B_XL  = B_XH  + (size_t)NN*64;
constexpr size_t B_TH  = B_XL  + (size_t)NN*64;
constexpr size_t B_TL  = B_TH  + (size_t)NN*256;
constexpr size_t B_HRH = B_TL  + (size_t)NN*256;
constexpr size_t B_HRL = B_HRH + (size_t)NN*128;
constexpr size_t B_AOH = B_HRL + (size_t)NN*128;
constexpr size_t B_AOL = B_AOH + (size_t)NN*128;
constexpr size_t B_QH  = B_AOL + (size_t)NN*128;
constexpr size_t B_QL  = B_QH  + (size_t)NN*128;
constexpr size_t B_KH  = B_QL  + (size_t)NN*128;
constexpr size_t B_KL  = B_KH  + (size_t)NN*128;
constexpr size_t B_VTH = B_KL  + (size_t)NN*128;
constexpr size_t B_VTL = B_VTH + (size_t)NN*128;
constexpr size_t B_PH  = B_VTL + (size_t)NN*128;
constexpr size_t B_PL  = B_PH  + SELEM;
constexpr size_t B_W1H = B_PL  + SELEM;
constexpr size_t B_W1L = B_W1H + 256*64;
constexpr size_t B_W2H = B_W1L + 256*64;
constexpr size_t B_W2L = B_W2H + 256*256;
constexpr size_t B_W3H = B_W2L + 256*256;
constexpr size_t B_W3L = B_W3H + 128*256;
constexpr size_t B_WRH = B_W3L + 128*256;
constexpr size_t B_WRL = B_WRH + 128*64;
constexpr size_t B_WQH = B_WRL + 128*64;
constexpr size_t B_WQL = B_WQH + 128*128;
constexpr size_t B_WKH = B_WQL + 128*128;
constexpr size_t B_WKL = B_WKH + 128*128;
constexpr size_t B_WVH = B_WKL + 128*128;
constexpr size_t B_WVL = B_WVH + 128*128;
constexpr size_t B_WOH = B_WVL + 128*128;
constexpr size_t B_WOL = B_WOH + 128*128;
constexpr size_t BF_TOTAL = B_WOL + 128*128;

__device__ __align__(256) __nv_bfloat16 g_bf[BF_TOTAL];

__device__ int g_rowptr[NN + 1];
__device__ int g_cnt[NN];
__device__ int g_cursor[NN];
__device__ int g_col[ET];

// ================= helpers =================
__device__ __forceinline__ uint32_t smem_u32(const void* p) {
    uint32_t a;
    asm("{ .reg .u64 t; cvta.to.shared.u64 t, %1; cvt.u32.u64 %0, t; }" : "=r"(a) : "l"(p));
    return a;
}
#define LDMX4(r, a) \
    asm volatile("ldmatrix.sync.aligned.m8n8.x4.shared.b16 {%0,%1,%2,%3}, [%4];" \
        : "=r"((r)[0]), "=r"((r)[1]), "=r"((r)[2]), "=r"((r)[3]) : "r"(a))
#define LDMX2(r, a) \
    asm volatile("ldmatrix.sync.aligned.m8n8.x2.shared.b16 {%0,%1}, [%2];" \
        : "=r"((r)[0]), "=r"((r)[1]) : "r"(a))
#define MMA16816(d, a, b) \
    asm volatile("mma.sync.aligned.m16n8k16.row.col.f32.bf16.bf16.f32 " \
        "{%0,%1,%2,%3}, {%4,%5,%6,%7}, {%8,%9}, {%0,%1,%2,%3};" \
        : "+f"((d)[0]), "+f"((d)[1]), "+f"((d)[2]), "+f"((d)[3]) \
        : "r"((a)[0]), "r"((a)[1]), "r"((a)[2]), "r"((a)[3]), \
          "r"((b)[0]), "r"((b)[1]))

__device__ __forceinline__ void split2(float v0, float v1, uint32_t& hh, uint32_t& ll) {
    __nv_bfloat16 h0 = __float2bfloat16(v0), h1 = __float2bfloat16(v1);
    __nv_bfloat16 l0 = __float2bfloat16(v0 - __bfloat162float(h0));
    __nv_bfloat16 l1 = __float2bfloat16(v1 - __bfloat162float(h1));
    __nv_bfloat162 H; H.x = h0; H.y = h1;
    __nv_bfloat162 L; L.x = l0; L.y = l1;
    hh = *(uint32_t*)&H; ll = *(uint32_t*)&L;
}

// ================= CSR build =================
__global__ void k_zero_cnt() {
    int i = blockIdx.x * blockDim.x + threadIdx.x;
    if (i < NN) g_cnt[i] = 0;
}
__global__ void k_count(const int* __restrict__ ei) {
    int stride = gridDim.x * blockDim.x;
    for (int idx = blockIdx.x * blockDim.x + threadIdx.x; idx < NE; idx += stride)
        atomicAdd(&g_cnt[ei[NE + idx]], 1);
}
__global__ void k_scan() {
    __shared__ int warpsum[32];
    __shared__ int s_carry;
    int tid = threadIdx.x, lane = tid & 31, wid = tid >> 5;
    if (tid == 0) s_carry = 0;
    __syncthreads();
    for (int base = 0; base < NN; base += 1024) {
        int v = g_cnt[base + tid] + 1;
        int x = v;
        #pragma unroll
        for (int o = 1; o < 32; o <<= 1) {
            int t = __shfl_up_sync(0xffffffffu, x, o);
            if (lane >= o) x += t;
        }
        if (lane == 31) warpsum[wid] = x;
        __syncthreads();
        if (wid == 0) {
            int w = warpsum[lane];
            #pragma unroll
            for (int o = 1; o < 32; o <<= 1) {
                int t = __shfl_up_sync(0xffffffffu, w, o);
                if (lane >= o) w += t;
            }
            warpsum[lane] = w;
        }
        __syncthreads();
        int excl = (x - v) + (wid > 0 ? warpsum[wid - 1] : 0) + s_carry;
        g_rowptr[base + tid] = excl;
        g_cursor[base + tid] = excl;
        __syncthreads();
        if (tid == 1023) s_carry = excl + v;
        __syncthreads();
    }
    if (tid == 0) g_rowptr[NN] = ET;
}
__global__ void k_fill(const int* __restrict__ ei) {
    int stride = gridDim.x * blockDim.x;
    for (int idx = blockIdx.x * blockDim.x + threadIdx.x; idx < ET; idx += stride) {
        int s, d;
        if (idx < NE) { s = ei[idx]; d = ei[NE + idx]; }
        else          { s = d = idx - NE; }
        int pos = atomicAdd(&g_cursor[d], 1);
        g_col[pos] = s;
    }
}

// ================= fp32 -> bf16 hi/lo split (x only) =================
__global__ void k_cvt_split(const float* __restrict__ in, __nv_bfloat16* __restrict__ hi,
                            __nv_bfloat16* __restrict__ lo, int n4) {
    int i = blockIdx.x * blockDim.x + threadIdx.x;
    if (i >= n4) return;
    float4 v = ((const float4*)in)[i];
    uint32_t h01, l01, h23, l23;
    split2(v.x, v.y, h01, l01);
    split2(v.z, v.w, h23, l23);
    ((uint32_t*)hi)[2 * i] = h01; ((uint32_t*)hi)[2 * i + 1] = h23;
    ((uint32_t*)lo)[2 * i] = l01; ((uint32_t*)lo)[2 * i + 1] = l23;
}

// transpose weight W[K,N] -> WT hi/lo [N,K]
__global__ void k_cvt_wT(const float* __restrict__ W, __nv_bfloat16* __restrict__ hiT,
                         __nv_bfloat16* __restrict__ loT, int K, int N) {
    int idx = blockIdx.x * blockDim.x + threadIdx.x;
    if (idx >= N * K) return;
    int n = idx / K, k = idx % K;
    float v = W[(size_t)k * N + n];
    __nv_bfloat16 h = __float2bfloat16(v);
    hiT[idx] = h;
    loT[idx] = __float2bfloat16(v - __bfloat162float(h));
}

// ================= mma.sync bf16-split GEMM =================
// C = (Ah+Al)[M,K] @ (Bh+Bl)[N,K]^T. Output: fp32 C (+bias) OR bf16 hi/lo pair.
constexpr int LDS_ = 40;

__global__ __launch_bounds__(256) void mma_gemm(
    const __nv_bfloat16* __restrict__ Ah, const __nv_bfloat16* __restrict__ Al,
    const __nv_bfloat16* __restrict__ Bh, const __nv_bfloat16* __restrict__ Bl,
    const float* __restrict__ bias, float* __restrict__ C,
    __nv_bfloat16* __restrict__ Chi, __nv_bfloat16* __restrict__ Clo,
    int M, int N, int K)
{
    __shared__ __nv_bfloat16 sAh[128 * LDS_];
    __shared__ __nv_bfloat16 sAl[128 * LDS_];
    __shared__ __nv_bfloat16 sBh[128 * LDS_];
    __shared__ __nv_bfloat16 sBl[128 * LDS_];

    int tid = threadIdx.x, lane = tid & 31, warp = tid >> 5;
    int wm = warp & 3, wn = warp >> 2;
    int bm = blockIdx.y, bn = blockIdx.x;
    const __nv_bfloat16* gAh = Ah + (size_t)bm * 128 * K;
    const __nv_bfloat16* gAl = Al + (size_t)bm * 128 * K;
    const __nv_bfloat16* gBh = Bh + (size_t)bn * 128 * K;
    const __nv_bfloat16* gBl = Bl + (size_t)bn * 128 * K;

    float d[2][8][4];
    #pragma unroll
    for (int mi = 0; mi < 2; mi++)
        #pragma unroll
        for (int ni = 0; ni < 8; ni++)
            #pragma unroll
            for (int j = 0; j < 4; j++) d[mi][ni][j] = 0.f;

    for (int k0 = 0; k0 < K; k0 += 32) {
        if (k0) __syncthreads();
        #pragma unroll
        for (int r = 0; r < 2; r++) {
            int idx = tid + r * 256;
            int row = idx >> 2, seg = idx & 3;
            size_t go = (size_t)row * K + k0 + seg * 8;
            int so = row * LDS_ + seg * 8;
            *(uint4*)&sAh[so] = *(const uint4*)(gAh + go);
            *(uint4*)&sAl[so] = *(const uint4*)(gAl + go);
            *(uint4*)&sBh[so] = *(const uint4*)(gBh + go);
            *(uint4*)&sBl[so] = *(const uint4*)(gBl + go);
        }
        __syncthreads();
        #pragma unroll
        for (int ks = 0; ks < 2; ks++) {
            uint32_t ah[2][4], al[2][4];
            #pragma unroll
            for (int mi = 0; mi < 2; mi++) {
                int row = wm * 32 + mi * 16 + (lane & 15);
                int col = ks * 16 + (lane >> 4) * 8;
                LDMX4(ah[mi], smem_u32(&sAh[row * LDS_ + col]));
                LDMX4(al[mi], smem_u32(&sAl[row * LDS_ + col]));
            }
            #pragma unroll
            for (int ni = 0; ni < 8; ni++) {
                uint32_t bh[2], bl[2];
                int row = wn * 64 + ni * 8 + (lane & 7);
                int col = ks * 16 + ((lane >> 3) & 1) * 8;
                LDMX2(bh, smem_u32(&sBh[row * LDS_ + col]));
                LDMX2(bl, smem_u32(&sBl[row * LDS_ + col]));
                #pragma unroll
                for (int mi = 0; mi < 2; mi++) {
                    MMA16816(d[mi][ni], ah[mi], bh);
                    MMA16816(d[mi][ni], al[mi], bh);
                    MMA16816(d[mi][ni], ah[mi], bl);
                }
            }
        }
    }
    // epilogue
    #pragma unroll
    for (int mi = 0; mi < 2; mi++) {
        int row = bm * 128 + wm * 32 + mi * 16 + (lane >> 2);
        #pragma unroll
        for (int ni = 0; ni < 8; ni++) {
            int col = bn * 128 + wn * 64 + ni * 8 + (lane & 3) * 2;
            if (C) {
                float b0 = bias ? bias[col] : 0.f;
                float b1 = bias ? bias[col + 1] : 0.f;
                *(float2*)(C + (size_t)row * N + col) =
                    make_float2(d[mi][ni][0] + b0, d[mi][ni][1] + b1);
                *(float2*)(C + (size_t)(row + 8) * N + col) =
                    make_float2(d[mi][ni][2] + b0, d[mi][ni][3] + b1);
            } else {
                uint32_t hh, ll;
                split2(d[mi][ni][0], d[mi][ni][1], hh, ll);
                *(uint32_t*)(Chi + (size_t)row * N + col) = hh;
                *(uint32_t*)(Clo + (size_t)row * N + col) = ll;
                split2(d[mi][ni][2], d[mi][ni][3], hh, ll);
                *(uint32_t*)(Chi + (size_t)(row + 8) * N + col) = hh;
                *(uint32_t*)(Clo + (size_t)(row + 8) * N + col) = ll;
            }
        }
    }
}

// ================= GAT score vectors =================
__global__ void k_scores(const float* __restrict__ h, const float* __restrict__ as_,
                         const float* __restrict__ ad_, float* __restrict__ es,
                         float* __restrict__ ed, int H, int C)
{
    int idx = blockIdx.x * blockDim.x + threadIdx.x;
    if (idx >= NN * H) return;
    int node = idx / H, hd = idx % H;
    const float4* hp = (const float4*)(h + (size_t)node * H * C + (size_t)hd * C);
    const float4* ap = (const float4*)(as_ + (size_t)hd * C);
    const float4* bp = (const float4*)(ad_ + (size_t)hd * C);
    float s = 0.f, d = 0.f;
    for (int c = 0; c < C / 4; c++) {
        float4 hv = hp[c], av = ap[c], bv = bp[c];
        s += hv.x * av.x + hv.y * av.y + hv.z * av.z + hv.w * av.w;
        d += hv.x * bv.x + hv.y * bv.y + hv.z * bv.z + hv.w * bv.w;
    }
    es[idx] = s;
    ed[idx] = d;
}

// ================= GAT aggregation (warp/node, fused epilogue, bf16 hi/lo out) ===
template <int D, int H>
__global__ __launch_bounds__(256) void k_gat_agg(
    const float* __restrict__ hfeat, const float* __restrict__ es,
    const float* __restrict__ ed, const float* __restrict__ bias,
    const float* __restrict__ gamma, const float* __restrict__ beta,
    const float* __restrict__ resid,
    __nv_bfloat16* __restrict__ outH, __nv_bfloat16* __restrict__ outL)
{
    constexpr int C = D / H;
    constexpr int R = D / 32;
    int warp = (blockIdx.x * blockDim.x + threadIdx.x) >> 5;
    int lane = threadIdx.x & 31;
    if (warp >= NN) return;
    int i = warp;
    int beg = g_rowptr[i], end = g_rowptr[i + 1];

    float edv[H], m[H], z[H];
    #pragma unroll
    for (int h = 0; h < H; h++) {
        edv[h] = ed[(size_t)i * H + h];
        m[h] = -1e30f; z[h] = 0.f;
    }
    for (int e = beg + lane; e < end; e += 32) {
        int s = g_col[e];
        #pragma unroll
        for (int h = 0; h < H; h++) {
            float v = es[(size_t)s * H + h] + edv[h];
            v = v > 0.f ? v : 0.2f * v;
            m[h] = fmaxf(m[h], v);
        }
    }
    #pragma unroll
    for (int h = 0; h < H; h++)
        #pragma unroll
        for (int o = 16; o; o >>= 1)
            m[h] = fmaxf(m[h], __shfl_xor_sync(0xffffffffu, m[h], o));
    for (int e = beg + lane; e < end; e += 32) {
        int s = g_col[e];
        #pragma unroll
        for (int h = 0; h < H; h++) {
            float v = es[(size_t)s * H + h] + edv[h];
            v = v > 0.f ? v : 0.2f * v;
            z[h] += expf(v - m[h]);
        }
    }
    #pragma unroll
    for (int h = 0; h < H; h++) {
        #pragma unroll
        for (int o = 16; o; o >>= 1)
            z[h] += __shfl_xor_sync(0xffffffffu, z[h], o);
        z[h] = 1.f / (z[h] + 1e-16f);
    }
    float acc[R];
    #pragma unroll
    for (int j = 0; j < R; j++) acc[j] = 0.f;
    for (int e = beg; e < end; e++) {
        int s = g_col[e];
        float al[H];
        #pragma unroll
        for (int h = 0; h < H; h++) {
            float v = es[(size_t)s * H + h] + edv[h];
            v = v > 0.f ? v : 0.2f * v;
            al[h] = expf(v - m[h]);
        }
        const float* hs = hfeat + (size_t)s * D;
        #pragma unroll
        for (int j = 0; j < R; j++) {
            int c = lane + 32 * j;
            acc[j] += al[(32 * j) / C] * hs[c];
        }
    }
    float x[R];
    #pragma unroll
    for (int j = 0; j < R; j++) {
        int c = lane + 32 * j;
        float val = acc[j] * z[(32 * j) / C] + bias[c];
        if (resid) val += resid[(size_t)i * D + c];
        x[j] = val;
    }
    if (gamma) {
        #pragma unroll
        for (int j = 0; j < R; j++)
            x[j] = x[j] > 0.f ? x[j] : (expf(x[j]) - 1.f);
        float s = 0.f;
        #pragma unroll
        for (int j = 0; j < R; j++) s += x[j];
        #pragma unroll
        for (int o = 16; o; o >>= 1) s += __shfl_xor_sync(0xffffffffu, s, o);
        float mu = s / (float)D;
        float vs = 0.f;
        #pragma unroll
        for (int j = 0; j < R; j++) { float d = x[j] - mu; vs += d * d; }
        #pragma unroll
        for (int o = 16; o; o >>= 1) vs += __shfl_xor_sync(0xffffffffu, vs, o);
        float inv = rsqrtf(vs / (float)D + 1e-5f);
        #pragma unroll
        for (int j = 0; j < R; j++) {
            int c = lane + 32 * j;
            x[j] = (x[j] - mu) * inv * gamma[c] + beta[c];
        }
    }
    #pragma unroll
    for (int j = 0; j < R; j++) {
        size_t idx = (size_t)i * D + lane + 32 * j;
        __nv_bfloat16 h = __float2bfloat16(x[j]);
        outH[idx] = h;
        outL[idx] = __float2bfloat16(x[j] - __bfloat162float(h));
    }
}

// ================= MHA: S = QK^T * scale via mma.sync =================
// grid (4, 4, 512 gh): 128x128 output tile, K=32 (head dim).
__global__ __launch_bounds__(256) void k_qkT_mma(
    const __nv_bfloat16* __restrict__ QH, const __nv_bfloat16* __restrict__ QL,
    const __nv_bfloat16* __restrict__ KH, const __nv_bfloat16* __restrict__ KL,
    float* __restrict__ S)
{
    __shared__ __nv_bfloat16 sQh[128 * LDS_];
    __shared__ __nv_bfloat16 sQl[128 * LDS_];
    __shared__ __nv_bfloat16 sKh[128 * LDS_];
    __shared__ __nv_bfloat16 sKl[128 * LDS_];
    int gh = blockIdx.z, g = gh >> 2, h = gh & 3;
    int tid = threadIdx.x, lane = tid & 31, warp = tid >> 5;
    int wm = warp & 3, wn = warp >> 2;
    const __nv_bfloat16* qh = QH + ((size_t)g * GS + blockIdx.y * 128) * 128 + h * 32;
    const __nv_bfloat16* ql = QL + ((size_t)g * GS + blockIdx.y * 128) * 128 + h * 32;
    const __nv_bfloat16* kh = KH + ((size_t)g * GS + blockIdx.x * 128) * 128 + h * 32;
    const __nv_bfloat16* kl = KL + ((size_t)g * GS + blockIdx.x * 128) * 128 + h * 32;
    #pragma unroll
    for (int r = 0; r < 2; r++) {
        int idx = tid + r * 256;
        int row = idx >> 2, col = (idx & 3) * 8;
        int so = row * LDS_ + col;
        size_t go = (size_t)row * 128 + col;
        *(uint4*)&sQh[so] = *(const uint4*)(qh + go);
        *(uint4*)&sQl[so] = *(const uint4*)(ql + go);
        *(uint4*)&sKh[so] = *(const uint4*)(kh + go);
        *(uint4*)&sKl[so] = *(const uint4*)(kl + go);
    }
    __syncthreads();
    float d[2][8][4];
    #pragma unroll
    for (int mi = 0; mi < 2; mi++)
        #pragma unroll
        for (int ni = 0; ni < 8; ni++)
            #pragma unroll
            for (int j = 0; j < 4; j++) d[mi][ni][j] = 0.f;
    #pragma unroll
    for (int ks = 0; ks < 2; ks++) {
        uint32_t ah[2][4], al[2][4];
        #pragma unroll
        for (int mi = 0; mi < 2; mi++) {
            int row = wm * 32 + mi * 16 + (lane & 15);
            int col = ks * 16 + (lane >> 4) * 8;
            LDMX4(ah[mi], smem_u32(&sQh[row * LDS_ + col]));
            LDMX4(al[mi], smem_u32(&sQl[row * LDS_ + col]));
        }
        #pragma unroll
        for (int ni = 0; ni < 8; ni++) {
            uint32_t bh[2], bl[2];
            int row = wn * 64 + ni * 8 + (lane & 7);
            int col = ks * 16 + ((lane >> 3) & 1) * 8;
            LDMX2(bh, smem_u32(&sKh[row * LDS_ + col]));
            LDMX2(bl, smem_u32(&sKl[row * LDS_ + col]));
            #pragma unroll
            for (int mi = 0; mi < 2; mi++) {
                MMA16816(d[mi][ni], ah[mi], bh);
                MMA16816(d[mi][ni], al[mi], bh);
                MMA16816(d[mi][ni], ah[mi], bl);
            }
        }
    }
    const float scale = 0.088388347648318447f;   // 1/sqrt(128)
    float* ob = S + (size_t)gh * GS * GS;
    #pragma unroll
    for (int mi = 0; mi < 2; mi++) {
        int row = blockIdx.y * 128 + wm * 32 + mi * 16 + (lane >> 2);
        #pragma unroll
        for (int ni = 0; ni < 8; ni++) {
            int col = blockIdx.x * 128 + wn * 64 + ni * 8 + (lane & 3) * 2;
            *(float2*)(ob + (size_t)row * GS + col) =
                make_float2(d[mi][ni][0] * scale, d[mi][ni][1] * scale);
            *(float2*)(ob + (size_t)(row + 8) * GS + col) =
                make_float2(d[mi][ni][2] * scale, d[mi][ni][3] * scale);
        }
    }
}

// ================= rowwise softmax, fp32 in -> bf16 hi/lo out =================
__global__ void k_softmax2(const float* __restrict__ S,
                           __nv_bfloat16* __restrict__ PH, __nv_bfloat16* __restrict__ PL)
{
    int r = (blockIdx.x * blockDim.x + threadIdx.x) >> 5;
    int lane = threadIdx.x & 31;
    const float4* row = (const float4*)(S + (size_t)r * GS);
    float v[16];
    #pragma unroll
    for (int p = 0; p < 4; p++) {
        float4 t = row[lane + 32 * p];
        v[p * 4 + 0] = t.x; v[p * 4 + 1] = t.y; v[p * 4 + 2] = t.z; v[p * 4 + 3] = t.w;
    }
    float m = -1e30f;
    #pragma unroll
    for (int j = 0; j < 16; j++) m = fmaxf(m, v[j]);
    #pragma unroll
    for (int o = 16; o; o >>= 1) m = fmaxf(m, __shfl_xor_sync(0xffffffffu, m, o));
    float s = 0.f;
    #pragma unroll
    for (int j = 0; j < 16; j++) { v[j] = expf(v[j] - m); s += v[j]; }
    #pragma unroll
    for (int o = 16; o; o >>= 1) s += __shfl_xor_sync(0xffffffffu, s, o);
    float inv = 1.f / s;
    uint2* ph = (uint2*)(PH + (size_t)r * GS);
    uint2* pl = (uint2*)(PL + (size_t)r * GS);
    #pragma unroll
    for (int p = 0; p < 4; p++) {
        uint32_t h01, l01, h23, l23;
        split2(v[p*4+0] * inv, v[p*4+1] * inv, h01, l01);
        split2(v[p*4+2] * inv, v[p*4+3] * inv, h23, l23);
        ph[lane + 32 * p] = make_uint2(h01, h23);
        pl[lane + 32 * p] = make_uint2(l01, l23);
    }
}

// ================= V transpose + bf16 hi/lo: VT[gh][n=32][k=512] =================
__global__ __launch_bounds__(256) void k_vT(const float* __restrict__ V,
                                            __nv_bfloat16* __restrict__ VTH,
                                            __nv_bfloat16* __restrict__ VTL)
{
    __shared__ float t[128][33];
    int gh = blockIdx.y, g = gh >> 2, h = gh & 3;
    int k0 = blockIdx.x * 128;
    int tid = threadIdx.x;
    #pragma unroll
    for (int it = 0; it < 16; it++) {
        int idx = tid + it * 256;
        int r = idx >> 5, c = idx & 31;
        t[r][c] = V[((size_t)g * GS + k0 + r) * 128 + h * 32 + c];
    }
    __syncthreads();
    #pragma unroll
    for (int it = 0; it < 16; it++) {
        int idx = tid + it * 256;
        int n = idx >> 7, k = idx & 127;
        float v = t[k][n];
        __nv_bfloat16 hh = __float2bfloat16(v);
        size_t o = ((size_t)gh * 32 + n) * 512 + k0 + k;
        VTH[o] = hh;
        VTL[o] = __float2bfloat16(v - __bfloat162float(hh));
    }
}

// ================= O = P @ V via mma.sync; out bf16 hi/lo =================
// grid (4, 512 gh): 128 rows x 32 cols per CTA, K=512.
__global__ __launch_bounds__(256) void k_pv_mma(
    const __nv_bfloat16* __restrict__ PH, const __nv_bfloat16* __restrict__ PL,
    const __nv_bfloat16* __restrict__ VTH, const __nv_bfloat16* __restrict__ VTL,
    __nv_bfloat16* __restrict__ OH, __nv_bfloat16* __restrict__ OL)
{
    __shared__ __nv_bfloat16 sPh[128 * LDS_];
    __shared__ __nv_bfloat16 sPl[128 * LDS_];
    __shared__ __nv_bfloat16 sVh[32 * LDS_];
    __shared__ __nv_bfloat16 sVl[32 * LDS_];
    int gh = blockIdx.y, g = gh >> 2, h = gh & 3;
    int bm = blockIdx.x;
    int tid = threadIdx.x, lane = tid & 31, warp = tid >> 5;
    const __nv_bfloat16* pb_h = PH + (size_t)gh * GS * GS + (size_t)bm * 128 * GS;
    const __nv_bfloat16* pb_l = PL + (size_t)gh * GS * GS + (size_t)bm * 128 * GS;
    const __nv_bfloat16* vb_h = VTH + (size_t)gh * 32 * 512;
    const __nv_bfloat16* vb_l = VTL + (size_t)gh * 32 * 512;

    float d[4][4];
    #pragma unroll
    for (int ni = 0; ni < 4; ni++)
        #pragma unroll
        for (int j = 0; j < 4; j++) d[ni][j] = 0.f;

    for (int k0 = 0; k0 < GS; k0 += 32) {
        if (k0) __syncthreads();
        #pragma unroll
        for (int r = 0; r < 2; r++) {
            int idx = tid + r * 256;
            int row = idx >> 2, col = (idx & 3) * 8;
            int so = row * LDS_ + col;
            size_t go = (size_t)row * GS + k0 + col;
            *(uint4*)&sPh[so] = *(const uint4*)(pb_h + go);
            *(uint4*)&sPl[so] = *(const uint4*)(pb_l + go);
        }
        if (tid < 128) {
            int r = tid >> 2, c = (tid & 3) * 8;
            *(uint4*)&sVh[r * LDS_ + c] = *(const uint4*)(vb_h + (size_t)r * 512 + k0 + c);
        } else {
            int t2 = tid - 128;
            int r = t2 >> 2, c = (t2 & 3) * 8;
            *(uint4*)&sVl[r * LDS_ + c] = *(const uint4*)(vb_l + (size_t)r * 512 + k0 + c);
        }
        __syncthreads();
        #pragma unroll
        for (int ks = 0; ks < 2; ks++) {
            uint32_t ah[4], al[4];
            int arow = warp * 16 + (lane & 15);
            int acol = ks * 16 + (lane >> 4) * 8;
            LDMX4(ah, smem_u32(&sPh[arow * LDS_ + acol]));
            LDMX4(al, smem_u32(&sPl[arow * LDS_ + acol]));
            #pragma unroll
            for (int ni = 0; ni < 4; ni++) {
                uint32_t bh[2], bl[2];
                int brow = ni * 8 + (lane & 7);
                int bcol = ks * 16 + ((lane >> 3) & 1) * 8;
                LDMX2(bh, smem_u32(&sVh[brow * LDS_ + bcol]));
                LDMX2(bl, smem_u32(&sVl[brow * LDS_ + bcol]));
                MMA16816(d[ni], ah, bh);
                MMA16816(d[ni], al, bh);
                MMA16816(d[ni], ah, bl);
            }
        }
    }
    // epilogue: write attention output bf16 hi/lo
    int node = g * GS + bm * 128 + warp * 16 + (lane >> 2);
    #pragma unroll
    for (int ni = 0; ni < 4; ni++) {
        int col = h * 32 + ni * 8 + (lane & 3) * 2;
        uint32_t hh, ll;
        split2(d[ni][0], d[ni][1], hh, ll);
        *(uint32_t*)(OH + (size_t)node * 128 + col) = hh;
        *(uint32_t*)(OL + (size_t)node * 128 + col) = ll;
        split2(d[ni][2], d[ni][3], hh, ll);
        *(uint32_t*)(OH + (size_t)(node + 8) * 128 + col) = hh;
        *(uint32_t*)(OL + (size_t)(node + 8) * 128 + col) = ll;
    }
}

// ================= host orchestration =================
extern "C" void kernel_launch(void* const* d_in, const int* in_sizes, int n_in,
                              void* d_out, int out_size)
{
    const float* x   = (const float*)d_in[0];
    const int*   ei  = (const int*)  d_in[1];
    const float* W1  = (const float*)d_in[3];
    const float* a1s = (const float*)d_in[4];
    const float* a1d = (const float*)d_in[5];
    const float* b1  = (const float*)d_in[6];
    const float* W2  = (const float*)d_in[7];
    const float* a2s = (const float*)d_in[8];
    const float* a2d = (const float*)d_in[9];
    const float* b2  = (const float*)d_in[10];
    const float* W3  = (const float*)d_in[11];
    const float* a3s = (const float*)d_in[12];
    const float* a3d = (const float*)d_in[13];
    const float* b3  = (const float*)d_in[14];
    const float* g1  = (const float*)d_in[15];
    const float* be1 = (const float*)d_in[16];
    const float* g2  = (const float*)d_in[17];
    const float* be2 = (const float*)d_in[18];
    const float* Wr  = (const float*)d_in[19];
    const float* br  = (const float*)d_in[20];
    const float* Wq  = (const float*)d_in[21];
    const float* Wk  = (const float*)d_in[22];
    const float* Wv  = (const float*)d_in[23];
    const float* Wo  = (const float*)d_in[24];
    const float* bo  = (const float*)d_in[25];
    float* out = (float*)d_out;

    float* sb = nullptr;
    cudaGetSymbolAddress((void**)&sb, g_scratch);
    __nv_bfloat16* bb = nullptr;
    cudaGetSymbolAddress((void**)&bb, g_bf);

    float* p_h  = sb + OFF_H;
    float* p_h3 = sb + OFF_H3;
    float* p_r  = sb + OFF_R;
    float* p_v  = sb + OFF_V;
    float* p_S  = sb + OFF_S;
    float* p_es = sb + OFF_ES;
    float* p_ed = sb + OFF_ED;

    // CSR
    k_zero_cnt<<<NN / 256, 256>>>();
    k_count<<<1024, 256>>>(ei);
    k_scan<<<1, 1024>>>();
    k_fill<<<1152, 256>>>(ei);

    // weight conversions (transposed, hi/lo)
    k_cvt_wT<<<(256*64 + 255)/256, 256>>>(W1, bb + B_W1H, bb + B_W1L, 64, 256);
    k_cvt_wT<<<(256*256 + 255)/256, 256>>>(W2, bb + B_W2H, bb + B_W2L, 256, 256);
    k_cvt_wT<<<(128*256 + 255)/256, 256>>>(W3, bb + B_W3H, bb + B_W3L, 256, 128);
    k_cvt_wT<<<(128*64 + 255)/256, 256>>>(Wr, bb + B_WRH, bb + B_WRL, 64, 128);
    k_cvt_wT<<<(128*128 + 255)/256, 256>>>(Wq, bb + B_WQH, bb + B_WQL, 128, 128);
    k_cvt_wT<<<(128*128 + 255)/256, 256>>>(Wk, bb + B_WKH, bb + B_WKL, 128, 128);
    k_cvt_wT<<<(128*128 + 255)/256, 256>>>(Wv, bb + B_WVH, bb + B_WVL, 128, 128);
    k_cvt_wT<<<(128*128 + 255)/256, 256>>>(Wo, bb + B_WOH, bb + B_WOL, 128, 128);

    // x -> bf16 hi/lo
    k_cvt_split<<<(NN*64/4 + 255)/256, 256>>>(x, bb + B_XH, bb + B_XL, NN*64/4);

    // layer 1
    mma_gemm<<<dim3(2, 512), 256>>>(bb + B_XH, bb + B_XL, bb + B_W1H, bb + B_W1L,
                                    nullptr, p_h, nullptr, nullptr, NN, 256, 64);
    k_scores<<<(NN * 4) / 256, 256>>>(p_h, a1s, a1d, p_es, p_ed, 4, 64);
    k_gat_agg<256, 4><<<NN / 8, 256>>>(p_h, p_es, p_ed, b1, g1, be1, nullptr,
                                       bb + B_TH, bb + B_TL);
    // layer 2
    mma_gemm<<<dim3(2, 512), 256>>>(bb + B_TH, bb + B_TL, bb + B_W2H, bb + B_W2L,
                                    nullptr, p_h, nullptr, nullptr, NN, 256, 256);
    k_scores<<<(NN * 4) / 256, 256>>>(p_h, a2s, a2d, p_es, p_ed, 4, 64);
    k_gat_agg<256, 4><<<NN / 8, 256>>>(p_h, p_es, p_ed, b2, g2, be2, nullptr,
                                       bb + B_TH, bb + B_TL);
    // layer 3 + residual
    mma_gemm<<<dim3(1, 512), 256>>>(bb + B_TH, bb + B_TL, bb + B_W3H, bb + B_W3L,
                                    nullptr, p_h3, nullptr, nullptr, NN, 128, 256);
    k_scores<<<NN / 256, 256>>>(p_h3, a3s, a3d, p_es, p_ed, 1, 128);
    mma_gemm<<<dim3(1, 512), 256>>>(bb + B_XH, bb + B_XL, bb + B_WRH, bb + B_WRL,
                                    br, p_r, nullptr, nullptr, NN, 128, 64);
    k_gat_agg<128, 1><<<NN / 8, 256>>>(p_h3, p_es, p_ed, b3, nullptr, nullptr, p_r,
                                       bb + B_HRH, bb + B_HRL);
    // MHA projections: Q,K -> bf16 hi/lo direct; V -> fp32 (for transpose)
    mma_gemm<<<dim3(1, 512), 256>>>(bb + B_HRH, bb + B_HRL, bb + B_WQH, bb + B_WQL,
                                    nullptr, nullptr, bb + B_QH, bb + B_QL, NN, 128, 128);
    mma_gemm<<<dim3(1, 512), 256>>>(bb + B_HRH, bb + B_HRL, bb + B_WKH, bb + B_WKL,
                                    nullptr, nullptr, bb + B_KH, bb + B_KL, NN, 128, 128);
    mma_gemm<<<dim3(1, 512), 256>>>(bb + B_HRH, bb + B_HRL, bb + B_WVH, bb + B_WVL,
                                    nullptr, p_v, nullptr, nullptr, NN, 128, 128);
    k_vT<<<dim3(4, NG * 4), 256>>>(p_v, bb + B_VTH, bb + B_VTL);
    // attention
    k_qkT_mma<<<dim3(4, 4, NG * 4), 256>>>(bb + B_QH, bb + B_QL, bb + B_KH, bb + B_KL, p_S);
    k_softmax2<<<(NG * 4 * GS) / 8, 256>>>(p_S, bb + B_PH, bb + B_PL);
    k_pv_mma<<<dim3(4, NG * 4), 256>>>(bb + B_PH, bb + B_PL, bb + B_VTH, bb + B_VTL,
                                       bb + B_AOH, bb + B_AOL);
    // output projection
    mma_gemm<<<dim3(1, 512), 256>>>(bb + B_AOH, bb + B_AOL, bb + B_WOH, bb + B_WOL,
                                    bo, out, nullptr, nullptr, NN, 128, 128);
}

// round 5
// speedup vs baseline: 1.6151x; 1.1988x over previous
#include <cuda_runtime.h>
#include <cuda_bf16.h>
#include <math.h>
#include <stdint.h>

// ---------------- problem constants ----------------
constexpr int NN   = 65536;          // nodes
constexpr int NE   = 524288;         // raw edges
constexpr int ET   = NE + NN;        // edges + self loops
constexpr int GS   = 512;            // graph size
constexpr int NG   = NN / GS;        // 128 graphs
constexpr int D1   = 256;            // heads*hid
constexpr int D3   = 128;            // out dim

// ---------------- fp32 scratch ----------------
constexpr size_t OFF_H    = 0;                        // NN*256
constexpr size_t OFF_H3   = OFF_H  + (size_t)NN*D1;   // NN*128
constexpr size_t OFF_R    = OFF_H3 + (size_t)NN*D3;   // NN*128
constexpr size_t OFF_V    = OFF_R  + (size_t)NN*D3;   // NN*128
constexpr size_t OFF_ES   = OFF_V  + (size_t)NN*D3;
constexpr size_t OFF_ED   = OFF_ES + (size_t)NN*4;
constexpr size_t SCRATCH  = OFF_ED + (size_t)NN*4;

__device__ __align__(256) float g_scratch[SCRATCH];

// ---------------- bf16 scratch ----------------
constexpr size_t B_XH  = 0;
constexpr size_t B_XL  = B_XH  + (size_t)NN*64;
constexpr size_t B_TH  = B_XL  + (size_t)NN*64;
constexpr size_t B_TL  = B_TH  + (size_t)NN*256;
constexpr size_t B_HRH = B_TL  + (size_t)NN*256;
constexpr size_t B_HRL = B_HRH + (size_t)NN*128;
constexpr size_t B_AOH = B_HRL + (size_t)NN*128;
constexpr size_t B_AOL = B_AOH + (size_t)NN*128;
constexpr size_t B_QH  = B_AOL + (size_t)NN*128;
constexpr size_t B_QL  = B_QH  + (size_t)NN*128;
constexpr size_t B_KH  = B_QL  + (size_t)NN*128;
constexpr size_t B_KL  = B_KH  + (size_t)NN*128;
constexpr size_t B_VTH = B_KL  + (size_t)NN*128;
constexpr size_t B_VTL = B_VTH + (size_t)NN*128;
constexpr size_t B_W1H = B_VTL + (size_t)NN*128;
constexpr size_t B_W1L = B_W1H + 256*64;
constexpr size_t B_W2H = B_W1L + 256*64;
constexpr size_t B_W2L = B_W2H + 256*256;
constexpr size_t B_W3H = B_W2L + 256*256;
constexpr size_t B_W3L = B_W3H + 128*256;
constexpr size_t B_WRH = B_W3L + 128*256;
constexpr size_t B_WRL = B_WRH + 128*64;
constexpr size_t B_WQH = B_WRL + 128*64;
constexpr size_t B_WQL = B_WQH + 128*128;
constexpr size_t B_WKH = B_WQL + 128*128;
constexpr size_t B_WKL = B_WKH + 128*128;
constexpr size_t B_WVH = B_WKL + 128*128;
constexpr size_t B_WVL = B_WVH + 128*128;
constexpr size_t B_WOH = B_WVL + 128*128;
constexpr size_t B_WOL = B_WOH + 128*128;
constexpr size_t BF_TOTAL = B_WOL + 128*128;

__device__ __align__(256) __nv_bfloat16 g_bf[BF_TOTAL];

__device__ int g_rowptr[NN + 1];
__device__ int g_cnt[NN];
__device__ int g_cursor[NN];
__device__ int g_col[ET];

// ================= helpers =================
__device__ __forceinline__ uint32_t smem_u32(const void* p) {
    uint32_t a;
    asm("{ .reg .u64 t; cvta.to.shared.u64 t, %1; cvt.u32.u64 %0, t; }" : "=r"(a) : "l"(p));
    return a;
}
#define LDMX4(r, a) \
    asm volatile("ldmatrix.sync.aligned.m8n8.x4.shared.b16 {%0,%1,%2,%3}, [%4];" \
        : "=r"((r)[0]), "=r"((r)[1]), "=r"((r)[2]), "=r"((r)[3]) : "r"(a))
#define LDMX2(r, a) \
    asm volatile("ldmatrix.sync.aligned.m8n8.x2.shared.b16 {%0,%1}, [%2];" \
        : "=r"((r)[0]), "=r"((r)[1]) : "r"(a))
#define MMA16816(d, a, b) \
    asm volatile("mma.sync.aligned.m16n8k16.row.col.f32.bf16.bf16.f32 " \
        "{%0,%1,%2,%3}, {%4,%5,%6,%7}, {%8,%9}, {%0,%1,%2,%3};" \
        : "+f"((d)[0]), "+f"((d)[1]), "+f"((d)[2]), "+f"((d)[3]) \
        : "r"((a)[0]), "r"((a)[1]), "r"((a)[2]), "r"((a)[3]), \
          "r"((b)[0]), "r"((b)[1]))

__device__ __forceinline__ void split2(float v0, float v1, uint32_t& hh, uint32_t& ll) {
    __nv_bfloat16 h0 = __float2bfloat16(v0), h1 = __float2bfloat16(v1);
    __nv_bfloat16 l0 = __float2bfloat16(v0 - __bfloat162float(h0));
    __nv_bfloat16 l1 = __float2bfloat16(v1 - __bfloat162float(h1));
    __nv_bfloat162 H; H.x = h0; H.y = h1;
    __nv_bfloat162 L; L.x = l0; L.y = l1;
    hh = *(uint32_t*)&H; ll = *(uint32_t*)&L;
}

// ================= CSR build =================
__global__ void k_zero_cnt() {
    int i = blockIdx.x * blockDim.x + threadIdx.x;
    if (i < NN) g_cnt[i] = 0;
}
__global__ void k_count(const int* __restrict__ ei) {
    int stride = gridDim.x * blockDim.x;
    for (int idx = blockIdx.x * blockDim.x + threadIdx.x; idx < NE; idx += stride)
        atomicAdd(&g_cnt[ei[NE + idx]], 1);
}
__global__ void k_scan() {
    __shared__ int warpsum[32];
    __shared__ int s_carry;
    int tid = threadIdx.x, lane = tid & 31, wid = tid >> 5;
    if (tid == 0) s_carry = 0;
    __syncthreads();
    for (int base = 0; base < NN; base += 1024) {
        int v = g_cnt[base + tid] + 1;
        int x = v;
        #pragma unroll
        for (int o = 1; o < 32; o <<= 1) {
            int t = __shfl_up_sync(0xffffffffu, x, o);
            if (lane >= o) x += t;
        }
        if (lane == 31) warpsum[wid] = x;
        __syncthreads();
        if (wid == 0) {
            int w = warpsum[lane];
            #pragma unroll
            for (int o = 1; o < 32; o <<= 1) {
                int t = __shfl_up_sync(0xffffffffu, w, o);
                if (lane >= o) w += t;
            }
            warpsum[lane] = w;
        }
        __syncthreads();
        int excl = (x - v) + (wid > 0 ? warpsum[wid - 1] : 0) + s_carry;
        g_rowptr[base + tid] = excl;
        g_cursor[base + tid] = excl;
        __syncthreads();
        if (tid == 1023) s_carry = excl + v;
        __syncthreads();
    }
    if (tid == 0) g_rowptr[NN] = ET;
}
__global__ void k_fill(const int* __restrict__ ei) {
    int stride = gridDim.x * blockDim.x;
    for (int idx = blockIdx.x * blockDim.x + threadIdx.x; idx < ET; idx += stride) {
        int s, d;
        if (idx < NE) { s = ei[idx]; d = ei[NE + idx]; }
        else          { s = d = idx - NE; }
        int pos = atomicAdd(&g_cursor[d], 1);
        g_col[pos] = s;
    }
}

// ================= fp32 -> bf16 hi/lo split (x only) =================
__global__ void k_cvt_split(const float* __restrict__ in, __nv_bfloat16* __restrict__ hi,
                            __nv_bfloat16* __restrict__ lo, int n4) {
    int i = blockIdx.x * blockDim.x + threadIdx.x;
    if (i >= n4) return;
    float4 v = ((const float4*)in)[i];
    uint32_t h01, l01, h23, l23;
    split2(v.x, v.y, h01, l01);
    split2(v.z, v.w, h23, l23);
    ((uint32_t*)hi)[2 * i] = h01; ((uint32_t*)hi)[2 * i + 1] = h23;
    ((uint32_t*)lo)[2 * i] = l01; ((uint32_t*)lo)[2 * i + 1] = l23;
}

// transpose weight W[K,N] -> WT hi/lo [N,K]
__global__ void k_cvt_wT(const float* __restrict__ W, __nv_bfloat16* __restrict__ hiT,
                         __nv_bfloat16* __restrict__ loT, int K, int N) {
    int idx = blockIdx.x * blockDim.x + threadIdx.x;
    if (idx >= N * K) return;
    int n = idx / K, k = idx % K;
    float v = W[(size_t)k * N + n];
    __nv_bfloat16 h = __float2bfloat16(v);
    hiT[idx] = h;
    loT[idx] = __float2bfloat16(v - __bfloat162float(h));
}

// ================= mma.sync bf16-split GEMM =================
constexpr int LDS_ = 40;

__global__ __launch_bounds__(256) void mma_gemm(
    const __nv_bfloat16* __restrict__ Ah, const __nv_bfloat16* __restrict__ Al,
    const __nv_bfloat16* __restrict__ Bh, const __nv_bfloat16* __restrict__ Bl,
    const float* __restrict__ bias, float* __restrict__ C,
    __nv_bfloat16* __restrict__ Chi, __nv_bfloat16* __restrict__ Clo,
    int M, int N, int K)
{
    __shared__ __nv_bfloat16 sAh[128 * LDS_];
    __shared__ __nv_bfloat16 sAl[128 * LDS_];
    __shared__ __nv_bfloat16 sBh[128 * LDS_];
    __shared__ __nv_bfloat16 sBl[128 * LDS_];

    int tid = threadIdx.x, lane = tid & 31, warp = tid >> 5;
    int wm = warp & 3, wn = warp >> 2;
    int bm = blockIdx.y, bn = blockIdx.x;
    const __nv_bfloat16* gAh = Ah + (size_t)bm * 128 * K;
    const __nv_bfloat16* gAl = Al + (size_t)bm * 128 * K;
    const __nv_bfloat16* gBh = Bh + (size_t)bn * 128 * K;
    const __nv_bfloat16* gBl = Bl + (size_t)bn * 128 * K;

    float d[2][8][4];
    #pragma unroll
    for (int mi = 0; mi < 2; mi++)
        #pragma unroll
        for (int ni = 0; ni < 8; ni++)
            #pragma unroll
            for (int j = 0; j < 4; j++) d[mi][ni][j] = 0.f;

    for (int k0 = 0; k0 < K; k0 += 32) {
        if (k0) __syncthreads();
        #pragma unroll
        for (int r = 0; r < 2; r++) {
            int idx = tid + r * 256;
            int row = idx >> 2, seg = idx & 3;
            size_t go = (size_t)row * K + k0 + seg * 8;
            int so = row * LDS_ + seg * 8;
            *(uint4*)&sAh[so] = *(const uint4*)(gAh + go);
            *(uint4*)&sAl[so] = *(const uint4*)(gAl + go);
            *(uint4*)&sBh[so] = *(const uint4*)(gBh + go);
            *(uint4*)&sBl[so] = *(const uint4*)(gBl + go);
        }
        __syncthreads();
        #pragma unroll
        for (int ks = 0; ks < 2; ks++) {
            uint32_t ah[2][4], al[2][4];
            #pragma unroll
            for (int mi = 0; mi < 2; mi++) {
                int row = wm * 32 + mi * 16 + (lane & 15);
                int col = ks * 16 + (lane >> 4) * 8;
                LDMX4(ah[mi], smem_u32(&sAh[row * LDS_ + col]));
                LDMX4(al[mi], smem_u32(&sAl[row * LDS_ + col]));
            }
            #pragma unroll
            for (int ni = 0; ni < 8; ni++) {
                uint32_t bh[2], bl[2];
                int row = wn * 64 + ni * 8 + (lane & 7);
                int col = ks * 16 + ((lane >> 3) & 1) * 8;
                LDMX2(bh, smem_u32(&sBh[row * LDS_ + col]));
                LDMX2(bl, smem_u32(&sBl[row * LDS_ + col]));
                #pragma unroll
                for (int mi = 0; mi < 2; mi++) {
                    MMA16816(d[mi][ni], ah[mi], bh);
                    MMA16816(d[mi][ni], al[mi], bh);
                    MMA16816(d[mi][ni], ah[mi], bl);
                }
            }
        }
    }
    #pragma unroll
    for (int mi = 0; mi < 2; mi++) {
        int row = bm * 128 + wm * 32 + mi * 16 + (lane >> 2);
        #pragma unroll
        for (int ni = 0; ni < 8; ni++) {
            int col = bn * 128 + wn * 64 + ni * 8 + (lane & 3) * 2;
            if (C) {
                float b0 = bias ? bias[col] : 0.f;
                float b1 = bias ? bias[col + 1] : 0.f;
                *(float2*)(C + (size_t)row * N + col) =
                    make_float2(d[mi][ni][0] + b0, d[mi][ni][1] + b1);
                *(float2*)(C + (size_t)(row + 8) * N + col) =
                    make_float2(d[mi][ni][2] + b0, d[mi][ni][3] + b1);
            } else {
                uint32_t hh, ll;
                split2(d[mi][ni][0], d[mi][ni][1], hh, ll);
                *(uint32_t*)(Chi + (size_t)row * N + col) = hh;
                *(uint32_t*)(Clo + (size_t)row * N + col) = ll;
                split2(d[mi][ni][2], d[mi][ni][3], hh, ll);
                *(uint32_t*)(Chi + (size_t)(row + 8) * N + col) = hh;
                *(uint32_t*)(Clo + (size_t)(row + 8) * N + col) = ll;
            }
        }
    }
}

// ================= GAT score vectors =================
__global__ void k_scores(const float* __restrict__ h, const float* __restrict__ as_,
                         const float* __restrict__ ad_, float* __restrict__ es,
                         float* __restrict__ ed, int H, int C)
{
    int idx = blockIdx.x * blockDim.x + threadIdx.x;
    if (idx >= NN * H) return;
    int node = idx / H, hd = idx % H;
    const float4* hp = (const float4*)(h + (size_t)node * H * C + (size_t)hd * C);
    const float4* ap = (const float4*)(as_ + (size_t)hd * C);
    const float4* bp = (const float4*)(ad_ + (size_t)hd * C);
    float s = 0.f, d = 0.f;
    for (int c = 0; c < C / 4; c++) {
        float4 hv = hp[c], av = ap[c], bv = bp[c];
        s += hv.x * av.x + hv.y * av.y + hv.z * av.z + hv.w * av.w;
        d += hv.x * bv.x + hv.y * bv.y + hv.z * bv.z + hv.w * bv.w;
    }
    es[idx] = s;
    ed[idx] = d;
}

// ================= GAT aggregation =================
template <int D, int H>
__global__ __launch_bounds__(256) void k_gat_agg(
    const float* __restrict__ hfeat, const float* __restrict__ es,
    const float* __restrict__ ed, const float* __restrict__ bias,
    const float* __restrict__ gamma, const float* __restrict__ beta,
    const float* __restrict__ resid,
    __nv_bfloat16* __restrict__ outH, __nv_bfloat16* __restrict__ outL)
{
    constexpr int C = D / H;
    constexpr int R = D / 32;
    int warp = (blockIdx.x * blockDim.x + threadIdx.x) >> 5;
    int lane = threadIdx.x & 31;
    if (warp >= NN) return;
    int i = warp;
    int beg = g_rowptr[i], end = g_rowptr[i + 1];

    float edv[H], m[H], z[H];
    #pragma unroll
    for (int h = 0; h < H; h++) {
        edv[h] = ed[(size_t)i * H + h];
        m[h] = -1e30f; z[h] = 0.f;
    }
    for (int e = beg + lane; e < end; e += 32) {
        int s = g_col[e];
        #pragma unroll
        for (int h = 0; h < H; h++) {
            float v = es[(size_t)s * H + h] + edv[h];
            v = v > 0.f ? v : 0.2f * v;
            m[h] = fmaxf(m[h], v);
        }
    }
    #pragma unroll
    for (int h = 0; h < H; h++)
        #pragma unroll
        for (int o = 16; o; o >>= 1)
            m[h] = fmaxf(m[h], __shfl_xor_sync(0xffffffffu, m[h], o));
    for (int e = beg + lane; e < end; e += 32) {
        int s = g_col[e];
        #pragma unroll
        for (int h = 0; h < H; h++) {
            float v = es[(size_t)s * H + h] + edv[h];
            v = v > 0.f ? v : 0.2f * v;
            z[h] += expf(v - m[h]);
        }
    }
    #pragma unroll
    for (int h = 0; h < H; h++) {
        #pragma unroll
        for (int o = 16; o; o >>= 1)
            z[h] += __shfl_xor_sync(0xffffffffu, z[h], o);
        z[h] = 1.f / (z[h] + 1e-16f);
    }
    float acc[R];
    #pragma unroll
    for (int j = 0; j < R; j++) acc[j] = 0.f;
    for (int e = beg; e < end; e++) {
        int s = g_col[e];
        float al[H];
        #pragma unroll
        for (int h = 0; h < H; h++) {
            float v = es[(size_t)s * H + h] + edv[h];
            v = v > 0.f ? v : 0.2f * v;
            al[h] = expf(v - m[h]);
        }
        const float* hs = hfeat + (size_t)s * D;
        #pragma unroll
        for (int j = 0; j < R; j++) {
            int c = lane + 32 * j;
            acc[j] += al[(32 * j) / C] * hs[c];
        }
    }
    float x[R];
    #pragma unroll
    for (int j = 0; j < R; j++) {
        int c = lane + 32 * j;
        float val = acc[j] * z[(32 * j) / C] + bias[c];
        if (resid) val += resid[(size_t)i * D + c];
        x[j] = val;
    }
    if (gamma) {
        #pragma unroll
        for (int j = 0; j < R; j++)
            x[j] = x[j] > 0.f ? x[j] : (expf(x[j]) - 1.f);
        float s = 0.f;
        #pragma unroll
        for (int j = 0; j < R; j++) s += x[j];
        #pragma unroll
        for (int o = 16; o; o >>= 1) s += __shfl_xor_sync(0xffffffffu, s, o);
        float mu = s / (float)D;
        float vs = 0.f;
        #pragma unroll
        for (int j = 0; j < R; j++) { float d = x[j] - mu; vs += d * d; }
        #pragma unroll
        for (int o = 16; o; o >>= 1) vs += __shfl_xor_sync(0xffffffffu, vs, o);
        float inv = rsqrtf(vs / (float)D + 1e-5f);
        #pragma unroll
        for (int j = 0; j < R; j++) {
            int c = lane + 32 * j;
            x[j] = (x[j] - mu) * inv * gamma[c] + beta[c];
        }
    }
    #pragma unroll
    for (int j = 0; j < R; j++) {
        size_t idx = (size_t)i * D + lane + 32 * j;
        __nv_bfloat16 h = __float2bfloat16(x[j]);
        outH[idx] = h;
        outL[idx] = __float2bfloat16(x[j] - __bfloat162float(h));
    }
}

// ================= V transpose + bf16 hi/lo: VT[gh][n=32][k=512] =================
__global__ __launch_bounds__(256) void k_vT(const float* __restrict__ V,
                                            __nv_bfloat16* __restrict__ VTH,
                                            __nv_bfloat16* __restrict__ VTL)
{
    __shared__ float t[128][33];
    int gh = blockIdx.y, g = gh >> 2, h = gh & 3;
    int k0 = blockIdx.x * 128;
    int tid = threadIdx.x;
    #pragma unroll
    for (int it = 0; it < 16; it++) {
        int idx = tid + it * 256;
        int r = idx >> 5, c = idx & 31;
        t[r][c] = V[((size_t)g * GS + k0 + r) * 128 + h * 32 + c];
    }
    __syncthreads();
    #pragma unroll
    for (int it = 0; it < 16; it++) {
        int idx = tid + it * 256;
        int n = idx >> 7, k = idx & 127;
        float v = t[k][n];
        __nv_bfloat16 hh = __float2bfloat16(v);
        size_t o = ((size_t)gh * 32 + n) * 512 + k0 + k;
        VTH[o] = hh;
        VTL[o] = __float2bfloat16(v - __bfloat162float(hh));
    }
}

// ================= fused flash attention =================
// grid (4 qtiles, 512 gh), 256 threads. Whole K/V head in smem; S in registers.
constexpr int VPAD = 520;
constexpr int SM_QH = 0;
constexpr int SM_QL = SM_QH + 128 * LDS_;
constexpr int SM_KH = SM_QL + 128 * LDS_;
constexpr int SM_KL = SM_KH + 512 * LDS_;
constexpr int SM_VH = SM_KL + 512 * LDS_;
constexpr int SM_VL = SM_VH + 32 * VPAD;
constexpr int SM_TOT = SM_VL + 32 * VPAD;
constexpr int FLASH_SMEM = SM_TOT * 2;

__global__ __launch_bounds__(256) void k_flash(
    const __nv_bfloat16* __restrict__ QH, const __nv_bfloat16* __restrict__ QL,
    const __nv_bfloat16* __restrict__ KH, const __nv_bfloat16* __restrict__ KL,
    const __nv_bfloat16* __restrict__ VTH, const __nv_bfloat16* __restrict__ VTL,
    __nv_bfloat16* __restrict__ OHo, __nv_bfloat16* __restrict__ OLo)
{
    extern __shared__ __nv_bfloat16 sm[];
    int gh = blockIdx.y, g = gh >> 2, h = gh & 3;
    int qt = blockIdx.x;
    int tid = threadIdx.x, lane = tid & 31, warp = tid >> 5;

    // load K (512x32), Q tile (128x32), V^T (32x512) hi/lo into smem
    {
        const __nv_bfloat16* kh = KH + (size_t)g * GS * 128 + h * 32;
        const __nv_bfloat16* kl = KL + (size_t)g * GS * 128 + h * 32;
        #pragma unroll
        for (int it = 0; it < 8; it++) {
            int idx = tid + it * 256;
            int row = idx >> 2, seg = (idx & 3) * 8;
            *(uint4*)&sm[SM_KH + row * LDS_ + seg] = *(const uint4*)(kh + (size_t)row * 128 + seg);
            *(uint4*)&sm[SM_KL + row * LDS_ + seg] = *(const uint4*)(kl + (size_t)row * 128 + seg);
        }
        const __nv_bfloat16* qh = QH + ((size_t)g * GS + qt * 128) * 128 + h * 32;
        const __nv_bfloat16* ql = QL + ((size_t)g * GS + qt * 128) * 128 + h * 32;
        #pragma unroll
        for (int it = 0; it < 2; it++) {
            int idx = tid + it * 256;
            int row = idx >> 2, seg = (idx & 3) * 8;
            *(uint4*)&sm[SM_QH + row * LDS_ + seg] = *(const uint4*)(qh + (size_t)row * 128 + seg);
            *(uint4*)&sm[SM_QL + row * LDS_ + seg] = *(const uint4*)(ql + (size_t)row * 128 + seg);
        }
        const __nv_bfloat16* vh = VTH + (size_t)gh * 32 * 512;
        const __nv_bfloat16* vl = VTL + (size_t)gh * 32 * 512;
        #pragma unroll
        for (int it = 0; it < 8; it++) {
            int idx = tid + it * 256;
            int row = idx >> 6, c8 = (idx & 63) * 8;
            *(uint4*)&sm[SM_VH + row * VPAD + c8] = *(const uint4*)(vh + (size_t)row * 512 + c8);
            *(uint4*)&sm[SM_VL + row * VPAD + c8] = *(const uint4*)(vl + (size_t)row * 512 + c8);
        }
    }
    __syncthreads();

    // Q fragments (resident)
    uint32_t qh_[2][4], ql_[2][4];
    #pragma unroll
    for (int kf = 0; kf < 2; kf++) {
        int row = warp * 16 + (lane & 15);
        int col = kf * 16 + (lane >> 4) * 8;
        LDMX4(qh_[kf], smem_u32(&sm[SM_QH + row * LDS_ + col]));
        LDMX4(ql_[kf], smem_u32(&sm[SM_QL + row * LDS_ + col]));
    }

    float m0 = -1e30f, m1 = -1e30f, l0 = 0.f, l1 = 0.f;
    float O[4][4];
    #pragma unroll
    for (int n = 0; n < 4; n++)
        #pragma unroll
        for (int j = 0; j < 4; j++) O[n][j] = 0.f;

    const float scale = 0.088388347648318447f;   // 1/sqrt(128)

    for (int kt = 0; kt < 4; kt++) {
        float S[16][4];
        #pragma unroll
        for (int j = 0; j < 16; j++)
            #pragma unroll
            for (int r = 0; r < 4; r++) S[j][r] = 0.f;
        #pragma unroll
        for (int j = 0; j < 16; j++) {
            #pragma unroll
            for (int kf = 0; kf < 2; kf++) {
                uint32_t bh[2], bl[2];
                int row = kt * 128 + j * 8 + (lane & 7);
                int col = kf * 16 + ((lane >> 3) & 1) * 8;
                LDMX2(bh, smem_u32(&sm[SM_KH + row * LDS_ + col]));
                LDMX2(bl, smem_u32(&sm[SM_KL + row * LDS_ + col]));
                MMA16816(S[j], qh_[kf], bh);
                MMA16816(S[j], ql_[kf], bh);
                MMA16816(S[j], qh_[kf], bl);
            }
        }
        // scale + row max
        float mx0 = -1e30f, mx1 = -1e30f;
        #pragma unroll
        for (int j = 0; j < 16; j++) {
            S[j][0] *= scale; S[j][1] *= scale; S[j][2] *= scale; S[j][3] *= scale;
            mx0 = fmaxf(mx0, fmaxf(S[j][0], S[j][1]));
            mx1 = fmaxf(mx1, fmaxf(S[j][2], S[j][3]));
        }
        #pragma unroll
        for (int o = 1; o < 4; o <<= 1) {
            mx0 = fmaxf(mx0, __shfl_xor_sync(0xffffffffu, mx0, o));
            mx1 = fmaxf(mx1, __shfl_xor_sync(0xffffffffu, mx1, o));
        }
        float nm0 = fmaxf(m0, mx0), nm1 = fmaxf(m1, mx1);
        float a0 = expf(m0 - nm0), a1 = expf(m1 - nm1);
        float rs0 = 0.f, rs1 = 0.f;
        #pragma unroll
        for (int j = 0; j < 16; j++) {
            S[j][0] = expf(S[j][0] - nm0); S[j][1] = expf(S[j][1] - nm0);
            S[j][2] = expf(S[j][2] - nm1); S[j][3] = expf(S[j][3] - nm1);
            rs0 += S[j][0] + S[j][1];
            rs1 += S[j][2] + S[j][3];
        }
        #pragma unroll
        for (int o = 1; o < 4; o <<= 1) {
            rs0 += __shfl_xor_sync(0xffffffffu, rs0, o);
            rs1 += __shfl_xor_sync(0xffffffffu, rs1, o);
        }
        l0 = l0 * a0 + rs0;
        l1 = l1 * a1 + rs1;
        #pragma unroll
        for (int n = 0; n < 4; n++) {
            O[n][0] *= a0; O[n][1] *= a0; O[n][2] *= a1; O[n][3] *= a1;
        }
        m0 = nm0; m1 = nm1;
        // P @ V
        #pragma unroll
        for (int jp = 0; jp < 8; jp++) {
            uint32_t aph[4], apl[4];
            split2(S[2 * jp][0],     S[2 * jp][1],     aph[0], apl[0]);
            split2(S[2 * jp][2],     S[2 * jp][3],     aph[1], apl[1]);
            split2(S[2 * jp + 1][0], S[2 * jp + 1][1], aph[2], apl[2]);
            split2(S[2 * jp + 1][2], S[2 * jp + 1][3], aph[3], apl[3]);
            #pragma unroll
            for (int n = 0; n < 4; n++) {
                uint32_t bh[2], bl[2];
                int row = n * 8 + (lane & 7);
                int col = kt * 128 + jp * 16 + ((lane >> 3) & 1) * 8;
                LDMX2(bh, smem_u32(&sm[SM_VH + row * VPAD + col]));
                LDMX2(bl, smem_u32(&sm[SM_VL + row * VPAD + col]));
                MMA16816(O[n], aph, bh);
                MMA16816(O[n], apl, bh);
                MMA16816(O[n], aph, bl);
            }
        }
    }
    // epilogue
    float il0 = 1.f / l0, il1 = 1.f / l1;
    int node = g * GS + qt * 128 + warp * 16 + (lane >> 2);
    #pragma unroll
    for (int n = 0; n < 4; n++) {
        int col = h * 32 + n * 8 + (lane & 3) * 2;
        uint32_t hh, ll;
        split2(O[n][0] * il0, O[n][1] * il0, hh, ll);
        *(uint32_t*)(OHo + (size_t)node * 128 + col) = hh;
        *(uint32_t*)(OLo + (size_t)node * 128 + col) = ll;
        split2(O[n][2] * il1, O[n][3] * il1, hh, ll);
        *(uint32_t*)(OHo + (size_t)(node + 8) * 128 + col) = hh;
        *(uint32_t*)(OLo + (size_t)(node + 8) * 128 + col) = ll;
    }
}

// ================= host orchestration =================
extern "C" void kernel_launch(void* const* d_in, const int* in_sizes, int n_in,
                              void* d_out, int out_size)
{
    const float* x   = (const float*)d_in[0];
    const int*   ei  = (const int*)  d_in[1];
    const float* W1  = (const float*)d_in[3];
    const float* a1s = (const float*)d_in[4];
    const float* a1d = (const float*)d_in[5];
    const float* b1  = (const float*)d_in[6];
    const float* W2  = (const float*)d_in[7];
    const float* a2s = (const float*)d_in[8];
    const float* a2d = (const float*)d_in[9];
    const float* b2  = (const float*)d_in[10];
    const float* W3  = (const float*)d_in[11];
    const float* a3s = (const float*)d_in[12];
    const float* a3d = (const float*)d_in[13];
    const float* b3  = (const float*)d_in[14];
    const float* g1  = (const float*)d_in[15];
    const float* be1 = (const float*)d_in[16];
    const float* g2  = (const float*)d_in[17];
    const float* be2 = (const float*)d_in[18];
    const float* Wr  = (const float*)d_in[19];
    const float* br  = (const float*)d_in[20];
    const float* Wq  = (const float*)d_in[21];
    const float* Wk  = (const float*)d_in[22];
    const float* Wv  = (const float*)d_in[23];
    const float* Wo  = (const float*)d_in[24];
    const float* bo  = (const float*)d_in[25];
    float* out = (float*)d_out;

    float* sb = nullptr;
    cudaGetSymbolAddress((void**)&sb, g_scratch);
    __nv_bfloat16* bb = nullptr;
    cudaGetSymbolAddress((void**)&bb, g_bf);
    cudaFuncSetAttribute(k_flash, cudaFuncAttributeMaxDynamicSharedMemorySize, FLASH_SMEM);

    float* p_h  = sb + OFF_H;
    float* p_h3 = sb + OFF_H3;
    float* p_r  = sb + OFF_R;
    float* p_v  = sb + OFF_V;
    float* p_es = sb + OFF_ES;
    float* p_ed = sb + OFF_ED;

    // CSR
    k_zero_cnt<<<NN / 256, 256>>>();
    k_count<<<1024, 256>>>(ei);
    k_scan<<<1, 1024>>>();
    k_fill<<<1152, 256>>>(ei);

    // weight conversions (transposed, hi/lo)
    k_cvt_wT<<<(256*64 + 255)/256, 256>>>(W1, bb + B_W1H, bb + B_W1L, 64, 256);
    k_cvt_wT<<<(256*256 + 255)/256, 256>>>(W2, bb + B_W2H, bb + B_W2L, 256, 256);
    k_cvt_wT<<<(128*256 + 255)/256, 256>>>(W3, bb + B_W3H, bb + B_W3L, 256, 128);
    k_cvt_wT<<<(128*64 + 255)/256, 256>>>(Wr, bb + B_WRH, bb + B_WRL, 64, 128);
    k_cvt_wT<<<(128*128 + 255)/256, 256>>>(Wq, bb + B_WQH, bb + B_WQL, 128, 128);
    k_cvt_wT<<<(128*128 + 255)/256, 256>>>(Wk, bb + B_WKH, bb + B_WKL, 128, 128);
    k_cvt_wT<<<(128*128 + 255)/256, 256>>>(Wv, bb + B_WVH, bb + B_WVL, 128, 128);
    k_cvt_wT<<<(128*128 + 255)/256, 256>>>(Wo, bb + B_WOH, bb + B_WOL, 128, 128);

    // x -> bf16 hi/lo
    k_cvt_split<<<(NN*64/4 + 255)/256, 256>>>(x, bb + B_XH, bb + B_XL, NN*64/4);

    // layer 1
    mma_gemm<<<dim3(2, 512), 256>>>(bb + B_XH, bb + B_XL, bb + B_W1H, bb + B_W1L,
                                    nullptr, p_h, nullptr, nullptr, NN, 256, 64);
    k_scores<<<(NN * 4) / 256, 256>>>(p_h, a1s, a1d, p_es, p_ed, 4, 64);
    k_gat_agg<256, 4><<<NN / 8, 256>>>(p_h, p_es, p_ed, b1, g1, be1, nullptr,
                                       bb + B_TH, bb + B_TL);
    // layer 2
    mma_gemm<<<dim3(2, 512), 256>>>(bb + B_TH, bb + B_TL, bb + B_W2H, bb + B_W2L,
                                    nullptr, p_h, nullptr, nullptr, NN, 256, 256);
    k_scores<<<(NN * 4) / 256, 256>>>(p_h, a2s, a2d, p_es, p_ed, 4, 64);
    k_gat_agg<256, 4><<<NN / 8, 256>>>(p_h, p_es, p_ed, b2, g2, be2, nullptr,
                                       bb + B_TH, bb + B_TL);
    // layer 3 + residual
    mma_gemm<<<dim3(1, 512), 256>>>(bb + B_TH, bb + B_TL, bb + B_W3H, bb + B_W3L,
                                    nullptr, p_h3, nullptr, nullptr, NN, 128, 256);
    k_scores<<<NN / 256, 256>>>(p_h3, a3s, a3d, p_es, p_ed, 1, 128);
    mma_gemm<<<dim3(1, 512), 256>>>(bb + B_XH, bb + B_XL, bb + B_WRH, bb + B_WRL,
                                    br, p_r, nullptr, nullptr, NN, 128, 64);
    k_gat_agg<128, 1><<<NN / 8, 256>>>(p_h3, p_es, p_ed, b3, nullptr, nullptr, p_r,
                                       bb + B_HRH, bb + B_HRL);
    // MHA projections
    mma_gemm<<<dim3(1, 512), 256>>>(bb + B_HRH, bb + B_HRL, bb + B_WQH, bb + B_WQL,
                                    nullptr, nullptr, bb + B_QH, bb + B_QL, NN, 128, 128);
    mma_gemm<<<dim3(1, 512), 256>>>(bb + B_HRH, bb + B_HRL, bb + B_WKH, bb + B_WKL,
                                    nullptr, nullptr, bb + B_KH, bb + B_KL, NN, 128, 128);
    mma_gemm<<<dim3(1, 512), 256>>>(bb + B_HRH, bb + B_HRL, bb + B_WVH, bb + B_WVL,
                                    nullptr, p_v, nullptr, nullptr, NN, 128, 128);
    k_vT<<<dim3(4, NG * 4), 256>>>(p_v, bb + B_VTH, bb + B_VTL);
    // fused attention (S never hits HBM)
    k_flash<<<dim3(4, NG * 4), 256, FLASH_SMEM>>>(
        bb + B_QH, bb + B_QL, bb + B_KH, bb + B_KL,
        bb + B_VTH, bb + B_VTL, bb + B_AOH, bb + B_AOL);
    // output projection
    mma_gemm<<<dim3(1, 512), 256>>>(bb + B_AOH, bb + B_AOL, bb + B_WOH, bb + B_WOL,
                                    bo, out, nullptr, nullptr, NN, 128, 128);
}

// round 6
// speedup vs baseline: 1.6776x; 1.0387x over previous
#include <cuda_runtime.h>
#include <cuda_bf16.h>
#include <math.h>
#include <stdint.h>

// ---------------- problem constants ----------------
constexpr int NN   = 65536;
constexpr int NE   = 524288;
constexpr int ET   = NE + NN;
constexpr int GS   = 512;
constexpr int NG   = NN / GS;
constexpr int D1   = 256;
constexpr int D3   = 128;

// ---------------- fp32 scratch ----------------
constexpr size_t OFF_H    = 0;                        // NN*256
constexpr size_t OFF_H3   = OFF_H  + (size_t)NN*D1;   // NN*128
constexpr size_t OFF_R    = OFF_H3 + (size_t)NN*D3;   // NN*128
constexpr size_t OFF_ES   = OFF_R  + (size_t)NN*D3;
constexpr size_t OFF_ED   = OFF_ES + (size_t)NN*4;
constexpr size_t SCRATCH  = OFF_ED + (size_t)NN*4;

__device__ __align__(256) float g_scratch[SCRATCH];

// ---------------- bf16 scratch ----------------
constexpr size_t B_XH  = 0;
constexpr size_t B_XL  = B_XH  + (size_t)NN*64;
constexpr size_t B_TH  = B_XL  + (size_t)NN*64;
constexpr size_t B_TL  = B_TH  + (size_t)NN*256;
constexpr size_t B_HRH = B_TL  + (size_t)NN*256;
constexpr size_t B_HRL = B_HRH + (size_t)NN*128;
constexpr size_t B_AOH = B_HRL + (size_t)NN*128;
constexpr size_t B_AOL = B_AOH + (size_t)NN*128;
constexpr size_t B_QH  = B_AOL + (size_t)NN*128;
constexpr size_t B_QL  = B_QH  + (size_t)NN*128;
constexpr size_t B_KH  = B_QL  + (size_t)NN*128;
constexpr size_t B_KL  = B_KH  + (size_t)NN*128;
constexpr size_t B_VH  = B_KL  + (size_t)NN*128;
constexpr size_t B_VL  = B_VH  + (size_t)NN*128;
constexpr size_t B_VTH = B_VL  + (size_t)NN*128;
constexpr size_t B_VTL = B_VTH + (size_t)NN*128;
constexpr size_t B_W1H = B_VTL + (size_t)NN*128;
constexpr size_t B_W1L = B_W1H + 256*64;
constexpr size_t B_W2H = B_W1L + 256*64;
constexpr size_t B_W2L = B_W2H + 256*256;
constexpr size_t B_W3H = B_W2L + 256*256;
constexpr size_t B_W3L = B_W3H + 128*256;
constexpr size_t B_WRH = B_W3L + 128*256;
constexpr size_t B_WRL = B_WRH + 128*64;
constexpr size_t B_WQKVH = B_WRL + 128*64;
constexpr size_t B_WQKVL = B_WQKVH + 384*128;
constexpr size_t B_WOH = B_WQKVL + 384*128;
constexpr size_t B_WOL = B_WOH + 128*128;
constexpr size_t BF_TOTAL = B_WOL + 128*128;

__device__ __align__(256) __nv_bfloat16 g_bf[BF_TOTAL];

__device__ int g_rowptr[NN + 1];
__device__ int g_cnt[NN];
__device__ int g_cursor[NN];
__device__ int g_col[ET];

// ================= helpers =================
__device__ __forceinline__ uint32_t smem_u32(const void* p) {
    uint32_t a;
    asm("{ .reg .u64 t; cvta.to.shared.u64 t, %1; cvt.u32.u64 %0, t; }" : "=r"(a) : "l"(p));
    return a;
}
#define LDMX4(r, a) \
    asm volatile("ldmatrix.sync.aligned.m8n8.x4.shared.b16 {%0,%1,%2,%3}, [%4];" \
        : "=r"((r)[0]), "=r"((r)[1]), "=r"((r)[2]), "=r"((r)[3]) : "r"(a))
#define LDMX2(r, a) \
    asm volatile("ldmatrix.sync.aligned.m8n8.x2.shared.b16 {%0,%1}, [%2];" \
        : "=r"((r)[0]), "=r"((r)[1]) : "r"(a))
#define MMA16816(d, a, b) \
    asm volatile("mma.sync.aligned.m16n8k16.row.col.f32.bf16.bf16.f32 " \
        "{%0,%1,%2,%3}, {%4,%5,%6,%7}, {%8,%9}, {%0,%1,%2,%3};" \
        : "+f"((d)[0]), "+f"((d)[1]), "+f"((d)[2]), "+f"((d)[3]) \
        : "r"((a)[0]), "r"((a)[1]), "r"((a)[2]), "r"((a)[3]), \
          "r"((b)[0]), "r"((b)[1]))

__device__ __forceinline__ void split2(float v0, float v1, uint32_t& hh, uint32_t& ll) {
    __nv_bfloat16 h0 = __float2bfloat16(v0), h1 = __float2bfloat16(v1);
    __nv_bfloat16 l0 = __float2bfloat16(v0 - __bfloat162float(h0));
    __nv_bfloat16 l1 = __float2bfloat16(v1 - __bfloat162float(h1));
    __nv_bfloat162 H; H.x = h0; H.y = h1;
    __nv_bfloat162 L; L.x = l0; L.y = l1;
    hh = *(uint32_t*)&H; ll = *(uint32_t*)&L;
}

// ================= CSR build =================
__global__ void k_zero_cnt() {
    int i = blockIdx.x * blockDim.x + threadIdx.x;
    if (i < NN) g_cnt[i] = 0;
}
__global__ void k_count(const int* __restrict__ ei) {
    int stride = gridDim.x * blockDim.x;
    for (int idx = blockIdx.x * blockDim.x + threadIdx.x; idx < NE; idx += stride)
        atomicAdd(&g_cnt[ei[NE + idx]], 1);
}
__global__ void k_scan() {
    __shared__ int warpsum[32];
    __shared__ int s_carry;
    int tid = threadIdx.x, lane = tid & 31, wid = tid >> 5;
    if (tid == 0) s_carry = 0;
    __syncthreads();
    for (int base = 0; base < NN; base += 1024) {
        int v = g_cnt[base + tid] + 1;
        int x = v;
        #pragma unroll
        for (int o = 1; o < 32; o <<= 1) {
            int t = __shfl_up_sync(0xffffffffu, x, o);
            if (lane >= o) x += t;
        }
        if (lane == 31) warpsum[wid] = x;
        __syncthreads();
        if (wid == 0) {
            int w = warpsum[lane];
            #pragma unroll
            for (int o = 1; o < 32; o <<= 1) {
                int t = __shfl_up_sync(0xffffffffu, w, o);
                if (lane >= o) w += t;
            }
            warpsum[lane] = w;
        }
        __syncthreads();
        int excl = (x - v) + (wid > 0 ? warpsum[wid - 1] : 0) + s_carry;
        g_rowptr[base + tid] = excl;
        g_cursor[base + tid] = excl;
        __syncthreads();
        if (tid == 1023) s_carry = excl + v;
        __syncthreads();
    }
    if (tid == 0) g_rowptr[NN] = ET;
}
__global__ void k_fill(const int* __restrict__ ei) {
    int stride = gridDim.x * blockDim.x;
    for (int idx = blockIdx.x * blockDim.x + threadIdx.x; idx < ET; idx += stride) {
        int s, d;
        if (idx < NE) { s = ei[idx]; d = ei[NE + idx]; }
        else          { s = d = idx - NE; }
        int pos = atomicAdd(&g_cursor[d], 1);
        g_col[pos] = s;
    }
}

// ================= conversions =================
__global__ void k_cvt_split(const float* __restrict__ in, __nv_bfloat16* __restrict__ hi,
                            __nv_bfloat16* __restrict__ lo, int n4) {
    int i = blockIdx.x * blockDim.x + threadIdx.x;
    if (i >= n4) return;
    float4 v = ((const float4*)in)[i];
    uint32_t h01, l01, h23, l23;
    split2(v.x, v.y, h01, l01);
    split2(v.z, v.w, h23, l23);
    ((uint32_t*)hi)[2 * i] = h01; ((uint32_t*)hi)[2 * i + 1] = h23;
    ((uint32_t*)lo)[2 * i] = l01; ((uint32_t*)lo)[2 * i + 1] = l23;
}

__global__ void k_cvt_wT(const float* __restrict__ W, __nv_bfloat16* __restrict__ hiT,
                         __nv_bfloat16* __restrict__ loT, int K, int N) {
    int idx = blockIdx.x * blockDim.x + threadIdx.x;
    if (idx >= N * K) return;
    int n = idx / K, k = idx % K;
    float v = W[(size_t)k * N + n];
    __nv_bfloat16 h = __float2bfloat16(v);
    hiT[idx] = h;
    loT[idx] = __float2bfloat16(v - __bfloat162float(h));
}

// concat Wq/Wk/Wv (each [128,128]) -> WT hi/lo [384,128]
__global__ void k_cvt_wqkv(const float* __restrict__ Wq, const float* __restrict__ Wk,
                           const float* __restrict__ Wv,
                           __nv_bfloat16* __restrict__ hiT, __nv_bfloat16* __restrict__ loT) {
    int idx = blockIdx.x * blockDim.x + threadIdx.x;
    if (idx >= 384 * 128) return;
    int n = idx / 128, k = idx % 128;
    const float* W = (n < 128) ? Wq : ((n < 256) ? Wk : Wv);
    float v = W[(size_t)k * 128 + (n & 127)];
    __nv_bfloat16 h = __float2bfloat16(v);
    hiT[idx] = h;
    loT[idx] = __float2bfloat16(v - __bfloat162float(h));
}

// ================= mma.sync bf16-split GEMM =================
constexpr int LDS_ = 40;

// Fused scores (asv!=null): N==256, heads=4, C=64; writes esv/edv per (row, head).
__global__ __launch_bounds__(256) void mma_gemm(
    const __nv_bfloat16* __restrict__ Ah, const __nv_bfloat16* __restrict__ Al,
    const __nv_bfloat16* __restrict__ Bh, const __nv_bfloat16* __restrict__ Bl,
    const float* __restrict__ bias, float* __restrict__ C,
    __nv_bfloat16* __restrict__ Chi, __nv_bfloat16* __restrict__ Clo,
    const float* __restrict__ asv, const float* __restrict__ adv,
    float* __restrict__ esv, float* __restrict__ edv_out,
    int M, int N, int K)
{
    __shared__ __nv_bfloat16 sAh[128 * LDS_];
    __shared__ __nv_bfloat16 sAl[128 * LDS_];
    __shared__ __nv_bfloat16 sBh[128 * LDS_];
    __shared__ __nv_bfloat16 sBl[128 * LDS_];

    int tid = threadIdx.x, lane = tid & 31, warp = tid >> 5;
    int wm = warp & 3, wn = warp >> 2;
    int bm = blockIdx.y, bn = blockIdx.x;
    const __nv_bfloat16* gAh = Ah + (size_t)bm * 128 * K;
    const __nv_bfloat16* gAl = Al + (size_t)bm * 128 * K;
    const __nv_bfloat16* gBh = Bh + (size_t)bn * 128 * K;
    const __nv_bfloat16* gBl = Bl + (size_t)bn * 128 * K;

    float d[2][8][4];
    #pragma unroll
    for (int mi = 0; mi < 2; mi++)
        #pragma unroll
        for (int ni = 0; ni < 8; ni++)
            #pragma unroll
            for (int j = 0; j < 4; j++) d[mi][ni][j] = 0.f;

    for (int k0 = 0; k0 < K; k0 += 32) {
        if (k0) __syncthreads();
        #pragma unroll
        for (int r = 0; r < 2; r++) {
            int idx = tid + r * 256;
            int row = idx >> 2, seg = idx & 3;
            size_t go = (size_t)row * K + k0 + seg * 8;
            int so = row * LDS_ + seg * 8;
            *(uint4*)&sAh[so] = *(const uint4*)(gAh + go);
            *(uint4*)&sAl[so] = *(const uint4*)(gAl + go);
            *(uint4*)&sBh[so] = *(const uint4*)(gBh + go);
            *(uint4*)&sBl[so] = *(const uint4*)(gBl + go);
        }
        __syncthreads();
        #pragma unroll
        for (int ks = 0; ks < 2; ks++) {
            uint32_t ah[2][4], al[2][4];
            #pragma unroll
            for (int mi = 0; mi < 2; mi++) {
                int row = wm * 32 + mi * 16 + (lane & 15);
                int col = ks * 16 + (lane >> 4) * 8;
                LDMX4(ah[mi], smem_u32(&sAh[row * LDS_ + col]));
                LDMX4(al[mi], smem_u32(&sAl[row * LDS_ + col]));
            }
            #pragma unroll
            for (int ni = 0; ni < 8; ni++) {
                uint32_t bh[2], bl[2];
                int row = wn * 64 + ni * 8 + (lane & 7);
                int col = ks * 16 + ((lane >> 3) & 1) * 8;
                LDMX2(bh, smem_u32(&sBh[row * LDS_ + col]));
                LDMX2(bl, smem_u32(&sBl[row * LDS_ + col]));
                #pragma unroll
                for (int mi = 0; mi < 2; mi++) {
                    MMA16816(d[mi][ni], ah[mi], bh);
                    MMA16816(d[mi][ni], al[mi], bh);
                    MMA16816(d[mi][ni], ah[mi], bl);
                }
            }
        }
    }
    #pragma unroll
    for (int mi = 0; mi < 2; mi++) {
        int row = bm * 128 + wm * 32 + mi * 16 + (lane >> 2);
        #pragma unroll
        for (int ni = 0; ni < 8; ni++) {
            int col = bn * 128 + wn * 64 + ni * 8 + (lane & 3) * 2;
            if (C) {
                float b0 = bias ? bias[col] : 0.f;
                float b1 = bias ? bias[col + 1] : 0.f;
                *(float2*)(C + (size_t)row * N + col) =
                    make_float2(d[mi][ni][0] + b0, d[mi][ni][1] + b1);
                *(float2*)(C + (size_t)(row + 8) * N + col) =
                    make_float2(d[mi][ni][2] + b0, d[mi][ni][3] + b1);
            } else {
                uint32_t hh, ll;
                split2(d[mi][ni][0], d[mi][ni][1], hh, ll);
                *(uint32_t*)(Chi + (size_t)row * N + col) = hh;
                *(uint32_t*)(Clo + (size_t)row * N + col) = ll;
                split2(d[mi][ni][2], d[mi][ni][3], hh, ll);
                *(uint32_t*)(Chi + (size_t)(row + 8) * N + col) = hh;
                *(uint32_t*)(Clo + (size_t)(row + 8) * N + col) = ll;
            }
        }
    }
    // fused GAT score dot-products (layers 1/2: head = bn*2+wn, C=64)
    if (asv) {
        int hd = bn * 2 + wn;
        float sv[4] = {0.f, 0.f, 0.f, 0.f}, dv[4] = {0.f, 0.f, 0.f, 0.f};
        #pragma unroll
        for (int mi = 0; mi < 2; mi++)
            #pragma unroll
            for (int ni = 0; ni < 8; ni++)
                #pragma unroll
                for (int j = 0; j < 2; j++) {
                    int cl = ni * 8 + (lane & 3) * 2 + j;
                    float a = asv[hd * 64 + cl], b = adv[hd * 64 + cl];
                    sv[mi * 2]     += d[mi][ni][j]     * a;
                    dv[mi * 2]     += d[mi][ni][j]     * b;
                    sv[mi * 2 + 1] += d[mi][ni][2 + j] * a;
                    dv[mi * 2 + 1] += d[mi][ni][2 + j] * b;
                }
        #pragma unroll
        for (int r = 0; r < 4; r++) {
            sv[r] += __shfl_xor_sync(0xffffffffu, sv[r], 1);
            sv[r] += __shfl_xor_sync(0xffffffffu, sv[r], 2);
            dv[r] += __shfl_xor_sync(0xffffffffu, dv[r], 1);
            dv[r] += __shfl_xor_sync(0xffffffffu, dv[r], 2);
        }
        if ((lane & 3) == 0) {
            #pragma unroll
            for (int r = 0; r < 4; r++) {
                int row = bm * 128 + wm * 32 + (r >> 1) * 16 + (lane >> 2) + (r & 1) * 8;
                esv[(size_t)row * 4 + hd]     = sv[r];
                edv_out[(size_t)row * 4 + hd] = dv[r];
            }
        }
    }
}

// ================= QKV fused GEMM: N=384, per-bn output routing =================
__global__ __launch_bounds__(256) void mma_gemm_qkv(
    const __nv_bfloat16* __restrict__ Ah, const __nv_bfloat16* __restrict__ Al,
    const __nv_bfloat16* __restrict__ Bh, const __nv_bfloat16* __restrict__ Bl,
    __nv_bfloat16* __restrict__ QH, __nv_bfloat16* __restrict__ QL,
    __nv_bfloat16* __restrict__ KH, __nv_bfloat16* __restrict__ KL,
    __nv_bfloat16* __restrict__ VH, __nv_bfloat16* __restrict__ VL)
{
    constexpr int K = 128;
    __shared__ __nv_bfloat16 sAh[128 * LDS_];
    __shared__ __nv_bfloat16 sAl[128 * LDS_];
    __shared__ __nv_bfloat16 sBh[128 * LDS_];
    __shared__ __nv_bfloat16 sBl[128 * LDS_];

    int tid = threadIdx.x, lane = tid & 31, warp = tid >> 5;
    int wm = warp & 3, wn = warp >> 2;
    int bm = blockIdx.y, bn = blockIdx.x;
    const __nv_bfloat16* gAh = Ah + (size_t)bm * 128 * K;
    const __nv_bfloat16* gAl = Al + (size_t)bm * 128 * K;
    const __nv_bfloat16* gBh = Bh + (size_t)bn * 128 * K;
    const __nv_bfloat16* gBl = Bl + (size_t)bn * 128 * K;

    float d[2][8][4];
    #pragma unroll
    for (int mi = 0; mi < 2; mi++)
        #pragma unroll
        for (int ni = 0; ni < 8; ni++)
            #pragma unroll
            for (int j = 0; j < 4; j++) d[mi][ni][j] = 0.f;

    for (int k0 = 0; k0 < K; k0 += 32) {
        if (k0) __syncthreads();
        #pragma unroll
        for (int r = 0; r < 2; r++) {
            int idx = tid + r * 256;
            int row = idx >> 2, seg = idx & 3;
            size_t go = (size_t)row * K + k0 + seg * 8;
            int so = row * LDS_ + seg * 8;
            *(uint4*)&sAh[so] = *(const uint4*)(gAh + go);
            *(uint4*)&sAl[so] = *(const uint4*)(gAl + go);
            *(uint4*)&sBh[so] = *(const uint4*)(gBh + go);
            *(uint4*)&sBl[so] = *(const uint4*)(gBl + go);
        }
        __syncthreads();
        #pragma unroll
        for (int ks = 0; ks < 2; ks++) {
            uint32_t ah[2][4], al[2][4];
            #pragma unroll
            for (int mi = 0; mi < 2; mi++) {
                int row = wm * 32 + mi * 16 + (lane & 15);
                int col = ks * 16 + (lane >> 4) * 8;
                LDMX4(ah[mi], smem_u32(&sAh[row * LDS_ + col]));
                LDMX4(al[mi], smem_u32(&sAl[row * LDS_ + col]));
            }
            #pragma unroll
            for (int ni = 0; ni < 8; ni++) {
                uint32_t bh[2], bl[2];
                int row = wn * 64 + ni * 8 + (lane & 7);
                int col = ks * 16 + ((lane >> 3) & 1) * 8;
                LDMX2(bh, smem_u32(&sBh[row * LDS_ + col]));
                LDMX2(bl, smem_u32(&sBl[row * LDS_ + col]));
                #pragma unroll
                for (int mi = 0; mi < 2; mi++) {
                    MMA16816(d[mi][ni], ah[mi], bh);
                    MMA16816(d[mi][ni], al[mi], bh);
                    MMA16816(d[mi][ni], ah[mi], bl);
                }
            }
        }
    }
    __nv_bfloat16 *Oh, *Ol;
    if (bn == 0)      { Oh = QH; Ol = QL; }
    else if (bn == 1) { Oh = KH; Ol = KL; }
    else              { Oh = VH; Ol = VL; }
    #pragma unroll
    for (int mi = 0; mi < 2; mi++) {
        int row = bm * 128 + wm * 32 + mi * 16 + (lane >> 2);
        #pragma unroll
        for (int ni = 0; ni < 8; ni++) {
            int col = wn * 64 + ni * 8 + (lane & 3) * 2;
            uint32_t hh, ll;
            split2(d[mi][ni][0], d[mi][ni][1], hh, ll);
            *(uint32_t*)(Oh + (size_t)row * 128 + col) = hh;
            *(uint32_t*)(Ol + (size_t)row * 128 + col) = ll;
            split2(d[mi][ni][2], d[mi][ni][3], hh, ll);
            *(uint32_t*)(Oh + (size_t)(row + 8) * 128 + col) = hh;
            *(uint32_t*)(Ol + (size_t)(row + 8) * 128 + col) = ll;
        }
    }
}

// ================= GAT score vectors (layer 3 only) =================
__global__ void k_scores(const float* __restrict__ h, const float* __restrict__ as_,
                         const float* __restrict__ ad_, float* __restrict__ es,
                         float* __restrict__ ed, int H, int C)
{
    int idx = blockIdx.x * blockDim.x + threadIdx.x;
    if (idx >= NN * H) return;
    int node = idx / H, hd = idx % H;
    const float4* hp = (const float4*)(h + (size_t)node * H * C + (size_t)hd * C);
    const float4* ap = (const float4*)(as_ + (size_t)hd * C);
    const float4* bp = (const float4*)(ad_ + (size_t)hd * C);
    float s = 0.f, d = 0.f;
    for (int c = 0; c < C / 4; c++) {
        float4 hv = hp[c], av = ap[c], bv = bp[c];
        s += hv.x * av.x + hv.y * av.y + hv.z * av.z + hv.w * av.w;
        d += hv.x * bv.x + hv.y * bv.y + hv.z * bv.z + hv.w * bv.w;
    }
    es[idx] = s;
    ed[idx] = d;
}

// ================= GAT aggregation — single pass (no max-sub) =================
template <int D, int H>
__global__ __launch_bounds__(256) void k_gat_agg(
    const float* __restrict__ hfeat, const float* __restrict__ es,
    const float* __restrict__ ed, const float* __restrict__ bias,
    const float* __restrict__ gamma, const float* __restrict__ beta,
    const float* __restrict__ resid,
    __nv_bfloat16* __restrict__ outH, __nv_bfloat16* __restrict__ outL)
{
    constexpr int C = D / H;
    constexpr int R = D / 32;
    int warp = (blockIdx.x * blockDim.x + threadIdx.x) >> 5;
    int lane = threadIdx.x & 31;
    if (warp >= NN) return;
    int i = warp;
    int beg = g_rowptr[i], end = g_rowptr[i + 1];

    float edv[H], z[H];
    #pragma unroll
    for (int h = 0; h < H; h++) {
        edv[h] = ed[(size_t)i * H + h];
        z[h] = 0.f;
    }
    float acc[R];
    #pragma unroll
    for (int j = 0; j < R; j++) acc[j] = 0.f;

    for (int e = beg; e < end; e++) {
        int s = g_col[e];
        float al[H];
        #pragma unroll
        for (int h = 0; h < H; h++) {
            float v = es[(size_t)s * H + h] + edv[h];
            v = v > 0.f ? v : 0.2f * v;
            al[h] = expf(v);
            z[h] += al[h];
        }
        const float* hs = hfeat + (size_t)s * D;
        #pragma unroll
        for (int j = 0; j < R; j++) {
            int c = lane + 32 * j;
            acc[j] += al[(32 * j) / C] * hs[c];
        }
    }
    #pragma unroll
    for (int h = 0; h < H; h++) z[h] = 1.f / (z[h] + 1e-16f);

    float x[R];
    #pragma unroll
    for (int j = 0; j < R; j++) {
        int c = lane + 32 * j;
        float val = acc[j] * z[(32 * j) / C] + bias[c];
        if (resid) val += resid[(size_t)i * D + c];
        x[j] = val;
    }
    if (gamma) {
        #pragma unroll
        for (int j = 0; j < R; j++)
            x[j] = x[j] > 0.f ? x[j] : (expf(x[j]) - 1.f);
        float s = 0.f;
        #pragma unroll
        for (int j = 0; j < R; j++) s += x[j];
        #pragma unroll
        for (int o = 16; o; o >>= 1) s += __shfl_xor_sync(0xffffffffu, s, o);
        float mu = s / (float)D;
        float vs = 0.f;
        #pragma unroll
        for (int j = 0; j < R; j++) { float dd = x[j] - mu; vs += dd * dd; }
        #pragma unroll
        for (int o = 16; o; o >>= 1) vs += __shfl_xor_sync(0xffffffffu, vs, o);
        float inv = rsqrtf(vs / (float)D + 1e-5f);
        #pragma unroll
        for (int j = 0; j < R; j++) {
            int c = lane + 32 * j;
            x[j] = (x[j] - mu) * inv * gamma[c] + beta[c];
        }
    }
    #pragma unroll
    for (int j = 0; j < R; j++) {
        size_t idx = (size_t)i * D + lane + 32 * j;
        __nv_bfloat16 h = __float2bfloat16(x[j]);
        outH[idx] = h;
        outL[idx] = __float2bfloat16(x[j] - __bfloat162float(h));
    }
}

// ================= V transpose (bf16 hi/lo in) -> VT[gh][32][512] hi/lo =================
__global__ __launch_bounds__(256) void k_vT(const __nv_bfloat16* __restrict__ VH,
                                            const __nv_bfloat16* __restrict__ VL,
                                            __nv_bfloat16* __restrict__ VTH,
                                            __nv_bfloat16* __restrict__ VTL)
{
    __shared__ float t[128][33];
    int gh = blockIdx.y, g = gh >> 2, h = gh & 3;
    int k0 = blockIdx.x * 128;
    int tid = threadIdx.x;
    #pragma unroll
    for (int it = 0; it < 16; it++) {
        int idx = tid + it * 256;
        int r = idx >> 5, c = idx & 31;
        size_t gi = ((size_t)g * GS + k0 + r) * 128 + h * 32 + c;
        t[r][c] = __bfloat162float(VH[gi]) + __bfloat162float(VL[gi]);
    }
    __syncthreads();
    #pragma unroll
    for (int it = 0; it < 16; it++) {
        int idx = tid + it * 256;
        int n = idx >> 7, k = idx & 127;
        float v = t[k][n];
        __nv_bfloat16 hh = __float2bfloat16(v);
        size_t o = ((size_t)gh * 32 + n) * 512 + k0 + k;
        VTH[o] = hh;
        VTL[o] = __float2bfloat16(v - __bfloat162float(hh));
    }
}

// ================= fused flash attention =================
constexpr int VPAD = 520;
constexpr int SM_QH = 0;
constexpr int SM_QL = SM_QH + 128 * LDS_;
constexpr int SM_KH = SM_QL + 128 * LDS_;
constexpr int SM_KL = SM_KH + 512 * LDS_;
constexpr int SM_VH = SM_KL + 512 * LDS_;
constexpr int SM_VL = SM_VH + 32 * VPAD;
constexpr int SM_TOT = SM_VL + 32 * VPAD;
constexpr int FLASH_SMEM = SM_TOT * 2;

__global__ __launch_bounds__(256) void k_flash(
    const __nv_bfloat16* __restrict__ QH, const __nv_bfloat16* __restrict__ QL,
    const __nv_bfloat16* __restrict__ KH, const __nv_bfloat16* __restrict__ KL,
    const __nv_bfloat16* __restrict__ VTH, const __nv_bfloat16* __restrict__ VTL,
    __nv_bfloat16* __restrict__ OHo, __nv_bfloat16* __restrict__ OLo)
{
    extern __shared__ __nv_bfloat16 sm[];
    int gh = blockIdx.y, g = gh >> 2, h = gh & 3;
    int qt = blockIdx.x;
    int tid = threadIdx.x, lane = tid & 31, warp = tid >> 5;

    {
        const __nv_bfloat16* kh = KH + (size_t)g * GS * 128 + h * 32;
        const __nv_bfloat16* kl = KL + (size_t)g * GS * 128 + h * 32;
        #pragma unroll
        for (int it = 0; it < 8; it++) {
            int idx = tid + it * 256;
            int row = idx >> 2, seg = (idx & 3) * 8;
            *(uint4*)&sm[SM_KH + row * LDS_ + seg] = *(const uint4*)(kh + (size_t)row * 128 + seg);
            *(uint4*)&sm[SM_KL + row * LDS_ + seg] = *(const uint4*)(kl + (size_t)row * 128 + seg);
        }
        const __nv_bfloat16* qh = QH + ((size_t)g * GS + qt * 128) * 128 + h * 32;
        const __nv_bfloat16* ql = QL + ((size_t)g * GS + qt * 128) * 128 + h * 32;
        #pragma unroll
        for (int it = 0; it < 2; it++) {
            int idx = tid + it * 256;
            int row = idx >> 2, seg = (idx & 3) * 8;
            *(uint4*)&sm[SM_QH + row * LDS_ + seg] = *(const uint4*)(qh + (size_t)row * 128 + seg);
            *(uint4*)&sm[SM_QL + row * LDS_ + seg] = *(const uint4*)(ql + (size_t)row * 128 + seg);
        }
        const __nv_bfloat16* vh = VTH + (size_t)gh * 32 * 512;
        const __nv_bfloat16* vl = VTL + (size_t)gh * 32 * 512;
        #pragma unroll
        for (int it = 0; it < 8; it++) {
            int idx = tid + it * 256;
            int row = idx >> 6, c8 = (idx & 63) * 8;
            *(uint4*)&sm[SM_VH + row * VPAD + c8] = *(const uint4*)(vh + (size_t)row * 512 + c8);
            *(uint4*)&sm[SM_VL + row * VPAD + c8] = *(const uint4*)(vl + (size_t)row * 512 + c8);
        }
    }
    __syncthreads();

    uint32_t qh_[2][4], ql_[2][4];
    #pragma unroll
    for (int kf = 0; kf < 2; kf++) {
        int row = warp * 16 + (lane & 15);
        int col = kf * 16 + (lane >> 4) * 8;
        LDMX4(qh_[kf], smem_u32(&sm[SM_QH + row * LDS_ + col]));
        LDMX4(ql_[kf], smem_u32(&sm[SM_QL + row * LDS_ + col]));
    }

    float m0 = -1e30f, m1 = -1e30f, l0 = 0.f, l1 = 0.f;
    float O[4][4];
    #pragma unroll
    for (int n = 0; n < 4; n++)
        #pragma unroll
        for (int j = 0; j < 4; j++) O[n][j] = 0.f;

    const float scale = 0.088388347648318447f;

    for (int kt = 0; kt < 4; kt++) {
        float S[16][4];
        #pragma unroll
        for (int j = 0; j < 16; j++)
            #pragma unroll
            for (int r = 0; r < 4; r++) S[j][r] = 0.f;
        #pragma unroll
        for (int j = 0; j < 16; j++) {
            #pragma unroll
            for (int kf = 0; kf < 2; kf++) {
                uint32_t bh[2], bl[2];
                int row = kt * 128 + j * 8 + (lane & 7);
                int col = kf * 16 + ((lane >> 3) & 1) * 8;
                LDMX2(bh, smem_u32(&sm[SM_KH + row * LDS_ + col]));
                LDMX2(bl, smem_u32(&sm[SM_KL + row * LDS_ + col]));
                MMA16816(S[j], qh_[kf], bh);
                MMA16816(S[j], ql_[kf], bh);
                MMA16816(S[j], qh_[kf], bl);
            }
        }
        float mx0 = -1e30f, mx1 = -1e30f;
        #pragma unroll
        for (int j = 0; j < 16; j++) {
            S[j][0] *= scale; S[j][1] *= scale; S[j][2] *= scale; S[j][3] *= scale;
            mx0 = fmaxf(mx0, fmaxf(S[j][0], S[j][1]));
            mx1 = fmaxf(mx1, fmaxf(S[j][2], S[j][3]));
        }
        #pragma unroll
        for (int o = 1; o < 4; o <<= 1) {
            mx0 = fmaxf(mx0, __shfl_xor_sync(0xffffffffu, mx0, o));
            mx1 = fmaxf(mx1, __shfl_xor_sync(0xffffffffu, mx1, o));
        }
        float nm0 = fmaxf(m0, mx0), nm1 = fmaxf(m1, mx1);
        float a0 = expf(m0 - nm0), a1 = expf(m1 - nm1);
        float rs0 = 0.f, rs1 = 0.f;
        #pragma unroll
        for (int j = 0; j < 16; j++) {
            S[j][0] = expf(S[j][0] - nm0); S[j][1] = expf(S[j][1] - nm0);
            S[j][2] = expf(S[j][2] - nm1); S[j][3] = expf(S[j][3] - nm1);
            rs0 += S[j][0] + S[j][1];
            rs1 += S[j][2] + S[j][3];
        }
        #pragma unroll
        for (int o = 1; o < 4; o <<= 1) {
            rs0 += __shfl_xor_sync(0xffffffffu, rs0, o);
            rs1 += __shfl_xor_sync(0xffffffffu, rs1, o);
        }
        l0 = l0 * a0 + rs0;
        l1 = l1 * a1 + rs1;
        #pragma unroll
        for (int n = 0; n < 4; n++) {
            O[n][0] *= a0; O[n][1] *= a0; O[n][2] *= a1; O[n][3] *= a1;
        }
        m0 = nm0; m1 = nm1;
        #pragma unroll
        for (int jp = 0; jp < 8; jp++) {
            uint32_t aph[4], apl[4];
            split2(S[2 * jp][0],     S[2 * jp][1],     aph[0], apl[0]);
            split2(S[2 * jp][2],     S[2 * jp][3],     aph[1], apl[1]);
            split2(S[2 * jp + 1][0], S[2 * jp + 1][1], aph[2], apl[2]);
            split2(S[2 * jp + 1][2], S[2 * jp + 1][3], aph[3], apl[3]);
            #pragma unroll
            for (int n = 0; n < 4; n++) {
                uint32_t bh[2], bl[2];
                int row = n * 8 + (lane & 7);
                int col = kt * 128 + jp * 16 + ((lane >> 3) & 1) * 8;
                LDMX2(bh, smem_u32(&sm[SM_VH + row * VPAD + col]));
                LDMX2(bl, smem_u32(&sm[SM_VL + row * VPAD + col]));
                MMA16816(O[n], aph, bh);
                MMA16816(O[n], apl, bh);
                MMA16816(O[n], aph, bl);
            }
        }
    }
    float il0 = 1.f / l0, il1 = 1.f / l1;
    int node = g * GS + qt * 128 + warp * 16 + (lane >> 2);
    #pragma unroll
    for (int n = 0; n < 4; n++) {
        int col = h * 32 + n * 8 + (lane & 3) * 2;
        uint32_t hh, ll;
        split2(O[n][0] * il0, O[n][1] * il0, hh, ll);
        *(uint32_t*)(OHo + (size_t)node * 128 + col) = hh;
        *(uint32_t*)(OLo + (size_t)node * 128 + col) = ll;
        split2(O[n][2] * il1, O[n][3] * il1, hh, ll);
        *(uint32_t*)(OHo + (size_t)(node + 8) * 128 + col) = hh;
        *(uint32_t*)(OLo + (size_t)(node + 8) * 128 + col) = ll;
    }
}

// ================= host orchestration =================
extern "C" void kernel_launch(void* const* d_in, const int* in_sizes, int n_in,
                              void* d_out, int out_size)
{
    const float* x   = (const float*)d_in[0];
    const int*   ei  = (const int*)  d_in[1];
    const float* W1  = (const float*)d_in[3];
    const float* a1s = (const float*)d_in[4];
    const float* a1d = (const float*)d_in[5];
    const float* b1  = (const float*)d_in[6];
    const float* W2  = (const float*)d_in[7];
    const float* a2s = (const float*)d_in[8];
    const float* a2d = (const float*)d_in[9];
    const float* b2  = (const float*)d_in[10];
    const float* W3  = (const float*)d_in[11];
    const float* a3s = (const float*)d_in[12];
    const float* a3d = (const float*)d_in[13];
    const float* b3  = (const float*)d_in[14];
    const float* g1  = (const float*)d_in[15];
    const float* be1 = (const float*)d_in[16];
    const float* g2  = (const float*)d_in[17];
    const float* be2 = (const float*)d_in[18];
    const float* Wr  = (const float*)d_in[19];
    const float* br  = (const float*)d_in[20];
    const float* Wq  = (const float*)d_in[21];
    const float* Wk  = (const float*)d_in[22];
    const float* Wv  = (const float*)d_in[23];
    const float* Wo  = (const float*)d_in[24];
    const float* bo  = (const float*)d_in[25];
    float* out = (float*)d_out;

    float* sb = nullptr;
    cudaGetSymbolAddress((void**)&sb, g_scratch);
    __nv_bfloat16* bb = nullptr;
    cudaGetSymbolAddress((void**)&bb, g_bf);
    cudaFuncSetAttribute(k_flash, cudaFuncAttributeMaxDynamicSharedMemorySize, FLASH_SMEM);

    float* p_h  = sb + OFF_H;
    float* p_h3 = sb + OFF_H3;
    float* p_r  = sb + OFF_R;
    float* p_es = sb + OFF_ES;
    float* p_ed = sb + OFF_ED;

    // CSR
    k_zero_cnt<<<NN / 256, 256>>>();
    k_count<<<1024, 256>>>(ei);
    k_scan<<<1, 1024>>>();
    k_fill<<<1152, 256>>>(ei);

    // weight conversions
    k_cvt_wT<<<(256*64 + 255)/256, 256>>>(W1, bb + B_W1H, bb + B_W1L, 64, 256);
    k_cvt_wT<<<(256*256 + 255)/256, 256>>>(W2, bb + B_W2H, bb + B_W2L, 256, 256);
    k_cvt_wT<<<(128*256 + 255)/256, 256>>>(W3, bb + B_W3H, bb + B_W3L, 256, 128);
    k_cvt_wT<<<(128*64 + 255)/256, 256>>>(Wr, bb + B_WRH, bb + B_WRL, 64, 128);
    k_cvt_wqkv<<<(384*128 + 255)/256, 256>>>(Wq, Wk, Wv, bb + B_WQKVH, bb + B_WQKVL);
    k_cvt_wT<<<(128*128 + 255)/256, 256>>>(Wo, bb + B_WOH, bb + B_WOL, 128, 128);

    // x -> bf16 hi/lo
    k_cvt_split<<<(NN*64/4 + 255)/256, 256>>>(x, bb + B_XH, bb + B_XL, NN*64/4);

    // layer 1 (fused scores)
    mma_gemm<<<dim3(2, 512), 256>>>(bb + B_XH, bb + B_XL, bb + B_W1H, bb + B_W1L,
                                    nullptr, p_h, nullptr, nullptr,
                                    a1s, a1d, p_es, p_ed, NN, 256, 64);
    k_gat_agg<256, 4><<<NN / 8, 256>>>(p_h, p_es, p_ed, b1, g1, be1, nullptr,
                                       bb + B_TH, bb + B_TL);
    // layer 2 (fused scores)
    mma_gemm<<<dim3(2, 512), 256>>>(bb + B_TH, bb + B_TL, bb + B_W2H, bb + B_W2L,
                                    nullptr, p_h, nullptr, nullptr,
                                    a2s, a2d, p_es, p_ed, NN, 256, 256);
    k_gat_agg<256, 4><<<NN / 8, 256>>>(p_h, p_es, p_ed, b2, g2, be2, nullptr,
                                       bb + B_TH, bb + B_TL);
    // layer 3 + residual
    mma_gemm<<<dim3(1, 512), 256>>>(bb + B_TH, bb + B_TL, bb + B_W3H, bb + B_W3L,
                                    nullptr, p_h3, nullptr, nullptr,
                                    nullptr, nullptr, nullptr, nullptr, NN, 128, 256);
    k_scores<<<NN / 256, 256>>>(p_h3, a3s, a3d, p_es, p_ed, 1, 128);
    mma_gemm<<<dim3(1, 512), 256>>>(bb + B_XH, bb + B_XL, bb + B_WRH, bb + B_WRL,
                                    br, p_r, nullptr, nullptr,
                                    nullptr, nullptr, nullptr, nullptr, NN, 128, 64);
    k_gat_agg<128, 1><<<NN / 8, 256>>>(p_h3, p_es, p_ed, b3, nullptr, nullptr, p_r,
                                       bb + B_HRH, bb + B_HRL);
    // fused QKV projection
    mma_gemm_qkv<<<dim3(3, 512), 256>>>(bb + B_HRH, bb + B_HRL,
                                        bb + B_WQKVH, bb + B_WQKVL,
                                        bb + B_QH, bb + B_QL,
                                        bb + B_KH, bb + B_KL,
                                        bb + B_VH, bb + B_VL);
    k_vT<<<dim3(4, NG * 4), 256>>>(bb + B_VH, bb + B_VL, bb + B_VTH, bb + B_VTL);
    // fused attention
    k_flash<<<dim3(4, NG * 4), 256, FLASH_SMEM>>>(
        bb + B_QH, bb + B_QL, bb + B_KH, bb + B_KL,
        bb + B_VTH, bb + B_VTL, bb + B_AOH, bb + B_AOL);
    // output projection
    mma_gemm<<<dim3(1, 512), 256>>>(bb + B_AOH, bb + B_AOL, bb + B_WOH, bb + B_WOL,
                                    bo, out, nullptr, nullptr,
                                    nullptr, nullptr, nullptr, nullptr, NN, 128, 128);
}

// round 7
// speedup vs baseline: 1.8545x; 1.1055x over previous
#include <cuda_runtime.h>
#include <cuda_bf16.h>
#include <math.h>
#include <stdint.h>

// ---------------- problem constants ----------------
constexpr int NN   = 65536;
constexpr int NE   = 524288;
constexpr int ET   = NE + NN;
constexpr int GS   = 512;
constexpr int NG   = NN / GS;
constexpr int D1   = 256;
constexpr int D3   = 128;

// ---------------- fp32 scratch ----------------
constexpr size_t OFF_H    = 0;
constexpr size_t OFF_H3   = OFF_H  + (size_t)NN*D1;
constexpr size_t OFF_R    = OFF_H3 + (size_t)NN*D3;
constexpr size_t OFF_ES   = OFF_R  + (size_t)NN*D3;
constexpr size_t OFF_ED   = OFF_ES + (size_t)NN*4;
constexpr size_t SCRATCH  = OFF_ED + (size_t)NN*4;

__device__ __align__(256) float g_scratch[SCRATCH];

// ---------------- bf16 scratch ----------------
constexpr size_t B_XH  = 0;
constexpr size_t B_XL  = B_XH  + (size_t)NN*64;
constexpr size_t B_TH  = B_XL  + (size_t)NN*64;
constexpr size_t B_TL  = B_TH  + (size_t)NN*256;
constexpr size_t B_HRH = B_TL  + (size_t)NN*256;
constexpr size_t B_HRL = B_HRH + (size_t)NN*128;
constexpr size_t B_AOH = B_HRL + (size_t)NN*128;
constexpr size_t B_AOL = B_AOH + (size_t)NN*128;
constexpr size_t B_QH  = B_AOL + (size_t)NN*128;
constexpr size_t B_QL  = B_QH  + (size_t)NN*128;
constexpr size_t B_KH  = B_QL  + (size_t)NN*128;
constexpr size_t B_KL  = B_KH  + (size_t)NN*128;
constexpr size_t B_VH  = B_KL  + (size_t)NN*128;
constexpr size_t B_VL  = B_VH  + (size_t)NN*128;
constexpr size_t B_VTH = B_VL  + (size_t)NN*128;
constexpr size_t B_VTL = B_VTH + (size_t)NN*128;
constexpr size_t B_W1H = B_VTL + (size_t)NN*128;
constexpr size_t B_W1L = B_W1H + 256*64;
constexpr size_t B_W2H = B_W1L + 256*64;
constexpr size_t B_W2L = B_W2H + 256*256;
constexpr size_t B_W3H = B_W2L + 256*256;
constexpr size_t B_W3L = B_W3H + 128*256;
constexpr size_t B_WRH = B_W3L + 128*256;
constexpr size_t B_WRL = B_WRH + 128*64;
constexpr size_t B_WQKVH = B_WRL + 128*64;
constexpr size_t B_WQKVL = B_WQKVH + 384*128;
constexpr size_t B_WOH = B_WQKVL + 384*128;
constexpr size_t B_WOL = B_WOH + 128*128;
constexpr size_t BF_TOTAL = B_WOL + 128*128;

__device__ __align__(256) __nv_bfloat16 g_bf[BF_TOTAL];

__device__ int g_rowptr[NN + 1];
__device__ int g_cnt[NN];
__device__ int g_cursor[NN];
__device__ int g_col[ET];

// ================= helpers =================
__device__ __forceinline__ uint32_t smem_u32(const void* p) {
    uint32_t a;
    asm("{ .reg .u64 t; cvta.to.shared.u64 t, %1; cvt.u32.u64 %0, t; }" : "=r"(a) : "l"(p));
    return a;
}
#define LDMX4(r, a) \
    asm volatile("ldmatrix.sync.aligned.m8n8.x4.shared.b16 {%0,%1,%2,%3}, [%4];" \
        : "=r"((r)[0]), "=r"((r)[1]), "=r"((r)[2]), "=r"((r)[3]) : "r"(a))
#define LDMX2(r, a) \
    asm volatile("ldmatrix.sync.aligned.m8n8.x2.shared.b16 {%0,%1}, [%2];" \
        : "=r"((r)[0]), "=r"((r)[1]) : "r"(a))
#define MMA16816(d, a, b) \
    asm volatile("mma.sync.aligned.m16n8k16.row.col.f32.bf16.bf16.f32 " \
        "{%0,%1,%2,%3}, {%4,%5,%6,%7}, {%8,%9}, {%0,%1,%2,%3};" \
        : "+f"((d)[0]), "+f"((d)[1]), "+f"((d)[2]), "+f"((d)[3]) \
        : "r"((a)[0]), "r"((a)[1]), "r"((a)[2]), "r"((a)[3]), \
          "r"((b)[0]), "r"((b)[1]))
#define CP16(dst, src) \
    asm volatile("cp.async.cg.shared.global [%0], [%1], 16;" :: "r"(dst), "l"(src))
#define CP_COMMIT() asm volatile("cp.async.commit_group;" ::: "memory")
#define CP_WAIT1()  asm volatile("cp.async.wait_group 1;" ::: "memory")
#define CP_WAIT0()  asm volatile("cp.async.wait_group 0;" ::: "memory")

__device__ __forceinline__ void split2(float v0, float v1, uint32_t& hh, uint32_t& ll) {
    __nv_bfloat16 h0 = __float2bfloat16(v0), h1 = __float2bfloat16(v1);
    __nv_bfloat16 l0 = __float2bfloat16(v0 - __bfloat162float(h0));
    __nv_bfloat16 l1 = __float2bfloat16(v1 - __bfloat162float(h1));
    __nv_bfloat162 H; H.x = h0; H.y = h1;
    __nv_bfloat162 L; L.x = l0; L.y = l1;
    hh = *(uint32_t*)&H; ll = *(uint32_t*)&L;
}

// ================= CSR build =================
__global__ void k_zero_cnt() {
    int i = blockIdx.x * blockDim.x + threadIdx.x;
    if (i < NN) g_cnt[i] = 0;
}
__global__ void k_count(const int* __restrict__ ei) {
    int stride = gridDim.x * blockDim.x;
    for (int idx = blockIdx.x * blockDim.x + threadIdx.x; idx < NE; idx += stride)
        atomicAdd(&g_cnt[ei[NE + idx]], 1);
}
__global__ void k_scan() {
    __shared__ int warpsum[32];
    __shared__ int s_carry;
    int tid = threadIdx.x, lane = tid & 31, wid = tid >> 5;
    if (tid == 0) s_carry = 0;
    __syncthreads();
    for (int base = 0; base < NN; base += 1024) {
        int v = g_cnt[base + tid] + 1;
        int x = v;
        #pragma unroll
        for (int o = 1; o < 32; o <<= 1) {
            int t = __shfl_up_sync(0xffffffffu, x, o);
            if (lane >= o) x += t;
        }
        if (lane == 31) warpsum[wid] = x;
        __syncthreads();
        if (wid == 0) {
            int w = warpsum[lane];
            #pragma unroll
            for (int o = 1; o < 32; o <<= 1) {
                int t = __shfl_up_sync(0xffffffffu, w, o);
                if (lane >= o) w += t;
            }
            warpsum[lane] = w;
        }
        __syncthreads();
        int excl = (x - v) + (wid > 0 ? warpsum[wid - 1] : 0) + s_carry;
        g_rowptr[base + tid] = excl;
        g_cursor[base + tid] = excl;
        __syncthreads();
        if (tid == 1023) s_carry = excl + v;
        __syncthreads();
    }
    if (tid == 0) g_rowptr[NN] = ET;
}
__global__ void k_fill(const int* __restrict__ ei) {
    int stride = gridDim.x * blockDim.x;
    for (int idx = blockIdx.x * blockDim.x + threadIdx.x; idx < ET; idx += stride) {
        int s, d;
        if (idx < NE) { s = ei[idx]; d = ei[NE + idx]; }
        else          { s = d = idx - NE; }
        int pos = atomicAdd(&g_cursor[d], 1);
        g_col[pos] = s;
    }
}

// ================= conversions =================
__global__ void k_cvt_split(const float* __restrict__ in, __nv_bfloat16* __restrict__ hi,
                            __nv_bfloat16* __restrict__ lo, int n4) {
    int i = blockIdx.x * blockDim.x + threadIdx.x;
    if (i >= n4) return;
    float4 v = ((const float4*)in)[i];
    uint32_t h01, l01, h23, l23;
    split2(v.x, v.y, h01, l01);
    split2(v.z, v.w, h23, l23);
    ((uint32_t*)hi)[2 * i] = h01; ((uint32_t*)hi)[2 * i + 1] = h23;
    ((uint32_t*)lo)[2 * i] = l01; ((uint32_t*)lo)[2 * i + 1] = l23;
}

__global__ void k_cvt_wT(const float* __restrict__ W, __nv_bfloat16* __restrict__ hiT,
                         __nv_bfloat16* __restrict__ loT, int K, int N) {
    int idx = blockIdx.x * blockDim.x + threadIdx.x;
    if (idx >= N * K) return;
    int n = idx / K, k = idx % K;
    float v = W[(size_t)k * N + n];
    __nv_bfloat16 h = __float2bfloat16(v);
    hiT[idx] = h;
    loT[idx] = __float2bfloat16(v - __bfloat162float(h));
}

__global__ void k_cvt_wqkv(const float* __restrict__ Wq, const float* __restrict__ Wk,
                           const float* __restrict__ Wv,
                           __nv_bfloat16* __restrict__ hiT, __nv_bfloat16* __restrict__ loT) {
    int idx = blockIdx.x * blockDim.x + threadIdx.x;
    if (idx >= 384 * 128) return;
    int n = idx / 128, k = idx % 128;
    const float* W = (n < 128) ? Wq : ((n < 256) ? Wk : Wv);
    float v = W[(size_t)k * 128 + (n & 127)];
    __nv_bfloat16 h = __float2bfloat16(v);
    hiT[idx] = h;
    loT[idx] = __float2bfloat16(v - __bfloat162float(h));
}

// ================= mma.sync bf16-split GEMM, cp.async 2-stage pipeline =========
constexpr int LDS_ = 40;
constexpr int G_OAL = 128 * LDS_;         // Al offset (elems)
constexpr int G_OBH = 2 * 128 * LDS_;
constexpr int G_OBL = 3 * 128 * LDS_;
constexpr int G_STAGE = 4 * 128 * LDS_;   // 20480 elems per stage
constexpr int GEMM_SMEM = 2 * G_STAGE * 2;  // 81920 bytes

__global__ __launch_bounds__(256) void mma_gemm(
    const __nv_bfloat16* __restrict__ Ah, const __nv_bfloat16* __restrict__ Al,
    const __nv_bfloat16* __restrict__ Bh, const __nv_bfloat16* __restrict__ Bl,
    const float* __restrict__ bias, float* __restrict__ C,
    __nv_bfloat16* __restrict__ Chi, __nv_bfloat16* __restrict__ Clo,
    const float* __restrict__ asv, const float* __restrict__ adv,
    float* __restrict__ esv, float* __restrict__ edv_out,
    int M, int N, int K)
{
    extern __shared__ __nv_bfloat16 smem[];
    int tid = threadIdx.x, lane = tid & 31, warp = tid >> 5;
    int wm = warp & 3, wn = warp >> 2;
    int bm = blockIdx.y, bn = blockIdx.x;
    const __nv_bfloat16* gAh = Ah + (size_t)bm * 128 * K;
    const __nv_bfloat16* gAl = Al + (size_t)bm * 128 * K;
    const __nv_bfloat16* gBh = Bh + (size_t)bn * 128 * K;
    const __nv_bfloat16* gBl = Bl + (size_t)bn * 128 * K;

    int row_c = tid >> 2, seg_c = (tid & 3) * 8;

    auto issue = [&](int ich, int st) {
        int k0 = ich << 5;
        __nv_bfloat16* s = smem + st * G_STAGE;
        #pragma unroll
        for (int r = 0; r < 2; r++) {
            int row = row_c + r * 64;
            size_t go = (size_t)row * K + k0 + seg_c;
            int so = row * LDS_ + seg_c;
            CP16(smem_u32(s + so), gAh + go);
            CP16(smem_u32(s + G_OAL + so), gAl + go);
            CP16(smem_u32(s + G_OBH + so), gBh + go);
            CP16(smem_u32(s + G_OBL + so), gBl + go);
        }
        CP_COMMIT();
    };

    float d[2][8][4];
    #pragma unroll
    for (int mi = 0; mi < 2; mi++)
        #pragma unroll
        for (int ni = 0; ni < 8; ni++)
            #pragma unroll
            for (int j = 0; j < 4; j++) d[mi][ni][j] = 0.f;

    int nch = K >> 5;
    issue(0, 0);
    if (nch > 1) issue(1, 1);

    for (int ich = 0; ich < nch; ich++) {
        if (ich + 1 < nch) CP_WAIT1(); else CP_WAIT0();
        __syncthreads();
        const __nv_bfloat16* s = smem + (ich & 1) * G_STAGE;
        #pragma unroll
        for (int ks = 0; ks < 2; ks++) {
            uint32_t ah[2][4], al[2][4];
            #pragma unroll
            for (int mi = 0; mi < 2; mi++) {
                int row = wm * 32 + mi * 16 + (lane & 15);
                int col = ks * 16 + (lane >> 4) * 8;
                LDMX4(ah[mi], smem_u32(s + row * LDS_ + col));
                LDMX4(al[mi], smem_u32(s + G_OAL + row * LDS_ + col));
            }
            #pragma unroll
            for (int ni = 0; ni < 8; ni++) {
                uint32_t bh[2], bl[2];
                int row = wn * 64 + ni * 8 + (lane & 7);
                int col = ks * 16 + ((lane >> 3) & 1) * 8;
                LDMX2(bh, smem_u32(s + G_OBH + row * LDS_ + col));
                LDMX2(bl, smem_u32(s + G_OBL + row * LDS_ + col));
                #pragma unroll
                for (int mi = 0; mi < 2; mi++) {
                    MMA16816(d[mi][ni], ah[mi], bh);
                    MMA16816(d[mi][ni], al[mi], bh);
                    MMA16816(d[mi][ni], ah[mi], bl);
                }
            }
        }
        __syncthreads();
        if (ich + 2 < nch) issue(ich + 2, ich & 1);
    }

    #pragma unroll
    for (int mi = 0; mi < 2; mi++) {
        int row = bm * 128 + wm * 32 + mi * 16 + (lane >> 2);
        #pragma unroll
        for (int ni = 0; ni < 8; ni++) {
            int col = bn * 128 + wn * 64 + ni * 8 + (lane & 3) * 2;
            if (C) {
                float b0 = bias ? bias[col] : 0.f;
                float b1 = bias ? bias[col + 1] : 0.f;
                *(float2*)(C + (size_t)row * N + col) =
                    make_float2(d[mi][ni][0] + b0, d[mi][ni][1] + b1);
                *(float2*)(C + (size_t)(row + 8) * N + col) =
                    make_float2(d[mi][ni][2] + b0, d[mi][ni][3] + b1);
            } else {
                uint32_t hh, ll;
                split2(d[mi][ni][0], d[mi][ni][1], hh, ll);
                *(uint32_t*)(Chi + (size_t)row * N + col) = hh;
                *(uint32_t*)(Clo + (size_t)row * N + col) = ll;
                split2(d[mi][ni][2], d[mi][ni][3], hh, ll);
                *(uint32_t*)(Chi + (size_t)(row + 8) * N + col) = hh;
                *(uint32_t*)(Clo + (size_t)(row + 8) * N + col) = ll;
            }
        }
    }
    // fused GAT score dot-products (layers 1/2: head = bn*2+wn, C=64)
    if (asv) {
        int hd = bn * 2 + wn;
        float sv[4] = {0.f, 0.f, 0.f, 0.f}, dv[4] = {0.f, 0.f, 0.f, 0.f};
        #pragma unroll
        for (int mi = 0; mi < 2; mi++)
            #pragma unroll
            for (int ni = 0; ni < 8; ni++)
                #pragma unroll
                for (int j = 0; j < 2; j++) {
                    int cl = ni * 8 + (lane & 3) * 2 + j;
                    float a = asv[hd * 64 + cl], b = adv[hd * 64 + cl];
                    sv[mi * 2]     += d[mi][ni][j]     * a;
                    dv[mi * 2]     += d[mi][ni][j]     * b;
                    sv[mi * 2 + 1] += d[mi][ni][2 + j] * a;
                    dv[mi * 2 + 1] += d[mi][ni][2 + j] * b;
                }
        #pragma unroll
        for (int r = 0; r < 4; r++) {
            sv[r] += __shfl_xor_sync(0xffffffffu, sv[r], 1);
            sv[r] += __shfl_xor_sync(0xffffffffu, sv[r], 2);
            dv[r] += __shfl_xor_sync(0xffffffffu, dv[r], 1);
            dv[r] += __shfl_xor_sync(0xffffffffu, dv[r], 2);
        }
        if ((lane & 3) == 0) {
            #pragma unroll
            for (int r = 0; r < 4; r++) {
                int row = bm * 128 + wm * 32 + (r >> 1) * 16 + (lane >> 2) + (r & 1) * 8;
                esv[(size_t)row * 4 + hd]     = sv[r];
                edv_out[(size_t)row * 4 + hd] = dv[r];
            }
        }
    }
}

// ================= QKV fused GEMM (pipelined): N=384 routing =================
__global__ __launch_bounds__(256) void mma_gemm_qkv(
    const __nv_bfloat16* __restrict__ Ah, const __nv_bfloat16* __restrict__ Al,
    const __nv_bfloat16* __restrict__ Bh, const __nv_bfloat16* __restrict__ Bl,
    __nv_bfloat16* __restrict__ QH, __nv_bfloat16* __restrict__ QL,
    __nv_bfloat16* __restrict__ KH, __nv_bfloat16* __restrict__ KL,
    __nv_bfloat16* __restrict__ VH, __nv_bfloat16* __restrict__ VL)
{
    constexpr int K = 128;
    extern __shared__ __nv_bfloat16 smem[];
    int tid = threadIdx.x, lane = tid & 31, warp = tid >> 5;
    int wm = warp & 3, wn = warp >> 2;
    int bm = blockIdx.y, bn = blockIdx.x;
    const __nv_bfloat16* gAh = Ah + (size_t)bm * 128 * K;
    const __nv_bfloat16* gAl = Al + (size_t)bm * 128 * K;
    const __nv_bfloat16* gBh = Bh + (size_t)bn * 128 * K;
    const __nv_bfloat16* gBl = Bl + (size_t)bn * 128 * K;

    int row_c = tid >> 2, seg_c = (tid & 3) * 8;
    auto issue = [&](int ich, int st) {
        int k0 = ich << 5;
        __nv_bfloat16* s = smem + st * G_STAGE;
        #pragma unroll
        for (int r = 0; r < 2; r++) {
            int row = row_c + r * 64;
            size_t go = (size_t)row * K + k0 + seg_c;
            int so = row * LDS_ + seg_c;
            CP16(smem_u32(s + so), gAh + go);
            CP16(smem_u32(s + G_OAL + so), gAl + go);
            CP16(smem_u32(s + G_OBH + so), gBh + go);
            CP16(smem_u32(s + G_OBL + so), gBl + go);
        }
        CP_COMMIT();
    };

    float d[2][8][4];
    #pragma unroll
    for (int mi = 0; mi < 2; mi++)
        #pragma unroll
        for (int ni = 0; ni < 8; ni++)
            #pragma unroll
            for (int j = 0; j < 4; j++) d[mi][ni][j] = 0.f;

    constexpr int nch = K >> 5;  // 4
    issue(0, 0);
    issue(1, 1);
    for (int ich = 0; ich < nch; ich++) {
        if (ich + 1 < nch) CP_WAIT1(); else CP_WAIT0();
        __syncthreads();
        const __nv_bfloat16* s = smem + (ich & 1) * G_STAGE;
        #pragma unroll
        for (int ks = 0; ks < 2; ks++) {
            uint32_t ah[2][4], al[2][4];
            #pragma unroll
            for (int mi = 0; mi < 2; mi++) {
                int row = wm * 32 + mi * 16 + (lane & 15);
                int col = ks * 16 + (lane >> 4) * 8;
                LDMX4(ah[mi], smem_u32(s + row * LDS_ + col));
                LDMX4(al[mi], smem_u32(s + G_OAL + row * LDS_ + col));
            }
            #pragma unroll
            for (int ni = 0; ni < 8; ni++) {
                uint32_t bh[2], bl[2];
                int row = wn * 64 + ni * 8 + (lane & 7);
                int col = ks * 16 + ((lane >> 3) & 1) * 8;
                LDMX2(bh, smem_u32(s + G_OBH + row * LDS_ + col));
                LDMX2(bl, smem_u32(s + G_OBL + row * LDS_ + col));
                #pragma unroll
                for (int mi = 0; mi < 2; mi++) {
                    MMA16816(d[mi][ni], ah[mi], bh);
                    MMA16816(d[mi][ni], al[mi], bh);
                    MMA16816(d[mi][ni], ah[mi], bl);
                }
            }
        }
        __syncthreads();
        if (ich + 2 < nch) issue(ich + 2, ich & 1);
    }
    __nv_bfloat16 *Oh, *Ol;
    if (bn == 0)      { Oh = QH; Ol = QL; }
    else if (bn == 1) { Oh = KH; Ol = KL; }
    else              { Oh = VH; Ol = VL; }
    #pragma unroll
    for (int mi = 0; mi < 2; mi++) {
        int row = bm * 128 + wm * 32 + mi * 16 + (lane >> 2);
        #pragma unroll
        for (int ni = 0; ni < 8; ni++) {
            int col = wn * 64 + ni * 8 + (lane & 3) * 2;
            uint32_t hh, ll;
            split2(d[mi][ni][0], d[mi][ni][1], hh, ll);
            *(uint32_t*)(Oh + (size_t)row * 128 + col) = hh;
            *(uint32_t*)(Ol + (size_t)row * 128 + col) = ll;
            split2(d[mi][ni][2], d[mi][ni][3], hh, ll);
            *(uint32_t*)(Oh + (size_t)(row + 8) * 128 + col) = hh;
            *(uint32_t*)(Ol + (size_t)(row + 8) * 128 + col) = ll;
        }
    }
}

// ================= GAT score vectors (layer 3 only) =================
__global__ void k_scores(const float* __restrict__ h, const float* __restrict__ as_,
                         const float* __restrict__ ad_, float* __restrict__ es,
                         float* __restrict__ ed, int H, int C)
{
    int idx = blockIdx.x * blockDim.x + threadIdx.x;
    if (idx >= NN * H) return;
    int node = idx / H, hd = idx % H;
    const float4* hp = (const float4*)(h + (size_t)node * H * C + (size_t)hd * C);
    const float4* ap = (const float4*)(as_ + (size_t)hd * C);
    const float4* bp = (const float4*)(ad_ + (size_t)hd * C);
    float s = 0.f, d = 0.f;
    for (int c = 0; c < C / 4; c++) {
        float4 hv = hp[c], av = ap[c], bv = bp[c];
        s += hv.x * av.x + hv.y * av.y + hv.z * av.z + hv.w * av.w;
        d += hv.x * bv.x + hv.y * bv.y + hv.z * bv.z + hv.w * bv.w;
    }
    es[idx] = s;
    ed[idx] = d;
}

// ================= GAT aggregation — single pass =================
template <int D, int H>
__global__ __launch_bounds__(256) void k_gat_agg(
    const float* __restrict__ hfeat, const float* __restrict__ es,
    const float* __restrict__ ed, const float* __restrict__ bias,
    const float* __restrict__ gamma, const float* __restrict__ beta,
    const float* __restrict__ resid,
    __nv_bfloat16* __restrict__ outH, __nv_bfloat16* __restrict__ outL)
{
    constexpr int C = D / H;
    constexpr int R = D / 32;
    int warp = (blockIdx.x * blockDim.x + threadIdx.x) >> 5;
    int lane = threadIdx.x & 31;
    if (warp >= NN) return;
    int i = warp;
    int beg = g_rowptr[i], end = g_rowptr[i + 1];

    float edv[H], z[H];
    #pragma unroll
    for (int h = 0; h < H; h++) {
        edv[h] = ed[(size_t)i * H + h];
        z[h] = 0.f;
    }
    float acc[R];
    #pragma unroll
    for (int j = 0; j < R; j++) acc[j] = 0.f;

    for (int e = beg; e < end; e++) {
        int s = g_col[e];
        float al[H];
        #pragma unroll
        for (int h = 0; h < H; h++) {
            float v = es[(size_t)s * H + h] + edv[h];
            v = v > 0.f ? v : 0.2f * v;
            al[h] = expf(v);
            z[h] += al[h];
        }
        const float* hs = hfeat + (size_t)s * D;
        #pragma unroll
        for (int j = 0; j < R; j++) {
            int c = lane + 32 * j;
            acc[j] += al[(32 * j) / C] * hs[c];
        }
    }
    #pragma unroll
    for (int h = 0; h < H; h++) z[h] = 1.f / (z[h] + 1e-16f);

    float x[R];
    #pragma unroll
    for (int j = 0; j < R; j++) {
        int c = lane + 32 * j;
        float val = acc[j] * z[(32 * j) / C] + bias[c];
        if (resid) val += resid[(size_t)i * D + c];
        x[j] = val;
    }
    if (gamma) {
        #pragma unroll
        for (int j = 0; j < R; j++)
            x[j] = x[j] > 0.f ? x[j] : (expf(x[j]) - 1.f);
        float s = 0.f;
        #pragma unroll
        for (int j = 0; j < R; j++) s += x[j];
        #pragma unroll
        for (int o = 16; o; o >>= 1) s += __shfl_xor_sync(0xffffffffu, s, o);
        float mu = s / (float)D;
        float vs = 0.f;
        #pragma unroll
        for (int j = 0; j < R; j++) { float dd = x[j] - mu; vs += dd * dd; }
        #pragma unroll
        for (int o = 16; o; o >>= 1) vs += __shfl_xor_sync(0xffffffffu, vs, o);
        float inv = rsqrtf(vs / (float)D + 1e-5f);
        #pragma unroll
        for (int j = 0; j < R; j++) {
            int c = lane + 32 * j;
            x[j] = (x[j] - mu) * inv * gamma[c] + beta[c];
        }
    }
    #pragma unroll
    for (int j = 0; j < R; j++) {
        size_t idx = (size_t)i * D + lane + 32 * j;
        __nv_bfloat16 h = __float2bfloat16(x[j]);
        outH[idx] = h;
        outL[idx] = __float2bfloat16(x[j] - __bfloat162float(h));
    }
}

// ================= V transpose =================
__global__ __launch_bounds__(256) void k_vT(const __nv_bfloat16* __restrict__ VH,
                                            const __nv_bfloat16* __restrict__ VL,
                                            __nv_bfloat16* __restrict__ VTH,
                                            __nv_bfloat16* __restrict__ VTL)
{
    __shared__ float t[128][33];
    int gh = blockIdx.y, g = gh >> 2, h = gh & 3;
    int k0 = blockIdx.x * 128;
    int tid = threadIdx.x;
    #pragma unroll
    for (int it = 0; it < 16; it++) {
        int idx = tid + it * 256;
        int r = idx >> 5, c = idx & 31;
        size_t gi = ((size_t)g * GS + k0 + r) * 128 + h * 32 + c;
        t[r][c] = __bfloat162float(VH[gi]) + __bfloat162float(VL[gi]);
    }
    __syncthreads();
    #pragma unroll
    for (int it = 0; it < 16; it++) {
        int idx = tid + it * 256;
        int n = idx >> 7, k = idx & 127;
        float v = t[k][n];
        __nv_bfloat16 hh = __float2bfloat16(v);
        size_t o = ((size_t)gh * 32 + n) * 512 + k0 + k;
        VTH[o] = hh;
        VTL[o] = __float2bfloat16(v - __bfloat162float(hh));
    }
}

// ================= fused flash attention =================
constexpr int VPAD = 520;
constexpr int SM_QH = 0;
constexpr int SM_QL = SM_QH + 128 * LDS_;
constexpr int SM_KH = SM_QL + 128 * LDS_;
constexpr int SM_KL = SM_KH + 512 * LDS_;
constexpr int SM_VH = SM_KL + 512 * LDS_;
constexpr int SM_VL = SM_VH + 32 * VPAD;
constexpr int SM_TOT = SM_VL + 32 * VPAD;
constexpr int FLASH_SMEM = SM_TOT * 2;

__global__ __launch_bounds__(256) void k_flash(
    const __nv_bfloat16* __restrict__ QH, const __nv_bfloat16* __restrict__ QL,
    const __nv_bfloat16* __restrict__ KH, const __nv_bfloat16* __restrict__ KL,
    const __nv_bfloat16* __restrict__ VTH, const __nv_bfloat16* __restrict__ VTL,
    __nv_bfloat16* __restrict__ OHo, __nv_bfloat16* __restrict__ OLo)
{
    extern __shared__ __nv_bfloat16 sm[];
    int gh = blockIdx.y, g = gh >> 2, h = gh & 3;
    int qt = blockIdx.x;
    int tid = threadIdx.x, lane = tid & 31, warp = tid >> 5;

    {
        const __nv_bfloat16* kh = KH + (size_t)g * GS * 128 + h * 32;
        const __nv_bfloat16* kl = KL + (size_t)g * GS * 128 + h * 32;
        #pragma unroll
        for (int it = 0; it < 8; it++) {
            int idx = tid + it * 256;
            int row = idx >> 2, seg = (idx & 3) * 8;
            *(uint4*)&sm[SM_KH + row * LDS_ + seg] = *(const uint4*)(kh + (size_t)row * 128 + seg);
            *(uint4*)&sm[SM_KL + row * LDS_ + seg] = *(const uint4*)(kl + (size_t)row * 128 + seg);
        }
        const __nv_bfloat16* qh = QH + ((size_t)g * GS + qt * 128) * 128 + h * 32;
        const __nv_bfloat16* ql = QL + ((size_t)g * GS + qt * 128) * 128 + h * 32;
        #pragma unroll
        for (int it = 0; it < 2; it++) {
            int idx = tid + it * 256;
            int row = idx >> 2, seg = (idx & 3) * 8;
            *(uint4*)&sm[SM_QH + row * LDS_ + seg] = *(const uint4*)(qh + (size_t)row * 128 + seg);
            *(uint4*)&sm[SM_QL + row * LDS_ + seg] = *(const uint4*)(ql + (size_t)row * 128 + seg);
        }
        const __nv_bfloat16* vh = VTH + (size_t)gh * 32 * 512;
        const __nv_bfloat16* vl = VTL + (size_t)gh * 32 * 512;
        #pragma unroll
        for (int it = 0; it < 8; it++) {
            int idx = tid + it * 256;
            int row = idx >> 6, c8 = (idx & 63) * 8;
            *(uint4*)&sm[SM_VH + row * VPAD + c8] = *(const uint4*)(vh + (size_t)row * 512 + c8);
            *(uint4*)&sm[SM_VL + row * VPAD + c8] = *(const uint4*)(vl + (size_t)row * 512 + c8);
        }
    }
    __syncthreads();

    uint32_t qh_[2][4], ql_[2][4];
    #pragma unroll
    for (int kf = 0; kf < 2; kf++) {
        int row = warp * 16 + (lane & 15);
        int col = kf * 16 + (lane >> 4) * 8;
        LDMX4(qh_[kf], smem_u32(&sm[SM_QH + row * LDS_ + col]));
        LDMX4(ql_[kf], smem_u32(&sm[SM_QL + row * LDS_ + col]));
    }

    float m0 = -1e30f, m1 = -1e30f, l0 = 0.f, l1 = 0.f;
    float O[4][4];
    #pragma unroll
    for (int n = 0; n < 4; n++)
        #pragma unroll
        for (int j = 0; j < 4; j++) O[n][j] = 0.f;

    const float scale = 0.088388347648318447f;

    for (int kt = 0; kt < 4; kt++) {
        float S[16][4];
        #pragma unroll
        for (int j = 0; j < 16; j++)
            #pragma unroll
            for (int r = 0; r < 4; r++) S[j][r] = 0.f;
        #pragma unroll
        for (int j = 0; j < 16; j++) {
            #pragma unroll
            for (int kf = 0; kf < 2; kf++) {
                uint32_t bh[2], bl[2];
                int row = kt * 128 + j * 8 + (lane & 7);
                int col = kf * 16 + ((lane >> 3) & 1) * 8;
                LDMX2(bh, smem_u32(&sm[SM_KH + row * LDS_ + col]));
                LDMX2(bl, smem_u32(&sm[SM_KL + row * LDS_ + col]));
                MMA16816(S[j], qh_[kf], bh);
                MMA16816(S[j], ql_[kf], bh);
                MMA16816(S[j], qh_[kf], bl);
            }
        }
        float mx0 = -1e30f, mx1 = -1e30f;
        #pragma unroll
        for (int j = 0; j < 16; j++) {
            S[j][0] *= scale; S[j][1] *= scale; S[j][2] *= scale; S[j][3] *= scale;
            mx0 = fmaxf(mx0, fmaxf(S[j][0], S[j][1]));
            mx1 = fmaxf(mx1, fmaxf(S[j][2], S[j][3]));
        }
        #pragma unroll
        for (int o = 1; o < 4; o <<= 1) {
            mx0 = fmaxf(mx0, __shfl_xor_sync(0xffffffffu, mx0, o));
            mx1 = fmaxf(mx1, __shfl_xor_sync(0xffffffffu, mx1, o));
        }
        float nm0 = fmaxf(m0, mx0), nm1 = fmaxf(m1, mx1);
        float a0 = expf(m0 - nm0), a1 = expf(m1 - nm1);
        float rs0 = 0.f, rs1 = 0.f;
        #pragma unroll
        for (int j = 0; j < 16; j++) {
            S[j][0] = expf(S[j][0] - nm0); S[j][1] = expf(S[j][1] - nm0);
            S[j][2] = expf(S[j][2] - nm1); S[j][3] = expf(S[j][3] - nm1);
            rs0 += S[j][0] + S[j][1];
            rs1 += S[j][2] + S[j][3];
        }
        #pragma unroll
        for (int o = 1; o < 4; o <<= 1) {
            rs0 += __shfl_xor_sync(0xffffffffu, rs0, o);
            rs1 += __shfl_xor_sync(0xffffffffu, rs1, o);
        }
        l0 = l0 * a0 + rs0;
        l1 = l1 * a1 + rs1;
        #pragma unroll
        for (int n = 0; n < 4; n++) {
            O[n][0] *= a0; O[n][1] *= a0; O[n][2] *= a1; O[n][3] *= a1;
        }
        m0 = nm0; m1 = nm1;
        #pragma unroll
        for (int jp = 0; jp < 8; jp++) {
            uint32_t aph[4], apl[4];
            split2(S[2 * jp][0],     S[2 * jp][1],     aph[0], apl[0]);
            split2(S[2 * jp][2],     S[2 * jp][3],     aph[1], apl[1]);
            split2(S[2 * jp + 1][0], S[2 * jp + 1][1], aph[2], apl[2]);
            split2(S[2 * jp + 1][2], S[2 * jp + 1][3], aph[3], apl[3]);
            #pragma unroll
            for (int n = 0; n < 4; n++) {
                uint32_t bh[2], bl[2];
                int row = n * 8 + (lane & 7);
                int col = kt * 128 + jp * 16 + ((lane >> 3) & 1) * 8;
                LDMX2(bh, smem_u32(&sm[SM_VH + row * VPAD + col]));
                LDMX2(bl, smem_u32(&sm[SM_VL + row * VPAD + col]));
                MMA16816(O[n], aph, bh);
                MMA16816(O[n], apl, bh);
                MMA16816(O[n], aph, bl);
            }
        }
    }
    float il0 = 1.f / l0, il1 = 1.f / l1;
    int node = g * GS + qt * 128 + warp * 16 + (lane >> 2);
    #pragma unroll
    for (int n = 0; n < 4; n++) {
        int col = h * 32 + n * 8 + (lane & 3) * 2;
        uint32_t hh, ll;
        split2(O[n][0] * il0, O[n][1] * il0, hh, ll);
        *(uint32_t*)(OHo + (size_t)node * 128 + col) = hh;
        *(uint32_t*)(OLo + (size_t)node * 128 + col) = ll;
        split2(O[n][2] * il1, O[n][3] * il1, hh, ll);
        *(uint32_t*)(OHo + (size_t)(node + 8) * 128 + col) = hh;
        *(uint32_t*)(OLo + (size_t)(node + 8) * 128 + col) = ll;
    }
}

// ================= host orchestration =================
extern "C" void kernel_launch(void* const* d_in, const int* in_sizes, int n_in,
                              void* d_out, int out_size)
{
    const float* x   = (const float*)d_in[0];
    const int*   ei  = (const int*)  d_in[1];
    const float* W1  = (const float*)d_in[3];
    const float* a1s = (const float*)d_in[4];
    const float* a1d = (const float*)d_in[5];
    const float* b1  = (const float*)d_in[6];
    const float* W2  = (const float*)d_in[7];
    const float* a2s = (const float*)d_in[8];
    const float* a2d = (const float*)d_in[9];
    const float* b2  = (const float*)d_in[10];
    const float* W3  = (const float*)d_in[11];
    const float* a3s = (const float*)d_in[12];
    const float* a3d = (const float*)d_in[13];
    const float* b3  = (const float*)d_in[14];
    const float* g1  = (const float*)d_in[15];
    const float* be1 = (const float*)d_in[16];
    const float* g2  = (const float*)d_in[17];
    const float* be2 = (const float*)d_in[18];
    const float* Wr  = (const float*)d_in[19];
    const float* br  = (const float*)d_in[20];
    const float* Wq  = (const float*)d_in[21];
    const float* Wk  = (const float*)d_in[22];
    const float* Wv  = (const float*)d_in[23];
    const float* Wo  = (const float*)d_in[24];
    const float* bo  = (const float*)d_in[25];
    float* out = (float*)d_out;

    float* sb = nullptr;
    cudaGetSymbolAddress((void**)&sb, g_scratch);
    __nv_bfloat16* bb = nullptr;
    cudaGetSymbolAddress((void**)&bb, g_bf);
    cudaFuncSetAttribute(k_flash, cudaFuncAttributeMaxDynamicSharedMemorySize, FLASH_SMEM);
    cudaFuncSetAttribute(mma_gemm, cudaFuncAttributeMaxDynamicSharedMemorySize, GEMM_SMEM);
    cudaFuncSetAttribute(mma_gemm_qkv, cudaFuncAttributeMaxDynamicSharedMemorySize, GEMM_SMEM);

    float* p_h  = sb + OFF_H;
    float* p_h3 = sb + OFF_H3;
    float* p_r  = sb + OFF_R;
    float* p_es = sb + OFF_ES;
    float* p_ed = sb + OFF_ED;

    // CSR
    k_zero_cnt<<<NN / 256, 256>>>();
    k_count<<<1024, 256>>>(ei);
    k_scan<<<1, 1024>>>();
    k_fill<<<1152, 256>>>(ei);

    // weight conversions
    k_cvt_wT<<<(256*64 + 255)/256, 256>>>(W1, bb + B_W1H, bb + B_W1L, 64, 256);
    k_cvt_wT<<<(256*256 + 255)/256, 256>>>(W2, bb + B_W2H, bb + B_W2L, 256, 256);
    k_cvt_wT<<<(128*256 + 255)/256, 256>>>(W3, bb + B_W3H, bb + B_W3L, 256, 128);
    k_cvt_wT<<<(128*64 + 255)/256, 256>>>(Wr, bb + B_WRH, bb + B_WRL, 64, 128);
    k_cvt_wqkv<<<(384*128 + 255)/256, 256>>>(Wq, Wk, Wv, bb + B_WQKVH, bb + B_WQKVL);
    k_cvt_wT<<<(128*128 + 255)/256, 256>>>(Wo, bb + B_WOH, bb + B_WOL, 128, 128);

    // x -> bf16 hi/lo
    k_cvt_split<<<(NN*64/4 + 255)/256, 256>>>(x, bb + B_XH, bb + B_XL, NN*64/4);

    // layer 1 (fused scores)
    mma_gemm<<<dim3(2, 512), 256, GEMM_SMEM>>>(bb + B_XH, bb + B_XL, bb + B_W1H, bb + B_W1L,
                                    nullptr, p_h, nullptr, nullptr,
                                    a1s, a1d, p_es, p_ed, NN, 256, 64);
    k_gat_agg<256, 4><<<NN / 8, 256>>>(p_h, p_es, p_ed, b1, g1, be1, nullptr,
                                       bb + B_TH, bb + B_TL);
    // layer 2 (fused scores)
    mma_gemm<<<dim3(2, 512), 256, GEMM_SMEM>>>(bb + B_TH, bb + B_TL, bb + B_W2H, bb + B_W2L,
                                    nullptr, p_h, nullptr, nullptr,
                                    a2s, a2d, p_es, p_ed, NN, 256, 256);
    k_gat_agg<256, 4><<<NN / 8, 256>>>(p_h, p_es, p_ed, b2, g2, be2, nullptr,
                                       bb + B_TH, bb + B_TL);
    // layer 3 + residual
    mma_gemm<<<dim3(1, 512), 256, GEMM_SMEM>>>(bb + B_TH, bb + B_TL, bb + B_W3H, bb + B_W3L,
                                    nullptr, p_h3, nullptr, nullptr,
                                    nullptr, nullptr, nullptr, nullptr, NN, 128, 256);
    k_scores<<<NN / 256, 256>>>(p_h3, a3s, a3d, p_es, p_ed, 1, 128);
    mma_gemm<<<dim3(1, 512), 256, GEMM_SMEM>>>(bb + B_XH, bb + B_XL, bb + B_WRH, bb + B_WRL,
                                    br, p_r, nullptr, nullptr,
                                    nullptr, nullptr, nullptr, nullptr, NN, 128, 64);
    k_gat_agg<128, 1><<<NN / 8, 256>>>(p_h3, p_es, p_ed, b3, nullptr, nullptr, p_r,
                                       bb + B_HRH, bb + B_HRL);
    // fused QKV projection
    mma_gemm_qkv<<<dim3(3, 512), 256, GEMM_SMEM>>>(bb + B_HRH, bb + B_HRL,
                                        bb + B_WQKVH, bb + B_WQKVL,
                                        bb + B_QH, bb + B_QL,
                                        bb + B_KH, bb + B_KL,
                                        bb + B_VH, bb + B_VL);
    k_vT<<<dim3(4, NG * 4), 256>>>(bb + B_VH, bb + B_VL, bb + B_VTH, bb + B_VTL);
    // fused attention
    k_flash<<<dim3(4, NG * 4), 256, FLASH_SMEM>>>(
        bb + B_QH, bb + B_QL, bb + B_KH, bb + B_KL,
        bb + B_VTH, bb + B_VTL, bb + B_AOH, bb + B_AOL);
    // output projection
    mma_gemm<<<dim3(1, 512), 256, GEMM_SMEM>>>(bb + B_AOH, bb + B_AOL, bb + B_WOH, bb + B_WOL,
                                    bo, out, nullptr, nullptr,
                                    nullptr, nullptr, nullptr, nullptr, NN, 128, 128);
}

// round 8
// speedup vs baseline: 2.0594x; 1.1104x over previous
#include <cuda_runtime.h>
#include <cuda_bf16.h>
#include <math.h>
#include <stdint.h>

// ---------------- problem constants ----------------
constexpr int NN   = 65536;
constexpr int NE   = 524288;
constexpr int ET   = NE + NN;
constexpr int GS   = 512;
constexpr int NG   = NN / GS;
constexpr int D1   = 256;
constexpr int D3   = 128;

// ---------------- fp32 scratch ----------------
constexpr size_t OFF_H    = 0;
constexpr size_t OFF_H3   = OFF_H  + (size_t)NN*D1;
constexpr size_t OFF_R    = OFF_H3 + (size_t)NN*D3;
constexpr size_t OFF_ES   = OFF_R  + (size_t)NN*D3;
constexpr size_t OFF_ED   = OFF_ES + (size_t)NN*4;
constexpr size_t SCRATCH  = OFF_ED + (size_t)NN*4;

__device__ __align__(256) float g_scratch[SCRATCH];

// ---------------- bf16 scratch ----------------
constexpr size_t B_XH  = 0;
constexpr size_t B_XL  = B_XH  + (size_t)NN*64;
constexpr size_t B_TH  = B_XL  + (size_t)NN*64;
constexpr size_t B_TL  = B_TH  + (size_t)NN*256;
constexpr size_t B_HRH = B_TL  + (size_t)NN*256;
constexpr size_t B_HRL = B_HRH + (size_t)NN*128;
constexpr size_t B_AOH = B_HRL + (size_t)NN*128;
constexpr size_t B_AOL = B_AOH + (size_t)NN*128;
constexpr size_t B_QH  = B_AOL + (size_t)NN*128;
constexpr size_t B_QL  = B_QH  + (size_t)NN*128;
constexpr size_t B_KH  = B_QL  + (size_t)NN*128;
constexpr size_t B_KL  = B_KH  + (size_t)NN*128;
constexpr size_t B_VH  = B_KL  + (size_t)NN*128;
constexpr size_t B_VL  = B_VH  + (size_t)NN*128;
constexpr size_t B_VTH = B_VL  + (size_t)NN*128;
constexpr size_t B_VTL = B_VTH + (size_t)NN*128;
constexpr size_t B_W1H = B_VTL + (size_t)NN*128;
constexpr size_t B_W1L = B_W1H + 256*64;
constexpr size_t B_W2H = B_W1L + 256*64;
constexpr size_t B_W2L = B_W2H + 256*256;
constexpr size_t B_W3H = B_W2L + 256*256;
constexpr size_t B_W3L = B_W3H + 128*256;
constexpr size_t B_WRH = B_W3L + 128*256;
constexpr size_t B_WRL = B_WRH + 128*64;
constexpr size_t B_WQKVH = B_WRL + 128*64;
constexpr size_t B_WQKVL = B_WQKVH + 384*128;
constexpr size_t B_WOH = B_WQKVL + 384*128;
constexpr size_t B_WOL = B_WOH + 128*128;
constexpr size_t BF_TOTAL = B_WOL + 128*128;

__device__ __align__(256) __nv_bfloat16 g_bf[BF_TOTAL];

__device__ int g_rowptr[NN + 1];
__device__ int g_cnt[NN];
__device__ int g_cursor[NN];
__device__ int g_col[ET];
__device__ int g_blocksum[256];

// ================= helpers =================
__device__ __forceinline__ uint32_t smem_u32(const void* p) {
    uint32_t a;
    asm("{ .reg .u64 t; cvta.to.shared.u64 t, %1; cvt.u32.u64 %0, t; }" : "=r"(a) : "l"(p));
    return a;
}
#define LDMX4(r, a) \
    asm volatile("ldmatrix.sync.aligned.m8n8.x4.shared.b16 {%0,%1,%2,%3}, [%4];" \
        : "=r"((r)[0]), "=r"((r)[1]), "=r"((r)[2]), "=r"((r)[3]) : "r"(a))
#define LDMX2(r, a) \
    asm volatile("ldmatrix.sync.aligned.m8n8.x2.shared.b16 {%0,%1}, [%2];" \
        : "=r"((r)[0]), "=r"((r)[1]) : "r"(a))
#define MMA16816(d, a, b) \
    asm volatile("mma.sync.aligned.m16n8k16.row.col.f32.bf16.bf16.f32 " \
        "{%0,%1,%2,%3}, {%4,%5,%6,%7}, {%8,%9}, {%0,%1,%2,%3};" \
        : "+f"((d)[0]), "+f"((d)[1]), "+f"((d)[2]), "+f"((d)[3]) \
        : "r"((a)[0]), "r"((a)[1]), "r"((a)[2]), "r"((a)[3]), \
          "r"((b)[0]), "r"((b)[1]))
#define CP16(dst, src) \
    asm volatile("cp.async.cg.shared.global [%0], [%1], 16;" :: "r"(dst), "l"(src))
#define CP_COMMIT() asm volatile("cp.async.commit_group;" ::: "memory")
#define CP_WAIT1()  asm volatile("cp.async.wait_group 1;" ::: "memory")
#define CP_WAIT0()  asm volatile("cp.async.wait_group 0;" ::: "memory")

__device__ __forceinline__ void split2(float v0, float v1, uint32_t& hh, uint32_t& ll) {
    __nv_bfloat16 h0 = __float2bfloat16(v0), h1 = __float2bfloat16(v1);
    __nv_bfloat16 l0 = __float2bfloat16(v0 - __bfloat162float(h0));
    __nv_bfloat16 l1 = __float2bfloat16(v1 - __bfloat162float(h1));
    __nv_bfloat162 H; H.x = h0; H.y = h1;
    __nv_bfloat162 L; L.x = l0; L.y = l1;
    hh = *(uint32_t*)&H; ll = *(uint32_t*)&L;
}

// ================= CSR build (parallel scan) =================
__global__ void k_zero_cnt() {
    int i = blockIdx.x * blockDim.x + threadIdx.x;
    if (i < NN) g_cnt[i] = 0;
}
__global__ void k_count(const int* __restrict__ ei) {
    int stride = gridDim.x * blockDim.x;
    for (int idx = blockIdx.x * blockDim.x + threadIdx.x; idx < NE; idx += stride)
        atomicAdd(&g_cnt[ei[NE + idx]], 1);
}
// 256 blocks x 256 threads: block-local exclusive scan of (cnt+1); blocksum out
__global__ void k_scan1() {
    __shared__ int ws[8];
    int b = blockIdx.x, tid = threadIdx.x, lane = tid & 31, wid = tid >> 5;
    int v = g_cnt[b * 256 + tid] + 1;
    int x = v;
    #pragma unroll
    for (int o = 1; o < 32; o <<= 1) {
        int t = __shfl_up_sync(0xffffffffu, x, o);
        if (lane >= o) x += t;
    }
    if (lane == 31) ws[wid] = x;
    __syncthreads();
    if (tid == 0) {
        int run = 0;
        #pragma unroll
        for (int k = 0; k < 8; k++) { int t = ws[k]; ws[k] = run; run += t; }
        g_blocksum[b] = run;
    }
    __syncthreads();
    g_rowptr[b * 256 + tid] = x - v + ws[wid];   // block-local exclusive
}
// 1 block: exclusive scan of 256 block sums
__global__ void k_scan2() {
    __shared__ int ws[8];
    int tid = threadIdx.x, lane = tid & 31, wid = tid >> 5;
    int v = g_blocksum[tid];
    int x = v;
    #pragma unroll
    for (int o = 1; o < 32; o <<= 1) {
        int t = __shfl_up_sync(0xffffffffu, x, o);
        if (lane >= o) x += t;
    }
    if (lane == 31) ws[wid] = x;
    __syncthreads();
    if (tid == 0) {
        int run = 0;
        #pragma unroll
        for (int k = 0; k < 8; k++) { int t = ws[k]; ws[k] = run; run += t; }
    }
    __syncthreads();
    g_blocksum[tid] = x - v + ws[wid];
}
// add block offsets
__global__ void k_scan3() {
    int idx = blockIdx.x * 256 + threadIdx.x;
    int v = g_rowptr[idx] + g_blocksum[blockIdx.x];
    g_rowptr[idx] = v;
    g_cursor[idx] = v;
    if (idx == 0) g_rowptr[NN] = ET;
}
__global__ void k_fill(const int* __restrict__ ei) {
    int stride = gridDim.x * blockDim.x;
    for (int idx = blockIdx.x * blockDim.x + threadIdx.x; idx < ET; idx += stride) {
        int s, d;
        if (idx < NE) { s = ei[idx]; d = ei[NE + idx]; }
        else          { s = d = idx - NE; }
        int pos = atomicAdd(&g_cursor[d], 1);
        g_col[pos] = s;
    }
}

// ================= conversions =================
__global__ void k_cvt_split(const float* __restrict__ in, __nv_bfloat16* __restrict__ hi,
                            __nv_bfloat16* __restrict__ lo, int n4) {
    int i = blockIdx.x * blockDim.x + threadIdx.x;
    if (i >= n4) return;
    float4 v = ((const float4*)in)[i];
    uint32_t h01, l01, h23, l23;
    split2(v.x, v.y, h01, l01);
    split2(v.z, v.w, h23, l23);
    ((uint32_t*)hi)[2 * i] = h01; ((uint32_t*)hi)[2 * i + 1] = h23;
    ((uint32_t*)lo)[2 * i] = l01; ((uint32_t*)lo)[2 * i + 1] = l23;
}

__global__ void k_cvt_wT(const float* __restrict__ W, __nv_bfloat16* __restrict__ hiT,
                         __nv_bfloat16* __restrict__ loT, int K, int N) {
    int idx = blockIdx.x * blockDim.x + threadIdx.x;
    if (idx >= N * K) return;
    int n = idx / K, k = idx % K;
    float v = W[(size_t)k * N + n];
    __nv_bfloat16 h = __float2bfloat16(v);
    hiT[idx] = h;
    loT[idx] = __float2bfloat16(v - __bfloat162float(h));
}

__global__ void k_cvt_wqkv(const float* __restrict__ Wq, const float* __restrict__ Wk,
                           const float* __restrict__ Wv,
                           __nv_bfloat16* __restrict__ hiT, __nv_bfloat16* __restrict__ loT) {
    int idx = blockIdx.x * blockDim.x + threadIdx.x;
    if (idx >= 384 * 128) return;
    int n = idx / 128, k = idx % 128;
    const float* W = (n < 128) ? Wq : ((n < 256) ? Wk : Wv);
    float v = W[(size_t)k * 128 + (n & 127)];
    __nv_bfloat16 h = __float2bfloat16(v);
    hiT[idx] = h;
    loT[idx] = __float2bfloat16(v - __bfloat162float(h));
}

// ================= mma.sync bf16-split GEMM, cp.async pipeline, 2 CTA/SM ======
constexpr int LDS_ = 40;
constexpr int G_OAL = 128 * LDS_;
constexpr int G_OBH = 2 * 128 * LDS_;
constexpr int G_OBL = 3 * 128 * LDS_;
constexpr int G_STAGE = 4 * 128 * LDS_;
constexpr int GEMM_SMEM = 2 * G_STAGE * 2;

__global__ __launch_bounds__(256, 2) void mma_gemm(
    const __nv_bfloat16* __restrict__ Ah, const __nv_bfloat16* __restrict__ Al,
    const __nv_bfloat16* __restrict__ Bh, const __nv_bfloat16* __restrict__ Bl,
    const float* __restrict__ bias, float* __restrict__ C,
    __nv_bfloat16* __restrict__ Chi, __nv_bfloat16* __restrict__ Clo,
    const float* __restrict__ asv, const float* __restrict__ adv,
    float* __restrict__ esv, float* __restrict__ edv_out,
    int M, int N, int K)
{
    extern __shared__ __nv_bfloat16 smem[];
    int tid = threadIdx.x, lane = tid & 31, warp = tid >> 5;
    int wm = warp & 3, wn = warp >> 2;
    int bm = blockIdx.y, bn = blockIdx.x;
    const __nv_bfloat16* gAh = Ah + (size_t)bm * 128 * K;
    const __nv_bfloat16* gAl = Al + (size_t)bm * 128 * K;
    const __nv_bfloat16* gBh = Bh + (size_t)bn * 128 * K;
    const __nv_bfloat16* gBl = Bl + (size_t)bn * 128 * K;

    int row_c = tid >> 2, seg_c = (tid & 3) * 8;

    auto issue = [&](int ich, int st) {
        int k0 = ich << 5;
        __nv_bfloat16* s = smem + st * G_STAGE;
        #pragma unroll
        for (int r = 0; r < 2; r++) {
            int row = row_c + r * 64;
            size_t go = (size_t)row * K + k0 + seg_c;
            int so = row * LDS_ + seg_c;
            CP16(smem_u32(s + so), gAh + go);
            CP16(smem_u32(s + G_OAL + so), gAl + go);
            CP16(smem_u32(s + G_OBH + so), gBh + go);
            CP16(smem_u32(s + G_OBL + so), gBl + go);
        }
        CP_COMMIT();
    };

    float d[2][8][4];
    #pragma unroll
    for (int mi = 0; mi < 2; mi++)
        #pragma unroll
        for (int ni = 0; ni < 8; ni++)
            #pragma unroll
            for (int j = 0; j < 4; j++) d[mi][ni][j] = 0.f;

    int nch = K >> 5;
    issue(0, 0);
    if (nch > 1) issue(1, 1);

    for (int ich = 0; ich < nch; ich++) {
        if (ich + 1 < nch) CP_WAIT1(); else CP_WAIT0();
        __syncthreads();
        const __nv_bfloat16* s = smem + (ich & 1) * G_STAGE;
        #pragma unroll
        for (int ks = 0; ks < 2; ks++) {
            uint32_t ah[2][4], al[2][4];
            #pragma unroll
            for (int mi = 0; mi < 2; mi++) {
                int row = wm * 32 + mi * 16 + (lane & 15);
                int col = ks * 16 + (lane >> 4) * 8;
                LDMX4(ah[mi], smem_u32(s + row * LDS_ + col));
                LDMX4(al[mi], smem_u32(s + G_OAL + row * LDS_ + col));
            }
            #pragma unroll
            for (int ni = 0; ni < 8; ni++) {
                uint32_t bh[2], bl[2];
                int row = wn * 64 + ni * 8 + (lane & 7);
                int col = ks * 16 + ((lane >> 3) & 1) * 8;
                LDMX2(bh, smem_u32(s + G_OBH + row * LDS_ + col));
                LDMX2(bl, smem_u32(s + G_OBL + row * LDS_ + col));
                #pragma unroll
                for (int mi = 0; mi < 2; mi++) {
                    MMA16816(d[mi][ni], ah[mi], bh);
                    MMA16816(d[mi][ni], al[mi], bh);
                    MMA16816(d[mi][ni], ah[mi], bl);
                }
            }
        }
        __syncthreads();
        if (ich + 2 < nch) issue(ich + 2, ich & 1);
    }

    #pragma unroll
    for (int mi = 0; mi < 2; mi++) {
        int row = bm * 128 + wm * 32 + mi * 16 + (lane >> 2);
        #pragma unroll
        for (int ni = 0; ni < 8; ni++) {
            int col = bn * 128 + wn * 64 + ni * 8 + (lane & 3) * 2;
            if (C) {
                float b0 = bias ? bias[col] : 0.f;
                float b1 = bias ? bias[col + 1] : 0.f;
                *(float2*)(C + (size_t)row * N + col) =
                    make_float2(d[mi][ni][0] + b0, d[mi][ni][1] + b1);
                *(float2*)(C + (size_t)(row + 8) * N + col) =
                    make_float2(d[mi][ni][2] + b0, d[mi][ni][3] + b1);
            } else {
                uint32_t hh, ll;
                split2(d[mi][ni][0], d[mi][ni][1], hh, ll);
                *(uint32_t*)(Chi + (size_t)row * N + col) = hh;
                *(uint32_t*)(Clo + (size_t)row * N + col) = ll;
                split2(d[mi][ni][2], d[mi][ni][3], hh, ll);
                *(uint32_t*)(Chi + (size_t)(row + 8) * N + col) = hh;
                *(uint32_t*)(Clo + (size_t)(row + 8) * N + col) = ll;
            }
        }
    }
    if (asv) {
        int hd = bn * 2 + wn;
        float sv[4] = {0.f, 0.f, 0.f, 0.f}, dv[4] = {0.f, 0.f, 0.f, 0.f};
        #pragma unroll
        for (int mi = 0; mi < 2; mi++)
            #pragma unroll
            for (int ni = 0; ni < 8; ni++)
                #pragma unroll
                for (int j = 0; j < 2; j++) {
                    int cl = ni * 8 + (lane & 3) * 2 + j;
                    float a = asv[hd * 64 + cl], b = adv[hd * 64 + cl];
                    sv[mi * 2]     += d[mi][ni][j]     * a;
                    dv[mi * 2]     += d[mi][ni][j]     * b;
                    sv[mi * 2 + 1] += d[mi][ni][2 + j] * a;
                    dv[mi * 2 + 1] += d[mi][ni][2 + j] * b;
                }
        #pragma unroll
        for (int r = 0; r < 4; r++) {
            sv[r] += __shfl_xor_sync(0xffffffffu, sv[r], 1);
            sv[r] += __shfl_xor_sync(0xffffffffu, sv[r], 2);
            dv[r] += __shfl_xor_sync(0xffffffffu, dv[r], 1);
            dv[r] += __shfl_xor_sync(0xffffffffu, dv[r], 2);
        }
        if ((lane & 3) == 0) {
            #pragma unroll
            for (int r = 0; r < 4; r++) {
                int row = bm * 128 + wm * 32 + (r >> 1) * 16 + (lane >> 2) + (r & 1) * 8;
                esv[(size_t)row * 4 + hd]     = sv[r];
                edv_out[(size_t)row * 4 + hd] = dv[r];
            }
        }
    }
}

// ================= QKV fused GEMM (pipelined, 2 CTA/SM) =================
__global__ __launch_bounds__(256, 2) void mma_gemm_qkv(
    const __nv_bfloat16* __restrict__ Ah, const __nv_bfloat16* __restrict__ Al,
    const __nv_bfloat16* __restrict__ Bh, const __nv_bfloat16* __restrict__ Bl,
    __nv_bfloat16* __restrict__ QH, __nv_bfloat16* __restrict__ QL,
    __nv_bfloat16* __restrict__ KH, __nv_bfloat16* __restrict__ KL,
    __nv_bfloat16* __restrict__ VH, __nv_bfloat16* __restrict__ VL)
{
    constexpr int K = 128;
    extern __shared__ __nv_bfloat16 smem[];
    int tid = threadIdx.x, lane = tid & 31, warp = tid >> 5;
    int wm = warp & 3, wn = warp >> 2;
    int bm = blockIdx.y, bn = blockIdx.x;
    const __nv_bfloat16* gAh = Ah + (size_t)bm * 128 * K;
    const __nv_bfloat16* gAl = Al + (size_t)bm * 128 * K;
    const __nv_bfloat16* gBh = Bh + (size_t)bn * 128 * K;
    const __nv_bfloat16* gBl = Bl + (size_t)bn * 128 * K;

    int row_c = tid >> 2, seg_c = (tid & 3) * 8;
    auto issue = [&](int ich, int st) {
        int k0 = ich << 5;
        __nv_bfloat16* s = smem + st * G_STAGE;
        #pragma unroll
        for (int r = 0; r < 2; r++) {
            int row = row_c + r * 64;
            size_t go = (size_t)row * K + k0 + seg_c;
            int so = row * LDS_ + seg_c;
            CP16(smem_u32(s + so), gAh + go);
            CP16(smem_u32(s + G_OAL + so), gAl + go);
            CP16(smem_u32(s + G_OBH + so), gBh + go);
            CP16(smem_u32(s + G_OBL + so), gBl + go);
        }
        CP_COMMIT();
    };

    float d[2][8][4];
    #pragma unroll
    for (int mi = 0; mi < 2; mi++)
        #pragma unroll
        for (int ni = 0; ni < 8; ni++)
            #pragma unroll
            for (int j = 0; j < 4; j++) d[mi][ni][j] = 0.f;

    constexpr int nch = K >> 5;
    issue(0, 0);
    issue(1, 1);
    for (int ich = 0; ich < nch; ich++) {
        if (ich + 1 < nch) CP_WAIT1(); else CP_WAIT0();
        __syncthreads();
        const __nv_bfloat16* s = smem + (ich & 1) * G_STAGE;
        #pragma unroll
        for (int ks = 0; ks < 2; ks++) {
            uint32_t ah[2][4], al[2][4];
            #pragma unroll
            for (int mi = 0; mi < 2; mi++) {
                int row = wm * 32 + mi * 16 + (lane & 15);
                int col = ks * 16 + (lane >> 4) * 8;
                LDMX4(ah[mi], smem_u32(s + row * LDS_ + col));
                LDMX4(al[mi], smem_u32(s + G_OAL + row * LDS_ + col));
            }
            #pragma unroll
            for (int ni = 0; ni < 8; ni++) {
                uint32_t bh[2], bl[2];
                int row = wn * 64 + ni * 8 + (lane & 7);
                int col = ks * 16 + ((lane >> 3) & 1) * 8;
                LDMX2(bh, smem_u32(s + G_OBH + row * LDS_ + col));
                LDMX2(bl, smem_u32(s + G_OBL + row * LDS_ + col));
                #pragma unroll
                for (int mi = 0; mi < 2; mi++) {
                    MMA16816(d[mi][ni], ah[mi], bh);
                    MMA16816(d[mi][ni], al[mi], bh);
                    MMA16816(d[mi][ni], ah[mi], bl);
                }
            }
        }
        __syncthreads();
        if (ich + 2 < nch) issue(ich + 2, ich & 1);
    }
    __nv_bfloat16 *Oh, *Ol;
    if (bn == 0)      { Oh = QH; Ol = QL; }
    else if (bn == 1) { Oh = KH; Ol = KL; }
    else              { Oh = VH; Ol = VL; }
    #pragma unroll
    for (int mi = 0; mi < 2; mi++) {
        int row = bm * 128 + wm * 32 + mi * 16 + (lane >> 2);
        #pragma unroll
        for (int ni = 0; ni < 8; ni++) {
            int col = wn * 64 + ni * 8 + (lane & 3) * 2;
            uint32_t hh, ll;
            split2(d[mi][ni][0], d[mi][ni][1], hh, ll);
            *(uint32_t*)(Oh + (size_t)row * 128 + col) = hh;
            *(uint32_t*)(Ol + (size_t)row * 128 + col) = ll;
            split2(d[mi][ni][2], d[mi][ni][3], hh, ll);
            *(uint32_t*)(Oh + (size_t)(row + 8) * 128 + col) = hh;
            *(uint32_t*)(Ol + (size_t)(row + 8) * 128 + col) = ll;
        }
    }
}

// ================= GAT score vectors (layer 3 only) =================
__global__ void k_scores(const float* __restrict__ h, const float* __restrict__ as_,
                         const float* __restrict__ ad_, float* __restrict__ es,
                         float* __restrict__ ed, int H, int C)
{
    int idx = blockIdx.x * blockDim.x + threadIdx.x;
    if (idx >= NN * H) return;
    int node = idx / H, hd = idx % H;
    const float4* hp = (const float4*)(h + (size_t)node * H * C + (size_t)hd * C);
    const float4* ap = (const float4*)(as_ + (size_t)hd * C);
    const float4* bp = (const float4*)(ad_ + (size_t)hd * C);
    float s = 0.f, d = 0.f;
    for (int c = 0; c < C / 4; c++) {
        float4 hv = hp[c], av = ap[c], bv = bp[c];
        s += hv.x * av.x + hv.y * av.y + hv.z * av.z + hv.w * av.w;
        d += hv.x * bv.x + hv.y * bv.y + hv.z * bv.z + hv.w * bv.w;
    }
    es[idx] = s;
    ed[idx] = d;
}

// ================= GAT aggregation — single pass, float4 vectorized ==========
template <int D, int H>
__global__ __launch_bounds__(256) void k_gat_agg(
    const float* __restrict__ hfeat, const float* __restrict__ es,
    const float* __restrict__ ed, const float* __restrict__ bias,
    const float* __restrict__ gamma, const float* __restrict__ beta,
    const float* __restrict__ resid,
    __nv_bfloat16* __restrict__ outH, __nv_bfloat16* __restrict__ outL)
{
    constexpr int C = D / H;
    constexpr int NV = D / 128;   // float4 groups per lane
    int warp = (blockIdx.x * blockDim.x + threadIdx.x) >> 5;
    int lane = threadIdx.x & 31;
    if (warp >= NN) return;
    int i = warp;
    int beg = g_rowptr[i], end = g_rowptr[i + 1];

    float edv[H], z[H];
    #pragma unroll
    for (int h = 0; h < H; h++) {
        edv[h] = ed[(size_t)i * H + h];
        z[h] = 0.f;
    }
    float4 acc[NV];
    #pragma unroll
    for (int j = 0; j < NV; j++) acc[j] = make_float4(0.f, 0.f, 0.f, 0.f);

    for (int e = beg; e < end; e++) {
        int s = g_col[e];
        float al[H];
        if (H == 4) {
            float4 ev = ((const float4*)es)[s];
            float vv[4] = {ev.x, ev.y, ev.z, ev.w};
            #pragma unroll
            for (int h = 0; h < 4; h++) {
                float v = vv[h] + edv[h];
                v = v > 0.f ? v : 0.2f * v;
                al[h] = expf(v);
                z[h] += al[h];
            }
        } else {
            float v = es[s] + edv[0];
            v = v > 0.f ? v : 0.2f * v;
            al[0] = expf(v);
            z[0] += al[0];
        }
        const float4* hs = (const float4*)(hfeat + (size_t)s * D);
        #pragma unroll
        for (int j = 0; j < NV; j++) {
            float4 hv = hs[lane + 32 * j];
            float a = (H == 1) ? al[0] : al[((lane + 32 * j) * 4) / C];
            acc[j].x += a * hv.x; acc[j].y += a * hv.y;
            acc[j].z += a * hv.z; acc[j].w += a * hv.w;
        }
    }
    #pragma unroll
    for (int h = 0; h < H; h++) z[h] = 1.f / (z[h] + 1e-16f);

    float4 x[NV];
    #pragma unroll
    for (int j = 0; j < NV; j++) {
        int g4 = lane + 32 * j;
        float zz = (H == 1) ? z[0] : z[(g4 * 4) / C];
        float4 b4 = ((const float4*)bias)[g4];
        x[j].x = acc[j].x * zz + b4.x;
        x[j].y = acc[j].y * zz + b4.y;
        x[j].z = acc[j].z * zz + b4.z;
        x[j].w = acc[j].w * zz + b4.w;
        if (resid) {
            float4 r4 = ((const float4*)(resid + (size_t)i * D))[g4];
            x[j].x += r4.x; x[j].y += r4.y; x[j].z += r4.z; x[j].w += r4.w;
        }
    }
    if (gamma) {
        #pragma unroll
        for (int j = 0; j < NV; j++) {
            x[j].x = x[j].x > 0.f ? x[j].x : (expf(x[j].x) - 1.f);
            x[j].y = x[j].y > 0.f ? x[j].y : (expf(x[j].y) - 1.f);
            x[j].z = x[j].z > 0.f ? x[j].z : (expf(x[j].z) - 1.f);
            x[j].w = x[j].w > 0.f ? x[j].w : (expf(x[j].w) - 1.f);
        }
        float s = 0.f;
        #pragma unroll
        for (int j = 0; j < NV; j++) s += x[j].x + x[j].y + x[j].z + x[j].w;
        #pragma unroll
        for (int o = 16; o; o >>= 1) s += __shfl_xor_sync(0xffffffffu, s, o);
        float mu = s / (float)D;
        float vs = 0.f;
        #pragma unroll
        for (int j = 0; j < NV; j++) {
            float a = x[j].x - mu, b = x[j].y - mu, c = x[j].z - mu, dd = x[j].w - mu;
            vs += a * a + b * b + c * c + dd * dd;
        }
        #pragma unroll
        for (int o = 16; o; o >>= 1) vs += __shfl_xor_sync(0xffffffffu, vs, o);
        float inv = rsqrtf(vs / (float)D + 1e-5f);
        #pragma unroll
        for (int j = 0; j < NV; j++) {
            int g4 = lane + 32 * j;
            float4 g = ((const float4*)gamma)[g4];
            float4 be = ((const float4*)beta)[g4];
            x[j].x = (x[j].x - mu) * inv * g.x + be.x;
            x[j].y = (x[j].y - mu) * inv * g.y + be.y;
            x[j].z = (x[j].z - mu) * inv * g.z + be.z;
            x[j].w = (x[j].w - mu) * inv * g.w + be.w;
        }
    }
    #pragma unroll
    for (int j = 0; j < NV; j++) {
        int g4 = lane + 32 * j;
        uint32_t h01, l01, h23, l23;
        split2(x[j].x, x[j].y, h01, l01);
        split2(x[j].z, x[j].w, h23, l23);
        *(uint2*)(outH + (size_t)i * D + g4 * 4) = make_uint2(h01, h23);
        *(uint2*)(outL + (size_t)i * D + g4 * 4) = make_uint2(l01, l23);
    }
}

// ================= V transpose =================
__global__ __launch_bounds__(256) void k_vT(const __nv_bfloat16* __restrict__ VH,
                                            const __nv_bfloat16* __restrict__ VL,
                                            __nv_bfloat16* __restrict__ VTH,
                                            __nv_bfloat16* __restrict__ VTL)
{
    __shared__ float t[128][33];
    int gh = blockIdx.y, g = gh >> 2, h = gh & 3;
    int k0 = blockIdx.x * 128;
    int tid = threadIdx.x;
    #pragma unroll
    for (int it = 0; it < 16; it++) {
        int idx = tid + it * 256;
        int r = idx >> 5, c = idx & 31;
        size_t gi = ((size_t)g * GS + k0 + r) * 128 + h * 32 + c;
        t[r][c] = __bfloat162float(VH[gi]) + __bfloat162float(VL[gi]);
    }
    __syncthreads();
    #pragma unroll
    for (int it = 0; it < 16; it++) {
        int idx = tid + it * 256;
        int n = idx >> 7, k = idx & 127;
        float v = t[k][n];
        __nv_bfloat16 hh = __float2bfloat16(v);
        size_t o = ((size_t)gh * 32 + n) * 512 + k0 + k;
        VTH[o] = hh;
        VTL[o] = __float2bfloat16(v - __bfloat162float(hh));
    }
}

// ================= fused flash attention =================
constexpr int VPAD = 520;
constexpr int SM_QH = 0;
constexpr int SM_QL = SM_QH + 128 * LDS_;
constexpr int SM_KH = SM_QL + 128 * LDS_;
constexpr int SM_KL = SM_KH + 512 * LDS_;
constexpr int SM_VH = SM_KL + 512 * LDS_;
constexpr int SM_VL = SM_VH + 32 * VPAD;
constexpr int SM_TOT = SM_VL + 32 * VPAD;
constexpr int FLASH_SMEM = SM_TOT * 2;

__global__ __launch_bounds__(256) void k_flash(
    const __nv_bfloat16* __restrict__ QH, const __nv_bfloat16* __restrict__ QL,
    const __nv_bfloat16* __restrict__ KH, const __nv_bfloat16* __restrict__ KL,
    const __nv_bfloat16* __restrict__ VTH, const __nv_bfloat16* __restrict__ VTL,
    __nv_bfloat16* __restrict__ OHo, __nv_bfloat16* __restrict__ OLo)
{
    extern __shared__ __nv_bfloat16 sm[];
    int gh = blockIdx.y, g = gh >> 2, h = gh & 3;
    int qt = blockIdx.x;
    int tid = threadIdx.x, lane = tid & 31, warp = tid >> 5;

    {
        const __nv_bfloat16* kh = KH + (size_t)g * GS * 128 + h * 32;
        const __nv_bfloat16* kl = KL + (size_t)g * GS * 128 + h * 32;
        #pragma unroll
        for (int it = 0; it < 8; it++) {
            int idx = tid + it * 256;
            int row = idx >> 2, seg = (idx & 3) * 8;
            *(uint4*)&sm[SM_KH + row * LDS_ + seg] = *(const uint4*)(kh + (size_t)row * 128 + seg);
            *(uint4*)&sm[SM_KL + row * LDS_ + seg] = *(const uint4*)(kl + (size_t)row * 128 + seg);
        }
        const __nv_bfloat16* qh = QH + ((size_t)g * GS + qt * 128) * 128 + h * 32;
        const __nv_bfloat16* ql = QL + ((size_t)g * GS + qt * 128) * 128 + h * 32;
        #pragma unroll
        for (int it = 0; it < 2; it++) {
            int idx = tid + it * 256;
            int row = idx >> 2, seg = (idx & 3) * 8;
            *(uint4*)&sm[SM_QH + row * LDS_ + seg] = *(const uint4*)(qh + (size_t)row * 128 + seg);
            *(uint4*)&sm[SM_QL + row * LDS_ + seg] = *(const uint4*)(ql + (size_t)row * 128 + seg);
        }
        const __nv_bfloat16* vh = VTH + (size_t)gh * 32 * 512;
        const __nv_bfloat16* vl = VTL + (size_t)gh * 32 * 512;
        #pragma unroll
        for (int it = 0; it < 8; it++) {
            int idx = tid + it * 256;
            int row = idx >> 6, c8 = (idx & 63) * 8;
            *(uint4*)&sm[SM_VH + row * VPAD + c8] = *(const uint4*)(vh + (size_t)row * 512 + c8);
            *(uint4*)&sm[SM_VL + row * VPAD + c8] = *(const uint4*)(vl + (size_t)row * 512 + c8);
        }
    }
    __syncthreads();

    uint32_t qh_[2][4], ql_[2][4];
    #pragma unroll
    for (int kf = 0; kf < 2; kf++) {
        int row = warp * 16 + (lane & 15);
        int col = kf * 16 + (lane >> 4) * 8;
        LDMX4(qh_[kf], smem_u32(&sm[SM_QH + row * LDS_ + col]));
        LDMX4(ql_[kf], smem_u32(&sm[SM_QL + row * LDS_ + col]));
    }

    float m0 = -1e30f, m1 = -1e30f, l0 = 0.f, l1 = 0.f;
    float O[4][4];
    #pragma unroll
    for (int n = 0; n < 4; n++)
        #pragma unroll
        for (int j = 0; j < 4; j++) O[n][j] = 0.f;

    const float scale = 0.088388347648318447f;

    for (int kt = 0; kt < 4; kt++) {
        float S[16][4];
        #pragma unroll
        for (int j = 0; j < 16; j++)
            #pragma unroll
            for (int r = 0; r < 4; r++) S[j][r] = 0.f;
        #pragma unroll
        for (int j = 0; j < 16; j++) {
            #pragma unroll
            for (int kf = 0; kf < 2; kf++) {
                uint32_t bh[2], bl[2];
                int row = kt * 128 + j * 8 + (lane & 7);
                int col = kf * 16 + ((lane >> 3) & 1) * 8;
                LDMX2(bh, smem_u32(&sm[SM_KH + row * LDS_ + col]));
                LDMX2(bl, smem_u32(&sm[SM_KL + row * LDS_ + col]));
                MMA16816(S[j], qh_[kf], bh);
                MMA16816(S[j], ql_[kf], bh);
                MMA16816(S[j], qh_[kf], bl);
            }
        }
        float mx0 = -1e30f, mx1 = -1e30f;
        #pragma unroll
        for (int j = 0; j < 16; j++) {
            S[j][0] *= scale; S[j][1] *= scale; S[j][2] *= scale; S[j][3] *= scale;
            mx0 = fmaxf(mx0, fmaxf(S[j][0], S[j][1]));
            mx1 = fmaxf(mx1, fmaxf(S[j][2], S[j][3]));
        }
        #pragma unroll
        for (int o = 1; o < 4; o <<= 1) {
            mx0 = fmaxf(mx0, __shfl_xor_sync(0xffffffffu, mx0, o));
            mx1 = fmaxf(mx1, __shfl_xor_sync(0xffffffffu, mx1, o));
        }
        float nm0 = fmaxf(m0, mx0), nm1 = fmaxf(m1, mx1);
        float a0 = expf(m0 - nm0), a1 = expf(m1 - nm1);
        float rs0 = 0.f, rs1 = 0.f;
        #pragma unroll
        for (int j = 0; j < 16; j++) {
            S[j][0] = expf(S[j][0] - nm0); S[j][1] = expf(S[j][1] - nm0);
            S[j][2] = expf(S[j][2] - nm1); S[j][3] = expf(S[j][3] - nm1);
            rs0 += S[j][0] + S[j][1];
            rs1 += S[j][2] + S[j][3];
        }
        #pragma unroll
        for (int o = 1; o < 4; o <<= 1) {
            rs0 += __shfl_xor_sync(0xffffffffu, rs0, o);
            rs1 += __shfl_xor_sync(0xffffffffu, rs1, o);
        }
        l0 = l0 * a0 + rs0;
        l1 = l1 * a1 + rs1;
        #pragma unroll
        for (int n = 0; n < 4; n++) {
            O[n][0] *= a0; O[n][1] *= a0; O[n][2] *= a1; O[n][3] *= a1;
        }
        m0 = nm0; m1 = nm1;
        #pragma unroll
        for (int jp = 0; jp < 8; jp++) {
            uint32_t aph[4], apl[4];
            split2(S[2 * jp][0],     S[2 * jp][1],     aph[0], apl[0]);
            split2(S[2 * jp][2],     S[2 * jp][3],     aph[1], apl[1]);
            split2(S[2 * jp + 1][0], S[2 * jp + 1][1], aph[2], apl[2]);
            split2(S[2 * jp + 1][2], S[2 * jp + 1][3], aph[3], apl[3]);
            #pragma unroll
            for (int n = 0; n < 4; n++) {
                uint32_t bh[2], bl[2];
                int row = n * 8 + (lane & 7);
                int col = kt * 128 + jp * 16 + ((lane >> 3) & 1) * 8;
                LDMX2(bh, smem_u32(&sm[SM_VH + row * VPAD + col]));
                LDMX2(bl, smem_u32(&sm[SM_VL + row * VPAD + col]));
                MMA16816(O[n], aph, bh);
                MMA16816(O[n], apl, bh);
                MMA16816(O[n], aph, bl);
            }
        }
    }
    float il0 = 1.f / l0, il1 = 1.f / l1;
    int node = g * GS + qt * 128 + warp * 16 + (lane >> 2);
    #pragma unroll
    for (int n = 0; n < 4; n++) {
        int col = h * 32 + n * 8 + (lane & 3) * 2;
        uint32_t hh, ll;
        split2(O[n][0] * il0, O[n][1] * il0, hh, ll);
        *(uint32_t*)(OHo + (size_t)node * 128 + col) = hh;
        *(uint32_t*)(OLo + (size_t)node * 128 + col) = ll;
        split2(O[n][2] * il1, O[n][3] * il1, hh, ll);
        *(uint32_t*)(OHo + (size_t)(node + 8) * 128 + col) = hh;
        *(uint32_t*)(OLo + (size_t)(node + 8) * 128 + col) = ll;
    }
}

// ================= host orchestration =================
extern "C" void kernel_launch(void* const* d_in, const int* in_sizes, int n_in,
                              void* d_out, int out_size)
{
    const float* x   = (const float*)d_in[0];
    const int*   ei  = (const int*)  d_in[1];
    const float* W1  = (const float*)d_in[3];
    const float* a1s = (const float*)d_in[4];
    const float* a1d = (const float*)d_in[5];
    const float* b1  = (const float*)d_in[6];
    const float* W2  = (const float*)d_in[7];
    const float* a2s = (const float*)d_in[8];
    const float* a2d = (const float*)d_in[9];
    const float* b2  = (const float*)d_in[10];
    const float* W3  = (const float*)d_in[11];
    const float* a3s = (const float*)d_in[12];
    const float* a3d = (const float*)d_in[13];
    const float* b3  = (const float*)d_in[14];
    const float* g1  = (const float*)d_in[15];
    const float* be1 = (const float*)d_in[16];
    const float* g2  = (const float*)d_in[17];
    const float* be2 = (const float*)d_in[18];
    const float* Wr  = (const float*)d_in[19];
    const float* br  = (const float*)d_in[20];
    const float* Wq  = (const float*)d_in[21];
    const float* Wk  = (const float*)d_in[22];
    const float* Wv  = (const float*)d_in[23];
    const float* Wo  = (const float*)d_in[24];
    const float* bo  = (const float*)d_in[25];
    float* out = (float*)d_out;

    float* sb = nullptr;
    cudaGetSymbolAddress((void**)&sb, g_scratch);
    __nv_bfloat16* bb = nullptr;
    cudaGetSymbolAddress((void**)&bb, g_bf);
    cudaFuncSetAttribute(k_flash, cudaFuncAttributeMaxDynamicSharedMemorySize, FLASH_SMEM);
    cudaFuncSetAttribute(mma_gemm, cudaFuncAttributeMaxDynamicSharedMemorySize, GEMM_SMEM);
    cudaFuncSetAttribute(mma_gemm_qkv, cudaFuncAttributeMaxDynamicSharedMemorySize, GEMM_SMEM);

    float* p_h  = sb + OFF_H;
    float* p_h3 = sb + OFF_H3;
    float* p_r  = sb + OFF_R;
    float* p_es = sb + OFF_ES;
    float* p_ed = sb + OFF_ED;

    // CSR
    k_zero_cnt<<<NN / 256, 256>>>();
    k_count<<<1024, 256>>>(ei);
    k_scan1<<<256, 256>>>();
    k_scan2<<<1, 256>>>();
    k_scan3<<<256, 256>>>();
    k_fill<<<1152, 256>>>(ei);

    // weight conversions
    k_cvt_wT<<<(256*64 + 255)/256, 256>>>(W1, bb + B_W1H, bb + B_W1L, 64, 256);
    k_cvt_wT<<<(256*256 + 255)/256, 256>>>(W2, bb + B_W2H, bb + B_W2L, 256, 256);
    k_cvt_wT<<<(128*256 + 255)/256, 256>>>(W3, bb + B_W3H, bb + B_W3L, 256, 128);
    k_cvt_wT<<<(128*64 + 255)/256, 256>>>(Wr, bb + B_WRH, bb + B_WRL, 64, 128);
    k_cvt_wqkv<<<(384*128 + 255)/256, 256>>>(Wq, Wk, Wv, bb + B_WQKVH, bb + B_WQKVL);
    k_cvt_wT<<<(128*128 + 255)/256, 256>>>(Wo, bb + B_WOH, bb + B_WOL, 128, 128);

    // x -> bf16 hi/lo
    k_cvt_split<<<(NN*64/4 + 255)/256, 256>>>(x, bb + B_XH, bb + B_XL, NN*64/4);

    // layer 1 (fused scores)
    mma_gemm<<<dim3(2, 512), 256, GEMM_SMEM>>>(bb + B_XH, bb + B_XL, bb + B_W1H, bb + B_W1L,
                                    nullptr, p_h, nullptr, nullptr,
                                    a1s, a1d, p_es, p_ed, NN, 256, 64);
    k_gat_agg<256, 4><<<NN / 8, 256>>>(p_h, p_es, p_ed, b1, g1, be1, nullptr,
                                       bb + B_TH, bb + B_TL);
    // layer 2 (fused scores)
    mma_gemm<<<dim3(2, 512), 256, GEMM_SMEM>>>(bb + B_TH, bb + B_TL, bb + B_W2H, bb + B_W2L,
                                    nullptr, p_h, nullptr, nullptr,
                                    a2s, a2d, p_es, p_ed, NN, 256, 256);
    k_gat_agg<256, 4><<<NN / 8, 256>>>(p_h, p_es, p_ed, b2, g2, be2, nullptr,
                                       bb + B_TH, bb + B_TL);
    // layer 3 + residual
    mma_gemm<<<dim3(1, 512), 256, GEMM_SMEM>>>(bb + B_TH, bb + B_TL, bb + B_W3H, bb + B_W3L,
                                    nullptr, p_h3, nullptr, nullptr,
                                    nullptr, nullptr, nullptr, nullptr, NN, 128, 256);
    k_scores<<<NN / 256, 256>>>(p_h3, a3s, a3d, p_es, p_ed, 1, 128);
    mma_gemm<<<dim3(1, 512), 256, GEMM_SMEM>>>(bb + B_XH, bb + B_XL, bb + B_WRH, bb + B_WRL,
                                    br, p_r, nullptr, nullptr,
                                    nullptr, nullptr, nullptr, nullptr, NN, 128, 64);
    k_gat_agg<128, 1><<<NN / 8, 256>>>(p_h3, p_es, p_ed, b3, nullptr, nullptr, p_r,
                                       bb + B_HRH, bb + B_HRL);
    // fused QKV projection
    mma_gemm_qkv<<<dim3(3, 512), 256, GEMM_SMEM>>>(bb + B_HRH, bb + B_HRL,
                                        bb + B_WQKVH, bb + B_WQKVL,
                                        bb + B_QH, bb + B_QL,
                                        bb + B_KH, bb + B_KL,
                                        bb + B_VH, bb + B_VL);
    k_vT<<<dim3(4, NG * 4), 256>>>(bb + B_VH, bb + B_VL, bb + B_VTH, bb + B_VTL);
    // fused attention
    k_flash<<<dim3(4, NG * 4), 256, FLASH_SMEM>>>(
        bb + B_QH, bb + B_QL, bb + B_KH, bb + B_KL,
        bb + B_VTH, bb + B_VTL, bb + B_AOH, bb + B_AOL);
    // output projection
    mma_gemm<<<dim3(1, 512), 256, GEMM_SMEM>>>(bb + B_AOH, bb + B_AOL, bb + B_WOH, bb + B_WOL,
                                    bo, out, nullptr, nullptr,
                                    nullptr, nullptr, nullptr, nullptr, NN, 128, 128);
}

// round 9
// speedup vs baseline: 2.0794x; 1.0097x over previous
#include <cuda_runtime.h>
#include <cuda_bf16.h>
#include <math.h>
#include <stdint.h>

// ---------------- problem constants ----------------
constexpr int NN   = 65536;
constexpr int NE   = 524288;
constexpr int ET   = NE + NN;
constexpr int GS   = 512;
constexpr int NG   = NN / GS;
constexpr int D1   = 256;
constexpr int D3   = 128;

// ---------------- fp32 scratch ----------------
constexpr size_t OFF_H    = 0;
constexpr size_t OFF_H3   = OFF_H  + (size_t)NN*D1;
constexpr size_t OFF_R    = OFF_H3 + (size_t)NN*D3;
constexpr size_t OFF_ES   = OFF_R  + (size_t)NN*D3;
constexpr size_t OFF_ED   = OFF_ES + (size_t)NN*4;
constexpr size_t SCRATCH  = OFF_ED + (size_t)NN*4;

__device__ __align__(256) float g_scratch[SCRATCH];

// ---------------- bf16 scratch ----------------
constexpr size_t B_XH  = 0;
constexpr size_t B_XL  = B_XH  + (size_t)NN*64;
constexpr size_t B_TH  = B_XL  + (size_t)NN*64;
constexpr size_t B_TL  = B_TH  + (size_t)NN*256;
constexpr size_t B_HRH = B_TL  + (size_t)NN*256;
constexpr size_t B_HRL = B_HRH + (size_t)NN*128;
constexpr size_t B_AOH = B_HRL + (size_t)NN*128;
constexpr size_t B_AOL = B_AOH + (size_t)NN*128;
constexpr size_t B_QH  = B_AOL + (size_t)NN*128;
constexpr size_t B_QL  = B_QH  + (size_t)NN*128;
constexpr size_t B_KH  = B_QL  + (size_t)NN*128;
constexpr size_t B_KL  = B_KH  + (size_t)NN*128;
constexpr size_t B_VH  = B_KL  + (size_t)NN*128;
constexpr size_t B_VL  = B_VH  + (size_t)NN*128;
constexpr size_t B_W1H = B_VL  + (size_t)NN*128;
constexpr size_t B_W1L = B_W1H + 256*64;
constexpr size_t B_W2H = B_W1L + 256*64;
constexpr size_t B_W2L = B_W2H + 256*256;
constexpr size_t B_W3H = B_W2L + 256*256;
constexpr size_t B_W3L = B_W3H + 128*256;
constexpr size_t B_WRH = B_W3L + 128*256;
constexpr size_t B_WRL = B_WRH + 128*64;
constexpr size_t B_WQKVH = B_WRL + 128*64;
constexpr size_t B_WQKVL = B_WQKVH + 384*128;
constexpr size_t B_WOH = B_WQKVL + 384*128;
constexpr size_t B_WOL = B_WOH + 128*128;
constexpr size_t BF_TOTAL = B_WOL + 128*128;

__device__ __align__(256) __nv_bfloat16 g_bf[BF_TOTAL];

__device__ int g_rowptr[NN + 1];
__device__ int g_cnt[NN];
__device__ int g_cursor[NN];
__device__ int g_col[ET];
__device__ int g_blocksum[256];

// ================= helpers =================
__device__ __forceinline__ uint32_t smem_u32(const void* p) {
    uint32_t a;
    asm("{ .reg .u64 t; cvta.to.shared.u64 t, %1; cvt.u32.u64 %0, t; }" : "=r"(a) : "l"(p));
    return a;
}
#define LDMX4(r, a) \
    asm volatile("ldmatrix.sync.aligned.m8n8.x4.shared.b16 {%0,%1,%2,%3}, [%4];" \
        : "=r"((r)[0]), "=r"((r)[1]), "=r"((r)[2]), "=r"((r)[3]) : "r"(a))
#define LDMX2(r, a) \
    asm volatile("ldmatrix.sync.aligned.m8n8.x2.shared.b16 {%0,%1}, [%2];" \
        : "=r"((r)[0]), "=r"((r)[1]) : "r"(a))
#define LDMX2T(r, a) \
    asm volatile("ldmatrix.sync.aligned.m8n8.x2.trans.shared.b16 {%0,%1}, [%2];" \
        : "=r"((r)[0]), "=r"((r)[1]) : "r"(a))
#define MMA16816(d, a, b) \
    asm volatile("mma.sync.aligned.m16n8k16.row.col.f32.bf16.bf16.f32 " \
        "{%0,%1,%2,%3}, {%4,%5,%6,%7}, {%8,%9}, {%0,%1,%2,%3};" \
        : "+f"((d)[0]), "+f"((d)[1]), "+f"((d)[2]), "+f"((d)[3]) \
        : "r"((a)[0]), "r"((a)[1]), "r"((a)[2]), "r"((a)[3]), \
          "r"((b)[0]), "r"((b)[1]))
#define CP16(dst, src) \
    asm volatile("cp.async.cg.shared.global [%0], [%1], 16;" :: "r"(dst), "l"(src))
#define CP_COMMIT() asm volatile("cp.async.commit_group;" ::: "memory")
#define CP_WAIT1()  asm volatile("cp.async.wait_group 1;" ::: "memory")
#define CP_WAIT0()  asm volatile("cp.async.wait_group 0;" ::: "memory")

__device__ __forceinline__ void split2(float v0, float v1, uint32_t& hh, uint32_t& ll) {
    __nv_bfloat16 h0 = __float2bfloat16(v0), h1 = __float2bfloat16(v1);
    __nv_bfloat16 l0 = __float2bfloat16(v0 - __bfloat162float(h0));
    __nv_bfloat16 l1 = __float2bfloat16(v1 - __bfloat162float(h1));
    __nv_bfloat162 H; H.x = h0; H.y = h1;
    __nv_bfloat162 L; L.x = l0; L.y = l1;
    hh = *(uint32_t*)&H; ll = *(uint32_t*)&L;
}

// ================= CSR build (parallel scan) =================
__global__ void k_zero_cnt() {
    int i = blockIdx.x * blockDim.x + threadIdx.x;
    if (i < NN) g_cnt[i] = 0;
}
__global__ void k_count(const int* __restrict__ ei) {
    int stride = gridDim.x * blockDim.x;
    for (int idx = blockIdx.x * blockDim.x + threadIdx.x; idx < NE; idx += stride)
        atomicAdd(&g_cnt[ei[NE + idx]], 1);
}
__global__ void k_scan1() {
    __shared__ int ws[8];
    int b = blockIdx.x, tid = threadIdx.x, lane = tid & 31, wid = tid >> 5;
    int v = g_cnt[b * 256 + tid] + 1;
    int x = v;
    #pragma unroll
    for (int o = 1; o < 32; o <<= 1) {
        int t = __shfl_up_sync(0xffffffffu, x, o);
        if (lane >= o) x += t;
    }
    if (lane == 31) ws[wid] = x;
    __syncthreads();
    if (tid == 0) {
        int run = 0;
        #pragma unroll
        for (int k = 0; k < 8; k++) { int t = ws[k]; ws[k] = run; run += t; }
        g_blocksum[b] = run;
    }
    __syncthreads();
    g_rowptr[b * 256 + tid] = x - v + ws[wid];
}
__global__ void k_scan2() {
    __shared__ int ws[8];
    int tid = threadIdx.x, lane = tid & 31, wid = tid >> 5;
    int v = g_blocksum[tid];
    int x = v;
    #pragma unroll
    for (int o = 1; o < 32; o <<= 1) {
        int t = __shfl_up_sync(0xffffffffu, x, o);
        if (lane >= o) x += t;
    }
    if (lane == 31) ws[wid] = x;
    __syncthreads();
    if (tid == 0) {
        int run = 0;
        #pragma unroll
        for (int k = 0; k < 8; k++) { int t = ws[k]; ws[k] = run; run += t; }
    }
    __syncthreads();
    g_blocksum[tid] = x - v + ws[wid];
}
__global__ void k_scan3() {
    int idx = blockIdx.x * 256 + threadIdx.x;
    int v = g_rowptr[idx] + g_blocksum[blockIdx.x];
    g_rowptr[idx] = v;
    g_cursor[idx] = v;
    if (idx == 0) g_rowptr[NN] = ET;
}
__global__ void k_fill(const int* __restrict__ ei) {
    int stride = gridDim.x * blockDim.x;
    for (int idx = blockIdx.x * blockDim.x + threadIdx.x; idx < ET; idx += stride) {
        int s, d;
        if (idx < NE) { s = ei[idx]; d = ei[NE + idx]; }
        else          { s = d = idx - NE; }
        int pos = atomicAdd(&g_cursor[d], 1);
        g_col[pos] = s;
    }
}

// ================= conversions =================
__global__ void k_cvt_split(const float* __restrict__ in, __nv_bfloat16* __restrict__ hi,
                            __nv_bfloat16* __restrict__ lo, int n4) {
    int i = blockIdx.x * blockDim.x + threadIdx.x;
    if (i >= n4) return;
    float4 v = ((const float4*)in)[i];
    uint32_t h01, l01, h23, l23;
    split2(v.x, v.y, h01, l01);
    split2(v.z, v.w, h23, l23);
    ((uint32_t*)hi)[2 * i] = h01; ((uint32_t*)hi)[2 * i + 1] = h23;
    ((uint32_t*)lo)[2 * i] = l01; ((uint32_t*)lo)[2 * i + 1] = l23;
}

__global__ void k_cvt_wT(const float* __restrict__ W, __nv_bfloat16* __restrict__ hiT,
                         __nv_bfloat16* __restrict__ loT, int K, int N) {
    int idx = blockIdx.x * blockDim.x + threadIdx.x;
    if (idx >= N * K) return;
    int n = idx / K, k = idx % K;
    float v = W[(size_t)k * N + n];
    __nv_bfloat16 h = __float2bfloat16(v);
    hiT[idx] = h;
    loT[idx] = __float2bfloat16(v - __bfloat162float(h));
}

__global__ void k_cvt_wqkv(const float* __restrict__ Wq, const float* __restrict__ Wk,
                           const float* __restrict__ Wv,
                           __nv_bfloat16* __restrict__ hiT, __nv_bfloat16* __restrict__ loT) {
    int idx = blockIdx.x * blockDim.x + threadIdx.x;
    if (idx >= 384 * 128) return;
    int n = idx / 128, k = idx % 128;
    const float* W = (n < 128) ? Wq : ((n < 256) ? Wk : Wv);
    float v = W[(size_t)k * 128 + (n & 127)];
    __nv_bfloat16 h = __float2bfloat16(v);
    hiT[idx] = h;
    loT[idx] = __float2bfloat16(v - __bfloat162float(h));
}

// ================= mma.sync bf16-split GEMM, cp.async pipeline, 2 CTA/SM ======
constexpr int LDS_ = 40;
constexpr int G_OAL = 128 * LDS_;
constexpr int G_OBH = 2 * 128 * LDS_;
constexpr int G_OBL = 3 * 128 * LDS_;
constexpr int G_STAGE = 4 * 128 * LDS_;
constexpr int GEMM_SMEM = 2 * G_STAGE * 2;

__global__ __launch_bounds__(256, 2) void mma_gemm(
    const __nv_bfloat16* __restrict__ Ah, const __nv_bfloat16* __restrict__ Al,
    const __nv_bfloat16* __restrict__ Bh, const __nv_bfloat16* __restrict__ Bl,
    const float* __restrict__ bias, float* __restrict__ C,
    __nv_bfloat16* __restrict__ Chi, __nv_bfloat16* __restrict__ Clo,
    const float* __restrict__ asv, const float* __restrict__ adv,
    float* __restrict__ esv, float* __restrict__ edv_out,
    int M, int N, int K)
{
    extern __shared__ __nv_bfloat16 smem[];
    int tid = threadIdx.x, lane = tid & 31, warp = tid >> 5;
    int wm = warp & 3, wn = warp >> 2;
    int bm = blockIdx.y, bn = blockIdx.x;
    const __nv_bfloat16* gAh = Ah + (size_t)bm * 128 * K;
    const __nv_bfloat16* gAl = Al + (size_t)bm * 128 * K;
    const __nv_bfloat16* gBh = Bh + (size_t)bn * 128 * K;
    const __nv_bfloat16* gBl = Bl + (size_t)bn * 128 * K;

    int row_c = tid >> 2, seg_c = (tid & 3) * 8;

    auto issue = [&](int ich, int st) {
        int k0 = ich << 5;
        __nv_bfloat16* s = smem + st * G_STAGE;
        #pragma unroll
        for (int r = 0; r < 2; r++) {
            int row = row_c + r * 64;
            size_t go = (size_t)row * K + k0 + seg_c;
            int so = row * LDS_ + seg_c;
            CP16(smem_u32(s + so), gAh + go);
            CP16(smem_u32(s + G_OAL + so), gAl + go);
            CP16(smem_u32(s + G_OBH + so), gBh + go);
            CP16(smem_u32(s + G_OBL + so), gBl + go);
        }
        CP_COMMIT();
    };

    float d[2][8][4];
    #pragma unroll
    for (int mi = 0; mi < 2; mi++)
        #pragma unroll
        for (int ni = 0; ni < 8; ni++)
            #pragma unroll
            for (int j = 0; j < 4; j++) d[mi][ni][j] = 0.f;

    int nch = K >> 5;
    issue(0, 0);
    if (nch > 1) issue(1, 1);

    for (int ich = 0; ich < nch; ich++) {
        if (ich + 1 < nch) CP_WAIT1(); else CP_WAIT0();
        __syncthreads();
        const __nv_bfloat16* s = smem + (ich & 1) * G_STAGE;
        #pragma unroll
        for (int ks = 0; ks < 2; ks++) {
            uint32_t ah[2][4], al[2][4];
            #pragma unroll
            for (int mi = 0; mi < 2; mi++) {
                int row = wm * 32 + mi * 16 + (lane & 15);
                int col = ks * 16 + (lane >> 4) * 8;
                LDMX4(ah[mi], smem_u32(s + row * LDS_ + col));
                LDMX4(al[mi], smem_u32(s + G_OAL + row * LDS_ + col));
            }
            #pragma unroll
            for (int ni = 0; ni < 8; ni++) {
                uint32_t bh[2], bl[2];
                int row = wn * 64 + ni * 8 + (lane & 7);
                int col = ks * 16 + ((lane >> 3) & 1) * 8;
                LDMX2(bh, smem_u32(s + G_OBH + row * LDS_ + col));
                LDMX2(bl, smem_u32(s + G_OBL + row * LDS_ + col));
                #pragma unroll
                for (int mi = 0; mi < 2; mi++) {
                    MMA16816(d[mi][ni], ah[mi], bh);
                    MMA16816(d[mi][ni], al[mi], bh);
                    MMA16816(d[mi][ni], ah[mi], bl);
                }
            }
        }
        __syncthreads();
        if (ich + 2 < nch) issue(ich + 2, ich & 1);
    }

    #pragma unroll
    for (int mi = 0; mi < 2; mi++) {
        int row = bm * 128 + wm * 32 + mi * 16 + (lane >> 2);
        #pragma unroll
        for (int ni = 0; ni < 8; ni++) {
            int col = bn * 128 + wn * 64 + ni * 8 + (lane & 3) * 2;
            if (C) {
                float b0 = bias ? bias[col] : 0.f;
                float b1 = bias ? bias[col + 1] : 0.f;
                *(float2*)(C + (size_t)row * N + col) =
                    make_float2(d[mi][ni][0] + b0, d[mi][ni][1] + b1);
                *(float2*)(C + (size_t)(row + 8) * N + col) =
                    make_float2(d[mi][ni][2] + b0, d[mi][ni][3] + b1);
            } else {
                uint32_t hh, ll;
                split2(d[mi][ni][0], d[mi][ni][1], hh, ll);
                *(uint32_t*)(Chi + (size_t)row * N + col) = hh;
                *(uint32_t*)(Clo + (size_t)row * N + col) = ll;
                split2(d[mi][ni][2], d[mi][ni][3], hh, ll);
                *(uint32_t*)(Chi + (size_t)(row + 8) * N + col) = hh;
                *(uint32_t*)(Clo + (size_t)(row + 8) * N + col) = ll;
            }
        }
    }
    if (asv) {
        int hd = bn * 2 + wn;
        float sv[4] = {0.f, 0.f, 0.f, 0.f}, dv[4] = {0.f, 0.f, 0.f, 0.f};
        #pragma unroll
        for (int mi = 0; mi < 2; mi++)
            #pragma unroll
            for (int ni = 0; ni < 8; ni++)
                #pragma unroll
                for (int j = 0; j < 2; j++) {
                    int cl = ni * 8 + (lane & 3) * 2 + j;
                    float a = asv[hd * 64 + cl], b = adv[hd * 64 + cl];
                    sv[mi * 2]     += d[mi][ni][j]     * a;
                    dv[mi * 2]     += d[mi][ni][j]     * b;
                    sv[mi * 2 + 1] += d[mi][ni][2 + j] * a;
                    dv[mi * 2 + 1] += d[mi][ni][2 + j] * b;
                }
        #pragma unroll
        for (int r = 0; r < 4; r++) {
            sv[r] += __shfl_xor_sync(0xffffffffu, sv[r], 1);
            sv[r] += __shfl_xor_sync(0xffffffffu, sv[r], 2);
            dv[r] += __shfl_xor_sync(0xffffffffu, dv[r], 1);
            dv[r] += __shfl_xor_sync(0xffffffffu, dv[r], 2);
        }
        if ((lane & 3) == 0) {
            #pragma unroll
            for (int r = 0; r < 4; r++) {
                int row = bm * 128 + wm * 32 + (r >> 1) * 16 + (lane >> 2) + (r & 1) * 8;
                esv[(size_t)row * 4 + hd]     = sv[r];
                edv_out[(size_t)row * 4 + hd] = dv[r];
            }
        }
    }
}

// ================= QKV fused GEMM (pipelined, 2 CTA/SM) =================
__global__ __launch_bounds__(256, 2) void mma_gemm_qkv(
    const __nv_bfloat16* __restrict__ Ah, const __nv_bfloat16* __restrict__ Al,
    const __nv_bfloat16* __restrict__ Bh, const __nv_bfloat16* __restrict__ Bl,
    __nv_bfloat16* __restrict__ QH, __nv_bfloat16* __restrict__ QL,
    __nv_bfloat16* __restrict__ KH, __nv_bfloat16* __restrict__ KL,
    __nv_bfloat16* __restrict__ VH, __nv_bfloat16* __restrict__ VL)
{
    constexpr int K = 128;
    extern __shared__ __nv_bfloat16 smem[];
    int tid = threadIdx.x, lane = tid & 31, warp = tid >> 5;
    int wm = warp & 3, wn = warp >> 2;
    int bm = blockIdx.y, bn = blockIdx.x;
    const __nv_bfloat16* gAh = Ah + (size_t)bm * 128 * K;
    const __nv_bfloat16* gAl = Al + (size_t)bm * 128 * K;
    const __nv_bfloat16* gBh = Bh + (size_t)bn * 128 * K;
    const __nv_bfloat16* gBl = Bl + (size_t)bn * 128 * K;

    int row_c = tid >> 2, seg_c = (tid & 3) * 8;
    auto issue = [&](int ich, int st) {
        int k0 = ich << 5;
        __nv_bfloat16* s = smem + st * G_STAGE;
        #pragma unroll
        for (int r = 0; r < 2; r++) {
            int row = row_c + r * 64;
            size_t go = (size_t)row * K + k0 + seg_c;
            int so = row * LDS_ + seg_c;
            CP16(smem_u32(s + so), gAh + go);
            CP16(smem_u32(s + G_OAL + so), gAl + go);
            CP16(smem_u32(s + G_OBH + so), gBh + go);
            CP16(smem_u32(s + G_OBL + so), gBl + go);
        }
        CP_COMMIT();
    };

    float d[2][8][4];
    #pragma unroll
    for (int mi = 0; mi < 2; mi++)
        #pragma unroll
        for (int ni = 0; ni < 8; ni++)
            #pragma unroll
            for (int j = 0; j < 4; j++) d[mi][ni][j] = 0.f;

    constexpr int nch = K >> 5;
    issue(0, 0);
    issue(1, 1);
    for (int ich = 0; ich < nch; ich++) {
        if (ich + 1 < nch) CP_WAIT1(); else CP_WAIT0();
        __syncthreads();
        const __nv_bfloat16* s = smem + (ich & 1) * G_STAGE;
        #pragma unroll
        for (int ks = 0; ks < 2; ks++) {
            uint32_t ah[2][4], al[2][4];
            #pragma unroll
            for (int mi = 0; mi < 2; mi++) {
                int row = wm * 32 + mi * 16 + (lane & 15);
                int col = ks * 16 + (lane >> 4) * 8;
                LDMX4(ah[mi], smem_u32(s + row * LDS_ + col));
                LDMX4(al[mi], smem_u32(s + G_OAL + row * LDS_ + col));
            }
            #pragma unroll
            for (int ni = 0; ni < 8; ni++) {
                uint32_t bh[2], bl[2];
                int row = wn * 64 + ni * 8 + (lane & 7);
                int col = ks * 16 + ((lane >> 3) & 1) * 8;
                LDMX2(bh, smem_u32(s + G_OBH + row * LDS_ + col));
                LDMX2(bl, smem_u32(s + G_OBL + row * LDS_ + col));
                #pragma unroll
                for (int mi = 0; mi < 2; mi++) {
                    MMA16816(d[mi][ni], ah[mi], bh);
                    MMA16816(d[mi][ni], al[mi], bh);
                    MMA16816(d[mi][ni], ah[mi], bl);
                }
            }
        }
        __syncthreads();
        if (ich + 2 < nch) issue(ich + 2, ich & 1);
    }
    __nv_bfloat16 *Oh, *Ol;
    if (bn == 0)      { Oh = QH; Ol = QL; }
    else if (bn == 1) { Oh = KH; Ol = KL; }
    else              { Oh = VH; Ol = VL; }
    #pragma unroll
    for (int mi = 0; mi < 2; mi++) {
        int row = bm * 128 + wm * 32 + mi * 16 + (lane >> 2);
        #pragma unroll
        for (int ni = 0; ni < 8; ni++) {
            int col = wn * 64 + ni * 8 + (lane & 3) * 2;
            uint32_t hh, ll;
            split2(d[mi][ni][0], d[mi][ni][1], hh, ll);
            *(uint32_t*)(Oh + (size_t)row * 128 + col) = hh;
            *(uint32_t*)(Ol + (size_t)row * 128 + col) = ll;
            split2(d[mi][ni][2], d[mi][ni][3], hh, ll);
            *(uint32_t*)(Oh + (size_t)(row + 8) * 128 + col) = hh;
            *(uint32_t*)(Ol + (size_t)(row + 8) * 128 + col) = ll;
        }
    }
}

// ================= GAT score vectors (layer 3 only) =================
__global__ void k_scores(const float* __restrict__ h, const float* __restrict__ as_,
                         const float* __restrict__ ad_, float* __restrict__ es,
                         float* __restrict__ ed, int H, int C)
{
    int idx = blockIdx.x * blockDim.x + threadIdx.x;
    if (idx >= NN * H) return;
    int node = idx / H, hd = idx % H;
    const float4* hp = (const float4*)(h + (size_t)node * H * C + (size_t)hd * C);
    const float4* ap = (const float4*)(as_ + (size_t)hd * C);
    const float4* bp = (const float4*)(ad_ + (size_t)hd * C);
    float s = 0.f, d = 0.f;
    for (int c = 0; c < C / 4; c++) {
        float4 hv = hp[c], av = ap[c], bv = bp[c];
        s += hv.x * av.x + hv.y * av.y + hv.z * av.z + hv.w * av.w;
        d += hv.x * bv.x + hv.y * bv.y + hv.z * bv.z + hv.w * bv.w;
    }
    es[idx] = s;
    ed[idx] = d;
}

// ================= GAT aggregation — single pass, float4 vectorized ==========
template <int D, int H>
__global__ __launch_bounds__(256) void k_gat_agg(
    const float* __restrict__ hfeat, const float* __restrict__ es,
    const float* __restrict__ ed, const float* __restrict__ bias,
    const float* __restrict__ gamma, const float* __restrict__ beta,
    const float* __restrict__ resid,
    __nv_bfloat16* __restrict__ outH, __nv_bfloat16* __restrict__ outL)
{
    constexpr int C = D / H;
    constexpr int NV = D / 128;
    int warp = (blockIdx.x * blockDim.x + threadIdx.x) >> 5;
    int lane = threadIdx.x & 31;
    if (warp >= NN) return;
    int i = warp;
    int beg = g_rowptr[i], end = g_rowptr[i + 1];

    float edv[H], z[H];
    #pragma unroll
    for (int h = 0; h < H; h++) {
        edv[h] = ed[(size_t)i * H + h];
        z[h] = 0.f;
    }
    float4 acc[NV];
    #pragma unroll
    for (int j = 0; j < NV; j++) acc[j] = make_float4(0.f, 0.f, 0.f, 0.f);

    for (int e = beg; e < end; e++) {
        int s = g_col[e];
        float al[H];
        if (H == 4) {
            float4 ev = ((const float4*)es)[s];
            float vv[4] = {ev.x, ev.y, ev.z, ev.w};
            #pragma unroll
            for (int h = 0; h < 4; h++) {
                float v = vv[h] + edv[h];
                v = v > 0.f ? v : 0.2f * v;
                al[h] = expf(v);
                z[h] += al[h];
            }
        } else {
            float v = es[s] + edv[0];
            v = v > 0.f ? v : 0.2f * v;
            al[0] = expf(v);
            z[0] += al[0];
        }
        const float4* hs = (const float4*)(hfeat + (size_t)s * D);
        #pragma unroll
        for (int j = 0; j < NV; j++) {
            float4 hv = hs[lane + 32 * j];
            float a = (H == 1) ? al[0] : al[((lane + 32 * j) * 4) / C];
            acc[j].x += a * hv.x; acc[j].y += a * hv.y;
            acc[j].z += a * hv.z; acc[j].w += a * hv.w;
        }
    }
    #pragma unroll
    for (int h = 0; h < H; h++) z[h] = 1.f / (z[h] + 1e-16f);

    float4 x[NV];
    #pragma unroll
    for (int j = 0; j < NV; j++) {
        int g4 = lane + 32 * j;
        float zz = (H == 1) ? z[0] : z[(g4 * 4) / C];
        float4 b4 = ((const float4*)bias)[g4];
        x[j].x = acc[j].x * zz + b4.x;
        x[j].y = acc[j].y * zz + b4.y;
        x[j].z = acc[j].z * zz + b4.z;
        x[j].w = acc[j].w * zz + b4.w;
        if (resid) {
            float4 r4 = ((const float4*)(resid + (size_t)i * D))[g4];
            x[j].x += r4.x; x[j].y += r4.y; x[j].z += r4.z; x[j].w += r4.w;
        }
    }
    if (gamma) {
        #pragma unroll
        for (int j = 0; j < NV; j++) {
            x[j].x = x[j].x > 0.f ? x[j].x : (expf(x[j].x) - 1.f);
            x[j].y = x[j].y > 0.f ? x[j].y : (expf(x[j].y) - 1.f);
            x[j].z = x[j].z > 0.f ? x[j].z : (expf(x[j].z) - 1.f);
            x[j].w = x[j].w > 0.f ? x[j].w : (expf(x[j].w) - 1.f);
        }
        float s = 0.f;
        #pragma unroll
        for (int j = 0; j < NV; j++) s += x[j].x + x[j].y + x[j].z + x[j].w;
        #pragma unroll
        for (int o = 16; o; o >>= 1) s += __shfl_xor_sync(0xffffffffu, s, o);
        float mu = s / (float)D;
        float vs = 0.f;
        #pragma unroll
        for (int j = 0; j < NV; j++) {
            float a = x[j].x - mu, b = x[j].y - mu, c = x[j].z - mu, dd = x[j].w - mu;
            vs += a * a + b * b + c * c + dd * dd;
        }
        #pragma unroll
        for (int o = 16; o; o >>= 1) vs += __shfl_xor_sync(0xffffffffu, vs, o);
        float inv = rsqrtf(vs / (float)D + 1e-5f);
        #pragma unroll
        for (int j = 0; j < NV; j++) {
            int g4 = lane + 32 * j;
            float4 g = ((const float4*)gamma)[g4];
            float4 be = ((const float4*)beta)[g4];
            x[j].x = (x[j].x - mu) * inv * g.x + be.x;
            x[j].y = (x[j].y - mu) * inv * g.y + be.y;
            x[j].z = (x[j].z - mu) * inv * g.z + be.z;
            x[j].w = (x[j].w - mu) * inv * g.w + be.w;
        }
    }
    #pragma unroll
    for (int j = 0; j < NV; j++) {
        int g4 = lane + 32 * j;
        uint32_t h01, l01, h23, l23;
        split2(x[j].x, x[j].y, h01, l01);
        split2(x[j].z, x[j].w, h23, l23);
        *(uint2*)(outH + (size_t)i * D + g4 * 4) = make_uint2(h01, h23);
        *(uint2*)(outL + (size_t)i * D + g4 * 4) = make_uint2(l01, l23);
    }
}

// ================= fused flash attention, cp.async K/V pipeline =============
// smem layout (bf16 elems):
//   Q hi: [0, 5120)  Q lo: [5120, 10240)
//   stage s: base 10240 + s*20480; within: KH 0, KL 5120, VH 10240, VL 15360
//   (V tile stored [k=128 rows][n=32 cols], stride 40 — read via ldmatrix.trans)
constexpr int FL_QH = 0;
constexpr int FL_QL = 128 * LDS_;
constexpr int FL_ST0 = 2 * 128 * LDS_;
constexpr int FL_KH = 0;
constexpr int FL_KL = 128 * LDS_;
constexpr int FL_VH = 2 * 128 * LDS_;
constexpr int FL_VL = 3 * 128 * LDS_;
constexpr int FL_STAGE = 4 * 128 * LDS_;
constexpr int FLASH_SMEM = (FL_ST0 + 2 * FL_STAGE) * 2;   // 102400 bytes

__global__ __launch_bounds__(256) void k_flash(
    const __nv_bfloat16* __restrict__ QH, const __nv_bfloat16* __restrict__ QL,
    const __nv_bfloat16* __restrict__ KH, const __nv_bfloat16* __restrict__ KL,
    const __nv_bfloat16* __restrict__ VH, const __nv_bfloat16* __restrict__ VL,
    __nv_bfloat16* __restrict__ OHo, __nv_bfloat16* __restrict__ OLo)
{
    extern __shared__ __nv_bfloat16 sm[];
    int gh = blockIdx.y, g = gh >> 2, h = gh & 3;
    int qt = blockIdx.x;
    int tid = threadIdx.x, lane = tid & 31, warp = tid >> 5;

    int row_c = tid >> 2, seg_c = (tid & 3) * 8;

    // K/V tile loader (128 rows x 32 cols, hi/lo)
    auto issue = [&](int kt, int st) {
        __nv_bfloat16* s = sm + FL_ST0 + st * FL_STAGE;
        #pragma unroll
        for (int r = 0; r < 2; r++) {
            int row = row_c + r * 64;
            size_t go = ((size_t)g * GS + kt * 128 + row) * 128 + h * 32 + seg_c;
            int so = row * LDS_ + seg_c;
            CP16(smem_u32(s + FL_KH + so), KH + go);
            CP16(smem_u32(s + FL_KL + so), KL + go);
            CP16(smem_u32(s + FL_VH + so), VH + go);
            CP16(smem_u32(s + FL_VL + so), VL + go);
        }
        CP_COMMIT();
    };

    // group 0: Q + stage 0
    {
        #pragma unroll
        for (int r = 0; r < 2; r++) {
            int row = row_c + r * 64;
            size_t go = ((size_t)g * GS + qt * 128 + row) * 128 + h * 32 + seg_c;
            int so = row * LDS_ + seg_c;
            CP16(smem_u32(sm + FL_QH + so), QH + go);
            CP16(smem_u32(sm + FL_QL + so), QL + go);
        }
        __nv_bfloat16* s = sm + FL_ST0;
        #pragma unroll
        for (int r = 0; r < 2; r++) {
            int row = row_c + r * 64;
            size_t go = ((size_t)g * GS + row) * 128 + h * 32 + seg_c;
            int so = row * LDS_ + seg_c;
            CP16(smem_u32(s + FL_KH + so), KH + go);
            CP16(smem_u32(s + FL_KL + so), KL + go);
            CP16(smem_u32(s + FL_VH + so), VH + go);
            CP16(smem_u32(s + FL_VL + so), VL + go);
        }
        CP_COMMIT();
    }
    issue(1, 1);   // group 1: stage 1

    uint32_t qh_[2][4], ql_[2][4];
    float m0 = -1e30f, m1 = -1e30f, l0 = 0.f, l1 = 0.f;
    float O[4][4];
    #pragma unroll
    for (int n = 0; n < 4; n++)
        #pragma unroll
        for (int j = 0; j < 4; j++) O[n][j] = 0.f;

    const float scale = 0.088388347648318447f;

    for (int kt = 0; kt < 4; kt++) {
        if (kt < 3) CP_WAIT1(); else CP_WAIT0();
        __syncthreads();
        const __nv_bfloat16* s = sm + FL_ST0 + (kt & 1) * FL_STAGE;

        if (kt == 0) {
            #pragma unroll
            for (int kf = 0; kf < 2; kf++) {
                int row = warp * 16 + (lane & 15);
                int col = kf * 16 + (lane >> 4) * 8;
                LDMX4(qh_[kf], smem_u32(sm + FL_QH + row * LDS_ + col));
                LDMX4(ql_[kf], smem_u32(sm + FL_QL + row * LDS_ + col));
            }
        }

        // S = Q K^T on this 128-key tile
        float S[16][4];
        #pragma unroll
        for (int j = 0; j < 16; j++)
            #pragma unroll
            for (int r = 0; r < 4; r++) S[j][r] = 0.f;
        #pragma unroll
        for (int j = 0; j < 16; j++) {
            #pragma unroll
            for (int kf = 0; kf < 2; kf++) {
                uint32_t bh[2], bl[2];
                int row = j * 8 + (lane & 7);
                int col = kf * 16 + ((lane >> 3) & 1) * 8;
                LDMX2(bh, smem_u32(s + FL_KH + row * LDS_ + col));
                LDMX2(bl, smem_u32(s + FL_KL + row * LDS_ + col));
                MMA16816(S[j], qh_[kf], bh);
                MMA16816(S[j], ql_[kf], bh);
                MMA16816(S[j], qh_[kf], bl);
            }
        }
        // online softmax
        float mx0 = -1e30f, mx1 = -1e30f;
        #pragma unroll
        for (int j = 0; j < 16; j++) {
            S[j][0] *= scale; S[j][1] *= scale; S[j][2] *= scale; S[j][3] *= scale;
            mx0 = fmaxf(mx0, fmaxf(S[j][0], S[j][1]));
            mx1 = fmaxf(mx1, fmaxf(S[j][2], S[j][3]));
        }
        #pragma unroll
        for (int o = 1; o < 4; o <<= 1) {
            mx0 = fmaxf(mx0, __shfl_xor_sync(0xffffffffu, mx0, o));
            mx1 = fmaxf(mx1, __shfl_xor_sync(0xffffffffu, mx1, o));
        }
        float nm0 = fmaxf(m0, mx0), nm1 = fmaxf(m1, mx1);
        float a0 = expf(m0 - nm0), a1 = expf(m1 - nm1);
        float rs0 = 0.f, rs1 = 0.f;
        #pragma unroll
        for (int j = 0; j < 16; j++) {
            S[j][0] = expf(S[j][0] - nm0); S[j][1] = expf(S[j][1] - nm0);
            S[j][2] = expf(S[j][2] - nm1); S[j][3] = expf(S[j][3] - nm1);
            rs0 += S[j][0] + S[j][1];
            rs1 += S[j][2] + S[j][3];
        }
        #pragma unroll
        for (int o = 1; o < 4; o <<= 1) {
            rs0 += __shfl_xor_sync(0xffffffffu, rs0, o);
            rs1 += __shfl_xor_sync(0xffffffffu, rs1, o);
        }
        l0 = l0 * a0 + rs0;
        l1 = l1 * a1 + rs1;
        #pragma unroll
        for (int n = 0; n < 4; n++) {
            O[n][0] *= a0; O[n][1] *= a0; O[n][2] *= a1; O[n][3] *= a1;
        }
        m0 = nm0; m1 = nm1;
        // P @ V (V tile [k][n], B-frags via ldmatrix.trans)
        #pragma unroll
        for (int jp = 0; jp < 8; jp++) {
            uint32_t aph[4], apl[4];
            split2(S[2 * jp][0],     S[2 * jp][1],     aph[0], apl[0]);
            split2(S[2 * jp][2],     S[2 * jp][3],     aph[1], apl[1]);
            split2(S[2 * jp + 1][0], S[2 * jp + 1][1], aph[2], apl[2]);
            split2(S[2 * jp + 1][2], S[2 * jp + 1][3], aph[3], apl[3]);
            #pragma unroll
            for (int n = 0; n < 4; n++) {
                uint32_t bh[2], bl[2];
                int row = jp * 16 + ((lane >> 3) & 1) * 8 + (lane & 7);
                int col = n * 8;
                LDMX2T(bh, smem_u32(s + FL_VH + row * LDS_ + col));
                LDMX2T(bl, smem_u32(s + FL_VL + row * LDS_ + col));
                MMA16816(O[n], aph, bh);
                MMA16816(O[n], apl, bh);
                MMA16816(O[n], aph, bl);
            }
        }
        __syncthreads();
        if (kt + 2 < 4) issue(kt + 2, kt & 1);
    }
    float il0 = 1.f / l0, il1 = 1.f / l1;
    int node = g * GS + qt * 128 + warp * 16 + (lane >> 2);
    #pragma unroll
    for (int n = 0; n < 4; n++) {
        int col = h * 32 + n * 8 + (lane & 3) * 2;
        uint32_t hh, ll;
        split2(O[n][0] * il0, O[n][1] * il0, hh, ll);
        *(uint32_t*)(OHo + (size_t)node * 128 + col) = hh;
        *(uint32_t*)(OLo + (size_t)node * 128 + col) = ll;
        split2(O[n][2] * il1, O[n][3] * il1, hh, ll);
        *(uint32_t*)(OHo + (size_t)(node + 8) * 128 + col) = hh;
        *(uint32_t*)(OLo + (size_t)(node + 8) * 128 + col) = ll;
    }
}

// ================= host orchestration =================
extern "C" void kernel_launch(void* const* d_in, const int* in_sizes, int n_in,
                              void* d_out, int out_size)
{
    const float* x   = (const float*)d_in[0];
    const int*   ei  = (const int*)  d_in[1];
    const float* W1  = (const float*)d_in[3];
    const float* a1s = (const float*)d_in[4];
    const float* a1d = (const float*)d_in[5];
    const float* b1  = (const float*)d_in[6];
    const float* W2  = (const float*)d_in[7];
    const float* a2s = (const float*)d_in[8];
    const float* a2d = (const float*)d_in[9];
    const float* b2  = (const float*)d_in[10];
    const float* W3  = (const float*)d_in[11];
    const float* a3s = (const float*)d_in[12];
    const float* a3d = (const float*)d_in[13];
    const float* b3  = (const float*)d_in[14];
    const float* g1  = (const float*)d_in[15];
    const float* be1 = (const float*)d_in[16];
    const float* g2  = (const float*)d_in[17];
    const float* be2 = (const float*)d_in[18];
    const float* Wr  = (const float*)d_in[19];
    const float* br  = (const float*)d_in[20];
    const float* Wq  = (const float*)d_in[21];
    const float* Wk  = (const float*)d_in[22];
    const float* Wv  = (const float*)d_in[23];
    const float* Wo  = (const float*)d_in[24];
    const float* bo  = (const float*)d_in[25];
    float* out = (float*)d_out;

    float* sb = nullptr;
    cudaGetSymbolAddress((void**)&sb, g_scratch);
    __nv_bfloat16* bb = nullptr;
    cudaGetSymbolAddress((void**)&bb, g_bf);
    cudaFuncSetAttribute(k_flash, cudaFuncAttributeMaxDynamicSharedMemorySize, FLASH_SMEM);
    cudaFuncSetAttribute(mma_gemm, cudaFuncAttributeMaxDynamicSharedMemorySize, GEMM_SMEM);
    cudaFuncSetAttribute(mma_gemm_qkv, cudaFuncAttributeMaxDynamicSharedMemorySize, GEMM_SMEM);

    float* p_h  = sb + OFF_H;
    float* p_h3 = sb + OFF_H3;
    float* p_r  = sb + OFF_R;
    float* p_es = sb + OFF_ES;
    float* p_ed = sb + OFF_ED;

    // CSR
    k_zero_cnt<<<NN / 256, 256>>>();
    k_count<<<1024, 256>>>(ei);
    k_scan1<<<256, 256>>>();
    k_scan2<<<1, 256>>>();
    k_scan3<<<256, 256>>>();
    k_fill<<<1152, 256>>>(ei);

    // weight conversions
    k_cvt_wT<<<(256*64 + 255)/256, 256>>>(W1, bb + B_W1H, bb + B_W1L, 64, 256);
    k_cvt_wT<<<(256*256 + 255)/256, 256>>>(W2, bb + B_W2H, bb + B_W2L, 256, 256);
    k_cvt_wT<<<(128*256 + 255)/256, 256>>>(W3, bb + B_W3H, bb + B_W3L, 256, 128);
    k_cvt_wT<<<(128*64 + 255)/256, 256>>>(Wr, bb + B_WRH, bb + B_WRL, 64, 128);
    k_cvt_wqkv<<<(384*128 + 255)/256, 256>>>(Wq, Wk, Wv, bb + B_WQKVH, bb + B_WQKVL);
    k_cvt_wT<<<(128*128 + 255)/256, 256>>>(Wo, bb + B_WOH, bb + B_WOL, 128, 128);

    // x -> bf16 hi/lo
    k_cvt_split<<<(NN*64/4 + 255)/256, 256>>>(x, bb + B_XH, bb + B_XL, NN*64/4);

    // layer 1 (fused scores)
    mma_gemm<<<dim3(2, 512), 256, GEMM_SMEM>>>(bb + B_XH, bb + B_XL, bb + B_W1H, bb + B_W1L,
                                    nullptr, p_h, nullptr, nullptr,
                                    a1s, a1d, p_es, p_ed, NN, 256, 64);
    k_gat_agg<256, 4><<<NN / 8, 256>>>(p_h, p_es, p_ed, b1, g1, be1, nullptr,
                                       bb + B_TH, bb + B_TL);
    // layer 2 (fused scores)
    mma_gemm<<<dim3(2, 512), 256, GEMM_SMEM>>>(bb + B_TH, bb + B_TL, bb + B_W2H, bb + B_W2L,
                                    nullptr, p_h, nullptr, nullptr,
                                    a2s, a2d, p_es, p_ed, NN, 256, 256);
    k_gat_agg<256, 4><<<NN / 8, 256>>>(p_h, p_es, p_ed, b2, g2, be2, nullptr,
                                       bb + B_TH, bb + B_TL);
    // layer 3 + residual
    mma_gemm<<<dim3(1, 512), 256, GEMM_SMEM>>>(bb + B_TH, bb + B_TL, bb + B_W3H, bb + B_W3L,
                                    nullptr, p_h3, nullptr, nullptr,
                                    nullptr, nullptr, nullptr, nullptr, NN, 128, 256);
    k_scores<<<NN / 256, 256>>>(p_h3, a3s, a3d, p_es, p_ed, 1, 128);
    mma_gemm<<<dim3(1, 512), 256, GEMM_SMEM>>>(bb + B_XH, bb + B_XL, bb + B_WRH, bb + B_WRL,
                                    br, p_r, nullptr, nullptr,
                                    nullptr, nullptr, nullptr, nullptr, NN, 128, 64);
    k_gat_agg<128, 1><<<NN / 8, 256>>>(p_h3, p_es, p_ed, b3, nullptr, nullptr, p_r,
                                       bb + B_HRH, bb + B_HRL);
    // fused QKV projection
    mma_gemm_qkv<<<dim3(3, 512), 256, GEMM_SMEM>>>(bb + B_HRH, bb + B_HRL,
                                        bb + B_WQKVH, bb + B_WQKVL,
                                        bb + B_QH, bb + B_QL,
                                        bb + B_KH, bb + B_KL,
                                        bb + B_VH, bb + B_VL);
    // fused attention (pipelined; V transposed in-register via ldmatrix.trans)
    k_flash<<<dim3(4, NG * 4), 256, FLASH_SMEM>>>(
        bb + B_QH, bb + B_QL, bb + B_KH, bb + B_KL,
        bb + B_VH, bb + B_VL, bb + B_AOH, bb + B_AOL);
    // output projection
    mma_gemm<<<dim3(1, 512), 256, GEMM_SMEM>>>(bb + B_AOH, bb + B_AOL, bb + B_WOH, bb + B_WOL,
                                    bo, out, nullptr, nullptr,
                                    nullptr, nullptr, nullptr, nullptr, NN, 128, 128);
}

// round 10
// speedup vs baseline: 2.2021x; 1.0590x over previous
#include <cuda_runtime.h>
#include <cuda_bf16.h>
#include <math.h>
#include <stdint.h>

// ---------------- problem constants ----------------
constexpr int NN   = 65536;
constexpr int NE   = 524288;
constexpr int ET   = NE + NN;
constexpr int GS   = 512;
constexpr int NG   = NN / GS;
constexpr int D1   = 256;
constexpr int D3   = 128;
constexpr int PERS = 296;   // 148 SMs x 2 CTAs

// ---------------- fp32 scratch ----------------
constexpr size_t OFF_H    = 0;
constexpr size_t OFF_H3   = OFF_H  + (size_t)NN*D1;
constexpr size_t OFF_R    = OFF_H3 + (size_t)NN*D3;
constexpr size_t OFF_ES   = OFF_R  + (size_t)NN*D3;
constexpr size_t OFF_ED   = OFF_ES + (size_t)NN*4;
constexpr size_t SCRATCH  = OFF_ED + (size_t)NN*4;

__device__ __align__(256) float g_scratch[SCRATCH];

// ---------------- bf16 scratch ----------------
constexpr size_t B_XH  = 0;
constexpr size_t B_XL  = B_XH  + (size_t)NN*64;
constexpr size_t B_TH  = B_XL  + (size_t)NN*64;
constexpr size_t B_TL  = B_TH  + (size_t)NN*256;
constexpr size_t B_HRH = B_TL  + (size_t)NN*256;
constexpr size_t B_HRL = B_HRH + (size_t)NN*128;
constexpr size_t B_AOH = B_HRL + (size_t)NN*128;
constexpr size_t B_AOL = B_AOH + (size_t)NN*128;
constexpr size_t B_QH  = B_AOL + (size_t)NN*128;
constexpr size_t B_QL  = B_QH  + (size_t)NN*128;
constexpr size_t B_KH  = B_QL  + (size_t)NN*128;
constexpr size_t B_KL  = B_KH  + (size_t)NN*128;
constexpr size_t B_VH  = B_KL  + (size_t)NN*128;
constexpr size_t B_VL  = B_VH  + (size_t)NN*128;
constexpr size_t B_W1H = B_VL  + (size_t)NN*128;
constexpr size_t B_W1L = B_W1H + 256*64;
constexpr size_t B_W2H = B_W1L + 256*64;
constexpr size_t B_W2L = B_W2H + 256*256;
constexpr size_t B_W3H = B_W2L + 256*256;
constexpr size_t B_W3L = B_W3H + 128*256;
constexpr size_t B_WRH = B_W3L + 128*256;
constexpr size_t B_WRL = B_WRH + 128*64;
constexpr size_t B_WQKVH = B_WRL + 128*64;
constexpr size_t B_WQKVL = B_WQKVH + 384*128;
constexpr size_t B_WOH = B_WQKVL + 384*128;
constexpr size_t B_WOL = B_WOH + 128*128;
constexpr size_t BF_TOTAL = B_WOL + 128*128;

__device__ __align__(256) __nv_bfloat16 g_bf[BF_TOTAL];

__device__ int g_rowptr[NN + 1];
__device__ int g_cnt[NN];
__device__ int g_cursor[NN];
__device__ int g_col[ET];
__device__ int g_blocksum[256];

// ================= helpers =================
__device__ __forceinline__ uint32_t smem_u32(const void* p) {
    uint32_t a;
    asm("{ .reg .u64 t; cvta.to.shared.u64 t, %1; cvt.u32.u64 %0, t; }" : "=r"(a) : "l"(p));
    return a;
}
#define LDMX4(r, a) \
    asm volatile("ldmatrix.sync.aligned.m8n8.x4.shared.b16 {%0,%1,%2,%3}, [%4];" \
        : "=r"((r)[0]), "=r"((r)[1]), "=r"((r)[2]), "=r"((r)[3]) : "r"(a))
#define LDMX2(r, a) \
    asm volatile("ldmatrix.sync.aligned.m8n8.x2.shared.b16 {%0,%1}, [%2];" \
        : "=r"((r)[0]), "=r"((r)[1]) : "r"(a))
#define LDMX2T(r, a) \
    asm volatile("ldmatrix.sync.aligned.m8n8.x2.trans.shared.b16 {%0,%1}, [%2];" \
        : "=r"((r)[0]), "=r"((r)[1]) : "r"(a))
#define MMA16816(d, a, b) \
    asm volatile("mma.sync.aligned.m16n8k16.row.col.f32.bf16.bf16.f32 " \
        "{%0,%1,%2,%3}, {%4,%5,%6,%7}, {%8,%9}, {%0,%1,%2,%3};" \
        : "+f"((d)[0]), "+f"((d)[1]), "+f"((d)[2]), "+f"((d)[3]) \
        : "r"((a)[0]), "r"((a)[1]), "r"((a)[2]), "r"((a)[3]), \
          "r"((b)[0]), "r"((b)[1]))
#define CP16(dst, src) \
    asm volatile("cp.async.cg.shared.global [%0], [%1], 16;" :: "r"(dst), "l"(src))
#define CP_COMMIT() asm volatile("cp.async.commit_group;" ::: "memory")
#define CP_WAIT1()  asm volatile("cp.async.wait_group 1;" ::: "memory")
#define CP_WAIT0()  asm volatile("cp.async.wait_group 0;" ::: "memory")

__device__ __forceinline__ void split2(float v0, float v1, uint32_t& hh, uint32_t& ll) {
    __nv_bfloat16 h0 = __float2bfloat16(v0), h1 = __float2bfloat16(v1);
    __nv_bfloat16 l0 = __float2bfloat16(v0 - __bfloat162float(h0));
    __nv_bfloat16 l1 = __float2bfloat16(v1 - __bfloat162float(h1));
    __nv_bfloat162 H; H.x = h0; H.y = h1;
    __nv_bfloat162 L; L.x = l0; L.y = l1;
    hh = *(uint32_t*)&H; ll = *(uint32_t*)&L;
}

// ================= CSR build (parallel scan) =================
__global__ void k_zero_cnt() {
    int i = blockIdx.x * blockDim.x + threadIdx.x;
    if (i < NN) g_cnt[i] = 0;
}
__global__ void k_count(const int* __restrict__ ei) {
    int stride = gridDim.x * blockDim.x;
    for (int idx = blockIdx.x * blockDim.x + threadIdx.x; idx < NE; idx += stride)
        atomicAdd(&g_cnt[ei[NE + idx]], 1);
}
__global__ void k_scan1() {
    __shared__ int ws[8];
    int b = blockIdx.x, tid = threadIdx.x, lane = tid & 31, wid = tid >> 5;
    int v = g_cnt[b * 256 + tid] + 1;
    int x = v;
    #pragma unroll
    for (int o = 1; o < 32; o <<= 1) {
        int t = __shfl_up_sync(0xffffffffu, x, o);
        if (lane >= o) x += t;
    }
    if (lane == 31) ws[wid] = x;
    __syncthreads();
    if (tid == 0) {
        int run = 0;
        #pragma unroll
        for (int k = 0; k < 8; k++) { int t = ws[k]; ws[k] = run; run += t; }
        g_blocksum[b] = run;
    }
    __syncthreads();
    g_rowptr[b * 256 + tid] = x - v + ws[wid];
}
__global__ void k_scan2() {
    __shared__ int ws[8];
    int tid = threadIdx.x, lane = tid & 31, wid = tid >> 5;
    int v = g_blocksum[tid];
    int x = v;
    #pragma unroll
    for (int o = 1; o < 32; o <<= 1) {
        int t = __shfl_up_sync(0xffffffffu, x, o);
        if (lane >= o) x += t;
    }
    if (lane == 31) ws[wid] = x;
    __syncthreads();
    if (tid == 0) {
        int run = 0;
        #pragma unroll
        for (int k = 0; k < 8; k++) { int t = ws[k]; ws[k] = run; run += t; }
    }
    __syncthreads();
    g_blocksum[tid] = x - v + ws[wid];
}
__global__ void k_scan3() {
    int idx = blockIdx.x * 256 + threadIdx.x;
    int v = g_rowptr[idx] + g_blocksum[blockIdx.x];
    g_rowptr[idx] = v;
    g_cursor[idx] = v;
    if (idx == 0) g_rowptr[NN] = ET;
}
__global__ void k_fill(const int* __restrict__ ei) {
    int stride = gridDim.x * blockDim.x;
    for (int idx = blockIdx.x * blockDim.x + threadIdx.x; idx < ET; idx += stride) {
        int s, d;
        if (idx < NE) { s = ei[idx]; d = ei[NE + idx]; }
        else          { s = d = idx - NE; }
        int pos = atomicAdd(&g_cursor[d], 1);
        g_col[pos] = s;
    }
}

// ================= conversions =================
__global__ void k_cvt_split(const float* __restrict__ in, __nv_bfloat16* __restrict__ hi,
                            __nv_bfloat16* __restrict__ lo, int n4) {
    int i = blockIdx.x * blockDim.x + threadIdx.x;
    if (i >= n4) return;
    float4 v = ((const float4*)in)[i];
    uint32_t h01, l01, h23, l23;
    split2(v.x, v.y, h01, l01);
    split2(v.z, v.w, h23, l23);
    ((uint32_t*)hi)[2 * i] = h01; ((uint32_t*)hi)[2 * i + 1] = h23;
    ((uint32_t*)lo)[2 * i] = l01; ((uint32_t*)lo)[2 * i + 1] = l23;
}

__global__ void k_cvt_wT(const float* __restrict__ W, __nv_bfloat16* __restrict__ hiT,
                         __nv_bfloat16* __restrict__ loT, int K, int N) {
    int idx = blockIdx.x * blockDim.x + threadIdx.x;
    if (idx >= N * K) return;
    int n = idx / K, k = idx % K;
    float v = W[(size_t)k * N + n];
    __nv_bfloat16 h = __float2bfloat16(v);
    hiT[idx] = h;
    loT[idx] = __float2bfloat16(v - __bfloat162float(h));
}

__global__ void k_cvt_wqkv(const float* __restrict__ Wq, const float* __restrict__ Wk,
                           const float* __restrict__ Wv,
                           __nv_bfloat16* __restrict__ hiT, __nv_bfloat16* __restrict__ loT) {
    int idx = blockIdx.x * blockDim.x + threadIdx.x;
    if (idx >= 384 * 128) return;
    int n = idx / 128, k = idx % 128;
    const float* W = (n < 128) ? Wq : ((n < 256) ? Wk : Wv);
    float v = W[(size_t)k * 128 + (n & 127)];
    __nv_bfloat16 h = __float2bfloat16(v);
    hiT[idx] = h;
    loT[idx] = __float2bfloat16(v - __bfloat162float(h));
}

// ================= mma.sync bf16-split GEMM, persistent tiles ================
// score_mode: 0 none; 1 fused H=4 scores (layers 1/2); 2 fused H=1 scores (layer 3)
constexpr int LDS_ = 40;
constexpr int G_OAL = 128 * LDS_;
constexpr int G_OBH = 2 * 128 * LDS_;
constexpr int G_OBL = 3 * 128 * LDS_;
constexpr int G_STAGE = 4 * 128 * LDS_;
constexpr int GEMM_SMEM = 2 * G_STAGE * 2;

__global__ __launch_bounds__(256, 2) void mma_gemm(
    const __nv_bfloat16* __restrict__ Ah, const __nv_bfloat16* __restrict__ Al,
    const __nv_bfloat16* __restrict__ Bh, const __nv_bfloat16* __restrict__ Bl,
    const float* __restrict__ bias, float* __restrict__ C,
    __nv_bfloat16* __restrict__ Chi, __nv_bfloat16* __restrict__ Clo,
    const float* __restrict__ asv, const float* __restrict__ adv,
    float* __restrict__ esv, float* __restrict__ edv_out,
    int score_mode, int M, int N, int K)
{
    extern __shared__ __nv_bfloat16 smem[];
    int tid = threadIdx.x, lane = tid & 31, warp = tid >> 5;
    int wm = warp & 3, wn = warp >> 2;
    int nbn = N >> 7;
    int ntiles = (M >> 7) * nbn;
    int row_c = tid >> 2, seg_c = (tid & 3) * 8;
    int nch = K >> 5;

    for (int tile = blockIdx.x; tile < ntiles; tile += gridDim.x) {
        int bm = tile / nbn, bn = tile - bm * nbn;
        const __nv_bfloat16* gAh = Ah + (size_t)bm * 128 * K;
        const __nv_bfloat16* gAl = Al + (size_t)bm * 128 * K;
        const __nv_bfloat16* gBh = Bh + (size_t)bn * 128 * K;
        const __nv_bfloat16* gBl = Bl + (size_t)bn * 128 * K;

        auto issue = [&](int ich, int st) {
            int k0 = ich << 5;
            __nv_bfloat16* s = smem + st * G_STAGE;
            #pragma unroll
            for (int r = 0; r < 2; r++) {
                int row = row_c + r * 64;
                size_t go = (size_t)row * K + k0 + seg_c;
                int so = row * LDS_ + seg_c;
                CP16(smem_u32(s + so), gAh + go);
                CP16(smem_u32(s + G_OAL + so), gAl + go);
                CP16(smem_u32(s + G_OBH + so), gBh + go);
                CP16(smem_u32(s + G_OBL + so), gBl + go);
            }
            CP_COMMIT();
        };

        float d[2][8][4];
        #pragma unroll
        for (int mi = 0; mi < 2; mi++)
            #pragma unroll
            for (int ni = 0; ni < 8; ni++)
                #pragma unroll
                for (int j = 0; j < 4; j++) d[mi][ni][j] = 0.f;

        issue(0, 0);
        if (nch > 1) issue(1, 1);

        for (int ich = 0; ich < nch; ich++) {
            if (ich + 1 < nch) CP_WAIT1(); else CP_WAIT0();
            __syncthreads();
            const __nv_bfloat16* s = smem + (ich & 1) * G_STAGE;
            #pragma unroll
            for (int ks = 0; ks < 2; ks++) {
                uint32_t ah[2][4], al[2][4];
                #pragma unroll
                for (int mi = 0; mi < 2; mi++) {
                    int row = wm * 32 + mi * 16 + (lane & 15);
                    int col = ks * 16 + (lane >> 4) * 8;
                    LDMX4(ah[mi], smem_u32(s + row * LDS_ + col));
                    LDMX4(al[mi], smem_u32(s + G_OAL + row * LDS_ + col));
                }
                #pragma unroll
                for (int ni = 0; ni < 8; ni++) {
                    uint32_t bh[2], bl[2];
                    int row = wn * 64 + ni * 8 + (lane & 7);
                    int col = ks * 16 + ((lane >> 3) & 1) * 8;
                    LDMX2(bh, smem_u32(s + G_OBH + row * LDS_ + col));
                    LDMX2(bl, smem_u32(s + G_OBL + row * LDS_ + col));
                    #pragma unroll
                    for (int mi = 0; mi < 2; mi++) {
                        MMA16816(d[mi][ni], ah[mi], bh);
                        MMA16816(d[mi][ni], al[mi], bh);
                        MMA16816(d[mi][ni], ah[mi], bl);
                    }
                }
            }
            __syncthreads();
            if (ich + 2 < nch) issue(ich + 2, ich & 1);
        }

        // main epilogue
        #pragma unroll
        for (int mi = 0; mi < 2; mi++) {
            int row = bm * 128 + wm * 32 + mi * 16 + (lane >> 2);
            #pragma unroll
            for (int ni = 0; ni < 8; ni++) {
                int col = bn * 128 + wn * 64 + ni * 8 + (lane & 3) * 2;
                if (C) {
                    float b0 = bias ? bias[col] : 0.f;
                    float b1 = bias ? bias[col + 1] : 0.f;
                    *(float2*)(C + (size_t)row * N + col) =
                        make_float2(d[mi][ni][0] + b0, d[mi][ni][1] + b1);
                    *(float2*)(C + (size_t)(row + 8) * N + col) =
                        make_float2(d[mi][ni][2] + b0, d[mi][ni][3] + b1);
                } else {
                    uint32_t hh, ll;
                    split2(d[mi][ni][0], d[mi][ni][1], hh, ll);
                    *(uint32_t*)(Chi + (size_t)row * N + col) = hh;
                    *(uint32_t*)(Clo + (size_t)row * N + col) = ll;
                    split2(d[mi][ni][2], d[mi][ni][3], hh, ll);
                    *(uint32_t*)(Chi + (size_t)(row + 8) * N + col) = hh;
                    *(uint32_t*)(Clo + (size_t)(row + 8) * N + col) = ll;
                }
            }
        }
        if (score_mode == 1) {
            // H=4 heads: head = bn*2 + wn, C=64 (fits within one warp's 64 cols)
            int hd = bn * 2 + wn;
            float sv[4] = {0.f, 0.f, 0.f, 0.f}, dv[4] = {0.f, 0.f, 0.f, 0.f};
            #pragma unroll
            for (int mi = 0; mi < 2; mi++)
                #pragma unroll
                for (int ni = 0; ni < 8; ni++)
                    #pragma unroll
                    for (int j = 0; j < 2; j++) {
                        int cl = ni * 8 + (lane & 3) * 2 + j;
                        float a = asv[hd * 64 + cl], b = adv[hd * 64 + cl];
                        sv[mi * 2]     += d[mi][ni][j]     * a;
                        dv[mi * 2]     += d[mi][ni][j]     * b;
                        sv[mi * 2 + 1] += d[mi][ni][2 + j] * a;
                        dv[mi * 2 + 1] += d[mi][ni][2 + j] * b;
                    }
            #pragma unroll
            for (int r = 0; r < 4; r++) {
                sv[r] += __shfl_xor_sync(0xffffffffu, sv[r], 1);
                sv[r] += __shfl_xor_sync(0xffffffffu, sv[r], 2);
                dv[r] += __shfl_xor_sync(0xffffffffu, dv[r], 1);
                dv[r] += __shfl_xor_sync(0xffffffffu, dv[r], 2);
            }
            if ((lane & 3) == 0) {
                #pragma unroll
                for (int r = 0; r < 4; r++) {
                    int row = bm * 128 + wm * 32 + (r >> 1) * 16 + (lane >> 2) + (r & 1) * 8;
                    esv[(size_t)row * 4 + hd]     = sv[r];
                    edv_out[(size_t)row * 4 + hd] = dv[r];
                }
            }
        } else if (score_mode == 2) {
            // H=1, C=128: per-row dot spans both wn halves -> smem reduction
            float* reds = (float*)smem;          // [128][2]
            float* redd = reds + 256;
            float sv[4] = {0.f, 0.f, 0.f, 0.f}, dv[4] = {0.f, 0.f, 0.f, 0.f};
            #pragma unroll
            for (int mi = 0; mi < 2; mi++)
                #pragma unroll
                for (int ni = 0; ni < 8; ni++)
                    #pragma unroll
                    for (int j = 0; j < 2; j++) {
                        int cl = wn * 64 + ni * 8 + (lane & 3) * 2 + j;
                        float a = asv[cl], b = adv[cl];
                        sv[mi * 2]     += d[mi][ni][j]     * a;
                        dv[mi * 2]     += d[mi][ni][j]     * b;
                        sv[mi * 2 + 1] += d[mi][ni][2 + j] * a;
                        dv[mi * 2 + 1] += d[mi][ni][2 + j] * b;
                    }
            #pragma unroll
            for (int r = 0; r < 4; r++) {
                sv[r] += __shfl_xor_sync(0xffffffffu, sv[r], 1);
                sv[r] += __shfl_xor_sync(0xffffffffu, sv[r], 2);
                dv[r] += __shfl_xor_sync(0xffffffffu, dv[r], 1);
                dv[r] += __shfl_xor_sync(0xffffffffu, dv[r], 2);
            }
            __syncthreads();   // smem stage buffers dead; reuse for reduction
            if ((lane & 3) == 0) {
                #pragma unroll
                for (int r = 0; r < 4; r++) {
                    int row = wm * 32 + (r >> 1) * 16 + (lane >> 2) + (r & 1) * 8;
                    reds[row * 2 + wn] = sv[r];
                    redd[row * 2 + wn] = dv[r];
                }
            }
            __syncthreads();
            if (tid < 128) {
                esv[(size_t)(bm * 128 + tid)]     = reds[tid * 2] + reds[tid * 2 + 1];
                edv_out[(size_t)(bm * 128 + tid)] = redd[tid * 2] + redd[tid * 2 + 1];
            }
            __syncthreads();   // protect smem before next tile's cp.async
        }
    }
}

// ================= QKV fused GEMM (persistent) =================
__global__ __launch_bounds__(256, 2) void mma_gemm_qkv(
    const __nv_bfloat16* __restrict__ Ah, const __nv_bfloat16* __restrict__ Al,
    const __nv_bfloat16* __restrict__ Bh, const __nv_bfloat16* __restrict__ Bl,
    __nv_bfloat16* __restrict__ QH, __nv_bfloat16* __restrict__ QL,
    __nv_bfloat16* __restrict__ KH, __nv_bfloat16* __restrict__ KL,
    __nv_bfloat16* __restrict__ VH, __nv_bfloat16* __restrict__ VL)
{
    constexpr int K = 128;
    constexpr int nch = K >> 5;
    extern __shared__ __nv_bfloat16 smem[];
    int tid = threadIdx.x, lane = tid & 31, warp = tid >> 5;
    int wm = warp & 3, wn = warp >> 2;
    int row_c = tid >> 2, seg_c = (tid & 3) * 8;
    constexpr int ntiles = 3 * 512;

    for (int tile = blockIdx.x; tile < ntiles; tile += gridDim.x) {
        int bm = tile / 3, bn = tile - bm * 3;
        const __nv_bfloat16* gAh = Ah + (size_t)bm * 128 * K;
        const __nv_bfloat16* gAl = Al + (size_t)bm * 128 * K;
        const __nv_bfloat16* gBh = Bh + (size_t)bn * 128 * K;
        const __nv_bfloat16* gBl = Bl + (size_t)bn * 128 * K;

        auto issue = [&](int ich, int st) {
            int k0 = ich << 5;
            __nv_bfloat16* s = smem + st * G_STAGE;
            #pragma unroll
            for (int r = 0; r < 2; r++) {
                int row = row_c + r * 64;
                size_t go = (size_t)row * K + k0 + seg_c;
                int so = row * LDS_ + seg_c;
                CP16(smem_u32(s + so), gAh + go);
                CP16(smem_u32(s + G_OAL + so), gAl + go);
                CP16(smem_u32(s + G_OBH + so), gBh + go);
                CP16(smem_u32(s + G_OBL + so), gBl + go);
            }
            CP_COMMIT();
        };

        float d[2][8][4];
        #pragma unroll
        for (int mi = 0; mi < 2; mi++)
            #pragma unroll
            for (int ni = 0; ni < 8; ni++)
                #pragma unroll
                for (int j = 0; j < 4; j++) d[mi][ni][j] = 0.f;

        issue(0, 0);
        issue(1, 1);
        for (int ich = 0; ich < nch; ich++) {
            if (ich + 1 < nch) CP_WAIT1(); else CP_WAIT0();
            __syncthreads();
            const __nv_bfloat16* s = smem + (ich & 1) * G_STAGE;
            #pragma unroll
            for (int ks = 0; ks < 2; ks++) {
                uint32_t ah[2][4], al[2][4];
                #pragma unroll
                for (int mi = 0; mi < 2; mi++) {
                    int row = wm * 32 + mi * 16 + (lane & 15);
                    int col = ks * 16 + (lane >> 4) * 8;
                    LDMX4(ah[mi], smem_u32(s + row * LDS_ + col));
                    LDMX4(al[mi], smem_u32(s + G_OAL + row * LDS_ + col));
                }
                #pragma unroll
                for (int ni = 0; ni < 8; ni++) {
                    uint32_t bh[2], bl[2];
                    int row = wn * 64 + ni * 8 + (lane & 7);
                    int col = ks * 16 + ((lane >> 3) & 1) * 8;
                    LDMX2(bh, smem_u32(s + G_OBH + row * LDS_ + col));
                    LDMX2(bl, smem_u32(s + G_OBL + row * LDS_ + col));
                    #pragma unroll
                    for (int mi = 0; mi < 2; mi++) {
                        MMA16816(d[mi][ni], ah[mi], bh);
                        MMA16816(d[mi][ni], al[mi], bh);
                        MMA16816(d[mi][ni], ah[mi], bl);
                    }
                }
            }
            __syncthreads();
            if (ich + 2 < nch) issue(ich + 2, ich & 1);
        }
        __nv_bfloat16 *Oh, *Ol;
        if (bn == 0)      { Oh = QH; Ol = QL; }
        else if (bn == 1) { Oh = KH; Ol = KL; }
        else              { Oh = VH; Ol = VL; }
        #pragma unroll
        for (int mi = 0; mi < 2; mi++) {
            int row = bm * 128 + wm * 32 + mi * 16 + (lane >> 2);
            #pragma unroll
            for (int ni = 0; ni < 8; ni++) {
                int col = wn * 64 + ni * 8 + (lane & 3) * 2;
                uint32_t hh, ll;
                split2(d[mi][ni][0], d[mi][ni][1], hh, ll);
                *(uint32_t*)(Oh + (size_t)row * 128 + col) = hh;
                *(uint32_t*)(Ol + (size_t)row * 128 + col) = ll;
                split2(d[mi][ni][2], d[mi][ni][3], hh, ll);
                *(uint32_t*)(Oh + (size_t)(row + 8) * 128 + col) = hh;
                *(uint32_t*)(Ol + (size_t)(row + 8) * 128 + col) = ll;
            }
        }
    }
}

// ================= GAT aggregation — single pass, float4 vectorized ==========
template <int D, int H>
__global__ __launch_bounds__(256) void k_gat_agg(
    const float* __restrict__ hfeat, const float* __restrict__ es,
    const float* __restrict__ ed, const float* __restrict__ bias,
    const float* __restrict__ gamma, const float* __restrict__ beta,
    const float* __restrict__ resid,
    __nv_bfloat16* __restrict__ outH, __nv_bfloat16* __restrict__ outL)
{
    constexpr int C = D / H;
    constexpr int NV = D / 128;
    int warp = (blockIdx.x * blockDim.x + threadIdx.x) >> 5;
    int lane = threadIdx.x & 31;
    if (warp >= NN) return;
    int i = warp;
    int beg = g_rowptr[i], end = g_rowptr[i + 1];

    float edv[H], z[H];
    #pragma unroll
    for (int h = 0; h < H; h++) {
        edv[h] = ed[(size_t)i * H + h];
        z[h] = 0.f;
    }
    float4 acc[NV];
    #pragma unroll
    for (int j = 0; j < NV; j++) acc[j] = make_float4(0.f, 0.f, 0.f, 0.f);

    for (int e = beg; e < end; e++) {
        int s = g_col[e];
        float al[H];
        if (H == 4) {
            float4 ev = ((const float4*)es)[s];
            float vv[4] = {ev.x, ev.y, ev.z, ev.w};
            #pragma unroll
            for (int h = 0; h < 4; h++) {
                float v = vv[h] + edv[h];
                v = v > 0.f ? v : 0.2f * v;
                al[h] = expf(v);
                z[h] += al[h];
            }
        } else {
            float v = es[s] + edv[0];
            v = v > 0.f ? v : 0.2f * v;
            al[0] = expf(v);
            z[0] += al[0];
        }
        const float4* hs = (const float4*)(hfeat + (size_t)s * D);
        #pragma unroll
        for (int j = 0; j < NV; j++) {
            float4 hv = hs[lane + 32 * j];
            float a = (H == 1) ? al[0] : al[((lane + 32 * j) * 4) / C];
            acc[j].x += a * hv.x; acc[j].y += a * hv.y;
            acc[j].z += a * hv.z; acc[j].w += a * hv.w;
        }
    }
    #pragma unroll
    for (int h = 0; h < H; h++) z[h] = 1.f / (z[h] + 1e-16f);

    float4 x[NV];
    #pragma unroll
    for (int j = 0; j < NV; j++) {
        int g4 = lane + 32 * j;
        float zz = (H == 1) ? z[0] : z[(g4 * 4) / C];
        float4 b4 = ((const float4*)bias)[g4];
        x[j].x = acc[j].x * zz + b4.x;
        x[j].y = acc[j].y * zz + b4.y;
        x[j].z = acc[j].z * zz + b4.z;
        x[j].w = acc[j].w * zz + b4.w;
        if (resid) {
            float4 r4 = ((const float4*)(resid + (size_t)i * D))[g4];
            x[j].x += r4.x; x[j].y += r4.y; x[j].z += r4.z; x[j].w += r4.w;
        }
    }
    if (gamma) {
        #pragma unroll
        for (int j = 0; j < NV; j++) {
            x[j].x = x[j].x > 0.f ? x[j].x : (expf(x[j].x) - 1.f);
            x[j].y = x[j].y > 0.f ? x[j].y : (expf(x[j].y) - 1.f);
            x[j].z = x[j].z > 0.f ? x[j].z : (expf(x[j].z) - 1.f);
            x[j].w = x[j].w > 0.f ? x[j].w : (expf(x[j].w) - 1.f);
        }
        float s = 0.f;
        #pragma unroll
        for (int j = 0; j < NV; j++) s += x[j].x + x[j].y + x[j].z + x[j].w;
        #pragma unroll
        for (int o = 16; o; o >>= 1) s += __shfl_xor_sync(0xffffffffu, s, o);
        float mu = s / (float)D;
        float vs = 0.f;
        #pragma unroll
        for (int j = 0; j < NV; j++) {
            float a = x[j].x - mu, b = x[j].y - mu, c = x[j].z - mu, dd = x[j].w - mu;
            vs += a * a + b * b + c * c + dd * dd;
        }
        #pragma unroll
        for (int o = 16; o; o >>= 1) vs += __shfl_xor_sync(0xffffffffu, vs, o);
        float inv = rsqrtf(vs / (float)D + 1e-5f);
        #pragma unroll
        for (int j = 0; j < NV; j++) {
            int g4 = lane + 32 * j;
            float4 g = ((const float4*)gamma)[g4];
            float4 be = ((const float4*)beta)[g4];
            x[j].x = (x[j].x - mu) * inv * g.x + be.x;
            x[j].y = (x[j].y - mu) * inv * g.y + be.y;
            x[j].z = (x[j].z - mu) * inv * g.z + be.z;
            x[j].w = (x[j].w - mu) * inv * g.w + be.w;
        }
    }
    #pragma unroll
    for (int j = 0; j < NV; j++) {
        int g4 = lane + 32 * j;
        uint32_t h01, l01, h23, l23;
        split2(x[j].x, x[j].y, h01, l01);
        split2(x[j].z, x[j].w, h23, l23);
        *(uint2*)(outH + (size_t)i * D + g4 * 4) = make_uint2(h01, h23);
        *(uint2*)(outL + (size_t)i * D + g4 * 4) = make_uint2(l01, l23);
    }
}

// ================= fused flash attention, cp.async K/V pipeline =============
constexpr int FL_QH = 0;
constexpr int FL_QL = 128 * LDS_;
constexpr int FL_ST0 = 2 * 128 * LDS_;
constexpr int FL_KH = 0;
constexpr int FL_KL = 128 * LDS_;
constexpr int FL_VH = 2 * 128 * LDS_;
constexpr int FL_VL = 3 * 128 * LDS_;
constexpr int FL_STAGE = 4 * 128 * LDS_;
constexpr int FLASH_SMEM = (FL_ST0 + 2 * FL_STAGE) * 2;   // 102400 bytes

__global__ __launch_bounds__(256, 2) void k_flash(
    const __nv_bfloat16* __restrict__ QH, const __nv_bfloat16* __restrict__ QL,
    const __nv_bfloat16* __restrict__ KH, const __nv_bfloat16* __restrict__ KL,
    const __nv_bfloat16* __restrict__ VH, const __nv_bfloat16* __restrict__ VL,
    __nv_bfloat16* __restrict__ OHo, __nv_bfloat16* __restrict__ OLo)
{
    extern __shared__ __nv_bfloat16 sm[];
    int gh = blockIdx.y, g = gh >> 2, h = gh & 3;
    int qt = blockIdx.x;
    int tid = threadIdx.x, lane = tid & 31, warp = tid >> 5;

    int row_c = tid >> 2, seg_c = (tid & 3) * 8;

    auto issue = [&](int kt, int st) {
        __nv_bfloat16* s = sm + FL_ST0 + st * FL_STAGE;
        #pragma unroll
        for (int r = 0; r < 2; r++) {
            int row = row_c + r * 64;
            size_t go = ((size_t)g * GS + kt * 128 + row) * 128 + h * 32 + seg_c;
            int so = row * LDS_ + seg_c;
            CP16(smem_u32(s + FL_KH + so), KH + go);
            CP16(smem_u32(s + FL_KL + so), KL + go);
            CP16(smem_u32(s + FL_VH + so), VH + go);
            CP16(smem_u32(s + FL_VL + so), VL + go);
        }
        CP_COMMIT();
    };

    {
        #pragma unroll
        for (int r = 0; r < 2; r++) {
            int row = row_c + r * 64;
            size_t go = ((size_t)g * GS + qt * 128 + row) * 128 + h * 32 + seg_c;
            int so = row * LDS_ + seg_c;
            CP16(smem_u32(sm + FL_QH + so), QH + go);
            CP16(smem_u32(sm + FL_QL + so), QL + go);
        }
        __nv_bfloat16* s = sm + FL_ST0;
        #pragma unroll
        for (int r = 0; r < 2; r++) {
            int row = row_c + r * 64;
            size_t go = ((size_t)g * GS + row) * 128 + h * 32 + seg_c;
            int so = row * LDS_ + seg_c;
            CP16(smem_u32(s + FL_KH + so), KH + go);
            CP16(smem_u32(s + FL_KL + so), KL + go);
            CP16(smem_u32(s + FL_VH + so), VH + go);
            CP16(smem_u32(s + FL_VL + so), VL + go);
        }
        CP_COMMIT();
    }
    issue(1, 1);

    uint32_t qh_[2][4], ql_[2][4];
    float m0 = -1e30f, m1 = -1e30f, l0 = 0.f, l1 = 0.f;
    float O[4][4];
    #pragma unroll
    for (int n = 0; n < 4; n++)
        #pragma unroll
        for (int j = 0; j < 4; j++) O[n][j] = 0.f;

    const float scale = 0.088388347648318447f;

    for (int kt = 0; kt < 4; kt++) {
        if (kt < 3) CP_WAIT1(); else CP_WAIT0();
        __syncthreads();
        const __nv_bfloat16* s = sm + FL_ST0 + (kt & 1) * FL_STAGE;

        if (kt == 0) {
            #pragma unroll
            for (int kf = 0; kf < 2; kf++) {
                int row = warp * 16 + (lane & 15);
                int col = kf * 16 + (lane >> 4) * 8;
                LDMX4(qh_[kf], smem_u32(sm + FL_QH + row * LDS_ + col));
                LDMX4(ql_[kf], smem_u32(sm + FL_QL + row * LDS_ + col));
            }
        }

        float S[16][4];
        #pragma unroll
        for (int j = 0; j < 16; j++)
            #pragma unroll
            for (int r = 0; r < 4; r++) S[j][r] = 0.f;
        #pragma unroll
        for (int j = 0; j < 16; j++) {
            #pragma unroll
            for (int kf = 0; kf < 2; kf++) {
                uint32_t bh[2], bl[2];
                int row = j * 8 + (lane & 7);
                int col = kf * 16 + ((lane >> 3) & 1) * 8;
                LDMX2(bh, smem_u32(s + FL_KH + row * LDS_ + col));
                LDMX2(bl, smem_u32(s + FL_KL + row * LDS_ + col));
                MMA16816(S[j], qh_[kf], bh);
                MMA16816(S[j], ql_[kf], bh);
                MMA16816(S[j], qh_[kf], bl);
            }
        }
        float mx0 = -1e30f, mx1 = -1e30f;
        #pragma unroll
        for (int j = 0; j < 16; j++) {
            S[j][0] *= scale; S[j][1] *= scale; S[j][2] *= scale; S[j][3] *= scale;
            mx0 = fmaxf(mx0, fmaxf(S[j][0], S[j][1]));
            mx1 = fmaxf(mx1, fmaxf(S[j][2], S[j][3]));
        }
        #pragma unroll
        for (int o = 1; o < 4; o <<= 1) {
            mx0 = fmaxf(mx0, __shfl_xor_sync(0xffffffffu, mx0, o));
            mx1 = fmaxf(mx1, __shfl_xor_sync(0xffffffffu, mx1, o));
        }
        float nm0 = fmaxf(m0, mx0), nm1 = fmaxf(m1, mx1);
        float a0 = expf(m0 - nm0), a1 = expf(m1 - nm1);
        float rs0 = 0.f, rs1 = 0.f;
        #pragma unroll
        for (int j = 0; j < 16; j++) {
            S[j][0] = expf(S[j][0] - nm0); S[j][1] = expf(S[j][1] - nm0);
            S[j][2] = expf(S[j][2] - nm1); S[j][3] = expf(S[j][3] - nm1);
            rs0 += S[j][0] + S[j][1];
            rs1 += S[j][2] + S[j][3];
        }
        #pragma unroll
        for (int o = 1; o < 4; o <<= 1) {
            rs0 += __shfl_xor_sync(0xffffffffu, rs0, o);
            rs1 += __shfl_xor_sync(0xffffffffu, rs1, o);
        }
        l0 = l0 * a0 + rs0;
        l1 = l1 * a1 + rs1;
        #pragma unroll
        for (int n = 0; n < 4; n++) {
            O[n][0] *= a0; O[n][1] *= a0; O[n][2] *= a1; O[n][3] *= a1;
        }
        m0 = nm0; m1 = nm1;
        #pragma unroll
        for (int jp = 0; jp < 8; jp++) {
            uint32_t aph[4], apl[4];
            split2(S[2 * jp][0],     S[2 * jp][1],     aph[0], apl[0]);
            split2(S[2 * jp][2],     S[2 * jp][3],     aph[1], apl[1]);
            split2(S[2 * jp + 1][0], S[2 * jp + 1][1], aph[2], apl[2]);
            split2(S[2 * jp + 1][2], S[2 * jp + 1][3], aph[3], apl[3]);
            #pragma unroll
            for (int n = 0; n < 4; n++) {
                uint32_t bh[2], bl[2];
                int row = jp * 16 + ((lane >> 3) & 1) * 8 + (lane & 7);
                int col = n * 8;
                LDMX2T(bh, smem_u32(s + FL_VH + row * LDS_ + col));
                LDMX2T(bl, smem_u32(s + FL_VL + row * LDS_ + col));
                MMA16816(O[n], aph, bh);
                MMA16816(O[n], apl, bh);
                MMA16816(O[n], aph, bl);
            }
        }
        __syncthreads();
        if (kt + 2 < 4) issue(kt + 2, kt & 1);
    }
    float il0 = 1.f / l0, il1 = 1.f / l1;
    int node = g * GS + qt * 128 + warp * 16 + (lane >> 2);
    #pragma unroll
    for (int n = 0; n < 4; n++) {
        int col = h * 32 + n * 8 + (lane & 3) * 2;
        uint32_t hh, ll;
        split2(O[n][0] * il0, O[n][1] * il0, hh, ll);
        *(uint32_t*)(OHo + (size_t)node * 128 + col) = hh;
        *(uint32_t*)(OLo + (size_t)node * 128 + col) = ll;
        split2(O[n][2] * il1, O[n][3] * il1, hh, ll);
        *(uint32_t*)(OHo + (size_t)(node + 8) * 128 + col) = hh;
        *(uint32_t*)(OLo + (size_t)(node + 8) * 128 + col) = ll;
    }
}

// ================= host orchestration =================
extern "C" void kernel_launch(void* const* d_in, const int* in_sizes, int n_in,
                              void* d_out, int out_size)
{
    const float* x   = (const float*)d_in[0];
    const int*   ei  = (const int*)  d_in[1];
    const float* W1  = (const float*)d_in[3];
    const float* a1s = (const float*)d_in[4];
    const float* a1d = (const float*)d_in[5];
    const float* b1  = (const float*)d_in[6];
    const float* W2  = (const float*)d_in[7];
    const float* a2s = (const float*)d_in[8];
    const float* a2d = (const float*)d_in[9];
    const float* b2  = (const float*)d_in[10];
    const float* W3  = (const float*)d_in[11];
    const float* a3s = (const float*)d_in[12];
    const float* a3d = (const float*)d_in[13];
    const float* b3  = (const float*)d_in[14];
    const float* g1  = (const float*)d_in[15];
    const float* be1 = (const float*)d_in[16];
    const float* g2  = (const float*)d_in[17];
    const float* be2 = (const float*)d_in[18];
    const float* Wr  = (const float*)d_in[19];
    const float* br  = (const float*)d_in[20];
    const float* Wq  = (const float*)d_in[21];
    const float* Wk  = (const float*)d_in[22];
    const float* Wv  = (const float*)d_in[23];
    const float* Wo  = (const float*)d_in[24];
    const float* bo  = (const float*)d_in[25];
    float* out = (float*)d_out;

    float* sb = nullptr;
    cudaGetSymbolAddress((void**)&sb, g_scratch);
    __nv_bfloat16* bb = nullptr;
    cudaGetSymbolAddress((void**)&bb, g_bf);
    cudaFuncSetAttribute(k_flash, cudaFuncAttributeMaxDynamicSharedMemorySize, FLASH_SMEM);
    cudaFuncSetAttribute(mma_gemm, cudaFuncAttributeMaxDynamicSharedMemorySize, GEMM_SMEM);
    cudaFuncSetAttribute(mma_gemm_qkv, cudaFuncAttributeMaxDynamicSharedMemorySize, GEMM_SMEM);

    float* p_h  = sb + OFF_H;
    float* p_h3 = sb + OFF_H3;
    float* p_r  = sb + OFF_R;
    float* p_es = sb + OFF_ES;
    float* p_ed = sb + OFF_ED;

    // CSR
    k_zero_cnt<<<NN / 256, 256>>>();
    k_count<<<1024, 256>>>(ei);
    k_scan1<<<256, 256>>>();
    k_scan2<<<1, 256>>>();
    k_scan3<<<256, 256>>>();
    k_fill<<<1152, 256>>>(ei);

    // weight conversions
    k_cvt_wT<<<(256*64 + 255)/256, 256>>>(W1, bb + B_W1H, bb + B_W1L, 64, 256);
    k_cvt_wT<<<(256*256 + 255)/256, 256>>>(W2, bb + B_W2H, bb + B_W2L, 256, 256);
    k_cvt_wT<<<(128*256 + 255)/256, 256>>>(W3, bb + B_W3H, bb + B_W3L, 256, 128);
    k_cvt_wT<<<(128*64 + 255)/256, 256>>>(Wr, bb + B_WRH, bb + B_WRL, 64, 128);
    k_cvt_wqkv<<<(384*128 + 255)/256, 256>>>(Wq, Wk, Wv, bb + B_WQKVH, bb + B_WQKVL);
    k_cvt_wT<<<(128*128 + 255)/256, 256>>>(Wo, bb + B_WOH, bb + B_WOL, 128, 128);

    // x -> bf16 hi/lo
    k_cvt_split<<<(NN*64/4 + 255)/256, 256>>>(x, bb + B_XH, bb + B_XL, NN*64/4);

    // layer 1 (fused H=4 scores)
    mma_gemm<<<PERS, 256, GEMM_SMEM>>>(bb + B_XH, bb + B_XL, bb + B_W1H, bb + B_W1L,
                                    nullptr, p_h, nullptr, nullptr,
                                    a1s, a1d, p_es, p_ed, 1, NN, 256, 64);
    k_gat_agg<256, 4><<<NN / 8, 256>>>(p_h, p_es, p_ed, b1, g1, be1, nullptr,
                                       bb + B_TH, bb + B_TL);
    // layer 2 (fused H=4 scores)
    mma_gemm<<<PERS, 256, GEMM_SMEM>>>(bb + B_TH, bb + B_TL, bb + B_W2H, bb + B_W2L,
                                    nullptr, p_h, nullptr, nullptr,
                                    a2s, a2d, p_es, p_ed, 1, NN, 256, 256);
    k_gat_agg<256, 4><<<NN / 8, 256>>>(p_h, p_es, p_ed, b2, g2, be2, nullptr,
                                       bb + B_TH, bb + B_TL);
    // layer 3 (fused H=1 scores) + residual
    mma_gemm<<<PERS, 256, GEMM_SMEM>>>(bb + B_TH, bb + B_TL, bb + B_W3H, bb + B_W3L,
                                    nullptr, p_h3, nullptr, nullptr,
                                    a3s, a3d, p_es, p_ed, 2, NN, 128, 256);
    mma_gemm<<<PERS, 256, GEMM_SMEM>>>(bb + B_XH, bb + B_XL, bb + B_WRH, bb + B_WRL,
                                    br, p_r, nullptr, nullptr,
                                    nullptr, nullptr, nullptr, nullptr, 0, NN, 128, 64);
    k_gat_agg<128, 1><<<NN / 8, 256>>>(p_h3, p_es, p_ed, b3, nullptr, nullptr, p_r,
                                       bb + B_HRH, bb + B_HRL);
    // fused QKV projection
    mma_gemm_qkv<<<PERS, 256, GEMM_SMEM>>>(bb + B_HRH, bb + B_HRL,
                                        bb + B_WQKVH, bb + B_WQKVL,
                                        bb + B_QH, bb + B_QL,
                                        bb + B_KH, bb + B_KL,
                                        bb + B_VH, bb + B_VL);
    // fused attention
    k_flash<<<dim3(4, NG * 4), 256, FLASH_SMEM>>>(
        bb + B_QH, bb + B_QL, bb + B_KH, bb + B_KL,
        bb + B_VH, bb + B_VL, bb + B_AOH, bb + B_AOL);
    // output projection
    mma_gemm<<<PERS, 256, GEMM_SMEM>>>(bb + B_AOH, bb + B_AOL, bb + B_WOH, bb + B_WOL,
                                    bo, out, nullptr, nullptr,
                                    nullptr, nullptr, nullptr, nullptr, 0, NN, 128, 128);
}

// round 11
// speedup vs baseline: 2.2938x; 1.0417x over previous
#include <cuda_runtime.h>
#include <cuda_bf16.h>
#include <math.h>
#include <stdint.h>

// ---------------- problem constants ----------------
constexpr int NN   = 65536;
constexpr int NE   = 524288;
constexpr int ET   = NE + NN;
constexpr int GS   = 512;
constexpr int NG   = NN / GS;
constexpr int D1   = 256;
constexpr int D3   = 128;
constexpr int PERS = 296;   // 148 SMs x 2 CTAs

// ---------------- fp32 scratch ----------------
constexpr size_t OFF_H    = 0;
constexpr size_t OFF_H3   = OFF_H  + (size_t)NN*D1;
constexpr size_t OFF_R    = OFF_H3 + (size_t)NN*D3;
constexpr size_t OFF_ES   = OFF_R  + (size_t)NN*D3;
constexpr size_t OFF_ED   = OFF_ES + (size_t)NN*4;
constexpr size_t SCRATCH  = OFF_ED + (size_t)NN*4;

__device__ __align__(256) float g_scratch[SCRATCH];

// ---------------- bf16 scratch ----------------
constexpr size_t B_XH  = 0;
constexpr size_t B_XL  = B_XH  + (size_t)NN*64;
constexpr size_t B_TH  = B_XL  + (size_t)NN*64;
constexpr size_t B_TL  = B_TH  + (size_t)NN*256;
constexpr size_t B_HRH = B_TL  + (size_t)NN*256;
constexpr size_t B_HRL = B_HRH + (size_t)NN*128;
constexpr size_t B_AOH = B_HRL + (size_t)NN*128;
constexpr size_t B_AOL = B_AOH + (size_t)NN*128;
constexpr size_t B_QH  = B_AOL + (size_t)NN*128;
constexpr size_t B_QL  = B_QH  + (size_t)NN*128;
constexpr size_t B_KH  = B_QL  + (size_t)NN*128;
constexpr size_t B_KL  = B_KH  + (size_t)NN*128;
constexpr size_t B_VH  = B_KL  + (size_t)NN*128;
constexpr size_t B_VL  = B_VH  + (size_t)NN*128;
constexpr size_t B_W1RH = B_VL  + (size_t)NN*128;   // concat [W1;Wr]^T: 384x64
constexpr size_t B_W1RL = B_W1RH + 384*64;
constexpr size_t B_W2H = B_W1RL + 384*64;
constexpr size_t B_W2L = B_W2H + 256*256;
constexpr size_t B_W3H = B_W2L + 256*256;
constexpr size_t B_W3L = B_W3H + 128*256;
constexpr size_t B_WQKVH = B_W3L + 128*256;
constexpr size_t B_WQKVL = B_WQKVH + 384*128;
constexpr size_t B_WOH = B_WQKVL + 384*128;
constexpr size_t B_WOL = B_WOH + 128*128;
constexpr size_t BF_TOTAL = B_WOL + 128*128;

__device__ __align__(256) __nv_bfloat16 g_bf[BF_TOTAL];

__device__ int g_rowptr[NN + 1];
__device__ int g_cnt[NN];
__device__ int g_cursor[NN];
__device__ int g_col[ET];
__device__ int g_blocksum[256];

// ================= helpers =================
__device__ __forceinline__ uint32_t smem_u32(const void* p) {
    uint32_t a;
    asm("{ .reg .u64 t; cvta.to.shared.u64 t, %1; cvt.u32.u64 %0, t; }" : "=r"(a) : "l"(p));
    return a;
}
#define LDMX4(r, a) \
    asm volatile("ldmatrix.sync.aligned.m8n8.x4.shared.b16 {%0,%1,%2,%3}, [%4];" \
        : "=r"((r)[0]), "=r"((r)[1]), "=r"((r)[2]), "=r"((r)[3]) : "r"(a))
#define LDMX4T(r, a) \
    asm volatile("ldmatrix.sync.aligned.m8n8.x4.trans.shared.b16 {%0,%1,%2,%3}, [%4];" \
        : "=r"((r)[0]), "=r"((r)[1]), "=r"((r)[2]), "=r"((r)[3]) : "r"(a))
#define MMA16816(d, a, b) \
    asm volatile("mma.sync.aligned.m16n8k16.row.col.f32.bf16.bf16.f32 " \
        "{%0,%1,%2,%3}, {%4,%5,%6,%7}, {%8,%9}, {%0,%1,%2,%3};" \
        : "+f"((d)[0]), "+f"((d)[1]), "+f"((d)[2]), "+f"((d)[3]) \
        : "r"((a)[0]), "r"((a)[1]), "r"((a)[2]), "r"((a)[3]), \
          "r"((b)[0]), "r"((b)[1]))
#define CP16(dst, src) \
    asm volatile("cp.async.cg.shared.global [%0], [%1], 16;" :: "r"(dst), "l"(src))
#define CP_COMMIT() asm volatile("cp.async.commit_group;" ::: "memory")
#define CP_WAIT1()  asm volatile("cp.async.wait_group 1;" ::: "memory")
#define CP_WAIT0()  asm volatile("cp.async.wait_group 0;" ::: "memory")

__device__ __forceinline__ void split2(float v0, float v1, uint32_t& hh, uint32_t& ll) {
    __nv_bfloat16 h0 = __float2bfloat16(v0), h1 = __float2bfloat16(v1);
    __nv_bfloat16 l0 = __float2bfloat16(v0 - __bfloat162float(h0));
    __nv_bfloat16 l1 = __float2bfloat16(v1 - __bfloat162float(h1));
    __nv_bfloat162 H; H.x = h0; H.y = h1;
    __nv_bfloat162 L; L.x = l0; L.y = l1;
    hh = *(uint32_t*)&H; ll = *(uint32_t*)&L;
}

// ================= CSR build (parallel scan) =================
__global__ void k_zero_cnt() {
    int i = blockIdx.x * blockDim.x + threadIdx.x;
    if (i < NN) g_cnt[i] = 0;
}
__global__ void k_count(const int* __restrict__ ei) {
    int stride = gridDim.x * blockDim.x;
    for (int idx = blockIdx.x * blockDim.x + threadIdx.x; idx < NE; idx += stride)
        atomicAdd(&g_cnt[ei[NE + idx]], 1);
}
__global__ void k_scan1() {
    __shared__ int ws[8];
    int b = blockIdx.x, tid = threadIdx.x, lane = tid & 31, wid = tid >> 5;
    int v = g_cnt[b * 256 + tid] + 1;
    int x = v;
    #pragma unroll
    for (int o = 1; o < 32; o <<= 1) {
        int t = __shfl_up_sync(0xffffffffu, x, o);
        if (lane >= o) x += t;
    }
    if (lane == 31) ws[wid] = x;
    __syncthreads();
    if (tid == 0) {
        int run = 0;
        #pragma unroll
        for (int k = 0; k < 8; k++) { int t = ws[k]; ws[k] = run; run += t; }
        g_blocksum[b] = run;
    }
    __syncthreads();
    g_rowptr[b * 256 + tid] = x - v + ws[wid];
}
__global__ void k_scan2() {
    __shared__ int ws[8];
    int tid = threadIdx.x, lane = tid & 31, wid = tid >> 5;
    int v = g_blocksum[tid];
    int x = v;
    #pragma unroll
    for (int o = 1; o < 32; o <<= 1) {
        int t = __shfl_up_sync(0xffffffffu, x, o);
        if (lane >= o) x += t;
    }
    if (lane == 31) ws[wid] = x;
    __syncthreads();
    if (tid == 0) {
        int run = 0;
        #pragma unroll
        for (int k = 0; k < 8; k++) { int t = ws[k]; ws[k] = run; run += t; }
    }
    __syncthreads();
    g_blocksum[tid] = x - v + ws[wid];
}
__global__ void k_scan3() {
    int idx = blockIdx.x * 256 + threadIdx.x;
    int v = g_rowptr[idx] + g_blocksum[blockIdx.x];
    g_rowptr[idx] = v;
    g_cursor[idx] = v;
    if (idx == 0) g_rowptr[NN] = ET;
}
__global__ void k_fill(const int* __restrict__ ei) {
    int stride = gridDim.x * blockDim.x;
    for (int idx = blockIdx.x * blockDim.x + threadIdx.x; idx < ET; idx += stride) {
        int s, d;
        if (idx < NE) { s = ei[idx]; d = ei[NE + idx]; }
        else          { s = d = idx - NE; }
        int pos = atomicAdd(&g_cursor[d], 1);
        g_col[pos] = s;
    }
}

// ================= conversions =================
__global__ void k_cvt_split(const float* __restrict__ in, __nv_bfloat16* __restrict__ hi,
                            __nv_bfloat16* __restrict__ lo, int n4) {
    int i = blockIdx.x * blockDim.x + threadIdx.x;
    if (i >= n4) return;
    float4 v = ((const float4*)in)[i];
    uint32_t h01, l01, h23, l23;
    split2(v.x, v.y, h01, l01);
    split2(v.z, v.w, h23, l23);
    ((uint32_t*)hi)[2 * i] = h01; ((uint32_t*)hi)[2 * i + 1] = h23;
    ((uint32_t*)lo)[2 * i] = l01; ((uint32_t*)lo)[2 * i + 1] = l23;
}

__global__ void k_cvt_wT(const float* __restrict__ W, __nv_bfloat16* __restrict__ hiT,
                         __nv_bfloat16* __restrict__ loT, int K, int N) {
    int idx = blockIdx.x * blockDim.x + threadIdx.x;
    if (idx >= N * K) return;
    int n = idx / K, k = idx % K;
    float v = W[(size_t)k * N + n];
    __nv_bfloat16 h = __float2bfloat16(v);
    hiT[idx] = h;
    loT[idx] = __float2bfloat16(v - __bfloat162float(h));
}

// concat W1 [64,256] and Wr [64,128] -> WT hi/lo [384,64]
__global__ void k_cvt_w1r(const float* __restrict__ W1, const float* __restrict__ Wr,
                          __nv_bfloat16* __restrict__ hiT, __nv_bfloat16* __restrict__ loT) {
    int idx = blockIdx.x * blockDim.x + threadIdx.x;
    if (idx >= 384 * 64) return;
    int n = idx / 64, k = idx % 64;
    float v = (n < 256) ? W1[(size_t)k * 256 + n] : Wr[(size_t)k * 128 + (n - 256)];
    __nv_bfloat16 h = __float2bfloat16(v);
    hiT[idx] = h;
    loT[idx] = __float2bfloat16(v - __bfloat162float(h));
}

__global__ void k_cvt_wqkv(const float* __restrict__ Wq, const float* __restrict__ Wk,
                           const float* __restrict__ Wv,
                           __nv_bfloat16* __restrict__ hiT, __nv_bfloat16* __restrict__ loT) {
    int idx = blockIdx.x * blockDim.x + threadIdx.x;
    if (idx >= 384 * 128) return;
    int n = idx / 128, k = idx % 128;
    const float* W = (n < 128) ? Wq : ((n < 256) ? Wk : Wv);
    float v = W[(size_t)k * 128 + (n & 127)];
    __nv_bfloat16 h = __float2bfloat16(v);
    hiT[idx] = h;
    loT[idx] = __float2bfloat16(v - __bfloat162float(h));
}

// ================= mma.sync bf16-split GEMM, persistent tiles ================
// score_mode: 0 none; 1 fused H=4 scores; 2 fused H=1 scores; 3 layer-1 combo
//   mode 3: N=384 (bn 0,1 -> C stride 256 + H=4 scores; bn 2 -> C2 stride 128 + bias2)
constexpr int LDS_ = 40;
constexpr int G_OAL = 128 * LDS_;
constexpr int G_OBH = 2 * 128 * LDS_;
constexpr int G_OBL = 3 * 128 * LDS_;
constexpr int G_STAGE = 4 * 128 * LDS_;
constexpr int GEMM_SMEM = 2 * G_STAGE * 2;

__global__ __launch_bounds__(256, 2) void mma_gemm(
    const __nv_bfloat16* __restrict__ Ah, const __nv_bfloat16* __restrict__ Al,
    const __nv_bfloat16* __restrict__ Bh, const __nv_bfloat16* __restrict__ Bl,
    const float* __restrict__ bias, float* __restrict__ C,
    __nv_bfloat16* __restrict__ Chi, __nv_bfloat16* __restrict__ Clo,
    float* __restrict__ C2, const float* __restrict__ bias2,
    const float* __restrict__ asv, const float* __restrict__ adv,
    float* __restrict__ esv, float* __restrict__ edv_out,
    int score_mode, int M, int N, int K)
{
    extern __shared__ __nv_bfloat16 smem[];
    int tid = threadIdx.x, lane = tid & 31, warp = tid >> 5;
    int wm = warp & 3, wn = warp >> 2;
    int nbn = N >> 7;
    int ntiles = (M >> 7) * nbn;
    int row_c = tid >> 2, seg_c = (tid & 3) * 8;
    int nch = K >> 5;

    for (int tile = blockIdx.x; tile < ntiles; tile += gridDim.x) {
        int bm = tile / nbn, bn = tile - bm * nbn;
        const __nv_bfloat16* gAh = Ah + (size_t)bm * 128 * K;
        const __nv_bfloat16* gAl = Al + (size_t)bm * 128 * K;
        const __nv_bfloat16* gBh = Bh + (size_t)bn * 128 * K;
        const __nv_bfloat16* gBl = Bl + (size_t)bn * 128 * K;

        auto issue = [&](int ich, int st) {
            int k0 = ich << 5;
            __nv_bfloat16* s = smem + st * G_STAGE;
            #pragma unroll
            for (int r = 0; r < 2; r++) {
                int row = row_c + r * 64;
                size_t go = (size_t)row * K + k0 + seg_c;
                int so = row * LDS_ + seg_c;
                CP16(smem_u32(s + so), gAh + go);
                CP16(smem_u32(s + G_OAL + so), gAl + go);
                CP16(smem_u32(s + G_OBH + so), gBh + go);
                CP16(smem_u32(s + G_OBL + so), gBl + go);
            }
            CP_COMMIT();
        };

        float d[2][8][4];
        #pragma unroll
        for (int mi = 0; mi < 2; mi++)
            #pragma unroll
            for (int ni = 0; ni < 8; ni++)
                #pragma unroll
                for (int j = 0; j < 4; j++) d[mi][ni][j] = 0.f;

        issue(0, 0);
        if (nch > 1) issue(1, 1);

        for (int ich = 0; ich < nch; ich++) {
            if (ich + 1 < nch) CP_WAIT1(); else CP_WAIT0();
            __syncthreads();
            const __nv_bfloat16* s = smem + (ich & 1) * G_STAGE;
            #pragma unroll
            for (int ks = 0; ks < 2; ks++) {
                uint32_t ah[2][4], al[2][4];
                #pragma unroll
                for (int mi = 0; mi < 2; mi++) {
                    int row = wm * 32 + mi * 16 + (lane & 15);
                    int col = ks * 16 + (lane >> 4) * 8;
                    LDMX4(ah[mi], smem_u32(s + row * LDS_ + col));
                    LDMX4(al[mi], smem_u32(s + G_OAL + row * LDS_ + col));
                }
                // B fragments via x4: pair p covers ni = 2p, 2p+1
                int brow = wn * 64 + ((lane >> 4) & 1) * 8 + (lane & 7);
                int bcol = ks * 16 + ((lane >> 3) & 1) * 8;
                #pragma unroll
                for (int p = 0; p < 4; p++) {
                    uint32_t bh4[4], bl4[4];
                    int off = (brow + p * 16) * LDS_ + bcol;
                    LDMX4(bh4, smem_u32(s + G_OBH + off));
                    LDMX4(bl4, smem_u32(s + G_OBL + off));
                    #pragma unroll
                    for (int mi = 0; mi < 2; mi++) {
                        MMA16816(d[mi][2 * p],     ah[mi], bh4);
                        MMA16816(d[mi][2 * p],     al[mi], bh4);
                        MMA16816(d[mi][2 * p],     ah[mi], bl4);
                        MMA16816(d[mi][2 * p + 1], ah[mi], bh4 + 2);
                        MMA16816(d[mi][2 * p + 1], al[mi], bh4 + 2);
                        MMA16816(d[mi][2 * p + 1], ah[mi], bl4 + 2);
                    }
                }
            }
            __syncthreads();
            if (ich + 2 < nch) issue(ich + 2, ich & 1);
        }

        // epilogue
        if (score_mode == 3 && bn == 2) {
            // residual output: stride 128, bias2
            #pragma unroll
            for (int mi = 0; mi < 2; mi++) {
                int row = bm * 128 + wm * 32 + mi * 16 + (lane >> 2);
                #pragma unroll
                for (int ni = 0; ni < 8; ni++) {
                    int col = wn * 64 + ni * 8 + (lane & 3) * 2;
                    float b0 = bias2[col], b1 = bias2[col + 1];
                    *(float2*)(C2 + (size_t)row * 128 + col) =
                        make_float2(d[mi][ni][0] + b0, d[mi][ni][1] + b1);
                    *(float2*)(C2 + (size_t)(row + 8) * 128 + col) =
                        make_float2(d[mi][ni][2] + b0, d[mi][ni][3] + b1);
                }
            }
        } else {
            int outN = (score_mode == 3) ? 256 : N;
            #pragma unroll
            for (int mi = 0; mi < 2; mi++) {
                int row = bm * 128 + wm * 32 + mi * 16 + (lane >> 2);
                #pragma unroll
                for (int ni = 0; ni < 8; ni++) {
                    int col = bn * 128 + wn * 64 + ni * 8 + (lane & 3) * 2;
                    if (C) {
                        float b0 = bias ? bias[col] : 0.f;
                        float b1 = bias ? bias[col + 1] : 0.f;
                        *(float2*)(C + (size_t)row * outN + col) =
                            make_float2(d[mi][ni][0] + b0, d[mi][ni][1] + b1);
                        *(float2*)(C + (size_t)(row + 8) * outN + col) =
                            make_float2(d[mi][ni][2] + b0, d[mi][ni][3] + b1);
                    } else {
                        uint32_t hh, ll;
                        split2(d[mi][ni][0], d[mi][ni][1], hh, ll);
                        *(uint32_t*)(Chi + (size_t)row * outN + col) = hh;
                        *(uint32_t*)(Clo + (size_t)row * outN + col) = ll;
                        split2(d[mi][ni][2], d[mi][ni][3], hh, ll);
                        *(uint32_t*)(Chi + (size_t)(row + 8) * outN + col) = hh;
                        *(uint32_t*)(Clo + (size_t)(row + 8) * outN + col) = ll;
                    }
                }
            }
        }
        if (score_mode == 1 || (score_mode == 3 && bn < 2)) {
            int hd = bn * 2 + wn;
            float sv[4] = {0.f, 0.f, 0.f, 0.f}, dv[4] = {0.f, 0.f, 0.f, 0.f};
            #pragma unroll
            for (int mi = 0; mi < 2; mi++)
                #pragma unroll
                for (int ni = 0; ni < 8; ni++)
                    #pragma unroll
                    for (int j = 0; j < 2; j++) {
                        int cl = ni * 8 + (lane & 3) * 2 + j;
                        float a = asv[hd * 64 + cl], b = adv[hd * 64 + cl];
                        sv[mi * 2]     += d[mi][ni][j]     * a;
                        dv[mi * 2]     += d[mi][ni][j]     * b;
                        sv[mi * 2 + 1] += d[mi][ni][2 + j] * a;
                        dv[mi * 2 + 1] += d[mi][ni][2 + j] * b;
                    }
            #pragma unroll
            for (int r = 0; r < 4; r++) {
                sv[r] += __shfl_xor_sync(0xffffffffu, sv[r], 1);
                sv[r] += __shfl_xor_sync(0xffffffffu, sv[r], 2);
                dv[r] += __shfl_xor_sync(0xffffffffu, dv[r], 1);
                dv[r] += __shfl_xor_sync(0xffffffffu, dv[r], 2);
            }
            if ((lane & 3) == 0) {
                #pragma unroll
                for (int r = 0; r < 4; r++) {
                    int row = bm * 128 + wm * 32 + (r >> 1) * 16 + (lane >> 2) + (r & 1) * 8;
                    esv[(size_t)row * 4 + hd]     = sv[r];
                    edv_out[(size_t)row * 4 + hd] = dv[r];
                }
            }
        } else if (score_mode == 2) {
            float* reds = (float*)smem;
            float* redd = reds + 256;
            float sv[4] = {0.f, 0.f, 0.f, 0.f}, dv[4] = {0.f, 0.f, 0.f, 0.f};
            #pragma unroll
            for (int mi = 0; mi < 2; mi++)
                #pragma unroll
                for (int ni = 0; ni < 8; ni++)
                    #pragma unroll
                    for (int j = 0; j < 2; j++) {
                        int cl = wn * 64 + ni * 8 + (lane & 3) * 2 + j;
                        float a = asv[cl], b = adv[cl];
                        sv[mi * 2]     += d[mi][ni][j]     * a;
                        dv[mi * 2]     += d[mi][ni][j]     * b;
                        sv[mi * 2 + 1] += d[mi][ni][2 + j] * a;
                        dv[mi * 2 + 1] += d[mi][ni][2 + j] * b;
                    }
            #pragma unroll
            for (int r = 0; r < 4; r++) {
                sv[r] += __shfl_xor_sync(0xffffffffu, sv[r], 1);
                sv[r] += __shfl_xor_sync(0xffffffffu, sv[r], 2);
                dv[r] += __shfl_xor_sync(0xffffffffu, dv[r], 1);
                dv[r] += __shfl_xor_sync(0xffffffffu, dv[r], 2);
            }
            __syncthreads();
            if ((lane & 3) == 0) {
                #pragma unroll
                for (int r = 0; r < 4; r++) {
                    int row = wm * 32 + (r >> 1) * 16 + (lane >> 2) + (r & 1) * 8;
                    reds[row * 2 + wn] = sv[r];
                    redd[row * 2 + wn] = dv[r];
                }
            }
            __syncthreads();
            if (tid < 128) {
                esv[(size_t)(bm * 128 + tid)]     = reds[tid * 2] + reds[tid * 2 + 1];
                edv_out[(size_t)(bm * 128 + tid)] = redd[tid * 2] + redd[tid * 2 + 1];
            }
            __syncthreads();
        }
    }
}

// ================= QKV fused GEMM (persistent) =================
__global__ __launch_bounds__(256, 2) void mma_gemm_qkv(
    const __nv_bfloat16* __restrict__ Ah, const __nv_bfloat16* __restrict__ Al,
    const __nv_bfloat16* __restrict__ Bh, const __nv_bfloat16* __restrict__ Bl,
    __nv_bfloat16* __restrict__ QH, __nv_bfloat16* __restrict__ QL,
    __nv_bfloat16* __restrict__ KH, __nv_bfloat16* __restrict__ KL,
    __nv_bfloat16* __restrict__ VH, __nv_bfloat16* __restrict__ VL)
{
    constexpr int K = 128;
    constexpr int nch = K >> 5;
    extern __shared__ __nv_bfloat16 smem[];
    int tid = threadIdx.x, lane = tid & 31, warp = tid >> 5;
    int wm = warp & 3, wn = warp >> 2;
    int row_c = tid >> 2, seg_c = (tid & 3) * 8;
    constexpr int ntiles = 3 * 512;

    for (int tile = blockIdx.x; tile < ntiles; tile += gridDim.x) {
        int bm = tile / 3, bn = tile - bm * 3;
        const __nv_bfloat16* gAh = Ah + (size_t)bm * 128 * K;
        const __nv_bfloat16* gAl = Al + (size_t)bm * 128 * K;
        const __nv_bfloat16* gBh = Bh + (size_t)bn * 128 * K;
        const __nv_bfloat16* gBl = Bl + (size_t)bn * 128 * K;

        auto issue = [&](int ich, int st) {
            int k0 = ich << 5;
            __nv_bfloat16* s = smem + st * G_STAGE;
            #pragma unroll
            for (int r = 0; r < 2; r++) {
                int row = row_c + r * 64;
                size_t go = (size_t)row * K + k0 + seg_c;
                int so = row * LDS_ + seg_c;
                CP16(smem_u32(s + so), gAh + go);
                CP16(smem_u32(s + G_OAL + so), gAl + go);
                CP16(smem_u32(s + G_OBH + so), gBh + go);
                CP16(smem_u32(s + G_OBL + so), gBl + go);
            }
            CP_COMMIT();
        };

        float d[2][8][4];
        #pragma unroll
        for (int mi = 0; mi < 2; mi++)
            #pragma unroll
            for (int ni = 0; ni < 8; ni++)
                #pragma unroll
                for (int j = 0; j < 4; j++) d[mi][ni][j] = 0.f;

        issue(0, 0);
        issue(1, 1);
        for (int ich = 0; ich < nch; ich++) {
            if (ich + 1 < nch) CP_WAIT1(); else CP_WAIT0();
            __syncthreads();
            const __nv_bfloat16* s = smem + (ich & 1) * G_STAGE;
            #pragma unroll
            for (int ks = 0; ks < 2; ks++) {
                uint32_t ah[2][4], al[2][4];
                #pragma unroll
                for (int mi = 0; mi < 2; mi++) {
                    int row = wm * 32 + mi * 16 + (lane & 15);
                    int col = ks * 16 + (lane >> 4) * 8;
                    LDMX4(ah[mi], smem_u32(s + row * LDS_ + col));
                    LDMX4(al[mi], smem_u32(s + G_OAL + row * LDS_ + col));
                }
                int brow = wn * 64 + ((lane >> 4) & 1) * 8 + (lane & 7);
                int bcol = ks * 16 + ((lane >> 3) & 1) * 8;
                #pragma unroll
                for (int p = 0; p < 4; p++) {
                    uint32_t bh4[4], bl4[4];
                    int off = (brow + p * 16) * LDS_ + bcol;
                    LDMX4(bh4, smem_u32(s + G_OBH + off));
                    LDMX4(bl4, smem_u32(s + G_OBL + off));
                    #pragma unroll
                    for (int mi = 0; mi < 2; mi++) {
                        MMA16816(d[mi][2 * p],     ah[mi], bh4);
                        MMA16816(d[mi][2 * p],     al[mi], bh4);
                        MMA16816(d[mi][2 * p],     ah[mi], bl4);
                        MMA16816(d[mi][2 * p + 1], ah[mi], bh4 + 2);
                        MMA16816(d[mi][2 * p + 1], al[mi], bh4 + 2);
                        MMA16816(d[mi][2 * p + 1], ah[mi], bl4 + 2);
                    }
                }
            }
            __syncthreads();
            if (ich + 2 < nch) issue(ich + 2, ich & 1);
        }
        __nv_bfloat16 *Oh, *Ol;
        if (bn == 0)      { Oh = QH; Ol = QL; }
        else if (bn == 1) { Oh = KH; Ol = KL; }
        else              { Oh = VH; Ol = VL; }
        #pragma unroll
        for (int mi = 0; mi < 2; mi++) {
            int row = bm * 128 + wm * 32 + mi * 16 + (lane >> 2);
            #pragma unroll
            for (int ni = 0; ni < 8; ni++) {
                int col = wn * 64 + ni * 8 + (lane & 3) * 2;
                uint32_t hh, ll;
                split2(d[mi][ni][0], d[mi][ni][1], hh, ll);
                *(uint32_t*)(Oh + (size_t)row * 128 + col) = hh;
                *(uint32_t*)(Ol + (size_t)row * 128 + col) = ll;
                split2(d[mi][ni][2], d[mi][ni][3], hh, ll);
                *(uint32_t*)(Oh + (size_t)(row + 8) * 128 + col) = hh;
                *(uint32_t*)(Ol + (size_t)(row + 8) * 128 + col) = ll;
            }
        }
    }
}

// ================= GAT aggregation — single pass, float4 vectorized ==========
template <int D, int H>
__global__ __launch_bounds__(256) void k_gat_agg(
    const float* __restrict__ hfeat, const float* __restrict__ es,
    const float* __restrict__ ed, const float* __restrict__ bias,
    const float* __restrict__ gamma, const float* __restrict__ beta,
    const float* __restrict__ resid,
    __nv_bfloat16* __restrict__ outH, __nv_bfloat16* __restrict__ outL)
{
    constexpr int C = D / H;
    constexpr int NV = D / 128;
    int warp = (blockIdx.x * blockDim.x + threadIdx.x) >> 5;
    int lane = threadIdx.x & 31;
    if (warp >= NN) return;
    int i = warp;
    int beg = g_rowptr[i], end = g_rowptr[i + 1];

    float edv[H], z[H];
    #pragma unroll
    for (int h = 0; h < H; h++) {
        edv[h] = ed[(size_t)i * H + h];
        z[h] = 0.f;
    }
    float4 acc[NV];
    #pragma unroll
    for (int j = 0; j < NV; j++) acc[j] = make_float4(0.f, 0.f, 0.f, 0.f);

    for (int e = beg; e < end; e++) {
        int s = g_col[e];
        float al[H];
        if (H == 4) {
            float4 ev = ((const float4*)es)[s];
            float vv[4] = {ev.x, ev.y, ev.z, ev.w};
            #pragma unroll
            for (int h = 0; h < 4; h++) {
                float v = vv[h] + edv[h];
                v = v > 0.f ? v : 0.2f * v;
                al[h] = expf(v);
                z[h] += al[h];
            }
        } else {
            float v = es[s] + edv[0];
            v = v > 0.f ? v : 0.2f * v;
            al[0] = expf(v);
            z[0] += al[0];
        }
        const float4* hs = (const float4*)(hfeat + (size_t)s * D);
        #pragma unroll
        for (int j = 0; j < NV; j++) {
            float4 hv = hs[lane + 32 * j];
            float a = (H == 1) ? al[0] : al[((lane + 32 * j) * 4) / C];
            acc[j].x += a * hv.x; acc[j].y += a * hv.y;
            acc[j].z += a * hv.z; acc[j].w += a * hv.w;
        }
    }
    #pragma unroll
    for (int h = 0; h < H; h++) z[h] = 1.f / (z[h] + 1e-16f);

    float4 x[NV];
    #pragma unroll
    for (int j = 0; j < NV; j++) {
        int g4 = lane + 32 * j;
        float zz = (H == 1) ? z[0] : z[(g4 * 4) / C];
        float4 b4 = ((const float4*)bias)[g4];
        x[j].x = acc[j].x * zz + b4.x;
        x[j].y = acc[j].y * zz + b4.y;
        x[j].z = acc[j].z * zz + b4.z;
        x[j].w = acc[j].w * zz + b4.w;
        if (resid) {
            float4 r4 = ((const float4*)(resid + (size_t)i * D))[g4];
            x[j].x += r4.x; x[j].y += r4.y; x[j].z += r4.z; x[j].w += r4.w;
        }
    }
    if (gamma) {
        #pragma unroll
        for (int j = 0; j < NV; j++) {
            x[j].x = x[j].x > 0.f ? x[j].x : (expf(x[j].x) - 1.f);
            x[j].y = x[j].y > 0.f ? x[j].y : (expf(x[j].y) - 1.f);
            x[j].z = x[j].z > 0.f ? x[j].z : (expf(x[j].z) - 1.f);
            x[j].w = x[j].w > 0.f ? x[j].w : (expf(x[j].w) - 1.f);
        }
        float s = 0.f;
        #pragma unroll
        for (int j = 0; j < NV; j++) s += x[j].x + x[j].y + x[j].z + x[j].w;
        #pragma unroll
        for (int o = 16; o; o >>= 1) s += __shfl_xor_sync(0xffffffffu, s, o);
        float mu = s / (float)D;
        float vs = 0.f;
        #pragma unroll
        for (int j = 0; j < NV; j++) {
            float a = x[j].x - mu, b = x[j].y - mu, c = x[j].z - mu, dd = x[j].w - mu;
            vs += a * a + b * b + c * c + dd * dd;
        }
        #pragma unroll
        for (int o = 16; o; o >>= 1) vs += __shfl_xor_sync(0xffffffffu, vs, o);
        float inv = rsqrtf(vs / (float)D + 1e-5f);
        #pragma unroll
        for (int j = 0; j < NV; j++) {
            int g4 = lane + 32 * j;
            float4 g = ((const float4*)gamma)[g4];
            float4 be = ((const float4*)beta)[g4];
            x[j].x = (x[j].x - mu) * inv * g.x + be.x;
            x[j].y = (x[j].y - mu) * inv * g.y + be.y;
            x[j].z = (x[j].z - mu) * inv * g.z + be.z;
            x[j].w = (x[j].w - mu) * inv * g.w + be.w;
        }
    }
    #pragma unroll
    for (int j = 0; j < NV; j++) {
        int g4 = lane + 32 * j;
        uint32_t h01, l01, h23, l23;
        split2(x[j].x, x[j].y, h01, l01);
        split2(x[j].z, x[j].w, h23, l23);
        *(uint2*)(outH + (size_t)i * D + g4 * 4) = make_uint2(h01, h23);
        *(uint2*)(outL + (size_t)i * D + g4 * 4) = make_uint2(l01, l23);
    }
}

// ================= fused flash attention, cp.async K/V pipeline =============
constexpr int FL_QH = 0;
constexpr int FL_QL = 128 * LDS_;
constexpr int FL_ST0 = 2 * 128 * LDS_;
constexpr int FL_KH = 0;
constexpr int FL_KL = 128 * LDS_;
constexpr int FL_VH = 2 * 128 * LDS_;
constexpr int FL_VL = 3 * 128 * LDS_;
constexpr int FL_STAGE = 4 * 128 * LDS_;
constexpr int FLASH_SMEM = (FL_ST0 + 2 * FL_STAGE) * 2;   // 102400 bytes

__global__ __launch_bounds__(256, 2) void k_flash(
    const __nv_bfloat16* __restrict__ QH, const __nv_bfloat16* __restrict__ QL,
    const __nv_bfloat16* __restrict__ KH, const __nv_bfloat16* __restrict__ KL,
    const __nv_bfloat16* __restrict__ VH, const __nv_bfloat16* __restrict__ VL,
    __nv_bfloat16* __restrict__ OHo, __nv_bfloat16* __restrict__ OLo)
{
    extern __shared__ __nv_bfloat16 sm[];
    int gh = blockIdx.y, g = gh >> 2, h = gh & 3;
    int qt = blockIdx.x;
    int tid = threadIdx.x, lane = tid & 31, warp = tid >> 5;

    int row_c = tid >> 2, seg_c = (tid & 3) * 8;

    auto issue = [&](int kt, int st) {
        __nv_bfloat16* s = sm + FL_ST0 + st * FL_STAGE;
        #pragma unroll
        for (int r = 0; r < 2; r++) {
            int row = row_c + r * 64;
            size_t go = ((size_t)g * GS + kt * 128 + row) * 128 + h * 32 + seg_c;
            int so = row * LDS_ + seg_c;
            CP16(smem_u32(s + FL_KH + so), KH + go);
            CP16(smem_u32(s + FL_KL + so), KL + go);
            CP16(smem_u32(s + FL_VH + so), VH + go);
            CP16(smem_u32(s + FL_VL + so), VL + go);
        }
        CP_COMMIT();
    };

    {
        #pragma unroll
        for (int r = 0; r < 2; r++) {
            int row = row_c + r * 64;
            size_t go = ((size_t)g * GS + qt * 128 + row) * 128 + h * 32 + seg_c;
            int so = row * LDS_ + seg_c;
            CP16(smem_u32(sm + FL_QH + so), QH + go);
            CP16(smem_u32(sm + FL_QL + so), QL + go);
        }
        __nv_bfloat16* s = sm + FL_ST0;
        #pragma unroll
        for (int r = 0; r < 2; r++) {
            int row = row_c + r * 64;
            size_t go = ((size_t)g * GS + row) * 128 + h * 32 + seg_c;
            int so = row * LDS_ + seg_c;
            CP16(smem_u32(s + FL_KH + so), KH + go);
            CP16(smem_u32(s + FL_KL + so), KL + go);
            CP16(smem_u32(s + FL_VH + so), VH + go);
            CP16(smem_u32(s + FL_VL + so), VL + go);
        }
        CP_COMMIT();
    }
    issue(1, 1);

    uint32_t qh_[2][4], ql_[2][4];
    float m0 = -1e30f, m1 = -1e30f, l0 = 0.f, l1 = 0.f;
    float O[4][4];
    #pragma unroll
    for (int n = 0; n < 4; n++)
        #pragma unroll
        for (int j = 0; j < 4; j++) O[n][j] = 0.f;

    const float scale = 0.088388347648318447f;

    for (int kt = 0; kt < 4; kt++) {
        if (kt < 3) CP_WAIT1(); else CP_WAIT0();
        __syncthreads();
        const __nv_bfloat16* s = sm + FL_ST0 + (kt & 1) * FL_STAGE;

        if (kt == 0) {
            #pragma unroll
            for (int kf = 0; kf < 2; kf++) {
                int row = warp * 16 + (lane & 15);
                int col = kf * 16 + (lane >> 4) * 8;
                LDMX4(qh_[kf], smem_u32(sm + FL_QH + row * LDS_ + col));
                LDMX4(ql_[kf], smem_u32(sm + FL_QL + row * LDS_ + col));
            }
        }

        // S = Q K^T on this 128-key tile (K frags via x4, pair jp -> j = 2jp, 2jp+1)
        float S[16][4];
        #pragma unroll
        for (int j = 0; j < 16; j++)
            #pragma unroll
            for (int r = 0; r < 4; r++) S[j][r] = 0.f;
        {
            int brow = ((lane >> 4) & 1) * 8 + (lane & 7);
            #pragma unroll
            for (int jp = 0; jp < 8; jp++) {
                #pragma unroll
                for (int kf = 0; kf < 2; kf++) {
                    uint32_t bh4[4], bl4[4];
                    int off = (jp * 16 + brow) * LDS_ + kf * 16 + ((lane >> 3) & 1) * 8;
                    LDMX4(bh4, smem_u32(s + FL_KH + off));
                    LDMX4(bl4, smem_u32(s + FL_KL + off));
                    MMA16816(S[2 * jp],     qh_[kf], bh4);
                    MMA16816(S[2 * jp],     ql_[kf], bh4);
                    MMA16816(S[2 * jp],     qh_[kf], bl4);
                    MMA16816(S[2 * jp + 1], qh_[kf], bh4 + 2);
                    MMA16816(S[2 * jp + 1], ql_[kf], bh4 + 2);
                    MMA16816(S[2 * jp + 1], qh_[kf], bl4 + 2);
                }
            }
        }
        float mx0 = -1e30f, mx1 = -1e30f;
        #pragma unroll
        for (int j = 0; j < 16; j++) {
            S[j][0] *= scale; S[j][1] *= scale; S[j][2] *= scale; S[j][3] *= scale;
            mx0 = fmaxf(mx0, fmaxf(S[j][0], S[j][1]));
            mx1 = fmaxf(mx1, fmaxf(S[j][2], S[j][3]));
        }
        #pragma unroll
        for (int o = 1; o < 4; o <<= 1) {
            mx0 = fmaxf(mx0, __shfl_xor_sync(0xffffffffu, mx0, o));
            mx1 = fmaxf(mx1, __shfl_xor_sync(0xffffffffu, mx1, o));
        }
        float nm0 = fmaxf(m0, mx0), nm1 = fmaxf(m1, mx1);
        float a0 = expf(m0 - nm0), a1 = expf(m1 - nm1);
        float rs0 = 0.f, rs1 = 0.f;
        #pragma unroll
        for (int j = 0; j < 16; j++) {
            S[j][0] = expf(S[j][0] - nm0); S[j][1] = expf(S[j][1] - nm0);
            S[j][2] = expf(S[j][2] - nm1); S[j][3] = expf(S[j][3] - nm1);
            rs0 += S[j][0] + S[j][1];
            rs1 += S[j][2] + S[j][3];
        }
        #pragma unroll
        for (int o = 1; o < 4; o <<= 1) {
            rs0 += __shfl_xor_sync(0xffffffffu, rs0, o);
            rs1 += __shfl_xor_sync(0xffffffffu, rs1, o);
        }
        l0 = l0 * a0 + rs0;
        l1 = l1 * a1 + rs1;
        #pragma unroll
        for (int n = 0; n < 4; n++) {
            O[n][0] *= a0; O[n][1] *= a0; O[n][2] *= a1; O[n][3] *= a1;
        }
        m0 = nm0; m1 = nm1;
        // P @ V (V tile [k][n]; frags via x4.trans, pair np -> n = 2np, 2np+1)
        #pragma unroll
        for (int jp = 0; jp < 8; jp++) {
            uint32_t aph[4], apl[4];
            split2(S[2 * jp][0],     S[2 * jp][1],     aph[0], apl[0]);
            split2(S[2 * jp][2],     S[2 * jp][3],     aph[1], apl[1]);
            split2(S[2 * jp + 1][0], S[2 * jp + 1][1], aph[2], apl[2]);
            split2(S[2 * jp + 1][2], S[2 * jp + 1][3], aph[3], apl[3]);
            int vrow = jp * 16 + ((lane >> 3) & 1) * 8 + (lane & 7);
            #pragma unroll
            for (int np = 0; np < 2; np++) {
                uint32_t bh4[4], bl4[4];
                int off = vrow * LDS_ + (2 * np + ((lane >> 4) & 1)) * 8;
                LDMX4T(bh4, smem_u32(s + FL_VH + off));
                LDMX4T(bl4, smem_u32(s + FL_VL + off));
                MMA16816(O[2 * np],     aph, bh4);
                MMA16816(O[2 * np],     apl, bh4);
                MMA16816(O[2 * np],     aph, bl4);
                MMA16816(O[2 * np + 1], aph, bh4 + 2);
                MMA16816(O[2 * np + 1], apl, bh4 + 2);
                MMA16816(O[2 * np + 1], aph, bl4 + 2);
            }
        }
        __syncthreads();
        if (kt + 2 < 4) issue(kt + 2, kt & 1);
    }
    float il0 = 1.f / l0, il1 = 1.f / l1;
    int node = g * GS + qt * 128 + warp * 16 + (lane >> 2);
    #pragma unroll
    for (int n = 0; n < 4; n++) {
        int col = h * 32 + n * 8 + (lane & 3) * 2;
        uint32_t hh, ll;
        split2(O[n][0] * il0, O[n][1] * il0, hh, ll);
        *(uint32_t*)(OHo + (size_t)node * 128 + col) = hh;
        *(uint32_t*)(OLo + (size_t)node * 128 + col) = ll;
        split2(O[n][2] * il1, O[n][3] * il1, hh, ll);
        *(uint32_t*)(OHo + (size_t)(node + 8) * 128 + col) = hh;
        *(uint32_t*)(OLo + (size_t)(node + 8) * 128 + col) = ll;
    }
}

// ================= host orchestration =================
extern "C" void kernel_launch(void* const* d_in, const int* in_sizes, int n_in,
                              void* d_out, int out_size)
{
    const float* x   = (const float*)d_in[0];
    const int*   ei  = (const int*)  d_in[1];
    const float* W1  = (const float*)d_in[3];
    const float* a1s = (const float*)d_in[4];
    const float* a1d = (const float*)d_in[5];
    const float* b1  = (const float*)d_in[6];
    const float* W2  = (const float*)d_in[7];
    const float* a2s = (const float*)d_in[8];
    const float* a2d = (const float*)d_in[9];
    const float* b2  = (const float*)d_in[10];
    const float* W3  = (const float*)d_in[11];
    const float* a3s = (const float*)d_in[12];
    const float* a3d = (const float*)d_in[13];
    const float* b3  = (const float*)d_in[14];
    const float* g1  = (const float*)d_in[15];
    const float* be1 = (const float*)d_in[16];
    const float* g2  = (const float*)d_in[17];
    const float* be2 = (const float*)d_in[18];
    const float* Wr  = (const float*)d_in[19];
    const float* br  = (const float*)d_in[20];
    const float* Wq  = (const float*)d_in[21];
    const float* Wk  = (const float*)d_in[22];
    const float* Wv  = (const float*)d_in[23];
    const float* Wo  = (const float*)d_in[24];
    const float* bo  = (const float*)d_in[25];
    float* out = (float*)d_out;

    float* sb = nullptr;
    cudaGetSymbolAddress((void**)&sb, g_scratch);
    __nv_bfloat16* bb = nullptr;
    cudaGetSymbolAddress((void**)&bb, g_bf);
    cudaFuncSetAttribute(k_flash, cudaFuncAttributeMaxDynamicSharedMemorySize, FLASH_SMEM);
    cudaFuncSetAttribute(mma_gemm, cudaFuncAttributeMaxDynamicSharedMemorySize, GEMM_SMEM);
    cudaFuncSetAttribute(mma_gemm_qkv, cudaFuncAttributeMaxDynamicSharedMemorySize, GEMM_SMEM);

    float* p_h  = sb + OFF_H;
    float* p_h3 = sb + OFF_H3;
    float* p_r  = sb + OFF_R;
    float* p_es = sb + OFF_ES;
    float* p_ed = sb + OFF_ED;

    // CSR
    k_zero_cnt<<<NN / 256, 256>>>();
    k_count<<<1024, 256>>>(ei);
    k_scan1<<<256, 256>>>();
    k_scan2<<<1, 256>>>();
    k_scan3<<<256, 256>>>();
    k_fill<<<1152, 256>>>(ei);

    // weight conversions
    k_cvt_w1r<<<(384*64 + 255)/256, 256>>>(W1, Wr, bb + B_W1RH, bb + B_W1RL);
    k_cvt_wT<<<(256*256 + 255)/256, 256>>>(W2, bb + B_W2H, bb + B_W2L, 256, 256);
    k_cvt_wT<<<(128*256 + 255)/256, 256>>>(W3, bb + B_W3H, bb + B_W3L, 256, 128);
    k_cvt_wqkv<<<(384*128 + 255)/256, 256>>>(Wq, Wk, Wv, bb + B_WQKVH, bb + B_WQKVL);
    k_cvt_wT<<<(128*128 + 255)/256, 256>>>(Wo, bb + B_WOH, bb + B_WOL, 128, 128);

    // x -> bf16 hi/lo
    k_cvt_split<<<(NN*64/4 + 255)/256, 256>>>(x, bb + B_XH, bb + B_XL, NN*64/4);

    // layer 1 combo: h (+H=4 scores) AND residual p_r in one GEMM (N=384)
    mma_gemm<<<PERS, 256, GEMM_SMEM>>>(bb + B_XH, bb + B_XL, bb + B_W1RH, bb + B_W1RL,
                                    nullptr, p_h, nullptr, nullptr, p_r, br,
                                    a1s, a1d, p_es, p_ed, 3, NN, 384, 64);
    k_gat_agg<256, 4><<<NN / 8, 256>>>(p_h, p_es, p_ed, b1, g1, be1, nullptr,
                                       bb + B_TH, bb + B_TL);
    // layer 2 (fused H=4 scores)
    mma_gemm<<<PERS, 256, GEMM_SMEM>>>(bb + B_TH, bb + B_TL, bb + B_W2H, bb + B_W2L,
                                    nullptr, p_h, nullptr, nullptr, nullptr, nullptr,
                                    a2s, a2d, p_es, p_ed, 1, NN, 256, 256);
    k_gat_agg<256, 4><<<NN / 8, 256>>>(p_h, p_es, p_ed, b2, g2, be2, nullptr,
                                       bb + B_TH, bb + B_TL);
    // layer 3 (fused H=1 scores)
    mma_gemm<<<PERS, 256, GEMM_SMEM>>>(bb + B_TH, bb + B_TL, bb + B_W3H, bb + B_W3L,
                                    nullptr, p_h3, nullptr, nullptr, nullptr, nullptr,
                                    a3s, a3d, p_es, p_ed, 2, NN, 128, 256);
    k_gat_agg<128, 1><<<NN / 8, 256>>>(p_h3, p_es, p_ed, b3, nullptr, nullptr, p_r,
                                       bb + B_HRH, bb + B_HRL);
    // fused QKV projection
    mma_gemm_qkv<<<PERS, 256, GEMM_SMEM>>>(bb + B_HRH, bb + B_HRL,
                                        bb + B_WQKVH, bb + B_WQKVL,
                                        bb + B_QH, bb + B_QL,
                                        bb + B_KH, bb + B_KL,
                                        bb + B_VH, bb + B_VL);
    // fused attention
    k_flash<<<dim3(4, NG * 4), 256, FLASH_SMEM>>>(
        bb + B_QH, bb + B_QL, bb + B_KH, bb + B_KL,
        bb + B_VH, bb + B_VL, bb + B_AOH, bb + B_AOL);
    // output projection
    mma_gemm<<<PERS, 256, GEMM_SMEM>>>(bb + B_AOH, bb + B_AOL, bb + B_WOH, bb + B_WOL,
                                    bo, out, nullptr, nullptr, nullptr, nullptr,
                                    nullptr, nullptr, nullptr, nullptr, 0, NN, 128, 128);
}

// round 12
// speedup vs baseline: 2.4526x; 1.0692x over previous
#include <cuda_runtime.h>
#include <cuda_bf16.h>
#include <math.h>
#include <stdint.h>

// ---------------- problem constants ----------------
constexpr int NN   = 65536;
constexpr int NE   = 524288;
constexpr int ET   = NE + NN;
constexpr int GS   = 512;
constexpr int NG   = NN / GS;
constexpr int D1   = 256;
constexpr int D3   = 128;
constexpr int PERS = 296;   // 148 SMs x 2 CTAs

// ---------------- fp32 scratch ----------------
constexpr size_t OFF_H    = 0;
constexpr size_t OFF_H3   = OFF_H  + (size_t)NN*D1;
constexpr size_t OFF_R    = OFF_H3 + (size_t)NN*D3;
constexpr size_t OFF_ES   = OFF_R  + (size_t)NN*D3;
constexpr size_t OFF_ED   = OFF_ES + (size_t)NN*4;
constexpr size_t SCRATCH  = OFF_ED + (size_t)NN*4;

__device__ __align__(256) float g_scratch[SCRATCH];

// ---------------- bf16 scratch ----------------
constexpr size_t B_XH  = 0;
constexpr size_t B_XL  = B_XH  + (size_t)NN*64;
constexpr size_t B_TH  = B_XL  + (size_t)NN*64;
constexpr size_t B_TL  = B_TH  + (size_t)NN*256;
constexpr size_t B_HRH = B_TL  + (size_t)NN*256;
constexpr size_t B_HRL = B_HRH + (size_t)NN*128;
constexpr size_t B_AOH = B_HRL + (size_t)NN*128;
constexpr size_t B_AOL = B_AOH + (size_t)NN*128;
constexpr size_t B_QH  = B_AOL + (size_t)NN*128;
constexpr size_t B_QL  = B_QH  + (size_t)NN*128;
constexpr size_t B_KH  = B_QL  + (size_t)NN*128;
constexpr size_t B_KL  = B_KH  + (size_t)NN*128;
constexpr size_t B_VH  = B_KL  + (size_t)NN*128;
constexpr size_t B_VL  = B_VH  + (size_t)NN*128;
constexpr size_t B_W1RH = B_VL  + (size_t)NN*128;   // concat [W1;Wr]^T: 384x64
constexpr size_t B_W1RL = B_W1RH + 384*64;
constexpr size_t B_W2H = B_W1RL + 384*64;
constexpr size_t B_W2L = B_W2H + 256*256;
constexpr size_t B_W3H = B_W2L + 256*256;
constexpr size_t B_W3L = B_W3H + 128*256;
constexpr size_t B_WQKVH = B_W3L + 128*256;
constexpr size_t B_WQKVL = B_WQKVH + 384*128;
constexpr size_t B_WOH = B_WQKVL + 384*128;
constexpr size_t B_WOL = B_WOH + 128*128;
constexpr size_t BF_TOTAL = B_WOL + 128*128;

__device__ __align__(256) __nv_bfloat16 g_bf[BF_TOTAL];

__device__ int g_rowptr[NN + 1];
__device__ int g_cnt[NN];
__device__ int g_cursor[NN];
__device__ int g_col[ET];
__device__ int g_blocksum[256];

// ================= helpers =================
__device__ __forceinline__ uint32_t smem_u32(const void* p) {
    uint32_t a;
    asm("{ .reg .u64 t; cvta.to.shared.u64 t, %1; cvt.u32.u64 %0, t; }" : "=r"(a) : "l"(p));
    return a;
}
#define LDMX4(r, a) \
    asm volatile("ldmatrix.sync.aligned.m8n8.x4.shared.b16 {%0,%1,%2,%3}, [%4];" \
        : "=r"((r)[0]), "=r"((r)[1]), "=r"((r)[2]), "=r"((r)[3]) : "r"(a))
#define LDMX4T(r, a) \
    asm volatile("ldmatrix.sync.aligned.m8n8.x4.trans.shared.b16 {%0,%1,%2,%3}, [%4];" \
        : "=r"((r)[0]), "=r"((r)[1]), "=r"((r)[2]), "=r"((r)[3]) : "r"(a))
#define MMA16816(d, a, b) \
    asm volatile("mma.sync.aligned.m16n8k16.row.col.f32.bf16.bf16.f32 " \
        "{%0,%1,%2,%3}, {%4,%5,%6,%7}, {%8,%9}, {%0,%1,%2,%3};" \
        : "+f"((d)[0]), "+f"((d)[1]), "+f"((d)[2]), "+f"((d)[3]) \
        : "r"((a)[0]), "r"((a)[1]), "r"((a)[2]), "r"((a)[3]), \
          "r"((b)[0]), "r"((b)[1]))
#define CP16(dst, src) \
    asm volatile("cp.async.cg.shared.global [%0], [%1], 16;" :: "r"(dst), "l"(src))
#define CP_COMMIT() asm volatile("cp.async.commit_group;" ::: "memory")
#define CP_WAIT1()  asm volatile("cp.async.wait_group 1;" ::: "memory")
#define CP_WAIT0()  asm volatile("cp.async.wait_group 0;" ::: "memory")

__device__ __forceinline__ void split2(float v0, float v1, uint32_t& hh, uint32_t& ll) {
    __nv_bfloat16 h0 = __float2bfloat16(v0), h1 = __float2bfloat16(v1);
    __nv_bfloat16 l0 = __float2bfloat16(v0 - __bfloat162float(h0));
    __nv_bfloat16 l1 = __float2bfloat16(v1 - __bfloat162float(h1));
    __nv_bfloat162 H; H.x = h0; H.y = h1;
    __nv_bfloat162 L; L.x = l0; L.y = l1;
    hh = *(uint32_t*)&H; ll = *(uint32_t*)&L;
}

// ================= CSR build (parallel scan, scan2 folded into scan3) ========
__global__ void k_zero_cnt() {
    int i = blockIdx.x * blockDim.x + threadIdx.x;
    if (i < NN) g_cnt[i] = 0;
}
__global__ void k_count(const int* __restrict__ ei) {
    int stride = gridDim.x * blockDim.x;
    for (int idx = blockIdx.x * blockDim.x + threadIdx.x; idx < NE; idx += stride)
        atomicAdd(&g_cnt[ei[NE + idx]], 1);
}
__global__ void k_scan1() {
    __shared__ int ws[8];
    int b = blockIdx.x, tid = threadIdx.x, lane = tid & 31, wid = tid >> 5;
    int v = g_cnt[b * 256 + tid] + 1;
    int x = v;
    #pragma unroll
    for (int o = 1; o < 32; o <<= 1) {
        int t = __shfl_up_sync(0xffffffffu, x, o);
        if (lane >= o) x += t;
    }
    if (lane == 31) ws[wid] = x;
    __syncthreads();
    if (tid == 0) {
        int run = 0;
        #pragma unroll
        for (int k = 0; k < 8; k++) { int t = ws[k]; ws[k] = run; run += t; }
        g_blocksum[b] = run;
    }
    __syncthreads();
    g_rowptr[b * 256 + tid] = x - v + ws[wid];
}
// each block computes its own offset = sum(blocksum[0..b-1]) then applies it
__global__ void k_scan3() {
    __shared__ int red[8];
    __shared__ int s_off;
    int b = blockIdx.x, tid = threadIdx.x, lane = tid & 31, wid = tid >> 5;
    int v = (tid < b) ? g_blocksum[tid] : 0;
    #pragma unroll
    for (int o = 16; o; o >>= 1) v += __shfl_xor_sync(0xffffffffu, v, o);
    if (lane == 0) red[wid] = v;
    __syncthreads();
    if (tid == 0) {
        int t = 0;
        #pragma unroll
        for (int k = 0; k < 8; k++) t += red[k];
        s_off = t;
    }
    __syncthreads();
    int idx = b * 256 + tid;
    int val = g_rowptr[idx] + s_off;
    g_rowptr[idx] = val;
    g_cursor[idx] = val;
    if (idx == 0) g_rowptr[NN] = ET;
}
__global__ void k_fill(const int* __restrict__ ei) {
    int stride = gridDim.x * blockDim.x;
    for (int idx = blockIdx.x * blockDim.x + threadIdx.x; idx < ET; idx += stride) {
        int s, d;
        if (idx < NE) { s = ei[idx]; d = ei[NE + idx]; }
        else          { s = d = idx - NE; }
        int pos = atomicAdd(&g_cursor[d], 1);
        g_col[pos] = s;
    }
}

// ================= conversions =================
__global__ void k_cvt_split(const float* __restrict__ in, __nv_bfloat16* __restrict__ hi,
                            __nv_bfloat16* __restrict__ lo, int n4) {
    int i = blockIdx.x * blockDim.x + threadIdx.x;
    if (i >= n4) return;
    float4 v = ((const float4*)in)[i];
    uint32_t h01, l01, h23, l23;
    split2(v.x, v.y, h01, l01);
    split2(v.z, v.w, h23, l23);
    ((uint32_t*)hi)[2 * i] = h01; ((uint32_t*)hi)[2 * i + 1] = h23;
    ((uint32_t*)lo)[2 * i] = l01; ((uint32_t*)lo)[2 * i + 1] = l23;
}

// all weight conversions fused into one launch (segment dispatch)
constexpr int WSEG0 = 384 * 64;                 // W1R
constexpr int WSEG1 = WSEG0 + 256 * 256;        // W2
constexpr int WSEG2 = WSEG1 + 128 * 256;        // W3
constexpr int WSEG3 = WSEG2 + 384 * 128;        // WQKV
constexpr int WSEG4 = WSEG3 + 128 * 128;        // WO
__global__ void k_cvt_weights(const float* __restrict__ W1, const float* __restrict__ Wr,
                              const float* __restrict__ W2, const float* __restrict__ W3,
                              const float* __restrict__ Wq, const float* __restrict__ Wk,
                              const float* __restrict__ Wv, const float* __restrict__ Wo,
                              __nv_bfloat16* __restrict__ bb) {
    int idx = blockIdx.x * blockDim.x + threadIdx.x;
    if (idx >= WSEG4) return;
    float v;
    size_t hoff, loff;
    if (idx < WSEG0) {
        int li = idx, n = li / 64, k = li % 64;
        v = (n < 256) ? W1[(size_t)k * 256 + n] : Wr[(size_t)k * 128 + (n - 256)];
        hoff = B_W1RH + li; loff = B_W1RL + li;
    } else if (idx < WSEG1) {
        int li = idx - WSEG0, n = li / 256, k = li % 256;
        v = W2[(size_t)k * 256 + n];
        hoff = B_W2H + li; loff = B_W2L + li;
    } else if (idx < WSEG2) {
        int li = idx - WSEG1, n = li / 256, k = li % 256;
        v = W3[(size_t)k * 128 + n];
        hoff = B_W3H + li; loff = B_W3L + li;
    } else if (idx < WSEG3) {
        int li = idx - WSEG2, n = li / 128, k = li % 128;
        const float* W = (n < 128) ? Wq : ((n < 256) ? Wk : Wv);
        v = W[(size_t)k * 128 + (n & 127)];
        hoff = B_WQKVH + li; loff = B_WQKVL + li;
    } else {
        int li = idx - WSEG3, n = li / 128, k = li % 128;
        v = Wo[(size_t)k * 128 + n];
        hoff = B_WOH + li; loff = B_WOL + li;
    }
    __nv_bfloat16 h = __float2bfloat16(v);
    g_bf[hoff] = h;
    g_bf[loff] = __float2bfloat16(v - __bfloat162float(h));
    (void)bb;
}

// ================= mma.sync bf16-split GEMM, persistent tiles ================
constexpr int LDS_ = 40;
constexpr int G_OAL = 128 * LDS_;
constexpr int G_OBH = 2 * 128 * LDS_;
constexpr int G_OBL = 3 * 128 * LDS_;
constexpr int G_STAGE = 4 * 128 * LDS_;
constexpr int GEMM_SMEM = 2 * G_STAGE * 2;

__global__ __launch_bounds__(256, 2) void mma_gemm(
    const __nv_bfloat16* __restrict__ Ah, const __nv_bfloat16* __restrict__ Al,
    const __nv_bfloat16* __restrict__ Bh, const __nv_bfloat16* __restrict__ Bl,
    const float* __restrict__ bias, float* __restrict__ C,
    __nv_bfloat16* __restrict__ Chi, __nv_bfloat16* __restrict__ Clo,
    float* __restrict__ C2, const float* __restrict__ bias2,
    const float* __restrict__ asv, const float* __restrict__ adv,
    float* __restrict__ esv, float* __restrict__ edv_out,
    int score_mode, int M, int N, int K)
{
    extern __shared__ __nv_bfloat16 smem[];
    int tid = threadIdx.x, lane = tid & 31, warp = tid >> 5;
    int wm = warp & 3, wn = warp >> 2;
    int nbn = N >> 7;
    int ntiles = (M >> 7) * nbn;
    int row_c = tid >> 2, seg_c = (tid & 3) * 8;
    int nch = K >> 5;

    for (int tile = blockIdx.x; tile < ntiles; tile += gridDim.x) {
        int bm = tile / nbn, bn = tile - bm * nbn;
        const __nv_bfloat16* gAh = Ah + (size_t)bm * 128 * K;
        const __nv_bfloat16* gAl = Al + (size_t)bm * 128 * K;
        const __nv_bfloat16* gBh = Bh + (size_t)bn * 128 * K;
        const __nv_bfloat16* gBl = Bl + (size_t)bn * 128 * K;

        auto issue = [&](int ich, int st) {
            int k0 = ich << 5;
            __nv_bfloat16* s = smem + st * G_STAGE;
            #pragma unroll
            for (int r = 0; r < 2; r++) {
                int row = row_c + r * 64;
                size_t go = (size_t)row * K + k0 + seg_c;
                int so = row * LDS_ + seg_c;
                CP16(smem_u32(s + so), gAh + go);
                CP16(smem_u32(s + G_OAL + so), gAl + go);
                CP16(smem_u32(s + G_OBH + so), gBh + go);
                CP16(smem_u32(s + G_OBL + so), gBl + go);
            }
            CP_COMMIT();
        };

        float d[2][8][4];
        #pragma unroll
        for (int mi = 0; mi < 2; mi++)
            #pragma unroll
            for (int ni = 0; ni < 8; ni++)
                #pragma unroll
                for (int j = 0; j < 4; j++) d[mi][ni][j] = 0.f;

        issue(0, 0);
        if (nch > 1) issue(1, 1);

        for (int ich = 0; ich < nch; ich++) {
            if (ich + 1 < nch) CP_WAIT1(); else CP_WAIT0();
            __syncthreads();
            const __nv_bfloat16* s = smem + (ich & 1) * G_STAGE;
            #pragma unroll
            for (int ks = 0; ks < 2; ks++) {
                uint32_t ah[2][4], al[2][4];
                #pragma unroll
                for (int mi = 0; mi < 2; mi++) {
                    int row = wm * 32 + mi * 16 + (lane & 15);
                    int col = ks * 16 + (lane >> 4) * 8;
                    LDMX4(ah[mi], smem_u32(s + row * LDS_ + col));
                    LDMX4(al[mi], smem_u32(s + G_OAL + row * LDS_ + col));
                }
                int brow = wn * 64 + ((lane >> 4) & 1) * 8 + (lane & 7);
                int bcol = ks * 16 + ((lane >> 3) & 1) * 8;
                #pragma unroll
                for (int p = 0; p < 4; p++) {
                    uint32_t bh4[4], bl4[4];
                    int off = (brow + p * 16) * LDS_ + bcol;
                    LDMX4(bh4, smem_u32(s + G_OBH + off));
                    LDMX4(bl4, smem_u32(s + G_OBL + off));
                    #pragma unroll
                    for (int mi = 0; mi < 2; mi++) {
                        MMA16816(d[mi][2 * p],     ah[mi], bh4);
                        MMA16816(d[mi][2 * p],     al[mi], bh4);
                        MMA16816(d[mi][2 * p],     ah[mi], bl4);
                        MMA16816(d[mi][2 * p + 1], ah[mi], bh4 + 2);
                        MMA16816(d[mi][2 * p + 1], al[mi], bh4 + 2);
                        MMA16816(d[mi][2 * p + 1], ah[mi], bl4 + 2);
                    }
                }
            }
            __syncthreads();
            if (ich + 2 < nch) issue(ich + 2, ich & 1);
        }

        // epilogue
        if (score_mode == 3 && bn == 2) {
            #pragma unroll
            for (int mi = 0; mi < 2; mi++) {
                int row = bm * 128 + wm * 32 + mi * 16 + (lane >> 2);
                #pragma unroll
                for (int ni = 0; ni < 8; ni++) {
                    int col = wn * 64 + ni * 8 + (lane & 3) * 2;
                    float b0 = bias2[col], b1 = bias2[col + 1];
                    *(float2*)(C2 + (size_t)row * 128 + col) =
                        make_float2(d[mi][ni][0] + b0, d[mi][ni][1] + b1);
                    *(float2*)(C2 + (size_t)(row + 8) * 128 + col) =
                        make_float2(d[mi][ni][2] + b0, d[mi][ni][3] + b1);
                }
            }
        } else {
            int outN = (score_mode == 3) ? 256 : N;
            #pragma unroll
            for (int mi = 0; mi < 2; mi++) {
                int row = bm * 128 + wm * 32 + mi * 16 + (lane >> 2);
                #pragma unroll
                for (int ni = 0; ni < 8; ni++) {
                    int col = bn * 128 + wn * 64 + ni * 8 + (lane & 3) * 2;
                    if (C) {
                        float b0 = bias ? bias[col] : 0.f;
                        float b1 = bias ? bias[col + 1] : 0.f;
                        *(float2*)(C + (size_t)row * outN + col) =
                            make_float2(d[mi][ni][0] + b0, d[mi][ni][1] + b1);
                        *(float2*)(C + (size_t)(row + 8) * outN + col) =
                            make_float2(d[mi][ni][2] + b0, d[mi][ni][3] + b1);
                    } else {
                        uint32_t hh, ll;
                        split2(d[mi][ni][0], d[mi][ni][1], hh, ll);
                        *(uint32_t*)(Chi + (size_t)row * outN + col) = hh;
                        *(uint32_t*)(Clo + (size_t)row * outN + col) = ll;
                        split2(d[mi][ni][2], d[mi][ni][3], hh, ll);
                        *(uint32_t*)(Chi + (size_t)(row + 8) * outN + col) = hh;
                        *(uint32_t*)(Clo + (size_t)(row + 8) * outN + col) = ll;
                    }
                }
            }
        }
        if (score_mode == 1 || (score_mode == 3 && bn < 2)) {
            int hd = bn * 2 + wn;
            float sv[4] = {0.f, 0.f, 0.f, 0.f}, dv[4] = {0.f, 0.f, 0.f, 0.f};
            #pragma unroll
            for (int mi = 0; mi < 2; mi++)
                #pragma unroll
                for (int ni = 0; ni < 8; ni++)
                    #pragma unroll
                    for (int j = 0; j < 2; j++) {
                        int cl = ni * 8 + (lane & 3) * 2 + j;
                        float a = asv[hd * 64 + cl], b = adv[hd * 64 + cl];
                        sv[mi * 2]     += d[mi][ni][j]     * a;
                        dv[mi * 2]     += d[mi][ni][j]     * b;
                        sv[mi * 2 + 1] += d[mi][ni][2 + j] * a;
                        dv[mi * 2 + 1] += d[mi][ni][2 + j] * b;
                    }
            #pragma unroll
            for (int r = 0; r < 4; r++) {
                sv[r] += __shfl_xor_sync(0xffffffffu, sv[r], 1);
                sv[r] += __shfl_xor_sync(0xffffffffu, sv[r], 2);
                dv[r] += __shfl_xor_sync(0xffffffffu, dv[r], 1);
                dv[r] += __shfl_xor_sync(0xffffffffu, dv[r], 2);
            }
            if ((lane & 3) == 0) {
                #pragma unroll
                for (int r = 0; r < 4; r++) {
                    int row = bm * 128 + wm * 32 + (r >> 1) * 16 + (lane >> 2) + (r & 1) * 8;
                    esv[(size_t)row * 4 + hd]     = sv[r];
                    edv_out[(size_t)row * 4 + hd] = dv[r];
                }
            }
        } else if (score_mode == 2) {
            float* reds = (float*)smem;
            float* redd = reds + 256;
            float sv[4] = {0.f, 0.f, 0.f, 0.f}, dv[4] = {0.f, 0.f, 0.f, 0.f};
            #pragma unroll
            for (int mi = 0; mi < 2; mi++)
                #pragma unroll
                for (int ni = 0; ni < 8; ni++)
                    #pragma unroll
                    for (int j = 0; j < 2; j++) {
                        int cl = wn * 64 + ni * 8 + (lane & 3) * 2 + j;
                        float a = asv[cl], b = adv[cl];
                        sv[mi * 2]     += d[mi][ni][j]     * a;
                        dv[mi * 2]     += d[mi][ni][j]     * b;
                        sv[mi * 2 + 1] += d[mi][ni][2 + j] * a;
                        dv[mi * 2 + 1] += d[mi][ni][2 + j] * b;
                    }
            #pragma unroll
            for (int r = 0; r < 4; r++) {
                sv[r] += __shfl_xor_sync(0xffffffffu, sv[r], 1);
                sv[r] += __shfl_xor_sync(0xffffffffu, sv[r], 2);
                dv[r] += __shfl_xor_sync(0xffffffffu, dv[r], 1);
                dv[r] += __shfl_xor_sync(0xffffffffu, dv[r], 2);
            }
            __syncthreads();
            if ((lane & 3) == 0) {
                #pragma unroll
                for (int r = 0; r < 4; r++) {
                    int row = wm * 32 + (r >> 1) * 16 + (lane >> 2) + (r & 1) * 8;
                    reds[row * 2 + wn] = sv[r];
                    redd[row * 2 + wn] = dv[r];
                }
            }
            __syncthreads();
            if (tid < 128) {
                esv[(size_t)(bm * 128 + tid)]     = reds[tid * 2] + reds[tid * 2 + 1];
                edv_out[(size_t)(bm * 128 + tid)] = redd[tid * 2] + redd[tid * 2 + 1];
            }
            __syncthreads();
        }
    }
}

// ================= QKV fused GEMM (persistent) =================
__global__ __launch_bounds__(256, 2) void mma_gemm_qkv(
    const __nv_bfloat16* __restrict__ Ah, const __nv_bfloat16* __restrict__ Al,
    const __nv_bfloat16* __restrict__ Bh, const __nv_bfloat16* __restrict__ Bl,
    __nv_bfloat16* __restrict__ QH, __nv_bfloat16* __restrict__ QL,
    __nv_bfloat16* __restrict__ KH, __nv_bfloat16* __restrict__ KL,
    __nv_bfloat16* __restrict__ VH, __nv_bfloat16* __restrict__ VL)
{
    constexpr int K = 128;
    constexpr int nch = K >> 5;
    extern __shared__ __nv_bfloat16 smem[];
    int tid = threadIdx.x, lane = tid & 31, warp = tid >> 5;
    int wm = warp & 3, wn = warp >> 2;
    int row_c = tid >> 2, seg_c = (tid & 3) * 8;
    constexpr int ntiles = 3 * 512;

    for (int tile = blockIdx.x; tile < ntiles; tile += gridDim.x) {
        int bm = tile / 3, bn = tile - bm * 3;
        const __nv_bfloat16* gAh = Ah + (size_t)bm * 128 * K;
        const __nv_bfloat16* gAl = Al + (size_t)bm * 128 * K;
        const __nv_bfloat16* gBh = Bh + (size_t)bn * 128 * K;
        const __nv_bfloat16* gBl = Bl + (size_t)bn * 128 * K;

        auto issue = [&](int ich, int st) {
            int k0 = ich << 5;
            __nv_bfloat16* s = smem + st * G_STAGE;
            #pragma unroll
            for (int r = 0; r < 2; r++) {
                int row = row_c + r * 64;
                size_t go = (size_t)row * K + k0 + seg_c;
                int so = row * LDS_ + seg_c;
                CP16(smem_u32(s + so), gAh + go);
                CP16(smem_u32(s + G_OAL + so), gAl + go);
                CP16(smem_u32(s + G_OBH + so), gBh + go);
                CP16(smem_u32(s + G_OBL + so), gBl + go);
            }
            CP_COMMIT();
        };

        float d[2][8][4];
        #pragma unroll
        for (int mi = 0; mi < 2; mi++)
            #pragma unroll
            for (int ni = 0; ni < 8; ni++)
                #pragma unroll
                for (int j = 0; j < 4; j++) d[mi][ni][j] = 0.f;

        issue(0, 0);
        issue(1, 1);
        for (int ich = 0; ich < nch; ich++) {
            if (ich + 1 < nch) CP_WAIT1(); else CP_WAIT0();
            __syncthreads();
            const __nv_bfloat16* s = smem + (ich & 1) * G_STAGE;
            #pragma unroll
            for (int ks = 0; ks < 2; ks++) {
                uint32_t ah[2][4], al[2][4];
                #pragma unroll
                for (int mi = 0; mi < 2; mi++) {
                    int row = wm * 32 + mi * 16 + (lane & 15);
                    int col = ks * 16 + (lane >> 4) * 8;
                    LDMX4(ah[mi], smem_u32(s + row * LDS_ + col));
                    LDMX4(al[mi], smem_u32(s + G_OAL + row * LDS_ + col));
                }
                int brow = wn * 64 + ((lane >> 4) & 1) * 8 + (lane & 7);
                int bcol = ks * 16 + ((lane >> 3) & 1) * 8;
                #pragma unroll
                for (int p = 0; p < 4; p++) {
                    uint32_t bh4[4], bl4[4];
                    int off = (brow + p * 16) * LDS_ + bcol;
                    LDMX4(bh4, smem_u32(s + G_OBH + off));
                    LDMX4(bl4, smem_u32(s + G_OBL + off));
                    #pragma unroll
                    for (int mi = 0; mi < 2; mi++) {
                        MMA16816(d[mi][2 * p],     ah[mi], bh4);
                        MMA16816(d[mi][2 * p],     al[mi], bh4);
                        MMA16816(d[mi][2 * p],     ah[mi], bl4);
                        MMA16816(d[mi][2 * p + 1], ah[mi], bh4 + 2);
                        MMA16816(d[mi][2 * p + 1], al[mi], bh4 + 2);
                        MMA16816(d[mi][2 * p + 1], ah[mi], bl4 + 2);
                    }
                }
            }
            __syncthreads();
            if (ich + 2 < nch) issue(ich + 2, ich & 1);
        }
        __nv_bfloat16 *Oh, *Ol;
        if (bn == 0)      { Oh = QH; Ol = QL; }
        else if (bn == 1) { Oh = KH; Ol = KL; }
        else              { Oh = VH; Ol = VL; }
        #pragma unroll
        for (int mi = 0; mi < 2; mi++) {
            int row = bm * 128 + wm * 32 + mi * 16 + (lane >> 2);
            #pragma unroll
            for (int ni = 0; ni < 8; ni++) {
                int col = wn * 64 + ni * 8 + (lane & 3) * 2;
                uint32_t hh, ll;
                split2(d[mi][ni][0], d[mi][ni][1], hh, ll);
                *(uint32_t*)(Oh + (size_t)row * 128 + col) = hh;
                *(uint32_t*)(Ol + (size_t)row * 128 + col) = ll;
                split2(d[mi][ni][2], d[mi][ni][3], hh, ll);
                *(uint32_t*)(Oh + (size_t)(row + 8) * 128 + col) = hh;
                *(uint32_t*)(Ol + (size_t)(row + 8) * 128 + col) = ll;
            }
        }
    }
}

// ================= GAT aggregation — single pass, float4 vectorized ==========
template <int D, int H>
__global__ __launch_bounds__(256) void k_gat_agg(
    const float* __restrict__ hfeat, const float* __restrict__ es,
    const float* __restrict__ ed, const float* __restrict__ bias,
    const float* __restrict__ gamma, const float* __restrict__ beta,
    const float* __restrict__ resid,
    __nv_bfloat16* __restrict__ outH, __nv_bfloat16* __restrict__ outL)
{
    constexpr int C = D / H;
    constexpr int NV = D / 128;
    int warp = (blockIdx.x * blockDim.x + threadIdx.x) >> 5;
    int lane = threadIdx.x & 31;
    if (warp >= NN) return;
    int i = warp;
    int beg = g_rowptr[i], end = g_rowptr[i + 1];

    float edv[H], z[H];
    #pragma unroll
    for (int h = 0; h < H; h++) {
        edv[h] = ed[(size_t)i * H + h];
        z[h] = 0.f;
    }
    float4 acc[NV];
    #pragma unroll
    for (int j = 0; j < NV; j++) acc[j] = make_float4(0.f, 0.f, 0.f, 0.f);

    for (int e = beg; e < end; e++) {
        int s = g_col[e];
        float al[H];
        if (H == 4) {
            float4 ev = ((const float4*)es)[s];
            float vv[4] = {ev.x, ev.y, ev.z, ev.w};
            #pragma unroll
            for (int h = 0; h < 4; h++) {
                float v = vv[h] + edv[h];
                v = v > 0.f ? v : 0.2f * v;
                al[h] = __expf(v);
                z[h] += al[h];
            }
        } else {
            float v = es[s] + edv[0];
            v = v > 0.f ? v : 0.2f * v;
            al[0] = __expf(v);
            z[0] += al[0];
        }
        const float4* hs = (const float4*)(hfeat + (size_t)s * D);
        #pragma unroll
        for (int j = 0; j < NV; j++) {
            float4 hv = hs[lane + 32 * j];
            float a = (H == 1) ? al[0] : al[((lane + 32 * j) * 4) / C];
            acc[j].x += a * hv.x; acc[j].y += a * hv.y;
            acc[j].z += a * hv.z; acc[j].w += a * hv.w;
        }
    }
    #pragma unroll
    for (int h = 0; h < H; h++) z[h] = 1.f / (z[h] + 1e-16f);

    float4 x[NV];
    #pragma unroll
    for (int j = 0; j < NV; j++) {
        int g4 = lane + 32 * j;
        float zz = (H == 1) ? z[0] : z[(g4 * 4) / C];
        float4 b4 = ((const float4*)bias)[g4];
        x[j].x = acc[j].x * zz + b4.x;
        x[j].y = acc[j].y * zz + b4.y;
        x[j].z = acc[j].z * zz + b4.z;
        x[j].w = acc[j].w * zz + b4.w;
        if (resid) {
            float4 r4 = ((const float4*)(resid + (size_t)i * D))[g4];
            x[j].x += r4.x; x[j].y += r4.y; x[j].z += r4.z; x[j].w += r4.w;
        }
    }
    if (gamma) {
        #pragma unroll
        for (int j = 0; j < NV; j++) {
            x[j].x = x[j].x > 0.f ? x[j].x : (__expf(x[j].x) - 1.f);
            x[j].y = x[j].y > 0.f ? x[j].y : (__expf(x[j].y) - 1.f);
            x[j].z = x[j].z > 0.f ? x[j].z : (__expf(x[j].z) - 1.f);
            x[j].w = x[j].w > 0.f ? x[j].w : (__expf(x[j].w) - 1.f);
        }
        float s = 0.f;
        #pragma unroll
        for (int j = 0; j < NV; j++) s += x[j].x + x[j].y + x[j].z + x[j].w;
        #pragma unroll
        for (int o = 16; o; o >>= 1) s += __shfl_xor_sync(0xffffffffu, s, o);
        float mu = s / (float)D;
        float vs = 0.f;
        #pragma unroll
        for (int j = 0; j < NV; j++) {
            float a = x[j].x - mu, b = x[j].y - mu, c = x[j].z - mu, dd = x[j].w - mu;
            vs += a * a + b * b + c * c + dd * dd;
        }
        #pragma unroll
        for (int o = 16; o; o >>= 1) vs += __shfl_xor_sync(0xffffffffu, vs, o);
        float inv = rsqrtf(vs / (float)D + 1e-5f);
        #pragma unroll
        for (int j = 0; j < NV; j++) {
            int g4 = lane + 32 * j;
            float4 g = ((const float4*)gamma)[g4];
            float4 be = ((const float4*)beta)[g4];
            x[j].x = (x[j].x - mu) * inv * g.x + be.x;
            x[j].y = (x[j].y - mu) * inv * g.y + be.y;
            x[j].z = (x[j].z - mu) * inv * g.z + be.z;
            x[j].w = (x[j].w - mu) * inv * g.w + be.w;
        }
    }
    #pragma unroll
    for (int j = 0; j < NV; j++) {
        int g4 = lane + 32 * j;
        uint32_t h01, l01, h23, l23;
        split2(x[j].x, x[j].y, h01, l01);
        split2(x[j].z, x[j].w, h23, l23);
        *(uint2*)(outH + (size_t)i * D + g4 * 4) = make_uint2(h01, h23);
        *(uint2*)(outL + (size_t)i * D + g4 * 4) = make_uint2(l01, l23);
    }
}

// ================= fused flash attention, cp.async K/V pipeline =============
constexpr int FL_QH = 0;
constexpr int FL_QL = 128 * LDS_;
constexpr int FL_ST0 = 2 * 128 * LDS_;
constexpr int FL_KH = 0;
constexpr int FL_KL = 128 * LDS_;
constexpr int FL_VH = 2 * 128 * LDS_;
constexpr int FL_VL = 3 * 128 * LDS_;
constexpr int FL_STAGE = 4 * 128 * LDS_;
constexpr int FLASH_SMEM = (FL_ST0 + 2 * FL_STAGE) * 2;   // 102400 bytes

__global__ __launch_bounds__(256, 2) void k_flash(
    const __nv_bfloat16* __restrict__ QH, const __nv_bfloat16* __restrict__ QL,
    const __nv_bfloat16* __restrict__ KH, const __nv_bfloat16* __restrict__ KL,
    const __nv_bfloat16* __restrict__ VH, const __nv_bfloat16* __restrict__ VL,
    __nv_bfloat16* __restrict__ OHo, __nv_bfloat16* __restrict__ OLo)
{
    extern __shared__ __nv_bfloat16 sm[];
    int gh = blockIdx.y, g = gh >> 2, h = gh & 3;
    int qt = blockIdx.x;
    int tid = threadIdx.x, lane = tid & 31, warp = tid >> 5;

    int row_c = tid >> 2, seg_c = (tid & 3) * 8;

    auto issue = [&](int kt, int st) {
        __nv_bfloat16* s = sm + FL_ST0 + st * FL_STAGE;
        #pragma unroll
        for (int r = 0; r < 2; r++) {
            int row = row_c + r * 64;
            size_t go = ((size_t)g * GS + kt * 128 + row) * 128 + h * 32 + seg_c;
            int so = row * LDS_ + seg_c;
            CP16(smem_u32(s + FL_KH + so), KH + go);
            CP16(smem_u32(s + FL_KL + so), KL + go);
            CP16(smem_u32(s + FL_VH + so), VH + go);
            CP16(smem_u32(s + FL_VL + so), VL + go);
        }
        CP_COMMIT();
    };

    {
        #pragma unroll
        for (int r = 0; r < 2; r++) {
            int row = row_c + r * 64;
            size_t go = ((size_t)g * GS + qt * 128 + row) * 128 + h * 32 + seg_c;
            int so = row * LDS_ + seg_c;
            CP16(smem_u32(sm + FL_QH + so), QH + go);
            CP16(smem_u32(sm + FL_QL + so), QL + go);
        }
        __nv_bfloat16* s = sm + FL_ST0;
        #pragma unroll
        for (int r = 0; r < 2; r++) {
            int row = row_c + r * 64;
            size_t go = ((size_t)g * GS + row) * 128 + h * 32 + seg_c;
            int so = row * LDS_ + seg_c;
            CP16(smem_u32(s + FL_KH + so), KH + go);
            CP16(smem_u32(s + FL_KL + so), KL + go);
            CP16(smem_u32(s + FL_VH + so), VH + go);
            CP16(smem_u32(s + FL_VL + so), VL + go);
        }
        CP_COMMIT();
    }
    issue(1, 1);

    uint32_t qh_[2][4], ql_[2][4];
    float m0 = -1e30f, m1 = -1e30f, l0 = 0.f, l1 = 0.f;
    float O[4][4];
    #pragma unroll
    for (int n = 0; n < 4; n++)
        #pragma unroll
        for (int j = 0; j < 4; j++) O[n][j] = 0.f;

    const float scale = 0.088388347648318447f;

    for (int kt = 0; kt < 4; kt++) {
        if (kt < 3) CP_WAIT1(); else CP_WAIT0();
        __syncthreads();
        const __nv_bfloat16* s = sm + FL_ST0 + (kt & 1) * FL_STAGE;

        if (kt == 0) {
            #pragma unroll
            for (int kf = 0; kf < 2; kf++) {
                int row = warp * 16 + (lane & 15);
                int col = kf * 16 + (lane >> 4) * 8;
                LDMX4(qh_[kf], smem_u32(sm + FL_QH + row * LDS_ + col));
                LDMX4(ql_[kf], smem_u32(sm + FL_QL + row * LDS_ + col));
            }
        }

        float S[16][4];
        #pragma unroll
        for (int j = 0; j < 16; j++)
            #pragma unroll
            for (int r = 0; r < 4; r++) S[j][r] = 0.f;
        {
            int brow = ((lane >> 4) & 1) * 8 + (lane & 7);
            #pragma unroll
            for (int jp = 0; jp < 8; jp++) {
                #pragma unroll
                for (int kf = 0; kf < 2; kf++) {
                    uint32_t bh4[4], bl4[4];
                    int off = (jp * 16 + brow) * LDS_ + kf * 16 + ((lane >> 3) & 1) * 8;
                    LDMX4(bh4, smem_u32(s + FL_KH + off));
                    LDMX4(bl4, smem_u32(s + FL_KL + off));
                    MMA16816(S[2 * jp],     qh_[kf], bh4);
                    MMA16816(S[2 * jp],     ql_[kf], bh4);
                    MMA16816(S[2 * jp],     qh_[kf], bl4);
                    MMA16816(S[2 * jp + 1], qh_[kf], bh4 + 2);
                    MMA16816(S[2 * jp + 1], ql_[kf], bh4 + 2);
                    MMA16816(S[2 * jp + 1], qh_[kf], bl4 + 2);
                }
            }
        }
        float mx0 = -1e30f, mx1 = -1e30f;
        #pragma unroll
        for (int j = 0; j < 16; j++) {
            S[j][0] *= scale; S[j][1] *= scale; S[j][2] *= scale; S[j][3] *= scale;
            mx0 = fmaxf(mx0, fmaxf(S[j][0], S[j][1]));
            mx1 = fmaxf(mx1, fmaxf(S[j][2], S[j][3]));
        }
        #pragma unroll
        for (int o = 1; o < 4; o <<= 1) {
            mx0 = fmaxf(mx0, __shfl_xor_sync(0xffffffffu, mx0, o));
            mx1 = fmaxf(mx1, __shfl_xor_sync(0xffffffffu, mx1, o));
        }
        float nm0 = fmaxf(m0, mx0), nm1 = fmaxf(m1, mx1);
        float a0 = __expf(m0 - nm0), a1 = __expf(m1 - nm1);
        float rs0 = 0.f, rs1 = 0.f;
        #pragma unroll
        for (int j = 0; j < 16; j++) {
            S[j][0] = __expf(S[j][0] - nm0); S[j][1] = __expf(S[j][1] - nm0);
            S[j][2] = __expf(S[j][2] - nm1); S[j][3] = __expf(S[j][3] - nm1);
            rs0 += S[j][0] + S[j][1];
            rs1 += S[j][2] + S[j][3];
        }
        #pragma unroll
        for (int o = 1; o < 4; o <<= 1) {
            rs0 += __shfl_xor_sync(0xffffffffu, rs0, o);
            rs1 += __shfl_xor_sync(0xffffffffu, rs1, o);
        }
        l0 = l0 * a0 + rs0;
        l1 = l1 * a1 + rs1;
        #pragma unroll
        for (int n = 0; n < 4; n++) {
            O[n][0] *= a0; O[n][1] *= a0; O[n][2] *= a1; O[n][3] *= a1;
        }
        m0 = nm0; m1 = nm1;
        #pragma unroll
        for (int jp = 0; jp < 8; jp++) {
            uint32_t aph[4], apl[4];
            split2(S[2 * jp][0],     S[2 * jp][1],     aph[0], apl[0]);
            split2(S[2 * jp][2],     S[2 * jp][3],     aph[1], apl[1]);
            split2(S[2 * jp + 1][0], S[2 * jp + 1][1], aph[2], apl[2]);
            split2(S[2 * jp + 1][2], S[2 * jp + 1][3], aph[3], apl[3]);
            int vrow = jp * 16 + ((lane >> 3) & 1) * 8 + (lane & 7);
            #pragma unroll
            for (int np = 0; np < 2; np++) {
                uint32_t bh4[4], bl4[4];
                int off = vrow * LDS_ + (2 * np + ((lane >> 4) & 1)) * 8;
                LDMX4T(bh4, smem_u32(s + FL_VH + off));
                LDMX4T(bl4, smem_u32(s + FL_VL + off));
                MMA16816(O[2 * np],     aph, bh4);
                MMA16816(O[2 * np],     apl, bh4);
                MMA16816(O[2 * np],     aph, bl4);
                MMA16816(O[2 * np + 1], aph, bh4 + 2);
                MMA16816(O[2 * np + 1], apl, bh4 + 2);
                MMA16816(O[2 * np + 1], aph, bl4 + 2);
            }
        }
        __syncthreads();
        if (kt + 2 < 4) issue(kt + 2, kt & 1);
    }
    float il0 = 1.f / l0, il1 = 1.f / l1;
    int node = g * GS + qt * 128 + warp * 16 + (lane >> 2);
    #pragma unroll
    for (int n = 0; n < 4; n++) {
        int col = h * 32 + n * 8 + (lane & 3) * 2;
        uint32_t hh, ll;
        split2(O[n][0] * il0, O[n][1] * il0, hh, ll);
        *(uint32_t*)(OHo + (size_t)node * 128 + col) = hh;
        *(uint32_t*)(OLo + (size_t)node * 128 + col) = ll;
        split2(O[n][2] * il1, O[n][3] * il1, hh, ll);
        *(uint32_t*)(OHo + (size_t)(node + 8) * 128 + col) = hh;
        *(uint32_t*)(OLo + (size_t)(node + 8) * 128 + col) = ll;
    }
}

// ================= host orchestration =================
extern "C" void kernel_launch(void* const* d_in, const int* in_sizes, int n_in,
                              void* d_out, int out_size)
{
    const float* x   = (const float*)d_in[0];
    const int*   ei  = (const int*)  d_in[1];
    const float* W1  = (const float*)d_in[3];
    const float* a1s = (const float*)d_in[4];
    const float* a1d = (const float*)d_in[5];
    const float* b1  = (const float*)d_in[6];
    const float* W2  = (const float*)d_in[7];
    const float* a2s = (const float*)d_in[8];
    const float* a2d = (const float*)d_in[9];
    const float* b2  = (const float*)d_in[10];
    const float* W3  = (const float*)d_in[11];
    const float* a3s = (const float*)d_in[12];
    const float* a3d = (const float*)d_in[13];
    const float* b3  = (const float*)d_in[14];
    const float* g1  = (const float*)d_in[15];
    const float* be1 = (const float*)d_in[16];
    const float* g2  = (const float*)d_in[17];
    const float* be2 = (const float*)d_in[18];
    const float* Wr  = (const float*)d_in[19];
    const float* br  = (const float*)d_in[20];
    const float* Wq  = (const float*)d_in[21];
    const float* Wk  = (const float*)d_in[22];
    const float* Wv  = (const float*)d_in[23];
    const float* Wo  = (const float*)d_in[24];
    const float* bo  = (const float*)d_in[25];
    float* out = (float*)d_out;

    float* sb = nullptr;
    cudaGetSymbolAddress((void**)&sb, g_scratch);
    __nv_bfloat16* bb = nullptr;
    cudaGetSymbolAddress((void**)&bb, g_bf);
    cudaFuncSetAttribute(k_flash, cudaFuncAttributeMaxDynamicSharedMemorySize, FLASH_SMEM);
    cudaFuncSetAttribute(mma_gemm, cudaFuncAttributeMaxDynamicSharedMemorySize, GEMM_SMEM);
    cudaFuncSetAttribute(mma_gemm_qkv, cudaFuncAttributeMaxDynamicSharedMemorySize, GEMM_SMEM);

    float* p_h  = sb + OFF_H;
    float* p_h3 = sb + OFF_H3;
    float* p_r  = sb + OFF_R;
    float* p_es = sb + OFF_ES;
    float* p_ed = sb + OFF_ED;

    // CSR (scan2 folded into scan3)
    k_zero_cnt<<<NN / 256, 256>>>();
    k_count<<<1024, 256>>>(ei);
    k_scan1<<<256, 256>>>();
    k_scan3<<<256, 256>>>();
    k_fill<<<1152, 256>>>(ei);

    // all weight conversions in ONE launch
    k_cvt_weights<<<(WSEG4 + 255) / 256, 256>>>(W1, Wr, W2, W3, Wq, Wk, Wv, Wo, bb);

    // x -> bf16 hi/lo
    k_cvt_split<<<(NN*64/4 + 255)/256, 256>>>(x, bb + B_XH, bb + B_XL, NN*64/4);

    // layer 1 combo: h (+H=4 scores) AND residual p_r in one GEMM (N=384)
    mma_gemm<<<PERS, 256, GEMM_SMEM>>>(bb + B_XH, bb + B_XL, bb + B_W1RH, bb + B_W1RL,
                                    nullptr, p_h, nullptr, nullptr, p_r, br,
                                    a1s, a1d, p_es, p_ed, 3, NN, 384, 64);
    k_gat_agg<256, 4><<<NN / 8, 256>>>(p_h, p_es, p_ed, b1, g1, be1, nullptr,
                                       bb + B_TH, bb + B_TL);
    // layer 2 (fused H=4 scores)
    mma_gemm<<<PERS, 256, GEMM_SMEM>>>(bb + B_TH, bb + B_TL, bb + B_W2H, bb + B_W2L,
                                    nullptr, p_h, nullptr, nullptr, nullptr, nullptr,
                                    a2s, a2d, p_es, p_ed, 1, NN, 256, 256);
    k_gat_agg<256, 4><<<NN / 8, 256>>>(p_h, p_es, p_ed, b2, g2, be2, nullptr,
                                       bb + B_TH, bb + B_TL);
    // layer 3 (fused H=1 scores)
    mma_gemm<<<PERS, 256, GEMM_SMEM>>>(bb + B_TH, bb + B_TL, bb + B_W3H, bb + B_W3L,
                                    nullptr, p_h3, nullptr, nullptr, nullptr, nullptr,
                                    a3s, a3d, p_es, p_ed, 2, NN, 128, 256);
    k_gat_agg<128, 1><<<NN / 8, 256>>>(p_h3, p_es, p_ed, b3, nullptr, nullptr, p_r,
                                       bb + B_HRH, bb + B_HRL);
    // fused QKV projection
    mma_gemm_qkv<<<PERS, 256, GEMM_SMEM>>>(bb + B_HRH, bb + B_HRL,
                                        bb + B_WQKVH, bb + B_WQKVL,
                                        bb + B_QH, bb + B_QL,
                                        bb + B_KH, bb + B_KL,
                                        bb + B_VH, bb + B_VL);
    // fused attention
    k_flash<<<dim3(4, NG * 4), 256, FLASH_SMEM>>>(
        bb + B_QH, bb + B_QL, bb + B_KH, bb + B_KL,
        bb + B_VH, bb + B_VL, bb + B_AOH, bb + B_AOL);
    // output projection
    mma_gemm<<<PERS, 256, GEMM_SMEM>>>(bb + B_AOH, bb + B_AOL, bb + B_WOH, bb + B_WOL,
                                    bo, out, nullptr, nullptr, nullptr, nullptr,
                                    nullptr, nullptr, nullptr, nullptr, 0, NN, 128, 128);
}